// round 2
// baseline (speedup 1.0000x reference)
#include <cuda_runtime.h>
#include <math.h>

// ---------------- problem constants ----------------
#define BB      8
#define CC      320
#define HWP     1024
#define NHEADS  8
#define DHEAD   40
#define CTX     77
#define CTXD    768
#define FFI     1280          // FF_INNER
#define MROWS   (BB*HWP)      // 8192
#define NEGMAX  (-3.402823466e38f)

// ---------------- scratch (device globals; no runtime allocs) ----------------
__device__ float g_gn [MROWS*CC];
__device__ float g_h  [MROWS*CC];
__device__ float g_ln [MROWS*CC];
__device__ float g_q  [MROWS*CC];
__device__ float g_k  [MROWS*CC];
__device__ float g_v  [MROWS*CC];
__device__ float g_ao [MROWS*CC];
__device__ float g_ff1[MROWS*2*FFI];
__device__ float g_ffu[(size_t)MROWS*FFI];

// ---------------- block reductions ----------------
__device__ __forceinline__ float blockReduceSum(float v, float* scratch) {
    int lane = threadIdx.x & 31, wid = threadIdx.x >> 5;
    #pragma unroll
    for (int o = 16; o > 0; o >>= 1) v += __shfl_down_sync(0xffffffffu, v, o);
    if (lane == 0) scratch[wid] = v;
    __syncthreads();
    int nw = (blockDim.x + 31) >> 5;
    v = (threadIdx.x < nw) ? scratch[threadIdx.x] : 0.f;
    if (wid == 0) {
        #pragma unroll
        for (int o = 16; o > 0; o >>= 1) v += __shfl_down_sync(0xffffffffu, v, o);
        if (lane == 0) scratch[0] = v;
    }
    __syncthreads();
    v = scratch[0];
    __syncthreads();
    return v;
}

__device__ __forceinline__ float blockReduceMax(float v, float* scratch) {
    int lane = threadIdx.x & 31, wid = threadIdx.x >> 5;
    #pragma unroll
    for (int o = 16; o > 0; o >>= 1) v = fmaxf(v, __shfl_down_sync(0xffffffffu, v, o));
    if (lane == 0) scratch[wid] = v;
    __syncthreads();
    int nw = (blockDim.x + 31) >> 5;
    v = (threadIdx.x < nw) ? scratch[threadIdx.x] : NEGMAX;
    if (wid == 0) {
        #pragma unroll
        for (int o = 16; o > 0; o >>= 1) v = fmaxf(v, __shfl_down_sync(0xffffffffu, v, o));
        if (lane == 0) scratch[0] = v;
    }
    __syncthreads();
    v = scratch[0];
    __syncthreads();
    return v;
}

// ---------------- GroupNorm (32 groups of 10 channels) + transpose to [B,HW,C] ----------------
__global__ __launch_bounds__(256) void groupnorm_kernel(
    const float* __restrict__ x, const float* __restrict__ scale,
    const float* __restrict__ bias, float* __restrict__ out)
{
    __shared__ float scratch[32];
    __shared__ float s_mu, s_inv;
    int b = blockIdx.x >> 5, g = blockIdx.x & 31;
    const float* xp = x + ((size_t)b*CC + g*10) * HWP;
    float sum = 0.f, sq = 0.f;
    for (int i = threadIdx.x; i < 10*HWP; i += 256) { float v = xp[i]; sum += v; sq += v*v; }
    sum = blockReduceSum(sum, scratch);
    sq  = blockReduceSum(sq,  scratch);
    if (threadIdx.x == 0) {
        float mu  = sum * (1.f/10240.f);
        float var = sq * (1.f/10240.f) - mu*mu;
        s_mu = mu; s_inv = rsqrtf(var + 1e-6f);
    }
    __syncthreads();
    float mu = s_mu, inv = s_inv;
    for (int i = threadIdx.x; i < 10*HWP; i += 256) {
        int cl = i >> 10, p = i & 1023;
        int c = g*10 + cl;
        float xn = (xp[i] - mu) * inv;
        out[((size_t)b*HWP + p)*CC + c] = xn * scale[c] + bias[c];
    }
}

// ---------------- LayerNorm over last dim = 320 ----------------
__global__ __launch_bounds__(CC) void layernorm_kernel(
    const float* __restrict__ X, const float* __restrict__ s,
    const float* __restrict__ bpar, float* __restrict__ Y)
{
    __shared__ float scratch[32];
    int row = blockIdx.x, t = threadIdx.x;
    float v = X[(size_t)row*CC + t];
    float mu = blockReduceSum(v, scratch) * (1.f/CC);
    float d = v - mu;
    float var = blockReduceSum(d*d, scratch) * (1.f/CC);
    Y[(size_t)row*CC + t] = d * rsqrtf(var + 1e-5f) * s[t] + bpar[t];
}

// ---------------- tiled SGEMM: C = A[MxK] @ B[KxN] (+bias) (+res) ----------------
// mode 0: C[m*N+n] = acc + bias + res[m*N+n]
// mode 1: final projection: out[((m/1024)*CC + n)*HWP + m%1024] = acc + bias + res[same]
#define TBM 64
#define TBN 64
#define TBK 16
__global__ __launch_bounds__(256) void sgemm_kernel(
    const float* __restrict__ A, const float* __restrict__ B,
    const float* __restrict__ bias, const float* __restrict__ res,
    float* __restrict__ C, int M, int N, int K, int mode)
{
    __shared__ float As[TBK][TBM+1];
    __shared__ float Bs[TBK][TBN];
    int tid = threadIdx.x;
    int bm = blockIdx.y * TBM, bn = blockIdx.x * TBN;
    int ty = tid >> 4, tx = tid & 15;
    int ar = tid >> 2, ac = (tid & 3) << 2;
    int br = tid >> 4, bc = (tid & 15) << 2;
    float acc[4][4] = {};
    for (int k0 = 0; k0 < K; k0 += TBK) {
        float4 av = make_float4(0.f,0.f,0.f,0.f);
        if (bm + ar < M) av = *(const float4*)(A + (size_t)(bm+ar)*K + k0 + ac);
        As[ac+0][ar] = av.x; As[ac+1][ar] = av.y; As[ac+2][ar] = av.z; As[ac+3][ar] = av.w;
        float4 bv = *(const float4*)(B + (size_t)(k0+br)*N + bn + bc);
        *(float4*)&Bs[br][bc] = bv;
        __syncthreads();
        #pragma unroll
        for (int kk = 0; kk < TBK; kk++) {
            float a[4], b[4];
            #pragma unroll
            for (int i = 0; i < 4; i++) a[i] = As[kk][ty*4+i];
            #pragma unroll
            for (int j = 0; j < 4; j++) b[j] = Bs[kk][tx*4+j];
            #pragma unroll
            for (int i = 0; i < 4; i++)
                #pragma unroll
                for (int j = 0; j < 4; j++) acc[i][j] += a[i]*b[j];
        }
        __syncthreads();
    }
    #pragma unroll
    for (int i = 0; i < 4; i++) {
        int m = bm + ty*4 + i;
        if (m >= M) continue;
        #pragma unroll
        for (int j = 0; j < 4; j++) {
            int n = bn + tx*4 + j;
            if (n >= N) continue;
            float v = acc[i][j];
            if (bias) v += bias[n];
            if (mode == 0) {
                if (res) v += res[(size_t)m*N + n];
                C[(size_t)m*N + n] = v;
            } else {
                size_t idx = ((size_t)(m >> 10)*CC + n)*HWP + (m & 1023);
                C[idx] = v + res[idx];
            }
        }
    }
}

// ---------------- masked self-attention (keys = 1024) ----------------
// mask elements are 4-byte (int32 or float32): nonzero == true
#define QT 8
__global__ __launch_bounds__(320) void self_attn_kernel(
    const float* __restrict__ Q, const float* __restrict__ K,
    const float* __restrict__ V, const unsigned int* __restrict__ mask,
    float* __restrict__ O)
{
    __shared__ float sq[QT][DHEAD];
    __shared__ float sc[QT][HWP];
    __shared__ float red[8][QT][DHEAD];
    __shared__ float sred[32];
    __shared__ float sinv[QT];
    int b = blockIdx.z, h = blockIdx.y, q0 = blockIdx.x * QT;
    int tid = threadIdx.x;

    for (int i = tid; i < QT*DHEAD; i += 320) {
        int qi = i / DHEAD, d = i % DHEAD;
        sq[qi][d] = Q[((size_t)b*HWP + q0 + qi)*CC + h*DHEAD + d];
    }
    __syncthreads();

    const float scale = rsqrtf((float)DHEAD);
    for (int j = tid; j < HWP; j += 320) {
        float kreg[DHEAD];
        const float* kp = K + ((size_t)b*HWP + j)*CC + h*DHEAD;
        #pragma unroll
        for (int d = 0; d < DHEAD; d += 4) {
            float4 t = *(const float4*)(kp + d);
            kreg[d]=t.x; kreg[d+1]=t.y; kreg[d+2]=t.z; kreg[d+3]=t.w;
        }
        const unsigned int* mp = mask + ((size_t)b*HWP + q0)*HWP + j;
        #pragma unroll
        for (int qi = 0; qi < QT; qi++) {
            float s = 0.f;
            #pragma unroll
            for (int d = 0; d < DHEAD; d++) s += sq[qi][d]*kreg[d];
            sc[qi][j] = (mp[(size_t)qi*HWP] != 0u) ? s*scale : NEGMAX;
        }
    }
    __syncthreads();

    for (int qi = 0; qi < QT; qi++) {
        float mx = NEGMAX;
        for (int j = tid; j < HWP; j += 320) mx = fmaxf(mx, sc[qi][j]);
        mx = blockReduceMax(mx, sred);
        float sum = 0.f;
        for (int j = tid; j < HWP; j += 320) {
            float e = __expf(sc[qi][j] - mx);
            sc[qi][j] = e; sum += e;
        }
        sum = blockReduceSum(sum, sred);
        if (tid == 0) sinv[qi] = 1.f/sum;
    }
    __syncthreads();

    int d = tid % DHEAD, jg = tid / DHEAD;   // 8 j-groups
    float acc[QT] = {};
    for (int j = jg; j < HWP; j += 8) {
        float vv = V[((size_t)b*HWP + j)*CC + h*DHEAD + d];
        #pragma unroll
        for (int qi = 0; qi < QT; qi++) acc[qi] += sc[qi][j]*vv;
    }
    #pragma unroll
    for (int qi = 0; qi < QT; qi++) red[jg][qi][d] = acc[qi];
    __syncthreads();

    int qi = tid / DHEAD, dd = tid % DHEAD;  // 320 = 8*40
    float s = 0.f;
    #pragma unroll
    for (int g2 = 0; g2 < 8; g2++) s += red[g2][qi][dd];
    O[((size_t)b*HWP + q0 + qi)*CC + h*DHEAD + dd] = s * sinv[qi];
}

// ---------------- masked cross-attention (keys = 77, K/V resident in SMEM) ----------------
#define QT2 16
__global__ __launch_bounds__(256) void cross_attn_kernel(
    const float* __restrict__ Q, const float* __restrict__ Kc,
    const float* __restrict__ Vc, const unsigned int* __restrict__ mask,
    float* __restrict__ O)
{
    __shared__ float sk[CTX][DHEAD];
    __shared__ float sv[CTX][DHEAD];
    __shared__ float sq[QT2][DHEAD];
    __shared__ float sc[QT2][CTX+3];
    int b = blockIdx.z, h = blockIdx.y, q0 = blockIdx.x * QT2;
    int tid = threadIdx.x;

    for (int i = tid; i < CTX*DHEAD; i += 256) {
        int r = i / DHEAD, d = i % DHEAD;
        sk[r][d] = Kc[((size_t)b*CTX + r)*CC + h*DHEAD + d];
        sv[r][d] = Vc[((size_t)b*CTX + r)*CC + h*DHEAD + d];
    }
    for (int i = tid; i < QT2*DHEAD; i += 256) {
        int r = i / DHEAD, d = i % DHEAD;
        sq[r][d] = Q[((size_t)b*HWP + q0 + r)*CC + h*DHEAD + d];
    }
    __syncthreads();

    const float scale = rsqrtf((float)DHEAD);
    for (int idx = tid; idx < QT2*CTX; idx += 256) {
        int qi = idx / CTX, j = idx % CTX;
        float s = 0.f;
        #pragma unroll
        for (int d = 0; d < DHEAD; d++) s += sq[qi][d]*sk[j][d];
        unsigned int m = mask[((size_t)b*HWP + q0 + qi)*CTX + j];
        sc[qi][j] = (m != 0u) ? s*scale : NEGMAX;
    }
    __syncthreads();

    if (tid < QT2) {
        int qi = tid;
        float mx = NEGMAX;
        for (int j = 0; j < CTX; j++) mx = fmaxf(mx, sc[qi][j]);
        float sum = 0.f;
        for (int j = 0; j < CTX; j++) { float e = __expf(sc[qi][j]-mx); sc[qi][j] = e; sum += e; }
        float inv = 1.f/sum;
        for (int j = 0; j < CTX; j++) sc[qi][j] *= inv;
    }
    __syncthreads();

    for (int idx = tid; idx < QT2*DHEAD; idx += 256) {
        int qi = idx / DHEAD, d = idx % DHEAD;
        float s = 0.f;
        #pragma unroll
        for (int j = 0; j < CTX; j++) s += sc[qi][j]*sv[j][d];
        O[((size_t)b*HWP + q0 + qi)*CC + h*DHEAD + d] = s;
    }
}

// ---------------- GEGLU: u = a * gelu_exact(g) ----------------
__global__ __launch_bounds__(256) void geglu_kernel(
    const float* __restrict__ Y, float* __restrict__ U)
{
    size_t i = (size_t)blockIdx.x*256 + threadIdx.x;
    if (i >= (size_t)MROWS*FFI) return;
    size_t m = i / FFI, c = i % FFI;
    float a = Y[m*2*FFI + c];
    float g = Y[m*2*FFI + FFI + c];
    float ge = 0.5f * g * (1.f + erff(g * 0.70710678118654752f));
    U[i] = a * ge;
}

// ---------------- host orchestration ----------------
static inline void run_sgemm(const float* A, const float* B, const float* bias,
                             const float* res, float* C, int M, int N, int K, int mode)
{
    dim3 grid((N + TBN - 1)/TBN, (M + TBM - 1)/TBM);
    sgemm_kernel<<<grid, 256>>>(A, B, bias, res, C, M, N, K, mode);
}

extern "C" void kernel_launch(void* const* d_in, const int* in_sizes, int n_in,
                              void* d_out, int out_size)
{
    const float* x         = (const float*)d_in[0];
    const float* context   = (const float*)d_in[1];
    const unsigned int* vis_mask = (const unsigned int*)d_in[2];
    const unsigned int* v2t_mask = (const unsigned int*)d_in[3];
    const float* gn_scale  = (const float*)d_in[4];
    const float* gn_bias   = (const float*)d_in[5];
    const float* proj_in_w = (const float*)d_in[6];
    const float* proj_in_b = (const float*)d_in[7];
    const float* n1_s = (const float*)d_in[8];
    const float* n1_b = (const float*)d_in[9];
    const float* wq1  = (const float*)d_in[10];
    const float* wk1  = (const float*)d_in[11];
    const float* wv1  = (const float*)d_in[12];
    const float* wo1  = (const float*)d_in[13];
    const float* bo1  = (const float*)d_in[14];
    const float* n2_s = (const float*)d_in[15];
    const float* n2_b = (const float*)d_in[16];
    const float* wq2  = (const float*)d_in[17];
    const float* wk2  = (const float*)d_in[18];
    const float* wv2  = (const float*)d_in[19];
    const float* wo2  = (const float*)d_in[20];
    const float* bo2  = (const float*)d_in[21];
    const float* n3_s = (const float*)d_in[22];
    const float* n3_b = (const float*)d_in[23];
    const float* ff_w1 = (const float*)d_in[24];
    const float* ff_b1 = (const float*)d_in[25];
    const float* ff_w2 = (const float*)d_in[26];
    const float* ff_b2 = (const float*)d_in[27];
    const float* proj_out_w = (const float*)d_in[28];
    const float* proj_out_b = (const float*)d_in[29];
    float* out = (float*)d_out;

    float *gn, *h, *ln, *q, *k, *v, *ao, *ff1, *ffu;
    cudaGetSymbolAddress((void**)&gn,  g_gn);
    cudaGetSymbolAddress((void**)&h,   g_h);
    cudaGetSymbolAddress((void**)&ln,  g_ln);
    cudaGetSymbolAddress((void**)&q,   g_q);
    cudaGetSymbolAddress((void**)&k,   g_k);
    cudaGetSymbolAddress((void**)&v,   g_v);
    cudaGetSymbolAddress((void**)&ao,  g_ao);
    cudaGetSymbolAddress((void**)&ff1, g_ff1);
    cudaGetSymbolAddress((void**)&ffu, g_ffu);

    // 1. GroupNorm + transpose to [B, HW, C]
    groupnorm_kernel<<<BB*32, 256>>>(x, gn_scale, gn_bias, gn);
    // 2. proj_in
    run_sgemm(gn, proj_in_w, proj_in_b, nullptr, h, MROWS, CC, CC, 0);
    // 3. LN1
    layernorm_kernel<<<MROWS, CC>>>(h, n1_s, n1_b, ln);
    // 4-6. q,k,v (self)
    run_sgemm(ln, wq1, nullptr, nullptr, q, MROWS, CC, CC, 0);
    run_sgemm(ln, wk1, nullptr, nullptr, k, MROWS, CC, CC, 0);
    run_sgemm(ln, wv1, nullptr, nullptr, v, MROWS, CC, CC, 0);
    // 7. masked self-attention
    {
        dim3 grid(HWP/QT, NHEADS, BB);
        self_attn_kernel<<<grid, 320>>>(q, k, v, vis_mask, ao);
    }
    // 8. out-proj + residual
    run_sgemm(ao, wo1, bo1, h, h, MROWS, CC, CC, 0);
    // 9. LN2
    layernorm_kernel<<<MROWS, CC>>>(h, n2_s, n2_b, ln);
    // 10. q (cross)
    run_sgemm(ln, wq2, nullptr, nullptr, q, MROWS, CC, CC, 0);
    // 11-12. k,v from context
    run_sgemm(context, wk2, nullptr, nullptr, k, BB*CTX, CC, CTXD, 0);
    run_sgemm(context, wv2, nullptr, nullptr, v, BB*CTX, CC, CTXD, 0);
    // 13. masked cross-attention
    {
        dim3 grid(HWP/QT2, NHEADS, BB);
        cross_attn_kernel<<<grid, 256>>>(q, k, v, v2t_mask, ao);
    }
    // 14. out-proj + residual
    run_sgemm(ao, wo2, bo2, h, h, MROWS, CC, CC, 0);
    // 15. LN3
    layernorm_kernel<<<MROWS, CC>>>(h, n3_s, n3_b, ln);
    // 16. FF up (GEGLU input)
    run_sgemm(ln, ff_w1, ff_b1, nullptr, ff1, MROWS, 2*FFI, CC, 0);
    // 17. GEGLU
    {
        size_t n = (size_t)MROWS*FFI;
        geglu_kernel<<<(unsigned)((n + 255)/256), 256>>>(ff1, ffu);
    }
    // 18. FF down + residual
    run_sgemm(ffu, ff_w2, ff_b2, h, h, MROWS, CC, FFI, 0);
    // 19. proj_out + transpose back to [B,C,H,W] + input residual
    run_sgemm(h, proj_out_w, proj_out_b, x, out, MROWS, CC, CC, 1);
}

// round 3
// speedup vs baseline: 1.1307x; 1.1307x over previous
#include <cuda_runtime.h>
#include <math.h>
#include <stdint.h>

// ---------------- problem constants ----------------
#define BB      8
#define CC      320
#define HWP     1024
#define NHEADS  8
#define DHEAD   40
#define CTX     77
#define CTXD    768
#define FFI     1280          // FF_INNER
#define MROWS   (BB*HWP)      // 8192
#define NEGMAX  (-3.402823466e38f)

// ---------------- scratch (device globals; no runtime allocs) ----------------
__device__ float g_gn [MROWS*CC];
__device__ float g_h  [MROWS*CC];
__device__ float g_ln [MROWS*CC];
__device__ float g_q  [MROWS*CC];
__device__ float g_k  [MROWS*CC];
__device__ float g_v  [MROWS*CC];
__device__ float g_ao [MROWS*CC];
__device__ float g_ff1[MROWS*2*FFI];
__device__ float g_ffu[(size_t)MROWS*FFI];

// ---------------- block reductions ----------------
__device__ __forceinline__ float blockReduceSum(float v, float* scratch) {
    int lane = threadIdx.x & 31, wid = threadIdx.x >> 5;
    #pragma unroll
    for (int o = 16; o > 0; o >>= 1) v += __shfl_down_sync(0xffffffffu, v, o);
    if (lane == 0) scratch[wid] = v;
    __syncthreads();
    int nw = (blockDim.x + 31) >> 5;
    v = (threadIdx.x < nw) ? scratch[threadIdx.x] : 0.f;
    if (wid == 0) {
        #pragma unroll
        for (int o = 16; o > 0; o >>= 1) v += __shfl_down_sync(0xffffffffu, v, o);
        if (lane == 0) scratch[0] = v;
    }
    __syncthreads();
    v = scratch[0];
    __syncthreads();
    return v;
}

__device__ __forceinline__ float blockReduceMax(float v, float* scratch) {
    int lane = threadIdx.x & 31, wid = threadIdx.x >> 5;
    #pragma unroll
    for (int o = 16; o > 0; o >>= 1) v = fmaxf(v, __shfl_down_sync(0xffffffffu, v, o));
    if (lane == 0) scratch[wid] = v;
    __syncthreads();
    int nw = (blockDim.x + 31) >> 5;
    v = (threadIdx.x < nw) ? scratch[threadIdx.x] : NEGMAX;
    if (wid == 0) {
        #pragma unroll
        for (int o = 16; o > 0; o >>= 1) v = fmaxf(v, __shfl_down_sync(0xffffffffu, v, o));
        if (lane == 0) scratch[0] = v;
    }
    __syncthreads();
    v = scratch[0];
    __syncthreads();
    return v;
}

// ---------------- GroupNorm (32 groups of 10 channels) + transpose to [B,HW,C] ----------------
__global__ __launch_bounds__(256) void groupnorm_kernel(
    const float* __restrict__ x, const float* __restrict__ scale,
    const float* __restrict__ bias, float* __restrict__ out)
{
    __shared__ float scratch[32];
    __shared__ float s_mu, s_inv;
    int b = blockIdx.x >> 5, g = blockIdx.x & 31;
    const float* xp = x + ((size_t)b*CC + g*10) * HWP;
    float sum = 0.f, sq = 0.f;
    for (int i = threadIdx.x; i < 10*HWP; i += 256) { float v = xp[i]; sum += v; sq += v*v; }
    sum = blockReduceSum(sum, scratch);
    sq  = blockReduceSum(sq,  scratch);
    if (threadIdx.x == 0) {
        float mu  = sum * (1.f/10240.f);
        float var = sq * (1.f/10240.f) - mu*mu;
        s_mu = mu; s_inv = rsqrtf(var + 1e-6f);
    }
    __syncthreads();
    float mu = s_mu, inv = s_inv;
    for (int i = threadIdx.x; i < 10*HWP; i += 256) {
        int cl = i >> 10, p = i & 1023;
        int c = g*10 + cl;
        float xn = (xp[i] - mu) * inv;
        out[((size_t)b*HWP + p)*CC + c] = xn * scale[c] + bias[c];
    }
}

// ---------------- LayerNorm over last dim = 320 ----------------
__global__ __launch_bounds__(CC) void layernorm_kernel(
    const float* __restrict__ X, const float* __restrict__ s,
    const float* __restrict__ bpar, float* __restrict__ Y)
{
    __shared__ float scratch[32];
    int row = blockIdx.x, t = threadIdx.x;
    float v = X[(size_t)row*CC + t];
    float mu = blockReduceSum(v, scratch) * (1.f/CC);
    float d = v - mu;
    float var = blockReduceSum(d*d, scratch) * (1.f/CC);
    Y[(size_t)row*CC + t] = d * rsqrtf(var + 1e-5f) * s[t] + bpar[t];
}

// ---------------- tf32 tensor-core GEMM: C = A[MxK] @ B[KxN] (+bias) (+res) ----------------
// mode 0: C[m*N+n] = acc + bias + res[m*N+n]
// mode 1: final projection: out[((m/1024)*CC + n)*HWP + m%1024] = acc + bias + res[same]
// Requirements: N % 64 == 0, K % 32 == 0 (true for all call sites). M arbitrary.
#define GBM 128
#define GBN 64
#define GBK 32
#define A_PAD 40
#define B_PAD 72

__device__ __forceinline__ uint32_t f2tf32(float f) {
    uint32_t r;
    asm("cvt.rna.tf32.f32 %0, %1;" : "=r"(r) : "f"(f));
    return r;
}

__device__ __forceinline__ void mma_tf32(float c[4], uint32_t a0, uint32_t a1,
                                         uint32_t a2, uint32_t a3,
                                         uint32_t b0, uint32_t b1) {
    asm volatile(
        "mma.sync.aligned.m16n8k8.row.col.f32.tf32.tf32.f32 "
        "{%0,%1,%2,%3}, {%4,%5,%6,%7}, {%8,%9}, {%0,%1,%2,%3};"
        : "+f"(c[0]), "+f"(c[1]), "+f"(c[2]), "+f"(c[3])
        : "r"(a0), "r"(a1), "r"(a2), "r"(a3), "r"(b0), "r"(b1));
}

__global__ __launch_bounds__(256) void mma_gemm_kernel(
    const float* __restrict__ A, const float* __restrict__ B,
    const float* __restrict__ bias, const float* __restrict__ res,
    float* __restrict__ C, int M, int N, int K, int mode)
{
    __shared__ uint32_t As[GBM][A_PAD];   // [m][k], tf32 bits
    __shared__ uint32_t Bs[GBK][B_PAD];   // [k][n], tf32 bits

    int tid = threadIdx.x;
    int lane = tid & 31, warp = tid >> 5;
    int wm = warp & 1, wn = warp >> 1;            // 2 x 4 warp grid
    int m0 = blockIdx.y * GBM, n0 = blockIdx.x * GBN;

    float acc[4][2][4];
    #pragma unroll
    for (int i = 0; i < 4; i++)
        #pragma unroll
        for (int j = 0; j < 2; j++)
            #pragma unroll
            for (int c = 0; c < 4; c++) acc[i][j][c] = 0.f;

    int g = lane >> 2, tk = lane & 3;             // group-of-4 id, k-in-group

    for (int k0 = 0; k0 < K; k0 += GBK) {
        // load A tile 128x32 (4 float4 per thread)
        #pragma unroll
        for (int j = 0; j < 4; j++) {
            int i = tid + j*256;
            int row = i >> 3, kf = (i & 7) << 2;
            float4 v = make_float4(0.f,0.f,0.f,0.f);
            if (m0 + row < M)
                v = *(const float4*)(A + (size_t)(m0+row)*K + k0 + kf);
            uint4 t;
            t.x = f2tf32(v.x); t.y = f2tf32(v.y); t.z = f2tf32(v.z); t.w = f2tf32(v.w);
            *(uint4*)&As[row][kf] = t;
        }
        // load B tile 32x64 (2 float4 per thread)
        #pragma unroll
        for (int j = 0; j < 2; j++) {
            int i = tid + j*256;
            int row = i >> 4, nf = (i & 15) << 2;
            float4 v = *(const float4*)(B + (size_t)(k0+row)*N + n0 + nf);
            uint4 t;
            t.x = f2tf32(v.x); t.y = f2tf32(v.y); t.z = f2tf32(v.z); t.w = f2tf32(v.w);
            *(uint4*)&Bs[row][nf] = t;
        }
        __syncthreads();

        #pragma unroll
        for (int kk = 0; kk < 4; kk++) {
            int kc = (kk << 3) + tk;
            uint32_t a[4][4];
            #pragma unroll
            for (int mt = 0; mt < 4; mt++) {
                int r0 = wm*64 + mt*16 + g;
                a[mt][0] = As[r0][kc];
                a[mt][1] = As[r0+8][kc];
                a[mt][2] = As[r0][kc+4];
                a[mt][3] = As[r0+8][kc+4];
            }
            uint32_t b[2][2];
            #pragma unroll
            for (int nt = 0; nt < 2; nt++) {
                int col = wn*16 + nt*8 + g;
                b[nt][0] = Bs[kc][col];
                b[nt][1] = Bs[kc+4][col];
            }
            #pragma unroll
            for (int mt = 0; mt < 4; mt++)
                #pragma unroll
                for (int nt = 0; nt < 2; nt++)
                    mma_tf32(acc[mt][nt], a[mt][0], a[mt][1], a[mt][2], a[mt][3],
                             b[nt][0], b[nt][1]);
        }
        __syncthreads();
    }

    // epilogue
    #pragma unroll
    for (int mt = 0; mt < 4; mt++) {
        #pragma unroll
        for (int nt = 0; nt < 2; nt++) {
            int mbase = m0 + wm*64 + mt*16 + g;
            int nbase = n0 + wn*16 + nt*8 + (tk << 1);
            #pragma unroll
            for (int c = 0; c < 4; c++) {
                int m = mbase + ((c >> 1) << 3);   // +8 for c2,c3
                int n = nbase + (c & 1);           // +1 for c1,c3
                if (m >= M) continue;
                float v = acc[mt][nt][c];
                if (bias) v += bias[n];
                if (mode == 0) {
                    size_t idx = (size_t)m*N + n;
                    if (res) v += res[idx];
                    C[idx] = v;
                } else {
                    size_t idx = ((size_t)(m >> 10)*CC + n)*HWP + (m & 1023);
                    C[idx] = v + res[idx];
                }
            }
        }
    }
}

// ---------------- masked self-attention (keys = 1024) ----------------
// mask elements are 4-byte (int32 or float32): nonzero == true
#define QT 8
__global__ __launch_bounds__(320) void self_attn_kernel(
    const float* __restrict__ Q, const float* __restrict__ K,
    const float* __restrict__ V, const unsigned int* __restrict__ mask,
    float* __restrict__ O)
{
    __shared__ float sq[QT][DHEAD];
    __shared__ float sc[QT][HWP];
    __shared__ float red[8][QT][DHEAD];
    __shared__ float sred[32];
    __shared__ float sinv[QT];
    int b = blockIdx.z, h = blockIdx.y, q0 = blockIdx.x * QT;
    int tid = threadIdx.x;

    for (int i = tid; i < QT*DHEAD; i += 320) {
        int qi = i / DHEAD, d = i % DHEAD;
        sq[qi][d] = Q[((size_t)b*HWP + q0 + qi)*CC + h*DHEAD + d];
    }
    __syncthreads();

    const float scale = rsqrtf((float)DHEAD);
    for (int j = tid; j < HWP; j += 320) {
        float kreg[DHEAD];
        const float* kp = K + ((size_t)b*HWP + j)*CC + h*DHEAD;
        #pragma unroll
        for (int d = 0; d < DHEAD; d += 4) {
            float4 t = *(const float4*)(kp + d);
            kreg[d]=t.x; kreg[d+1]=t.y; kreg[d+2]=t.z; kreg[d+3]=t.w;
        }
        const unsigned int* mp = mask + ((size_t)b*HWP + q0)*HWP + j;
        #pragma unroll
        for (int qi = 0; qi < QT; qi++) {
            float s = 0.f;
            #pragma unroll
            for (int d = 0; d < DHEAD; d++) s += sq[qi][d]*kreg[d];
            sc[qi][j] = (mp[(size_t)qi*HWP] != 0u) ? s*scale : NEGMAX;
        }
    }
    __syncthreads();

    for (int qi = 0; qi < QT; qi++) {
        float mx = NEGMAX;
        for (int j = tid; j < HWP; j += 320) mx = fmaxf(mx, sc[qi][j]);
        mx = blockReduceMax(mx, sred);
        float sum = 0.f;
        for (int j = tid; j < HWP; j += 320) {
            float e = __expf(sc[qi][j] - mx);
            sc[qi][j] = e; sum += e;
        }
        sum = blockReduceSum(sum, sred);
        if (tid == 0) sinv[qi] = 1.f/sum;
    }
    __syncthreads();

    int d = tid % DHEAD, jg = tid / DHEAD;   // 8 j-groups
    float acc[QT] = {};
    for (int j = jg; j < HWP; j += 8) {
        float vv = V[((size_t)b*HWP + j)*CC + h*DHEAD + d];
        #pragma unroll
        for (int qi = 0; qi < QT; qi++) acc[qi] += sc[qi][j]*vv;
    }
    #pragma unroll
    for (int qi = 0; qi < QT; qi++) red[jg][qi][d] = acc[qi];
    __syncthreads();

    int qi = tid / DHEAD, dd = tid % DHEAD;  // 320 = 8*40
    float s = 0.f;
    #pragma unroll
    for (int g2 = 0; g2 < 8; g2++) s += red[g2][qi][dd];
    O[((size_t)b*HWP + q0 + qi)*CC + h*DHEAD + dd] = s * sinv[qi];
}

// ---------------- masked cross-attention (keys = 77, K/V resident in SMEM) ----------------
#define QT2 16
__global__ __launch_bounds__(256) void cross_attn_kernel(
    const float* __restrict__ Q, const float* __restrict__ Kc,
    const float* __restrict__ Vc, const unsigned int* __restrict__ mask,
    float* __restrict__ O)
{
    __shared__ float sk[CTX][DHEAD];
    __shared__ float sv[CTX][DHEAD];
    __shared__ float sq[QT2][DHEAD];
    __shared__ float sc[QT2][CTX+3];
    int b = blockIdx.z, h = blockIdx.y, q0 = blockIdx.x * QT2;
    int tid = threadIdx.x;

    for (int i = tid; i < CTX*DHEAD; i += 256) {
        int r = i / DHEAD, d = i % DHEAD;
        sk[r][d] = Kc[((size_t)b*CTX + r)*CC + h*DHEAD + d];
        sv[r][d] = Vc[((size_t)b*CTX + r)*CC + h*DHEAD + d];
    }
    for (int i = tid; i < QT2*DHEAD; i += 256) {
        int r = i / DHEAD, d = i % DHEAD;
        sq[r][d] = Q[((size_t)b*HWP + q0 + r)*CC + h*DHEAD + d];
    }
    __syncthreads();

    const float scale = rsqrtf((float)DHEAD);
    for (int idx = tid; idx < QT2*CTX; idx += 256) {
        int qi = idx / CTX, j = idx % CTX;
        float s = 0.f;
        #pragma unroll
        for (int d = 0; d < DHEAD; d++) s += sq[qi][d]*sk[j][d];
        unsigned int m = mask[((size_t)b*HWP + q0 + qi)*CTX + j];
        sc[qi][j] = (m != 0u) ? s*scale : NEGMAX;
    }
    __syncthreads();

    if (tid < QT2) {
        int qi = tid;
        float mx = NEGMAX;
        for (int j = 0; j < CTX; j++) mx = fmaxf(mx, sc[qi][j]);
        float sum = 0.f;
        for (int j = 0; j < CTX; j++) { float e = __expf(sc[qi][j]-mx); sc[qi][j] = e; sum += e; }
        float inv = 1.f/sum;
        for (int j = 0; j < CTX; j++) sc[qi][j] *= inv;
    }
    __syncthreads();

    for (int idx = tid; idx < QT2*DHEAD; idx += 256) {
        int qi = idx / DHEAD, d = idx % DHEAD;
        float s = 0.f;
        #pragma unroll
        for (int j = 0; j < CTX; j++) s += sc[qi][j]*sv[j][d];
        O[((size_t)b*HWP + q0 + qi)*CC + h*DHEAD + d] = s;
    }
}

// ---------------- GEGLU: u = a * gelu_exact(g) ----------------
__global__ __launch_bounds__(256) void geglu_kernel(
    const float* __restrict__ Y, float* __restrict__ U)
{
    size_t i = (size_t)blockIdx.x*256 + threadIdx.x;
    if (i >= (size_t)MROWS*FFI) return;
    size_t m = i / FFI, c = i % FFI;
    float a = Y[m*2*FFI + c];
    float g = Y[m*2*FFI + FFI + c];
    float ge = 0.5f * g * (1.f + erff(g * 0.70710678118654752f));
    U[i] = a * ge;
}

// ---------------- host orchestration ----------------
static inline void run_sgemm(const float* A, const float* B, const float* bias,
                             const float* res, float* C, int M, int N, int K, int mode)
{
    dim3 grid(N / GBN, (M + GBM - 1) / GBM);
    mma_gemm_kernel<<<grid, 256>>>(A, B, bias, res, C, M, N, K, mode);
}

extern "C" void kernel_launch(void* const* d_in, const int* in_sizes, int n_in,
                              void* d_out, int out_size)
{
    const float* x         = (const float*)d_in[0];
    const float* context   = (const float*)d_in[1];
    const unsigned int* vis_mask = (const unsigned int*)d_in[2];
    const unsigned int* v2t_mask = (const unsigned int*)d_in[3];
    const float* gn_scale  = (const float*)d_in[4];
    const float* gn_bias   = (const float*)d_in[5];
    const float* proj_in_w = (const float*)d_in[6];
    const float* proj_in_b = (const float*)d_in[7];
    const float* n1_s = (const float*)d_in[8];
    const float* n1_b = (const float*)d_in[9];
    const float* wq1  = (const float*)d_in[10];
    const float* wk1  = (const float*)d_in[11];
    const float* wv1  = (const float*)d_in[12];
    const float* wo1  = (const float*)d_in[13];
    const float* bo1  = (const float*)d_in[14];
    const float* n2_s = (const float*)d_in[15];
    const float* n2_b = (const float*)d_in[16];
    const float* wq2  = (const float*)d_in[17];
    const float* wk2  = (const float*)d_in[18];
    const float* wv2  = (const float*)d_in[19];
    const float* wo2  = (const float*)d_in[20];
    const float* bo2  = (const float*)d_in[21];
    const float* n3_s = (const float*)d_in[22];
    const float* n3_b = (const float*)d_in[23];
    const float* ff_w1 = (const float*)d_in[24];
    const float* ff_b1 = (const float*)d_in[25];
    const float* ff_w2 = (const float*)d_in[26];
    const float* ff_b2 = (const float*)d_in[27];
    const float* proj_out_w = (const float*)d_in[28];
    const float* proj_out_b = (const float*)d_in[29];
    float* out = (float*)d_out;

    float *gn, *h, *ln, *q, *k, *v, *ao, *ff1, *ffu;
    cudaGetSymbolAddress((void**)&gn,  g_gn);
    cudaGetSymbolAddress((void**)&h,   g_h);
    cudaGetSymbolAddress((void**)&ln,  g_ln);
    cudaGetSymbolAddress((void**)&q,   g_q);
    cudaGetSymbolAddress((void**)&k,   g_k);
    cudaGetSymbolAddress((void**)&v,   g_v);
    cudaGetSymbolAddress((void**)&ao,  g_ao);
    cudaGetSymbolAddress((void**)&ff1, g_ff1);
    cudaGetSymbolAddress((void**)&ffu, g_ffu);

    // 1. GroupNorm + transpose to [B, HW, C]
    groupnorm_kernel<<<BB*32, 256>>>(x, gn_scale, gn_bias, gn);
    // 2. proj_in
    run_sgemm(gn, proj_in_w, proj_in_b, nullptr, h, MROWS, CC, CC, 0);
    // 3. LN1
    layernorm_kernel<<<MROWS, CC>>>(h, n1_s, n1_b, ln);
    // 4-6. q,k,v (self)
    run_sgemm(ln, wq1, nullptr, nullptr, q, MROWS, CC, CC, 0);
    run_sgemm(ln, wk1, nullptr, nullptr, k, MROWS, CC, CC, 0);
    run_sgemm(ln, wv1, nullptr, nullptr, v, MROWS, CC, CC, 0);
    // 7. masked self-attention
    {
        dim3 grid(HWP/QT, NHEADS, BB);
        self_attn_kernel<<<grid, 320>>>(q, k, v, vis_mask, ao);
    }
    // 8. out-proj + residual
    run_sgemm(ao, wo1, bo1, h, h, MROWS, CC, CC, 0);
    // 9. LN2
    layernorm_kernel<<<MROWS, CC>>>(h, n2_s, n2_b, ln);
    // 10. q (cross)
    run_sgemm(ln, wq2, nullptr, nullptr, q, MROWS, CC, CC, 0);
    // 11-12. k,v from context
    run_sgemm(context, wk2, nullptr, nullptr, k, BB*CTX, CC, CTXD, 0);
    run_sgemm(context, wv2, nullptr, nullptr, v, BB*CTX, CC, CTXD, 0);
    // 13. masked cross-attention
    {
        dim3 grid(HWP/QT2, NHEADS, BB);
        cross_attn_kernel<<<grid, 256>>>(q, k, v, v2t_mask, ao);
    }
    // 14. out-proj + residual
    run_sgemm(ao, wo2, bo2, h, h, MROWS, CC, CC, 0);
    // 15. LN3
    layernorm_kernel<<<MROWS, CC>>>(h, n3_s, n3_b, ln);
    // 16. FF up (GEGLU input)
    run_sgemm(ln, ff_w1, ff_b1, nullptr, ff1, MROWS, 2*FFI, CC, 0);
    // 17. GEGLU
    {
        size_t n = (size_t)MROWS*FFI;
        geglu_kernel<<<(unsigned)((n + 255)/256), 256>>>(ff1, ffu);
    }
    // 18. FF down + residual
    run_sgemm(ffu, ff_w2, ff_b2, h, h, MROWS, CC, FFI, 0);
    // 19. proj_out + transpose back to [B,C,H,W] + input residual
    run_sgemm(h, proj_out_w, proj_out_b, x, out, MROWS, CC, CC, 1);
}

// round 4
// speedup vs baseline: 1.8674x; 1.6516x over previous
#include <cuda_runtime.h>
#include <math.h>
#include <stdint.h>

// ---------------- problem constants ----------------
#define BB      8
#define CC      320
#define HWP     1024
#define NHEADS  8
#define DHEAD   40
#define CTX     77
#define CTXD    768
#define FFI     1280          // FF_INNER
#define MROWS   (BB*HWP)      // 8192
#define NEGMAX  (-3.402823466e38f)

// ---------------- scratch (device globals; no runtime allocs) ----------------
__device__ float g_gn [MROWS*CC];
__device__ float g_h  [MROWS*CC];
__device__ float g_ln [MROWS*CC];
__device__ float g_q  [MROWS*CC];
__device__ float g_k  [MROWS*CC];
__device__ float g_v  [MROWS*CC];
__device__ float g_ao [MROWS*CC];
__device__ float g_ff1[MROWS*2*FFI];
__device__ float g_ffu[(size_t)MROWS*FFI];

// ---------------- block reductions ----------------
__device__ __forceinline__ float blockReduceSum(float v, float* scratch) {
    int lane = threadIdx.x & 31, wid = threadIdx.x >> 5;
    #pragma unroll
    for (int o = 16; o > 0; o >>= 1) v += __shfl_down_sync(0xffffffffu, v, o);
    if (lane == 0) scratch[wid] = v;
    __syncthreads();
    int nw = (blockDim.x + 31) >> 5;
    v = (threadIdx.x < nw) ? scratch[threadIdx.x] : 0.f;
    if (wid == 0) {
        #pragma unroll
        for (int o = 16; o > 0; o >>= 1) v += __shfl_down_sync(0xffffffffu, v, o);
        if (lane == 0) scratch[0] = v;
    }
    __syncthreads();
    v = scratch[0];
    __syncthreads();
    return v;
}

// ---------------- GroupNorm (32 groups of 10 channels) + transpose to [B,HW,C] ----------------
__global__ __launch_bounds__(256) void groupnorm_kernel(
    const float* __restrict__ x, const float* __restrict__ scale,
    const float* __restrict__ bias, float* __restrict__ out)
{
    __shared__ float scratch[32];
    __shared__ float s_mu, s_inv;
    int b = blockIdx.x >> 5, g = blockIdx.x & 31;
    const float* xp = x + ((size_t)b*CC + g*10) * HWP;
    float sum = 0.f, sq = 0.f;
    for (int i = threadIdx.x; i < 10*HWP; i += 256) { float v = xp[i]; sum += v; sq += v*v; }
    sum = blockReduceSum(sum, scratch);
    sq  = blockReduceSum(sq,  scratch);
    if (threadIdx.x == 0) {
        float mu  = sum * (1.f/10240.f);
        float var = sq * (1.f/10240.f) - mu*mu;
        s_mu = mu; s_inv = rsqrtf(var + 1e-6f);
    }
    __syncthreads();
    float mu = s_mu, inv = s_inv;
    for (int i = threadIdx.x; i < 10*HWP; i += 256) {
        int cl = i >> 10, p = i & 1023;
        int c = g*10 + cl;
        float xn = (xp[i] - mu) * inv;
        out[((size_t)b*HWP + p)*CC + c] = xn * scale[c] + bias[c];
    }
}

// ---------------- LayerNorm over last dim = 320 ----------------
__global__ __launch_bounds__(CC) void layernorm_kernel(
    const float* __restrict__ X, const float* __restrict__ s,
    const float* __restrict__ bpar, float* __restrict__ Y)
{
    __shared__ float scratch[32];
    int row = blockIdx.x, t = threadIdx.x;
    float v = X[(size_t)row*CC + t];
    float mu = blockReduceSum(v, scratch) * (1.f/CC);
    float d = v - mu;
    float var = blockReduceSum(d*d, scratch) * (1.f/CC);
    Y[(size_t)row*CC + t] = d * rsqrtf(var + 1e-5f) * s[t] + bpar[t];
}

// ---------------- tf32 helpers ----------------
__device__ __forceinline__ uint32_t f2tf32(float f) {
    uint32_t r;
    asm("cvt.rna.tf32.f32 %0, %1;" : "=r"(r) : "f"(f));
    return r;
}

__device__ __forceinline__ void mma_tf32(float c[4], uint32_t a0, uint32_t a1,
                                         uint32_t a2, uint32_t a3,
                                         uint32_t b0, uint32_t b1) {
    asm volatile(
        "mma.sync.aligned.m16n8k8.row.col.f32.tf32.tf32.f32 "
        "{%0,%1,%2,%3}, {%4,%5,%6,%7}, {%8,%9}, {%0,%1,%2,%3};"
        : "+f"(c[0]), "+f"(c[1]), "+f"(c[2]), "+f"(c[3])
        : "r"(a0), "r"(a1), "r"(a2), "r"(a3), "r"(b0), "r"(b1));
}

// ---------------- tf32 tensor-core GEMM: C = A[MxK] @ B[KxN] (+bias) (+res) ----------------
#define GBM 128
#define GBN 64
#define GBK 32
#define A_PAD 40
#define B_PAD 72

__global__ __launch_bounds__(256) void mma_gemm_kernel(
    const float* __restrict__ A, const float* __restrict__ B,
    const float* __restrict__ bias, const float* __restrict__ res,
    float* __restrict__ C, int M, int N, int K, int mode)
{
    __shared__ uint32_t As[GBM][A_PAD];   // [m][k], tf32 bits
    __shared__ uint32_t Bs[GBK][B_PAD];   // [k][n], tf32 bits

    int tid = threadIdx.x;
    int lane = tid & 31, warp = tid >> 5;
    int wm = warp & 1, wn = warp >> 1;            // 2 x 4 warp grid
    int m0 = blockIdx.y * GBM, n0 = blockIdx.x * GBN;

    float acc[4][2][4];
    #pragma unroll
    for (int i = 0; i < 4; i++)
        #pragma unroll
        for (int j = 0; j < 2; j++)
            #pragma unroll
            for (int c = 0; c < 4; c++) acc[i][j][c] = 0.f;

    int g = lane >> 2, tk = lane & 3;

    for (int k0 = 0; k0 < K; k0 += GBK) {
        #pragma unroll
        for (int j = 0; j < 4; j++) {
            int i = tid + j*256;
            int row = i >> 3, kf = (i & 7) << 2;
            float4 v = make_float4(0.f,0.f,0.f,0.f);
            if (m0 + row < M)
                v = *(const float4*)(A + (size_t)(m0+row)*K + k0 + kf);
            uint4 t;
            t.x = f2tf32(v.x); t.y = f2tf32(v.y); t.z = f2tf32(v.z); t.w = f2tf32(v.w);
            *(uint4*)&As[row][kf] = t;
        }
        #pragma unroll
        for (int j = 0; j < 2; j++) {
            int i = tid + j*256;
            int row = i >> 4, nf = (i & 15) << 2;
            float4 v = *(const float4*)(B + (size_t)(k0+row)*N + n0 + nf);
            uint4 t;
            t.x = f2tf32(v.x); t.y = f2tf32(v.y); t.z = f2tf32(v.z); t.w = f2tf32(v.w);
            *(uint4*)&Bs[row][nf] = t;
        }
        __syncthreads();

        #pragma unroll
        for (int kk = 0; kk < 4; kk++) {
            int kc = (kk << 3) + tk;
            uint32_t a[4][4];
            #pragma unroll
            for (int mt = 0; mt < 4; mt++) {
                int r0 = wm*64 + mt*16 + g;
                a[mt][0] = As[r0][kc];
                a[mt][1] = As[r0+8][kc];
                a[mt][2] = As[r0][kc+4];
                a[mt][3] = As[r0+8][kc+4];
            }
            uint32_t b[2][2];
            #pragma unroll
            for (int nt = 0; nt < 2; nt++) {
                int col = wn*16 + nt*8 + g;
                b[nt][0] = Bs[kc][col];
                b[nt][1] = Bs[kc+4][col];
            }
            #pragma unroll
            for (int mt = 0; mt < 4; mt++)
                #pragma unroll
                for (int nt = 0; nt < 2; nt++)
                    mma_tf32(acc[mt][nt], a[mt][0], a[mt][1], a[mt][2], a[mt][3],
                             b[nt][0], b[nt][1]);
        }
        __syncthreads();
    }

    #pragma unroll
    for (int mt = 0; mt < 4; mt++) {
        #pragma unroll
        for (int nt = 0; nt < 2; nt++) {
            int mbase = m0 + wm*64 + mt*16 + g;
            int nbase = n0 + wn*16 + nt*8 + (tk << 1);
            #pragma unroll
            for (int c = 0; c < 4; c++) {
                int m = mbase + ((c >> 1) << 3);
                int n = nbase + (c & 1);
                if (m >= M) continue;
                float v = acc[mt][nt][c];
                if (bias) v += bias[n];
                if (mode == 0) {
                    size_t idx = (size_t)m*N + n;
                    if (res) v += res[idx];
                    C[idx] = v;
                } else {
                    size_t idx = ((size_t)(m >> 10)*CC + n)*HWP + (m & 1023);
                    C[idx] = v + res[idx];
                }
            }
        }
    }
}

// ---------------- flash-style masked self-attention (tf32 MMA) ----------------
// Block: 64 queries x one (b,h). 256 threads = 8 warps in 4x2 grid:
//   wm (0..3): 16-row query band; wn (0..1): key/col half.
#define AT_TQ 64
#define AT_TK 64
#define KV_PAD 44
#define PS_PAD 68

__global__ __launch_bounds__(256) void self_attn_mma_kernel(
    const float* __restrict__ Q, const float* __restrict__ K,
    const float* __restrict__ V, const unsigned int* __restrict__ mask,
    float* __restrict__ O)
{
    __shared__ uint32_t Ks[AT_TK][KV_PAD];
    __shared__ uint32_t Vs[AT_TK][KV_PAD];
    __shared__ uint32_t Ps[AT_TQ][PS_PAD];   // Q staging, then P tiles, then O-combine
    __shared__ float sm_m[64], sm_l[64], sm_alpha[64];
    __shared__ float smx[2][64], ssum[2][64];

    int b = blockIdx.z, h = blockIdx.y, q0 = blockIdx.x * AT_TQ;
    int tid = threadIdx.x, lane = tid & 31, w = tid >> 5;
    int wm = w >> 1, wn = w & 1;
    int g = lane >> 2, tk = lane & 3;
    int r_lo = wm*16 + g, r_hi = r_lo + 8;

    const float scale = rsqrtf((float)DHEAD);

    // stage Q tile (scaled) into Ps as tf32
    for (int i = tid; i < AT_TQ*DHEAD; i += 256) {
        int r = i / DHEAD, c = i % DHEAD;
        Ps[r][c] = f2tf32(Q[((size_t)b*HWP + q0 + r)*CC + h*DHEAD + c] * scale);
    }
    if (tid < 64) { sm_m[tid] = NEGMAX; sm_l[tid] = 0.f; }
    __syncthreads();

    // register-resident Q fragments (rows wm*16..wm*16+15, all 40 k)
    uint32_t aq[5][4];
    #pragma unroll
    for (int kk = 0; kk < 5; kk++) {
        int kc = kk*8 + tk;
        aq[kk][0] = Ps[r_lo][kc];
        aq[kk][1] = Ps[r_hi][kc];
        aq[kk][2] = Ps[r_lo][kc+4];
        aq[kk][3] = Ps[r_hi][kc+4];
    }

    float o[5][4] = {};

    for (int jt = 0; jt < HWP/AT_TK; jt++) {
        __syncthreads();
        // load K,V tiles (tf32)
        for (int i = tid; i < AT_TK*DHEAD; i += 256) {
            int j = i / DHEAD, c = i % DHEAD;
            size_t base = ((size_t)b*HWP + jt*AT_TK + j)*CC + h*DHEAD + c;
            Ks[j][c] = f2tf32(K[base]);
            Vs[j][c] = f2tf32(V[base]);
        }
        __syncthreads();

        // S = Q K^T : warp's 16 x 32 band
        float s_[4][4] = {};
        #pragma unroll
        for (int kk = 0; kk < 5; kk++) {
            int kc = kk*8 + tk;
            #pragma unroll
            for (int nt = 0; nt < 4; nt++) {
                int jn = wn*32 + nt*8 + g;
                uint32_t b0 = Ks[jn][kc];
                uint32_t b1 = Ks[jn][kc+4];
                mma_tf32(s_[nt], aq[kk][0], aq[kk][1], aq[kk][2], aq[kk][3], b0, b1);
            }
        }

        // mask + per-thread partial row max
        const unsigned int* mlo_p = mask + ((size_t)b*HWP + q0 + r_lo)*HWP + (size_t)jt*AT_TK;
        const unsigned int* mhi_p = mask + ((size_t)b*HWP + q0 + r_hi)*HWP + (size_t)jt*AT_TK;
        float mlo = NEGMAX, mhi = NEGMAX;
        #pragma unroll
        for (int nt = 0; nt < 4; nt++) {
            int col = wn*32 + nt*8 + tk*2;
            uint2 m0 = *(const uint2*)(mlo_p + col);
            uint2 m1 = *(const uint2*)(mhi_p + col);
            s_[nt][0] = m0.x ? s_[nt][0] : NEGMAX;
            s_[nt][1] = m0.y ? s_[nt][1] : NEGMAX;
            s_[nt][2] = m1.x ? s_[nt][2] : NEGMAX;
            s_[nt][3] = m1.y ? s_[nt][3] : NEGMAX;
            mlo = fmaxf(mlo, fmaxf(s_[nt][0], s_[nt][1]));
            mhi = fmaxf(mhi, fmaxf(s_[nt][2], s_[nt][3]));
        }
        mlo = fmaxf(mlo, __shfl_xor_sync(0xffffffffu, mlo, 1));
        mlo = fmaxf(mlo, __shfl_xor_sync(0xffffffffu, mlo, 2));
        mhi = fmaxf(mhi, __shfl_xor_sync(0xffffffffu, mhi, 1));
        mhi = fmaxf(mhi, __shfl_xor_sync(0xffffffffu, mhi, 2));
        if (tk == 0) { smx[wn][r_lo] = mlo; smx[wn][r_hi] = mhi; }
        __syncthreads();

        if (tid < 64) {
            float mo = sm_m[tid];
            float mn = fmaxf(mo, fmaxf(smx[0][tid], smx[1][tid]));
            sm_m[tid] = mn;
            sm_alpha[tid] = __expf(mo - mn);
        }
        __syncthreads();

        // P = exp(S - m), write tf32 to Ps, accumulate row sums
        float mn_lo = sm_m[r_lo], mn_hi = sm_m[r_hi];
        float slo = 0.f, shi = 0.f;
        #pragma unroll
        for (int nt = 0; nt < 4; nt++) {
            int col = wn*32 + nt*8 + tk*2;
            float p0 = __expf(s_[nt][0] - mn_lo);
            float p1 = __expf(s_[nt][1] - mn_lo);
            float p2 = __expf(s_[nt][2] - mn_hi);
            float p3 = __expf(s_[nt][3] - mn_hi);
            slo += p0 + p1; shi += p2 + p3;
            uint2 wlo; wlo.x = f2tf32(p0); wlo.y = f2tf32(p1);
            uint2 whi; whi.x = f2tf32(p2); whi.y = f2tf32(p3);
            *(uint2*)&Ps[r_lo][col] = wlo;
            *(uint2*)&Ps[r_hi][col] = whi;
        }
        slo += __shfl_xor_sync(0xffffffffu, slo, 1);
        slo += __shfl_xor_sync(0xffffffffu, slo, 2);
        shi += __shfl_xor_sync(0xffffffffu, shi, 1);
        shi += __shfl_xor_sync(0xffffffffu, shi, 2);
        if (tk == 0) { ssum[wn][r_lo] = slo; ssum[wn][r_hi] = shi; }

        // rescale O accumulators
        float alo = sm_alpha[r_lo], ahi = sm_alpha[r_hi];
        #pragma unroll
        for (int nt = 0; nt < 5; nt++) {
            o[nt][0] *= alo; o[nt][1] *= alo;
            o[nt][2] *= ahi; o[nt][3] *= ahi;
        }
        __syncthreads();

        if (tid < 64)
            sm_l[tid] = sm_alpha[tid]*sm_l[tid] + ssum[0][tid] + ssum[1][tid];

        // O += P V : warp's k-half (wn), all 40 cols
        #pragma unroll
        for (int kk = 0; kk < 4; kk++) {
            int kb = wn*32 + kk*8;
            uint32_t a0 = Ps[r_lo][kb+tk];
            uint32_t a1 = Ps[r_hi][kb+tk];
            uint32_t a2 = Ps[r_lo][kb+4+tk];
            uint32_t a3 = Ps[r_hi][kb+4+tk];
            #pragma unroll
            for (int nt = 0; nt < 5; nt++) {
                uint32_t b0 = Vs[kb+tk][nt*8+g];
                uint32_t b1 = Vs[kb+4+tk][nt*8+g];
                mma_tf32(o[nt], a0, a1, a2, a3, b0, b1);
            }
        }
    }
    __syncthreads();

    // combine wn halves via Ps (as raw float bits), normalize, write out
    if (wn == 1) {
        #pragma unroll
        for (int nt = 0; nt < 5; nt++) {
            int c = nt*8 + tk*2;
            Ps[r_lo][c]   = __float_as_uint(o[nt][0]);
            Ps[r_lo][c+1] = __float_as_uint(o[nt][1]);
            Ps[r_hi][c]   = __float_as_uint(o[nt][2]);
            Ps[r_hi][c+1] = __float_as_uint(o[nt][3]);
        }
    }
    __syncthreads();
    if (wn == 0) {
        float il_lo = 1.f / sm_l[r_lo];
        float il_hi = 1.f / sm_l[r_hi];
        float* out_lo = O + ((size_t)b*HWP + q0 + r_lo)*CC + h*DHEAD;
        float* out_hi = O + ((size_t)b*HWP + q0 + r_hi)*CC + h*DHEAD;
        #pragma unroll
        for (int nt = 0; nt < 5; nt++) {
            int c = nt*8 + tk*2;
            out_lo[c]   = (o[nt][0] + __uint_as_float(Ps[r_lo][c]))   * il_lo;
            out_lo[c+1] = (o[nt][1] + __uint_as_float(Ps[r_lo][c+1])) * il_lo;
            out_hi[c]   = (o[nt][2] + __uint_as_float(Ps[r_hi][c]))   * il_hi;
            out_hi[c+1] = (o[nt][3] + __uint_as_float(Ps[r_hi][c+1])) * il_hi;
        }
    }
}

// ---------------- masked cross-attention (keys = 77, K/V resident in SMEM) ----------------
#define QT2 16
__global__ __launch_bounds__(256) void cross_attn_kernel(
    const float* __restrict__ Q, const float* __restrict__ Kc,
    const float* __restrict__ Vc, const unsigned int* __restrict__ mask,
    float* __restrict__ O)
{
    __shared__ float sk[CTX][DHEAD];
    __shared__ float sv[CTX][DHEAD];
    __shared__ float sq[QT2][DHEAD];
    __shared__ float sc[QT2][CTX+3];
    int b = blockIdx.z, h = blockIdx.y, q0 = blockIdx.x * QT2;
    int tid = threadIdx.x;

    for (int i = tid; i < CTX*DHEAD; i += 256) {
        int r = i / DHEAD, d = i % DHEAD;
        sk[r][d] = Kc[((size_t)b*CTX + r)*CC + h*DHEAD + d];
        sv[r][d] = Vc[((size_t)b*CTX + r)*CC + h*DHEAD + d];
    }
    for (int i = tid; i < QT2*DHEAD; i += 256) {
        int r = i / DHEAD, d = i % DHEAD;
        sq[r][d] = Q[((size_t)b*HWP + q0 + r)*CC + h*DHEAD + d];
    }
    __syncthreads();

    const float scale = rsqrtf((float)DHEAD);
    for (int idx = tid; idx < QT2*CTX; idx += 256) {
        int qi = idx / CTX, j = idx % CTX;
        float s = 0.f;
        #pragma unroll
        for (int d = 0; d < DHEAD; d++) s += sq[qi][d]*sk[j][d];
        unsigned int m = mask[((size_t)b*HWP + q0 + qi)*CTX + j];
        sc[qi][j] = (m != 0u) ? s*scale : NEGMAX;
    }
    __syncthreads();

    if (tid < QT2) {
        int qi = tid;
        float mx = NEGMAX;
        for (int j = 0; j < CTX; j++) mx = fmaxf(mx, sc[qi][j]);
        float sum = 0.f;
        for (int j = 0; j < CTX; j++) { float e = __expf(sc[qi][j]-mx); sc[qi][j] = e; sum += e; }
        float inv = 1.f/sum;
        for (int j = 0; j < CTX; j++) sc[qi][j] *= inv;
    }
    __syncthreads();

    for (int idx = tid; idx < QT2*DHEAD; idx += 256) {
        int qi = idx / DHEAD, d = idx % DHEAD;
        float s = 0.f;
        #pragma unroll
        for (int j = 0; j < CTX; j++) s += sc[qi][j]*sv[j][d];
        O[((size_t)b*HWP + q0 + qi)*CC + h*DHEAD + d] = s;
    }
}

// ---------------- GEGLU: u = a * gelu_exact(g) ----------------
__global__ __launch_bounds__(256) void geglu_kernel(
    const float* __restrict__ Y, float* __restrict__ U)
{
    size_t i = (size_t)blockIdx.x*256 + threadIdx.x;
    if (i >= (size_t)MROWS*FFI) return;
    size_t m = i / FFI, c = i % FFI;
    float a = Y[m*2*FFI + c];
    float g = Y[m*2*FFI + FFI + c];
    float ge = 0.5f * g * (1.f + erff(g * 0.70710678118654752f));
    U[i] = a * ge;
}

// ---------------- host orchestration ----------------
static inline void run_sgemm(const float* A, const float* B, const float* bias,
                             const float* res, float* C, int M, int N, int K, int mode)
{
    dim3 grid(N / GBN, (M + GBM - 1) / GBM);
    mma_gemm_kernel<<<grid, 256>>>(A, B, bias, res, C, M, N, K, mode);
}

extern "C" void kernel_launch(void* const* d_in, const int* in_sizes, int n_in,
                              void* d_out, int out_size)
{
    const float* x         = (const float*)d_in[0];
    const float* context   = (const float*)d_in[1];
    const unsigned int* vis_mask = (const unsigned int*)d_in[2];
    const unsigned int* v2t_mask = (const unsigned int*)d_in[3];
    const float* gn_scale  = (const float*)d_in[4];
    const float* gn_bias   = (const float*)d_in[5];
    const float* proj_in_w = (const float*)d_in[6];
    const float* proj_in_b = (const float*)d_in[7];
    const float* n1_s = (const float*)d_in[8];
    const float* n1_b = (const float*)d_in[9];
    const float* wq1  = (const float*)d_in[10];
    const float* wk1  = (const float*)d_in[11];
    const float* wv1  = (const float*)d_in[12];
    const float* wo1  = (const float*)d_in[13];
    const float* bo1  = (const float*)d_in[14];
    const float* n2_s = (const float*)d_in[15];
    const float* n2_b = (const float*)d_in[16];
    const float* wq2  = (const float*)d_in[17];
    const float* wk2  = (const float*)d_in[18];
    const float* wv2  = (const float*)d_in[19];
    const float* wo2  = (const float*)d_in[20];
    const float* bo2  = (const float*)d_in[21];
    const float* n3_s = (const float*)d_in[22];
    const float* n3_b = (const float*)d_in[23];
    const float* ff_w1 = (const float*)d_in[24];
    const float* ff_b1 = (const float*)d_in[25];
    const float* ff_w2 = (const float*)d_in[26];
    const float* ff_b2 = (const float*)d_in[27];
    const float* proj_out_w = (const float*)d_in[28];
    const float* proj_out_b = (const float*)d_in[29];
    float* out = (float*)d_out;

    float *gn, *h, *ln, *q, *k, *v, *ao, *ff1, *ffu;
    cudaGetSymbolAddress((void**)&gn,  g_gn);
    cudaGetSymbolAddress((void**)&h,   g_h);
    cudaGetSymbolAddress((void**)&ln,  g_ln);
    cudaGetSymbolAddress((void**)&q,   g_q);
    cudaGetSymbolAddress((void**)&k,   g_k);
    cudaGetSymbolAddress((void**)&v,   g_v);
    cudaGetSymbolAddress((void**)&ao,  g_ao);
    cudaGetSymbolAddress((void**)&ff1, g_ff1);
    cudaGetSymbolAddress((void**)&ffu, g_ffu);

    // 1. GroupNorm + transpose to [B, HW, C]
    groupnorm_kernel<<<BB*32, 256>>>(x, gn_scale, gn_bias, gn);
    // 2. proj_in
    run_sgemm(gn, proj_in_w, proj_in_b, nullptr, h, MROWS, CC, CC, 0);
    // 3. LN1
    layernorm_kernel<<<MROWS, CC>>>(h, n1_s, n1_b, ln);
    // 4-6. q,k,v (self)
    run_sgemm(ln, wq1, nullptr, nullptr, q, MROWS, CC, CC, 0);
    run_sgemm(ln, wk1, nullptr, nullptr, k, MROWS, CC, CC, 0);
    run_sgemm(ln, wv1, nullptr, nullptr, v, MROWS, CC, CC, 0);
    // 7. masked self-attention (flash tf32 MMA)
    {
        dim3 grid(HWP/AT_TQ, NHEADS, BB);
        self_attn_mma_kernel<<<grid, 256>>>(q, k, v, vis_mask, ao);
    }
    // 8. out-proj + residual
    run_sgemm(ao, wo1, bo1, h, h, MROWS, CC, CC, 0);
    // 9. LN2
    layernorm_kernel<<<MROWS, CC>>>(h, n2_s, n2_b, ln);
    // 10. q (cross)
    run_sgemm(ln, wq2, nullptr, nullptr, q, MROWS, CC, CC, 0);
    // 11-12. k,v from context
    run_sgemm(context, wk2, nullptr, nullptr, k, BB*CTX, CC, CTXD, 0);
    run_sgemm(context, wv2, nullptr, nullptr, v, BB*CTX, CC, CTXD, 0);
    // 13. masked cross-attention
    {
        dim3 grid(HWP/QT2, NHEADS, BB);
        cross_attn_kernel<<<grid, 256>>>(q, k, v, v2t_mask, ao);
    }
    // 14. out-proj + residual
    run_sgemm(ao, wo2, bo2, h, h, MROWS, CC, CC, 0);
    // 15. LN3
    layernorm_kernel<<<MROWS, CC>>>(h, n3_s, n3_b, ln);
    // 16. FF up (GEGLU input)
    run_sgemm(ln, ff_w1, ff_b1, nullptr, ff1, MROWS, 2*FFI, CC, 0);
    // 17. GEGLU
    {
        size_t n = (size_t)MROWS*FFI;
        geglu_kernel<<<(unsigned)((n + 255)/256), 256>>>(ff1, ffu);
    }
    // 18. FF down + residual
    run_sgemm(ffu, ff_w2, ff_b2, h, h, MROWS, CC, FFI, 0);
    // 19. proj_out + transpose back to [B,C,H,W] + input residual
    run_sgemm(h, proj_out_w, proj_out_b, x, out, MROWS, CC, CC, 1);
}

// round 5
// speedup vs baseline: 3.3636x; 1.8012x over previous
#include <cuda_runtime.h>
#include <math.h>
#include <stdint.h>

// ---------------- problem constants ----------------
#define BB      8
#define CC      320
#define HWP     1024
#define NHEADS  8
#define DHEAD   40
#define CTX     77
#define CTXD    768
#define FFI     1280          // FF_INNER
#define MROWS   (BB*HWP)      // 8192
#define NEGMAX  (-3.402823466e38f)

// ---------------- scratch (device globals; no runtime allocs) ----------------
__device__ float g_gn [MROWS*CC];
__device__ float g_h  [MROWS*CC];
__device__ float g_ln [MROWS*CC];
__device__ float g_q  [MROWS*CC];
__device__ float g_k  [MROWS*CC];
__device__ float g_v  [MROWS*CC];
__device__ float g_ao [MROWS*CC];
__device__ float g_ff1[MROWS*2*FFI];
__device__ float g_ffu[(size_t)MROWS*FFI];

// ---------------- block reductions ----------------
__device__ __forceinline__ float blockReduceSum(float v, float* scratch) {
    int lane = threadIdx.x & 31, wid = threadIdx.x >> 5;
    #pragma unroll
    for (int o = 16; o > 0; o >>= 1) v += __shfl_down_sync(0xffffffffu, v, o);
    if (lane == 0) scratch[wid] = v;
    __syncthreads();
    int nw = (blockDim.x + 31) >> 5;
    v = (threadIdx.x < nw) ? scratch[threadIdx.x] : 0.f;
    if (wid == 0) {
        #pragma unroll
        for (int o = 16; o > 0; o >>= 1) v += __shfl_down_sync(0xffffffffu, v, o);
        if (lane == 0) scratch[0] = v;
    }
    __syncthreads();
    v = scratch[0];
    __syncthreads();
    return v;
}

// ---------------- GroupNorm (32 groups of 10 channels) + transpose to [B,HW,C] ----------------
__global__ __launch_bounds__(256) void groupnorm_kernel(
    const float* __restrict__ x, const float* __restrict__ scale,
    const float* __restrict__ bias, float* __restrict__ out)
{
    __shared__ float scratch[32];
    __shared__ float s_mu, s_inv;
    int b = blockIdx.x >> 5, g = blockIdx.x & 31;
    const float* xp = x + ((size_t)b*CC + g*10) * HWP;
    float sum = 0.f, sq = 0.f;
    for (int i = threadIdx.x; i < 10*HWP; i += 256) { float v = xp[i]; sum += v; sq += v*v; }
    sum = blockReduceSum(sum, scratch);
    sq  = blockReduceSum(sq,  scratch);
    if (threadIdx.x == 0) {
        float mu  = sum * (1.f/10240.f);
        float var = sq * (1.f/10240.f) - mu*mu;
        s_mu = mu; s_inv = rsqrtf(var + 1e-6f);
    }
    __syncthreads();
    float mu = s_mu, inv = s_inv;
    for (int i = threadIdx.x; i < 10*HWP; i += 256) {
        int cl = i >> 10, p = i & 1023;
        int c = g*10 + cl;
        float xn = (xp[i] - mu) * inv;
        out[((size_t)b*HWP + p)*CC + c] = xn * scale[c] + bias[c];
    }
}

// ---------------- LayerNorm over last dim = 320 ----------------
__global__ __launch_bounds__(CC) void layernorm_kernel(
    const float* __restrict__ X, const float* __restrict__ s,
    const float* __restrict__ bpar, float* __restrict__ Y)
{
    __shared__ float scratch[32];
    int row = blockIdx.x, t = threadIdx.x;
    float v = X[(size_t)row*CC + t];
    float mu = blockReduceSum(v, scratch) * (1.f/CC);
    float d = v - mu;
    float var = blockReduceSum(d*d, scratch) * (1.f/CC);
    Y[(size_t)row*CC + t] = d * rsqrtf(var + 1e-5f) * s[t] + bpar[t];
}

// ---------------- tf32 mma (raw fp32 bits; HW truncates to tf32) ----------------
__device__ __forceinline__ void mma_tf32(float c[4], uint32_t a0, uint32_t a1,
                                         uint32_t a2, uint32_t a3,
                                         uint32_t b0, uint32_t b1) {
    asm volatile(
        "mma.sync.aligned.m16n8k8.row.col.f32.tf32.tf32.f32 "
        "{%0,%1,%2,%3}, {%4,%5,%6,%7}, {%8,%9}, {%0,%1,%2,%3};"
        : "+f"(c[0]), "+f"(c[1]), "+f"(c[2]), "+f"(c[3])
        : "r"(a0), "r"(a1), "r"(a2), "r"(a3), "r"(b0), "r"(b1));
}

__device__ __forceinline__ void cp_async16(void* smem_dst, const void* gsrc, int src_bytes) {
    uint32_t s = (uint32_t)__cvta_generic_to_shared(smem_dst);
    asm volatile("cp.async.cg.shared.global [%0], [%1], 16, %2;"
                 :: "r"(s), "l"(gsrc), "r"(src_bytes));
}
#define CP_COMMIT()  asm volatile("cp.async.commit_group;")
#define CP_WAIT0()   asm volatile("cp.async.wait_group 0;")

// ---------------- tf32 tensor-core GEMM (cp.async double-buffered) ----------------
// C = A[MxK] @ B[KxN] (+bias) (+res); N%64==0, K%32==0; M arbitrary.
#define GBM 128
#define GBN 64
#define GBK 32
#define A_PAD 40
#define B_PAD 72
#define GEMM_SMEM_BYTES ((2*(GBM*A_PAD + GBK*B_PAD))*4)

__global__ __launch_bounds__(256) void mma_gemm_kernel(
    const float* __restrict__ A, const float* __restrict__ B,
    const float* __restrict__ bias, const float* __restrict__ res,
    float* __restrict__ C, int M, int N, int K, int mode)
{
    extern __shared__ uint32_t dynsmem[];
    // layout: As[2][GBM][A_PAD] then Bs[2][GBK][B_PAD]
    uint32_t* AsBase = dynsmem;
    uint32_t* BsBase = dynsmem + 2*GBM*A_PAD;

    int tid = threadIdx.x;
    int lane = tid & 31, warp = tid >> 5;
    int wm = warp & 1, wn = warp >> 1;            // 2 x 4 warp grid
    int m0 = blockIdx.y * GBM, n0 = blockIdx.x * GBN;

    float acc[4][2][4];
    #pragma unroll
    for (int i = 0; i < 4; i++)
        #pragma unroll
        for (int j = 0; j < 2; j++)
            #pragma unroll
            for (int c = 0; c < 4; c++) acc[i][j][c] = 0.f;

    int g = lane >> 2, tk = lane & 3;

    // per-thread load coordinates
    int a_row = tid >> 3, a_kf = (tid & 7) << 2;     // + j*32 rows
    int b_row = tid >> 4, b_nf = (tid & 15) << 2;    // + j*16 rows

    int KT = K / GBK;

    // prefetch helper (macro-ish lambda)
    auto prefetch = [&](int kt, int buf) {
        uint32_t* As = AsBase + buf*GBM*A_PAD;
        uint32_t* Bs = BsBase + buf*GBK*B_PAD;
        int k0 = kt * GBK;
        #pragma unroll
        for (int j = 0; j < 4; j++) {
            int row = a_row + j*32;
            int gr = m0 + row;
            const float* src = A + ((gr < M) ? ((size_t)gr*K + k0 + a_kf) : 0);
            cp_async16(&As[row*A_PAD + a_kf], src, (gr < M) ? 16 : 0);
        }
        #pragma unroll
        for (int j = 0; j < 2; j++) {
            int row = b_row + j*16;
            cp_async16(&Bs[row*B_PAD + b_nf], B + (size_t)(k0+row)*N + n0 + b_nf, 16);
        }
        CP_COMMIT();
    };

    prefetch(0, 0);

    for (int kt = 0; kt < KT; kt++) {
        int buf = kt & 1;
        CP_WAIT0();
        __syncthreads();
        if (kt + 1 < KT) prefetch(kt+1, buf ^ 1);

        uint32_t* As = AsBase + buf*GBM*A_PAD;
        uint32_t* Bs = BsBase + buf*GBK*B_PAD;

        #pragma unroll
        for (int kk = 0; kk < 4; kk++) {
            int kc = (kk << 3) + tk;
            uint32_t a[4][4];
            #pragma unroll
            for (int mt = 0; mt < 4; mt++) {
                int r0 = wm*64 + mt*16 + g;
                a[mt][0] = As[r0*A_PAD + kc];
                a[mt][1] = As[(r0+8)*A_PAD + kc];
                a[mt][2] = As[r0*A_PAD + kc+4];
                a[mt][3] = As[(r0+8)*A_PAD + kc+4];
            }
            uint32_t b[2][2];
            #pragma unroll
            for (int nt = 0; nt < 2; nt++) {
                int col = wn*16 + nt*8 + g;
                b[nt][0] = Bs[kc*B_PAD + col];
                b[nt][1] = Bs[(kc+4)*B_PAD + col];
            }
            #pragma unroll
            for (int mt = 0; mt < 4; mt++)
                #pragma unroll
                for (int nt = 0; nt < 2; nt++)
                    mma_tf32(acc[mt][nt], a[mt][0], a[mt][1], a[mt][2], a[mt][3],
                             b[nt][0], b[nt][1]);
        }
        __syncthreads();
    }

    #pragma unroll
    for (int mt = 0; mt < 4; mt++) {
        #pragma unroll
        for (int nt = 0; nt < 2; nt++) {
            int mbase = m0 + wm*64 + mt*16 + g;
            int nbase = n0 + wn*16 + nt*8 + (tk << 1);
            #pragma unroll
            for (int c = 0; c < 4; c++) {
                int m = mbase + ((c >> 1) << 3);
                int n = nbase + (c & 1);
                if (m >= M) continue;
                float v = acc[mt][nt][c];
                if (bias) v += bias[n];
                if (mode == 0) {
                    size_t idx = (size_t)m*N + n;
                    if (res) v += res[idx];
                    C[idx] = v;
                } else {
                    size_t idx = ((size_t)(m >> 10)*CC + n)*HWP + (m & 1023);
                    C[idx] = v + res[idx];
                }
            }
        }
    }
}

// ---------------- flash-style masked self-attention (tf32 MMA, raw fp32 bits) ----------------
#define AT_TQ 64
#define AT_TK 64
#define KV_PAD 44
#define PS_PAD 68

__global__ __launch_bounds__(256) void self_attn_mma_kernel(
    const float* __restrict__ Q, const float* __restrict__ K,
    const float* __restrict__ V, const unsigned int* __restrict__ mask,
    float* __restrict__ O)
{
    __shared__ uint32_t Ks[AT_TK][KV_PAD];
    __shared__ uint32_t Vs[AT_TK][KV_PAD];
    __shared__ uint32_t Ps[AT_TQ][PS_PAD];
    __shared__ float sm_m[64], sm_l[64], sm_alpha[64];
    __shared__ float smx[2][64], ssum[2][64];

    int b = blockIdx.z, h = blockIdx.y, q0 = blockIdx.x * AT_TQ;
    int tid = threadIdx.x, lane = tid & 31, w = tid >> 5;
    int wm = w >> 1, wn = w & 1;
    int g = lane >> 2, tk = lane & 3;
    int r_lo = wm*16 + g, r_hi = r_lo + 8;

    const float scale = rsqrtf((float)DHEAD);

    for (int i = tid; i < AT_TQ*DHEAD; i += 256) {
        int r = i / DHEAD, c = i % DHEAD;
        Ps[r][c] = __float_as_uint(Q[((size_t)b*HWP + q0 + r)*CC + h*DHEAD + c] * scale);
    }
    if (tid < 64) { sm_m[tid] = NEGMAX; sm_l[tid] = 0.f; }
    __syncthreads();

    uint32_t aq[5][4];
    #pragma unroll
    for (int kk = 0; kk < 5; kk++) {
        int kc = kk*8 + tk;
        aq[kk][0] = Ps[r_lo][kc];
        aq[kk][1] = Ps[r_hi][kc];
        aq[kk][2] = Ps[r_lo][kc+4];
        aq[kk][3] = Ps[r_hi][kc+4];
    }

    float o[5][4] = {};

    for (int jt = 0; jt < HWP/AT_TK; jt++) {
        __syncthreads();
        for (int i = tid; i < AT_TK*DHEAD; i += 256) {
            int j = i / DHEAD, c = i % DHEAD;
            size_t base = ((size_t)b*HWP + jt*AT_TK + j)*CC + h*DHEAD + c;
            Ks[j][c] = __float_as_uint(K[base]);
            Vs[j][c] = __float_as_uint(V[base]);
        }
        __syncthreads();

        float s_[4][4] = {};
        #pragma unroll
        for (int kk = 0; kk < 5; kk++) {
            int kc = kk*8 + tk;
            #pragma unroll
            for (int nt = 0; nt < 4; nt++) {
                int jn = wn*32 + nt*8 + g;
                mma_tf32(s_[nt], aq[kk][0], aq[kk][1], aq[kk][2], aq[kk][3],
                         Ks[jn][kc], Ks[jn][kc+4]);
            }
        }

        const unsigned int* mlo_p = mask + ((size_t)b*HWP + q0 + r_lo)*HWP + (size_t)jt*AT_TK;
        const unsigned int* mhi_p = mask + ((size_t)b*HWP + q0 + r_hi)*HWP + (size_t)jt*AT_TK;
        float mlo = NEGMAX, mhi = NEGMAX;
        #pragma unroll
        for (int nt = 0; nt < 4; nt++) {
            int col = wn*32 + nt*8 + tk*2;
            uint2 m0 = *(const uint2*)(mlo_p + col);
            uint2 m1 = *(const uint2*)(mhi_p + col);
            s_[nt][0] = m0.x ? s_[nt][0] : NEGMAX;
            s_[nt][1] = m0.y ? s_[nt][1] : NEGMAX;
            s_[nt][2] = m1.x ? s_[nt][2] : NEGMAX;
            s_[nt][3] = m1.y ? s_[nt][3] : NEGMAX;
            mlo = fmaxf(mlo, fmaxf(s_[nt][0], s_[nt][1]));
            mhi = fmaxf(mhi, fmaxf(s_[nt][2], s_[nt][3]));
        }
        mlo = fmaxf(mlo, __shfl_xor_sync(0xffffffffu, mlo, 1));
        mlo = fmaxf(mlo, __shfl_xor_sync(0xffffffffu, mlo, 2));
        mhi = fmaxf(mhi, __shfl_xor_sync(0xffffffffu, mhi, 1));
        mhi = fmaxf(mhi, __shfl_xor_sync(0xffffffffu, mhi, 2));
        if (tk == 0) { smx[wn][r_lo] = mlo; smx[wn][r_hi] = mhi; }
        __syncthreads();

        if (tid < 64) {
            float mo = sm_m[tid];
            float mn = fmaxf(mo, fmaxf(smx[0][tid], smx[1][tid]));
            sm_m[tid] = mn;
            sm_alpha[tid] = __expf(mo - mn);
        }
        __syncthreads();

        float mn_lo = sm_m[r_lo], mn_hi = sm_m[r_hi];
        float slo = 0.f, shi = 0.f;
        #pragma unroll
        for (int nt = 0; nt < 4; nt++) {
            int col = wn*32 + nt*8 + tk*2;
            float p0 = __expf(s_[nt][0] - mn_lo);
            float p1 = __expf(s_[nt][1] - mn_lo);
            float p2 = __expf(s_[nt][2] - mn_hi);
            float p3 = __expf(s_[nt][3] - mn_hi);
            slo += p0 + p1; shi += p2 + p3;
            uint2 wlo; wlo.x = __float_as_uint(p0); wlo.y = __float_as_uint(p1);
            uint2 whi; whi.x = __float_as_uint(p2); whi.y = __float_as_uint(p3);
            *(uint2*)&Ps[r_lo][col] = wlo;
            *(uint2*)&Ps[r_hi][col] = whi;
        }
        slo += __shfl_xor_sync(0xffffffffu, slo, 1);
        slo += __shfl_xor_sync(0xffffffffu, slo, 2);
        shi += __shfl_xor_sync(0xffffffffu, shi, 1);
        shi += __shfl_xor_sync(0xffffffffu, shi, 2);
        if (tk == 0) { ssum[wn][r_lo] = slo; ssum[wn][r_hi] = shi; }

        float alo = sm_alpha[r_lo], ahi = sm_alpha[r_hi];
        #pragma unroll
        for (int nt = 0; nt < 5; nt++) {
            o[nt][0] *= alo; o[nt][1] *= alo;
            o[nt][2] *= ahi; o[nt][3] *= ahi;
        }
        __syncthreads();

        if (tid < 64)
            sm_l[tid] = sm_alpha[tid]*sm_l[tid] + ssum[0][tid] + ssum[1][tid];

        #pragma unroll
        for (int kk = 0; kk < 4; kk++) {
            int kb = wn*32 + kk*8;
            uint32_t a0 = Ps[r_lo][kb+tk];
            uint32_t a1 = Ps[r_hi][kb+tk];
            uint32_t a2 = Ps[r_lo][kb+4+tk];
            uint32_t a3 = Ps[r_hi][kb+4+tk];
            #pragma unroll
            for (int nt = 0; nt < 5; nt++) {
                mma_tf32(o[nt], a0, a1, a2, a3,
                         Vs[kb+tk][nt*8+g], Vs[kb+4+tk][nt*8+g]);
            }
        }
    }
    __syncthreads();

    if (wn == 1) {
        #pragma unroll
        for (int nt = 0; nt < 5; nt++) {
            int c = nt*8 + tk*2;
            Ps[r_lo][c]   = __float_as_uint(o[nt][0]);
            Ps[r_lo][c+1] = __float_as_uint(o[nt][1]);
            Ps[r_hi][c]   = __float_as_uint(o[nt][2]);
            Ps[r_hi][c+1] = __float_as_uint(o[nt][3]);
        }
    }
    __syncthreads();
    if (wn == 0) {
        float il_lo = 1.f / sm_l[r_lo];
        float il_hi = 1.f / sm_l[r_hi];
        float* out_lo = O + ((size_t)b*HWP + q0 + r_lo)*CC + h*DHEAD;
        float* out_hi = O + ((size_t)b*HWP + q0 + r_hi)*CC + h*DHEAD;
        #pragma unroll
        for (int nt = 0; nt < 5; nt++) {
            int c = nt*8 + tk*2;
            out_lo[c]   = (o[nt][0] + __uint_as_float(Ps[r_lo][c]))   * il_lo;
            out_lo[c+1] = (o[nt][1] + __uint_as_float(Ps[r_lo][c+1])) * il_lo;
            out_hi[c]   = (o[nt][2] + __uint_as_float(Ps[r_hi][c]))   * il_hi;
            out_hi[c+1] = (o[nt][3] + __uint_as_float(Ps[r_hi][c+1])) * il_hi;
        }
    }
}

// ---------------- masked cross-attention (keys = 77, K/V resident in SMEM) ----------------
#define QT2 16
__global__ __launch_bounds__(256) void cross_attn_kernel(
    const float* __restrict__ Q, const float* __restrict__ Kc,
    const float* __restrict__ Vc, const unsigned int* __restrict__ mask,
    float* __restrict__ O)
{
    __shared__ float sk[CTX][DHEAD];
    __shared__ float sv[CTX][DHEAD];
    __shared__ float sq[QT2][DHEAD];
    __shared__ float sc[QT2][CTX+3];
    int b = blockIdx.z, h = blockIdx.y, q0 = blockIdx.x * QT2;
    int tid = threadIdx.x;

    for (int i = tid; i < CTX*DHEAD; i += 256) {
        int r = i / DHEAD, d = i % DHEAD;
        sk[r][d] = Kc[((size_t)b*CTX + r)*CC + h*DHEAD + d];
        sv[r][d] = Vc[((size_t)b*CTX + r)*CC + h*DHEAD + d];
    }
    for (int i = tid; i < QT2*DHEAD; i += 256) {
        int r = i / DHEAD, d = i % DHEAD;
        sq[r][d] = Q[((size_t)b*HWP + q0 + r)*CC + h*DHEAD + d];
    }
    __syncthreads();

    const float scale = rsqrtf((float)DHEAD);
    for (int idx = tid; idx < QT2*CTX; idx += 256) {
        int qi = idx / CTX, j = idx % CTX;
        float s = 0.f;
        #pragma unroll
        for (int d = 0; d < DHEAD; d++) s += sq[qi][d]*sk[j][d];
        unsigned int m = mask[((size_t)b*HWP + q0 + qi)*CTX + j];
        sc[qi][j] = (m != 0u) ? s*scale : NEGMAX;
    }
    __syncthreads();

    if (tid < QT2) {
        int qi = tid;
        float mx = NEGMAX;
        for (int j = 0; j < CTX; j++) mx = fmaxf(mx, sc[qi][j]);
        float sum = 0.f;
        for (int j = 0; j < CTX; j++) { float e = __expf(sc[qi][j]-mx); sc[qi][j] = e; sum += e; }
        float inv = 1.f/sum;
        for (int j = 0; j < CTX; j++) sc[qi][j] *= inv;
    }
    __syncthreads();

    for (int idx = tid; idx < QT2*DHEAD; idx += 256) {
        int qi = idx / DHEAD, d = idx % DHEAD;
        float s = 0.f;
        #pragma unroll
        for (int j = 0; j < CTX; j++) s += sc[qi][j]*sv[j][d];
        O[((size_t)b*HWP + q0 + qi)*CC + h*DHEAD + d] = s;
    }
}

// ---------------- GEGLU: u = a * gelu_exact(g) ----------------
__global__ __launch_bounds__(256) void geglu_kernel(
    const float* __restrict__ Y, float* __restrict__ U)
{
    size_t i = (size_t)blockIdx.x*256 + threadIdx.x;
    if (i >= (size_t)MROWS*FFI) return;
    size_t m = i / FFI, c = i % FFI;
    float a = Y[m*2*FFI + c];
    float g = Y[m*2*FFI + FFI + c];
    float ge = 0.5f * g * (1.f + erff(g * 0.70710678118654752f));
    U[i] = a * ge;
}

// ---------------- host orchestration ----------------
static inline void run_sgemm(const float* A, const float* B, const float* bias,
                             const float* res, float* C, int M, int N, int K, int mode)
{
    dim3 grid(N / GBN, (M + GBM - 1) / GBM);
    mma_gemm_kernel<<<grid, 256, GEMM_SMEM_BYTES>>>(A, B, bias, res, C, M, N, K, mode);
}

extern "C" void kernel_launch(void* const* d_in, const int* in_sizes, int n_in,
                              void* d_out, int out_size)
{
    const float* x         = (const float*)d_in[0];
    const float* context   = (const float*)d_in[1];
    const unsigned int* vis_mask = (const unsigned int*)d_in[2];
    const unsigned int* v2t_mask = (const unsigned int*)d_in[3];
    const float* gn_scale  = (const float*)d_in[4];
    const float* gn_bias   = (const float*)d_in[5];
    const float* proj_in_w = (const float*)d_in[6];
    const float* proj_in_b = (const float*)d_in[7];
    const float* n1_s = (const float*)d_in[8];
    const float* n1_b = (const float*)d_in[9];
    const float* wq1  = (const float*)d_in[10];
    const float* wk1  = (const float*)d_in[11];
    const float* wv1  = (const float*)d_in[12];
    const float* wo1  = (const float*)d_in[13];
    const float* bo1  = (const float*)d_in[14];
    const float* n2_s = (const float*)d_in[15];
    const float* n2_b = (const float*)d_in[16];
    const float* wq2  = (const float*)d_in[17];
    const float* wk2  = (const float*)d_in[18];
    const float* wv2  = (const float*)d_in[19];
    const float* wo2  = (const float*)d_in[20];
    const float* bo2  = (const float*)d_in[21];
    const float* n3_s = (const float*)d_in[22];
    const float* n3_b = (const float*)d_in[23];
    const float* ff_w1 = (const float*)d_in[24];
    const float* ff_b1 = (const float*)d_in[25];
    const float* ff_w2 = (const float*)d_in[26];
    const float* ff_b2 = (const float*)d_in[27];
    const float* proj_out_w = (const float*)d_in[28];
    const float* proj_out_b = (const float*)d_in[29];
    float* out = (float*)d_out;

    cudaFuncSetAttribute(mma_gemm_kernel,
                         cudaFuncAttributeMaxDynamicSharedMemorySize, GEMM_SMEM_BYTES);

    float *gn, *h, *ln, *q, *k, *v, *ao, *ff1, *ffu;
    cudaGetSymbolAddress((void**)&gn,  g_gn);
    cudaGetSymbolAddress((void**)&h,   g_h);
    cudaGetSymbolAddress((void**)&ln,  g_ln);
    cudaGetSymbolAddress((void**)&q,   g_q);
    cudaGetSymbolAddress((void**)&k,   g_k);
    cudaGetSymbolAddress((void**)&v,   g_v);
    cudaGetSymbolAddress((void**)&ao,  g_ao);
    cudaGetSymbolAddress((void**)&ff1, g_ff1);
    cudaGetSymbolAddress((void**)&ffu, g_ffu);

    // 1. GroupNorm + transpose to [B, HW, C]
    groupnorm_kernel<<<BB*32, 256>>>(x, gn_scale, gn_bias, gn);
    // 2. proj_in
    run_sgemm(gn, proj_in_w, proj_in_b, nullptr, h, MROWS, CC, CC, 0);
    // 3. LN1
    layernorm_kernel<<<MROWS, CC>>>(h, n1_s, n1_b, ln);
    // 4-6. q,k,v (self)
    run_sgemm(ln, wq1, nullptr, nullptr, q, MROWS, CC, CC, 0);
    run_sgemm(ln, wk1, nullptr, nullptr, k, MROWS, CC, CC, 0);
    run_sgemm(ln, wv1, nullptr, nullptr, v, MROWS, CC, CC, 0);
    // 7. masked self-attention (flash tf32 MMA)
    {
        dim3 grid(HWP/AT_TQ, NHEADS, BB);
        self_attn_mma_kernel<<<grid, 256>>>(q, k, v, vis_mask, ao);
    }
    // 8. out-proj + residual
    run_sgemm(ao, wo1, bo1, h, h, MROWS, CC, CC, 0);
    // 9. LN2
    layernorm_kernel<<<MROWS, CC>>>(h, n2_s, n2_b, ln);
    // 10. q (cross)
    run_sgemm(ln, wq2, nullptr, nullptr, q, MROWS, CC, CC, 0);
    // 11-12. k,v from context
    run_sgemm(context, wk2, nullptr, nullptr, k, BB*CTX, CC, CTXD, 0);
    run_sgemm(context, wv2, nullptr, nullptr, v, BB*CTX, CC, CTXD, 0);
    // 13. masked cross-attention
    {
        dim3 grid(HWP/QT2, NHEADS, BB);
        cross_attn_kernel<<<grid, 256>>>(q, k, v, v2t_mask, ao);
    }
    // 14. out-proj + residual
    run_sgemm(ao, wo2, bo2, h, h, MROWS, CC, CC, 0);
    // 15. LN3
    layernorm_kernel<<<MROWS, CC>>>(h, n3_s, n3_b, ln);
    // 16. FF up (GEGLU input)
    run_sgemm(ln, ff_w1, ff_b1, nullptr, ff1, MROWS, 2*FFI, CC, 0);
    // 17. GEGLU
    {
        size_t n = (size_t)MROWS*FFI;
        geglu_kernel<<<(unsigned)((n + 255)/256), 256>>>(ff1, ffu);
    }
    // 18. FF down + residual
    run_sgemm(ffu, ff_w2, ff_b2, h, h, MROWS, CC, FFI, 0);
    // 19. proj_out + transpose back to [B,C,H,W] + input residual
    run_sgemm(h, proj_out_w, proj_out_b, x, out, MROWS, CC, CC, 1);
}

// round 6
// speedup vs baseline: 3.4273x; 1.0189x over previous
#include <cuda_runtime.h>
#include <math.h>
#include <stdint.h>

// ---------------- problem constants ----------------
#define BB      8
#define CC      320
#define HWP     1024
#define NHEADS  8
#define DHEAD   40
#define CTX     77
#define CTXD    768
#define FFI     1280          // FF_INNER
#define MROWS   (BB*HWP)      // 8192
#define NEGMAX  (-3.402823466e38f)

// ---------------- scratch (device globals; no runtime allocs) ----------------
__device__ float g_gn [MROWS*CC];
__device__ float g_h  [MROWS*CC];
__device__ float g_ln [MROWS*CC];
__device__ float g_q  [MROWS*CC];
__device__ float g_k  [MROWS*CC];
__device__ float g_v  [MROWS*CC];
__device__ float g_ao [MROWS*CC];
__device__ float g_ff1[MROWS*2*FFI];
__device__ float g_ffu[(size_t)MROWS*FFI];

// ---------------- block reductions ----------------
__device__ __forceinline__ float blockReduceSum(float v, float* scratch) {
    int lane = threadIdx.x & 31, wid = threadIdx.x >> 5;
    #pragma unroll
    for (int o = 16; o > 0; o >>= 1) v += __shfl_down_sync(0xffffffffu, v, o);
    if (lane == 0) scratch[wid] = v;
    __syncthreads();
    int nw = (blockDim.x + 31) >> 5;
    v = (threadIdx.x < nw) ? scratch[threadIdx.x] : 0.f;
    if (wid == 0) {
        #pragma unroll
        for (int o = 16; o > 0; o >>= 1) v += __shfl_down_sync(0xffffffffu, v, o);
        if (lane == 0) scratch[0] = v;
    }
    __syncthreads();
    v = scratch[0];
    __syncthreads();
    return v;
}

// ---------------- GroupNorm (32 groups of 10 channels) + transpose to [B,HW,C] ----------------
__global__ __launch_bounds__(256) void groupnorm_kernel(
    const float* __restrict__ x, const float* __restrict__ scale,
    const float* __restrict__ bias, float* __restrict__ out)
{
    __shared__ float scratch[32];
    __shared__ float s_mu, s_inv;
    int b = blockIdx.x >> 5, g = blockIdx.x & 31;
    const float* xp = x + ((size_t)b*CC + g*10) * HWP;
    float sum = 0.f, sq = 0.f;
    for (int i = threadIdx.x; i < 10*HWP; i += 256) { float v = xp[i]; sum += v; sq += v*v; }
    sum = blockReduceSum(sum, scratch);
    sq  = blockReduceSum(sq,  scratch);
    if (threadIdx.x == 0) {
        float mu  = sum * (1.f/10240.f);
        float var = sq * (1.f/10240.f) - mu*mu;
        s_mu = mu; s_inv = rsqrtf(var + 1e-6f);
    }
    __syncthreads();
    float mu = s_mu, inv = s_inv;
    for (int i = threadIdx.x; i < 10*HWP; i += 256) {
        int cl = i >> 10, p = i & 1023;
        int c = g*10 + cl;
        float xn = (xp[i] - mu) * inv;
        out[((size_t)b*HWP + p)*CC + c] = xn * scale[c] + bias[c];
    }
}

// ---------------- LayerNorm over last dim = 320 ----------------
__global__ __launch_bounds__(CC) void layernorm_kernel(
    const float* __restrict__ X, const float* __restrict__ s,
    const float* __restrict__ bpar, float* __restrict__ Y)
{
    __shared__ float scratch[32];
    int row = blockIdx.x, t = threadIdx.x;
    float v = X[(size_t)row*CC + t];
    float mu = blockReduceSum(v, scratch) * (1.f/CC);
    float d = v - mu;
    float var = blockReduceSum(d*d, scratch) * (1.f/CC);
    Y[(size_t)row*CC + t] = d * rsqrtf(var + 1e-5f) * s[t] + bpar[t];
}

// ---------------- tf32 mma (raw fp32 bits; HW truncates to tf32) ----------------
__device__ __forceinline__ void mma_tf32(float c[4], uint32_t a0, uint32_t a1,
                                         uint32_t a2, uint32_t a3,
                                         uint32_t b0, uint32_t b1) {
    asm volatile(
        "mma.sync.aligned.m16n8k8.row.col.f32.tf32.tf32.f32 "
        "{%0,%1,%2,%3}, {%4,%5,%6,%7}, {%8,%9}, {%0,%1,%2,%3};"
        : "+f"(c[0]), "+f"(c[1]), "+f"(c[2]), "+f"(c[3])
        : "r"(a0), "r"(a1), "r"(a2), "r"(a3), "r"(b0), "r"(b1));
}

__device__ __forceinline__ void cp_async16(void* smem_dst, const void* gsrc, int src_bytes) {
    uint32_t s = (uint32_t)__cvta_generic_to_shared(smem_dst);
    asm volatile("cp.async.cg.shared.global [%0], [%1], 16, %2;"
                 :: "r"(s), "l"(gsrc), "r"(src_bytes));
}
#define CP_COMMIT()  asm volatile("cp.async.commit_group;")
#define CP_WAIT1()   asm volatile("cp.async.wait_group 1;")

// ---------------- tf32 tensor-core GEMM (cp.async 3-stage pipelined) ----------------
// Computes up to 3 GEMMs sharing A: C[mat] = A @ B[mat] (+bias) (+res).
// mat = blockIdx.x / nblk; n-block = blockIdx.x % nblk.  N%64==0, K%32==0; M arbitrary.
#define GBM 128
#define GBN 64
#define GBK 32
#define A_PAD 40
#define B_PAD 72
#define STAGES 3
#define GEMM_SMEM_BYTES ((STAGES*(GBM*A_PAD + GBK*B_PAD))*4)

__global__ __launch_bounds__(256) void mma_gemm_kernel(
    const float* __restrict__ A,
    const float* __restrict__ B0, const float* __restrict__ B1, const float* __restrict__ B2,
    const float* __restrict__ bias, const float* __restrict__ res,
    float* __restrict__ C0, float* __restrict__ C1, float* __restrict__ C2,
    int M, int N, int K, int mode, int nblk)
{
    extern __shared__ uint32_t dynsmem[];
    uint32_t* AsBase = dynsmem;                          // STAGES x GBM x A_PAD
    uint32_t* BsBase = dynsmem + STAGES*GBM*A_PAD;       // STAGES x GBK x B_PAD

    int mat = blockIdx.x / nblk;
    const float* B = (mat == 0) ? B0 : ((mat == 1) ? B1 : B2);
    float* C       = (mat == 0) ? C0 : ((mat == 1) ? C1 : C2);
    int n0 = (blockIdx.x - mat*nblk) * GBN;

    int tid = threadIdx.x;
    int lane = tid & 31, warp = tid >> 5;
    int wm = warp & 1, wn = warp >> 1;            // 2 x 4 warp grid
    int m0 = blockIdx.y * GBM;

    float acc[4][2][4];
    #pragma unroll
    for (int i = 0; i < 4; i++)
        #pragma unroll
        for (int j = 0; j < 2; j++)
            #pragma unroll
            for (int c = 0; c < 4; c++) acc[i][j][c] = 0.f;

    int g = lane >> 2, tk = lane & 3;

    int a_row = tid >> 3, a_kf = (tid & 7) << 2;     // + j*32 rows
    int b_row = tid >> 4, b_nf = (tid & 15) << 2;    // + j*16 rows

    int KT = K / GBK;

    auto prefetch = [&](int kt, int buf) {
        uint32_t* As = AsBase + buf*GBM*A_PAD;
        uint32_t* Bs = BsBase + buf*GBK*B_PAD;
        int k0 = kt * GBK;
        #pragma unroll
        for (int j = 0; j < 4; j++) {
            int row = a_row + j*32;
            int gr = m0 + row;
            const float* src = A + ((gr < M) ? ((size_t)gr*K + k0 + a_kf) : 0);
            cp_async16(&As[row*A_PAD + a_kf], src, (gr < M) ? 16 : 0);
        }
        #pragma unroll
        for (int j = 0; j < 2; j++) {
            int row = b_row + j*16;
            cp_async16(&Bs[row*B_PAD + b_nf], B + (size_t)(k0+row)*N + n0 + b_nf, 16);
        }
        CP_COMMIT();
    };

    prefetch(0, 0);
    prefetch(1, 1);

    for (int kt = 0; kt < KT; kt++) {
        CP_WAIT1();            // group kt complete (kt+1 may still be in flight)
        __syncthreads();       // also protects buffer (kt+2)%3 from early overwrite
        if (kt + 2 < KT) prefetch(kt+2, (kt+2) % STAGES);
        else CP_COMMIT();      // keep one-group-per-iter accounting

        int buf = kt % STAGES;
        uint32_t* As = AsBase + buf*GBM*A_PAD;
        uint32_t* Bs = BsBase + buf*GBK*B_PAD;

        #pragma unroll
        for (int kk = 0; kk < 4; kk++) {
            int kc = (kk << 3) + tk;
            uint32_t a[4][4];
            #pragma unroll
            for (int mt = 0; mt < 4; mt++) {
                int r0 = wm*64 + mt*16 + g;
                a[mt][0] = As[r0*A_PAD + kc];
                a[mt][1] = As[(r0+8)*A_PAD + kc];
                a[mt][2] = As[r0*A_PAD + kc+4];
                a[mt][3] = As[(r0+8)*A_PAD + kc+4];
            }
            uint32_t b[2][2];
            #pragma unroll
            for (int nt = 0; nt < 2; nt++) {
                int col = wn*16 + nt*8 + g;
                b[nt][0] = Bs[kc*B_PAD + col];
                b[nt][1] = Bs[(kc+4)*B_PAD + col];
            }
            #pragma unroll
            for (int mt = 0; mt < 4; mt++)
                #pragma unroll
                for (int nt = 0; nt < 2; nt++)
                    mma_tf32(acc[mt][nt], a[mt][0], a[mt][1], a[mt][2], a[mt][3],
                             b[nt][0], b[nt][1]);
        }
    }

    #pragma unroll
    for (int mt = 0; mt < 4; mt++) {
        #pragma unroll
        for (int nt = 0; nt < 2; nt++) {
            int mbase = m0 + wm*64 + mt*16 + g;
            int nbase = n0 + wn*16 + nt*8 + (tk << 1);
            #pragma unroll
            for (int c = 0; c < 4; c++) {
                int m = mbase + ((c >> 1) << 3);
                int n = nbase + (c & 1);
                if (m >= M) continue;
                float v = acc[mt][nt][c];
                if (bias) v += bias[n];
                if (mode == 0) {
                    size_t idx = (size_t)m*N + n;
                    if (res) v += res[idx];
                    C[idx] = v;
                } else {
                    size_t idx = ((size_t)(m >> 10)*CC + n)*HWP + (m & 1023);
                    C[idx] = v + res[idx];
                }
            }
        }
    }
}

// ---------------- flash-style masked self-attention (tf32 MMA, raw fp32 bits) ----------------
#define AT_TQ 64
#define AT_TK 64
#define KV_PAD 44
#define PS_PAD 68

__global__ __launch_bounds__(256) void self_attn_mma_kernel(
    const float* __restrict__ Q, const float* __restrict__ K,
    const float* __restrict__ V, const unsigned int* __restrict__ mask,
    float* __restrict__ O)
{
    __shared__ uint32_t Ks[AT_TK][KV_PAD];
    __shared__ uint32_t Vs[AT_TK][KV_PAD];
    __shared__ uint32_t Ps[AT_TQ][PS_PAD];
    __shared__ float sm_m[64], sm_l[64], sm_alpha[64];
    __shared__ float smx[2][64], ssum[2][64];

    int b = blockIdx.z, h = blockIdx.y, q0 = blockIdx.x * AT_TQ;
    int tid = threadIdx.x, lane = tid & 31, w = tid >> 5;
    int wm = w >> 1, wn = w & 1;
    int g = lane >> 2, tk = lane & 3;
    int r_lo = wm*16 + g, r_hi = r_lo + 8;

    const float scale = rsqrtf((float)DHEAD);

    for (int i = tid; i < AT_TQ*DHEAD; i += 256) {
        int r = i / DHEAD, c = i % DHEAD;
        Ps[r][c] = __float_as_uint(Q[((size_t)b*HWP + q0 + r)*CC + h*DHEAD + c] * scale);
    }
    if (tid < 64) { sm_m[tid] = NEGMAX; sm_l[tid] = 0.f; }
    __syncthreads();

    uint32_t aq[5][4];
    #pragma unroll
    for (int kk = 0; kk < 5; kk++) {
        int kc = kk*8 + tk;
        aq[kk][0] = Ps[r_lo][kc];
        aq[kk][1] = Ps[r_hi][kc];
        aq[kk][2] = Ps[r_lo][kc+4];
        aq[kk][3] = Ps[r_hi][kc+4];
    }

    float o[5][4] = {};

    for (int jt = 0; jt < HWP/AT_TK; jt++) {
        __syncthreads();
        for (int i = tid; i < AT_TK*DHEAD; i += 256) {
            int j = i / DHEAD, c = i % DHEAD;
            size_t base = ((size_t)b*HWP + jt*AT_TK + j)*CC + h*DHEAD + c;
            Ks[j][c] = __float_as_uint(K[base]);
            Vs[j][c] = __float_as_uint(V[base]);
        }
        __syncthreads();

        float s_[4][4] = {};
        #pragma unroll
        for (int kk = 0; kk < 5; kk++) {
            int kc = kk*8 + tk;
            #pragma unroll
            for (int nt = 0; nt < 4; nt++) {
                int jn = wn*32 + nt*8 + g;
                mma_tf32(s_[nt], aq[kk][0], aq[kk][1], aq[kk][2], aq[kk][3],
                         Ks[jn][kc], Ks[jn][kc+4]);
            }
        }

        const unsigned int* mlo_p = mask + ((size_t)b*HWP + q0 + r_lo)*HWP + (size_t)jt*AT_TK;
        const unsigned int* mhi_p = mask + ((size_t)b*HWP + q0 + r_hi)*HWP + (size_t)jt*AT_TK;
        float mlo = NEGMAX, mhi = NEGMAX;
        #pragma unroll
        for (int nt = 0; nt < 4; nt++) {
            int col = wn*32 + nt*8 + tk*2;
            uint2 m0 = *(const uint2*)(mlo_p + col);
            uint2 m1 = *(const uint2*)(mhi_p + col);
            s_[nt][0] = m0.x ? s_[nt][0] : NEGMAX;
            s_[nt][1] = m0.y ? s_[nt][1] : NEGMAX;
            s_[nt][2] = m1.x ? s_[nt][2] : NEGMAX;
            s_[nt][3] = m1.y ? s_[nt][3] : NEGMAX;
            mlo = fmaxf(mlo, fmaxf(s_[nt][0], s_[nt][1]));
            mhi = fmaxf(mhi, fmaxf(s_[nt][2], s_[nt][3]));
        }
        mlo = fmaxf(mlo, __shfl_xor_sync(0xffffffffu, mlo, 1));
        mlo = fmaxf(mlo, __shfl_xor_sync(0xffffffffu, mlo, 2));
        mhi = fmaxf(mhi, __shfl_xor_sync(0xffffffffu, mhi, 1));
        mhi = fmaxf(mhi, __shfl_xor_sync(0xffffffffu, mhi, 2));
        if (tk == 0) { smx[wn][r_lo] = mlo; smx[wn][r_hi] = mhi; }
        __syncthreads();

        if (tid < 64) {
            float mo = sm_m[tid];
            float mn = fmaxf(mo, fmaxf(smx[0][tid], smx[1][tid]));
            sm_m[tid] = mn;
            sm_alpha[tid] = __expf(mo - mn);
        }
        __syncthreads();

        float mn_lo = sm_m[r_lo], mn_hi = sm_m[r_hi];
        float slo = 0.f, shi = 0.f;
        #pragma unroll
        for (int nt = 0; nt < 4; nt++) {
            int col = wn*32 + nt*8 + tk*2;
            float p0 = __expf(s_[nt][0] - mn_lo);
            float p1 = __expf(s_[nt][1] - mn_lo);
            float p2 = __expf(s_[nt][2] - mn_hi);
            float p3 = __expf(s_[nt][3] - mn_hi);
            slo += p0 + p1; shi += p2 + p3;
            uint2 wlo; wlo.x = __float_as_uint(p0); wlo.y = __float_as_uint(p1);
            uint2 whi; whi.x = __float_as_uint(p2); whi.y = __float_as_uint(p3);
            *(uint2*)&Ps[r_lo][col] = wlo;
            *(uint2*)&Ps[r_hi][col] = whi;
        }
        slo += __shfl_xor_sync(0xffffffffu, slo, 1);
        slo += __shfl_xor_sync(0xffffffffu, slo, 2);
        shi += __shfl_xor_sync(0xffffffffu, shi, 1);
        shi += __shfl_xor_sync(0xffffffffu, shi, 2);
        if (tk == 0) { ssum[wn][r_lo] = slo; ssum[wn][r_hi] = shi; }

        float alo = sm_alpha[r_lo], ahi = sm_alpha[r_hi];
        #pragma unroll
        for (int nt = 0; nt < 5; nt++) {
            o[nt][0] *= alo; o[nt][1] *= alo;
            o[nt][2] *= ahi; o[nt][3] *= ahi;
        }
        __syncthreads();

        if (tid < 64)
            sm_l[tid] = sm_alpha[tid]*sm_l[tid] + ssum[0][tid] + ssum[1][tid];

        #pragma unroll
        for (int kk = 0; kk < 4; kk++) {
            int kb = wn*32 + kk*8;
            uint32_t a0 = Ps[r_lo][kb+tk];
            uint32_t a1 = Ps[r_hi][kb+tk];
            uint32_t a2 = Ps[r_lo][kb+4+tk];
            uint32_t a3 = Ps[r_hi][kb+4+tk];
            #pragma unroll
            for (int nt = 0; nt < 5; nt++) {
                mma_tf32(o[nt], a0, a1, a2, a3,
                         Vs[kb+tk][nt*8+g], Vs[kb+4+tk][nt*8+g]);
            }
        }
    }
    __syncthreads();

    if (wn == 1) {
        #pragma unroll
        for (int nt = 0; nt < 5; nt++) {
            int c = nt*8 + tk*2;
            Ps[r_lo][c]   = __float_as_uint(o[nt][0]);
            Ps[r_lo][c+1] = __float_as_uint(o[nt][1]);
            Ps[r_hi][c]   = __float_as_uint(o[nt][2]);
            Ps[r_hi][c+1] = __float_as_uint(o[nt][3]);
        }
    }
    __syncthreads();
    if (wn == 0) {
        float il_lo = 1.f / sm_l[r_lo];
        float il_hi = 1.f / sm_l[r_hi];
        float* out_lo = O + ((size_t)b*HWP + q0 + r_lo)*CC + h*DHEAD;
        float* out_hi = O + ((size_t)b*HWP + q0 + r_hi)*CC + h*DHEAD;
        #pragma unroll
        for (int nt = 0; nt < 5; nt++) {
            int c = nt*8 + tk*2;
            out_lo[c]   = (o[nt][0] + __uint_as_float(Ps[r_lo][c]))   * il_lo;
            out_lo[c+1] = (o[nt][1] + __uint_as_float(Ps[r_lo][c+1])) * il_lo;
            out_hi[c]   = (o[nt][2] + __uint_as_float(Ps[r_hi][c]))   * il_hi;
            out_hi[c+1] = (o[nt][3] + __uint_as_float(Ps[r_hi][c+1])) * il_hi;
        }
    }
}

// ---------------- masked cross-attention (keys = 77, K/V resident in SMEM) ----------------
#define QT2 16
__global__ __launch_bounds__(256) void cross_attn_kernel(
    const float* __restrict__ Q, const float* __restrict__ Kc,
    const float* __restrict__ Vc, const unsigned int* __restrict__ mask,
    float* __restrict__ O)
{
    __shared__ float sk[CTX][DHEAD];
    __shared__ float sv[CTX][DHEAD];
    __shared__ float sq[QT2][DHEAD];
    __shared__ float sc[QT2][CTX+3];
    int b = blockIdx.z, h = blockIdx.y, q0 = blockIdx.x * QT2;
    int tid = threadIdx.x;

    for (int i = tid; i < CTX*DHEAD; i += 256) {
        int r = i / DHEAD, d = i % DHEAD;
        sk[r][d] = Kc[((size_t)b*CTX + r)*CC + h*DHEAD + d];
        sv[r][d] = Vc[((size_t)b*CTX + r)*CC + h*DHEAD + d];
    }
    for (int i = tid; i < QT2*DHEAD; i += 256) {
        int r = i / DHEAD, d = i % DHEAD;
        sq[r][d] = Q[((size_t)b*HWP + q0 + r)*CC + h*DHEAD + d];
    }
    __syncthreads();

    const float scale = rsqrtf((float)DHEAD);
    for (int idx = tid; idx < QT2*CTX; idx += 256) {
        int qi = idx / CTX, j = idx % CTX;
        float s = 0.f;
        #pragma unroll
        for (int d = 0; d < DHEAD; d++) s += sq[qi][d]*sk[j][d];
        unsigned int m = mask[((size_t)b*HWP + q0 + qi)*CTX + j];
        sc[qi][j] = (m != 0u) ? s*scale : NEGMAX;
    }
    __syncthreads();

    if (tid < QT2) {
        int qi = tid;
        float mx = NEGMAX;
        for (int j = 0; j < CTX; j++) mx = fmaxf(mx, sc[qi][j]);
        float sum = 0.f;
        for (int j = 0; j < CTX; j++) { float e = __expf(sc[qi][j]-mx); sc[qi][j] = e; sum += e; }
        float inv = 1.f/sum;
        for (int j = 0; j < CTX; j++) sc[qi][j] *= inv;
    }
    __syncthreads();

    for (int idx = tid; idx < QT2*DHEAD; idx += 256) {
        int qi = idx / DHEAD, d = idx % DHEAD;
        float s = 0.f;
        #pragma unroll
        for (int j = 0; j < CTX; j++) s += sc[qi][j]*sv[j][d];
        O[((size_t)b*HWP + q0 + qi)*CC + h*DHEAD + d] = s;
    }
}

// ---------------- GEGLU: u = a * gelu_exact(g) ----------------
__global__ __launch_bounds__(256) void geglu_kernel(
    const float* __restrict__ Y, float* __restrict__ U)
{
    size_t i = (size_t)blockIdx.x*256 + threadIdx.x;
    if (i >= (size_t)MROWS*FFI) return;
    size_t m = i / FFI, c = i % FFI;
    float a = Y[m*2*FFI + c];
    float g = Y[m*2*FFI + FFI + c];
    float ge = 0.5f * g * (1.f + erff(g * 0.70710678118654752f));
    U[i] = a * ge;
}

// ---------------- host orchestration ----------------
static inline void run_gemm1(const float* A, const float* B, const float* bias,
                             const float* res, float* C, int M, int N, int K, int mode)
{
    int nblk = N / GBN;
    dim3 grid(nblk, (M + GBM - 1) / GBM);
    mma_gemm_kernel<<<grid, 256, GEMM_SMEM_BYTES>>>(
        A, B, nullptr, nullptr, bias, res, C, nullptr, nullptr, M, N, K, mode, nblk);
}

static inline void run_gemm3(const float* A,
                             const float* B0, const float* B1, const float* B2,
                             float* C0, float* C1, float* C2,
                             int M, int N, int K, int nmat)
{
    int nblk = N / GBN;
    dim3 grid(nblk * nmat, (M + GBM - 1) / GBM);
    mma_gemm_kernel<<<grid, 256, GEMM_SMEM_BYTES>>>(
        A, B0, B1, B2, nullptr, nullptr, C0, C1, C2, M, N, K, 0, nblk);
}

extern "C" void kernel_launch(void* const* d_in, const int* in_sizes, int n_in,
                              void* d_out, int out_size)
{
    const float* x         = (const float*)d_in[0];
    const float* context   = (const float*)d_in[1];
    const unsigned int* vis_mask = (const unsigned int*)d_in[2];
    const unsigned int* v2t_mask = (const unsigned int*)d_in[3];
    const float* gn_scale  = (const float*)d_in[4];
    const float* gn_bias   = (const float*)d_in[5];
    const float* proj_in_w = (const float*)d_in[6];
    const float* proj_in_b = (const float*)d_in[7];
    const float* n1_s = (const float*)d_in[8];
    const float* n1_b = (const float*)d_in[9];
    const float* wq1  = (const float*)d_in[10];
    const float* wk1  = (const float*)d_in[11];
    const float* wv1  = (const float*)d_in[12];
    const float* wo1  = (const float*)d_in[13];
    const float* bo1  = (const float*)d_in[14];
    const float* n2_s = (const float*)d_in[15];
    const float* n2_b = (const float*)d_in[16];
    const float* wq2  = (const float*)d_in[17];
    const float* wk2  = (const float*)d_in[18];
    const float* wv2  = (const float*)d_in[19];
    const float* wo2  = (const float*)d_in[20];
    const float* bo2  = (const float*)d_in[21];
    const float* n3_s = (const float*)d_in[22];
    const float* n3_b = (const float*)d_in[23];
    const float* ff_w1 = (const float*)d_in[24];
    const float* ff_b1 = (const float*)d_in[25];
    const float* ff_w2 = (const float*)d_in[26];
    const float* ff_b2 = (const float*)d_in[27];
    const float* proj_out_w = (const float*)d_in[28];
    const float* proj_out_b = (const float*)d_in[29];
    float* out = (float*)d_out;

    cudaFuncSetAttribute(mma_gemm_kernel,
                         cudaFuncAttributeMaxDynamicSharedMemorySize, GEMM_SMEM_BYTES);

    float *gn, *h, *ln, *q, *k, *v, *ao, *ff1, *ffu;
    cudaGetSymbolAddress((void**)&gn,  g_gn);
    cudaGetSymbolAddress((void**)&h,   g_h);
    cudaGetSymbolAddress((void**)&ln,  g_ln);
    cudaGetSymbolAddress((void**)&q,   g_q);
    cudaGetSymbolAddress((void**)&k,   g_k);
    cudaGetSymbolAddress((void**)&v,   g_v);
    cudaGetSymbolAddress((void**)&ao,  g_ao);
    cudaGetSymbolAddress((void**)&ff1, g_ff1);
    cudaGetSymbolAddress((void**)&ffu, g_ffu);

    // 1. GroupNorm + transpose to [B, HW, C]
    groupnorm_kernel<<<BB*32, 256>>>(x, gn_scale, gn_bias, gn);
    // 2. proj_in
    run_gemm1(gn, proj_in_w, proj_in_b, nullptr, h, MROWS, CC, CC, 0);
    // 3. LN1
    layernorm_kernel<<<MROWS, CC>>>(h, n1_s, n1_b, ln);
    // 4. fused q,k,v (self)
    run_gemm3(ln, wq1, wk1, wv1, q, k, v, MROWS, CC, CC, 3);
    // 5. masked self-attention (flash tf32 MMA)
    {
        dim3 grid(HWP/AT_TQ, NHEADS, BB);
        self_attn_mma_kernel<<<grid, 256>>>(q, k, v, vis_mask, ao);
    }
    // 6. out-proj + residual
    run_gemm1(ao, wo1, bo1, h, h, MROWS, CC, CC, 0);
    // 7. LN2
    layernorm_kernel<<<MROWS, CC>>>(h, n2_s, n2_b, ln);
    // 8. q (cross)
    run_gemm1(ln, wq2, nullptr, nullptr, q, MROWS, CC, CC, 0);
    // 9. fused k,v from context
    run_gemm3(context, wk2, wv2, nullptr, k, v, nullptr, BB*CTX, CC, CTXD, 2);
    // 10. masked cross-attention
    {
        dim3 grid(HWP/QT2, NHEADS, BB);
        cross_attn_kernel<<<grid, 256>>>(q, k, v, v2t_mask, ao);
    }
    // 11. out-proj + residual
    run_gemm1(ao, wo2, bo2, h, h, MROWS, CC, CC, 0);
    // 12. LN3
    layernorm_kernel<<<MROWS, CC>>>(h, n3_s, n3_b, ln);
    // 13. FF up (GEGLU input)
    run_gemm1(ln, ff_w1, ff_b1, nullptr, ff1, MROWS, 2*FFI, CC, 0);
    // 14. GEGLU
    {
        size_t n = (size_t)MROWS*FFI;
        geglu_kernel<<<(unsigned)((n + 255)/256), 256>>>(ff1, ffu);
    }
    // 15. FF down + residual
    run_gemm1(ffu, ff_w2, ff_b2, h, h, MROWS, CC, FFI, 0);
    // 16. proj_out + transpose back to [B,C,H,W] + input residual
    run_gemm1(h, proj_out_w, proj_out_b, x, out, MROWS, CC, CC, 1);
}

// round 7
// speedup vs baseline: 3.5848x; 1.0460x over previous
#include <cuda_runtime.h>
#include <math.h>
#include <stdint.h>

// ---------------- problem constants ----------------
#define BB      8
#define CC      320
#define HWP     1024
#define NHEADS  8
#define DHEAD   40
#define CTX     77
#define CTXD    768
#define FFI     1280          // FF_INNER
#define MROWS   (BB*HWP)      // 8192
#define NEGMAX  (-3.402823466e38f)

// ---------------- scratch (device globals; no runtime allocs) ----------------
__device__ float g_gn [MROWS*CC];
__device__ float g_h  [MROWS*CC];
__device__ float g_ln [MROWS*CC];
__device__ float g_q  [MROWS*CC];
__device__ float g_k  [MROWS*CC];
__device__ float g_v  [MROWS*CC];
__device__ float g_ao [MROWS*CC];
__device__ float g_ff1[MROWS*2*FFI];
__device__ float g_ffu[(size_t)MROWS*FFI];

// ---------------- block reductions ----------------
__device__ __forceinline__ float blockReduceSum(float v, float* scratch) {
    int lane = threadIdx.x & 31, wid = threadIdx.x >> 5;
    #pragma unroll
    for (int o = 16; o > 0; o >>= 1) v += __shfl_down_sync(0xffffffffu, v, o);
    if (lane == 0) scratch[wid] = v;
    __syncthreads();
    int nw = (blockDim.x + 31) >> 5;
    v = (threadIdx.x < nw) ? scratch[threadIdx.x] : 0.f;
    if (wid == 0) {
        #pragma unroll
        for (int o = 16; o > 0; o >>= 1) v += __shfl_down_sync(0xffffffffu, v, o);
        if (lane == 0) scratch[0] = v;
    }
    __syncthreads();
    v = scratch[0];
    __syncthreads();
    return v;
}

// ---------------- GroupNorm (32 groups of 10 channels) + transpose to [B,HW,C] ----------------
__global__ __launch_bounds__(256) void groupnorm_kernel(
    const float* __restrict__ x, const float* __restrict__ scale,
    const float* __restrict__ bias, float* __restrict__ out)
{
    __shared__ float scratch[32];
    __shared__ float s_mu, s_inv;
    int b = blockIdx.x >> 5, g = blockIdx.x & 31;
    const float* xp = x + ((size_t)b*CC + g*10) * HWP;
    float sum = 0.f, sq = 0.f;
    for (int i = threadIdx.x; i < 10*HWP; i += 256) { float v = xp[i]; sum += v; sq += v*v; }
    sum = blockReduceSum(sum, scratch);
    sq  = blockReduceSum(sq,  scratch);
    if (threadIdx.x == 0) {
        float mu  = sum * (1.f/10240.f);
        float var = sq * (1.f/10240.f) - mu*mu;
        s_mu = mu; s_inv = rsqrtf(var + 1e-6f);
    }
    __syncthreads();
    float mu = s_mu, inv = s_inv;
    for (int i = threadIdx.x; i < 10*HWP; i += 256) {
        int cl = i >> 10, p = i & 1023;
        int c = g*10 + cl;
        float xn = (xp[i] - mu) * inv;
        out[((size_t)b*HWP + p)*CC + c] = xn * scale[c] + bias[c];
    }
}

// ---------------- LayerNorm over last dim = 320 ----------------
__global__ __launch_bounds__(CC) void layernorm_kernel(
    const float* __restrict__ X, const float* __restrict__ s,
    const float* __restrict__ bpar, float* __restrict__ Y)
{
    __shared__ float scratch[32];
    int row = blockIdx.x, t = threadIdx.x;
    float v = X[(size_t)row*CC + t];
    float mu = blockReduceSum(v, scratch) * (1.f/CC);
    float d = v - mu;
    float var = blockReduceSum(d*d, scratch) * (1.f/CC);
    Y[(size_t)row*CC + t] = d * rsqrtf(var + 1e-5f) * s[t] + bpar[t];
}

// ---------------- tf32 mma (raw fp32 bits; HW truncates to tf32) ----------------
__device__ __forceinline__ void mma_tf32(float c[4], uint32_t a0, uint32_t a1,
                                         uint32_t a2, uint32_t a3,
                                         uint32_t b0, uint32_t b1) {
    asm volatile(
        "mma.sync.aligned.m16n8k8.row.col.f32.tf32.tf32.f32 "
        "{%0,%1,%2,%3}, {%4,%5,%6,%7}, {%8,%9}, {%0,%1,%2,%3};"
        : "+f"(c[0]), "+f"(c[1]), "+f"(c[2]), "+f"(c[3])
        : "r"(a0), "r"(a1), "r"(a2), "r"(a3), "r"(b0), "r"(b1));
}

__device__ __forceinline__ void cp_async16(void* smem_dst, const void* gsrc, int src_bytes) {
    uint32_t s = (uint32_t)__cvta_generic_to_shared(smem_dst);
    asm volatile("cp.async.cg.shared.global [%0], [%1], 16, %2;"
                 :: "r"(s), "l"(gsrc), "r"(src_bytes));
}
#define CP_COMMIT()  asm volatile("cp.async.commit_group;")
#define CP_WAIT1()   asm volatile("cp.async.wait_group 1;")

// ---------------- tf32 tensor-core GEMM (cp.async 3-stage, 2x2x2 k-split warps) ----------
// Computes up to 3 GEMMs sharing A: C[mat] = A @ B[mat] (+bias) (+res).
// mat = blockIdx.x / nblk; n-block = blockIdx.x % nblk.  N%64==0, K%32==0; M arbitrary.
#define GBM 128
#define GBN 64
#define GBK 32
#define A_PAD 40
#define B_PAD 72
#define STAGES 3
#define GEMM_SMEM_BYTES ((STAGES*(GBM*A_PAD + GBK*B_PAD))*4)

__global__ __launch_bounds__(256, 2) void mma_gemm_kernel(
    const float* __restrict__ A,
    const float* __restrict__ B0, const float* __restrict__ B1, const float* __restrict__ B2,
    const float* __restrict__ bias, const float* __restrict__ res,
    float* __restrict__ C0, float* __restrict__ C1, float* __restrict__ C2,
    int M, int N, int K, int mode, int nblk)
{
    extern __shared__ uint32_t dynsmem[];
    uint32_t* AsBase = dynsmem;                          // STAGES x GBM x A_PAD
    uint32_t* BsBase = dynsmem + STAGES*GBM*A_PAD;       // STAGES x GBK x B_PAD

    int mat = blockIdx.x / nblk;
    const float* B = (mat == 0) ? B0 : ((mat == 1) ? B1 : B2);
    float* C       = (mat == 0) ? C0 : ((mat == 1) ? C1 : C2);
    int n0 = (blockIdx.x - mat*nblk) * GBN;

    int tid = threadIdx.x;
    int lane = tid & 31, warp = tid >> 5;
    // warp grid: wm x wn x wk = 2 x 2 x 2 ; warp tile 64 x 32, k-split halves of 16
    int wm = (warp >> 2) & 1, wn = (warp >> 1) & 1, wk = warp & 1;
    int m0 = blockIdx.y * GBM;

    float acc[4][4][4];   // mt, nt, c
    #pragma unroll
    for (int i = 0; i < 4; i++)
        #pragma unroll
        for (int j = 0; j < 4; j++)
            #pragma unroll
            for (int c = 0; c < 4; c++) acc[i][j][c] = 0.f;

    int g = lane >> 2, tk = lane & 3;

    int a_row = tid >> 3, a_kf = (tid & 7) << 2;     // + j*32 rows
    int b_row = tid >> 4, b_nf = (tid & 15) << 2;    // + j*16 rows

    int KT = K / GBK;

    auto prefetch = [&](int kt, int buf) {
        uint32_t* As = AsBase + buf*GBM*A_PAD;
        uint32_t* Bs = BsBase + buf*GBK*B_PAD;
        int k0 = kt * GBK;
        #pragma unroll
        for (int j = 0; j < 4; j++) {
            int row = a_row + j*32;
            int gr = m0 + row;
            const float* src = A + ((gr < M) ? ((size_t)gr*K + k0 + a_kf) : 0);
            cp_async16(&As[row*A_PAD + a_kf], src, (gr < M) ? 16 : 0);
        }
        #pragma unroll
        for (int j = 0; j < 2; j++) {
            int row = b_row + j*16;
            cp_async16(&Bs[row*B_PAD + b_nf], B + (size_t)(k0+row)*N + n0 + b_nf, 16);
        }
        CP_COMMIT();
    };

    prefetch(0, 0);
    prefetch(1, 1);

    for (int kt = 0; kt < KT; kt++) {
        CP_WAIT1();            // group kt complete (kt+1 may still be in flight)
        __syncthreads();       // also protects buffer (kt+2)%3 from early overwrite
        if (kt + 2 < KT) prefetch(kt+2, (kt+2) % STAGES);
        else CP_COMMIT();      // keep one-group-per-iter accounting

        int buf = kt % STAGES;
        uint32_t* As = AsBase + buf*GBM*A_PAD;
        uint32_t* Bs = BsBase + buf*GBK*B_PAD;

        #pragma unroll
        for (int kk = 0; kk < 2; kk++) {
            int kc = wk*16 + (kk << 3) + tk;
            uint32_t a[4][4];
            #pragma unroll
            for (int mt = 0; mt < 4; mt++) {
                int r0 = wm*64 + mt*16 + g;
                a[mt][0] = As[r0*A_PAD + kc];
                a[mt][1] = As[(r0+8)*A_PAD + kc];
                a[mt][2] = As[r0*A_PAD + kc+4];
                a[mt][3] = As[(r0+8)*A_PAD + kc+4];
            }
            uint32_t b[4][2];
            #pragma unroll
            for (int nt = 0; nt < 4; nt++) {
                int col = wn*32 + nt*8 + g;
                b[nt][0] = Bs[kc*B_PAD + col];
                b[nt][1] = Bs[(kc+4)*B_PAD + col];
            }
            #pragma unroll
            for (int mt = 0; mt < 4; mt++)
                #pragma unroll
                for (int nt = 0; nt < 4; nt++)
                    mma_tf32(acc[mt][nt], a[mt][0], a[mt][1], a[mt][2], a[mt][3],
                             b[nt][0], b[nt][1]);
        }
    }

    // ---- k-split reduction: wk=1 partials -> wk=0 via SMEM ----
    __syncthreads();
    float* red = (float*)dynsmem;     // [64 idx][4 pairs * 32 lanes] = 32 KB
    int pairIdx = wm*2 + wn;
    if (wk == 1) {
        #pragma unroll
        for (int mt = 0; mt < 4; mt++)
            #pragma unroll
            for (int nt = 0; nt < 4; nt++)
                #pragma unroll
                for (int c = 0; c < 4; c++) {
                    int idx = (mt*4 + nt)*4 + c;
                    red[idx*128 + pairIdx*32 + lane] = acc[mt][nt][c];
                }
    }
    __syncthreads();
    if (wk == 0) {
        #pragma unroll
        for (int mt = 0; mt < 4; mt++)
            #pragma unroll
            for (int nt = 0; nt < 4; nt++)
                #pragma unroll
                for (int c = 0; c < 4; c++) {
                    int idx = (mt*4 + nt)*4 + c;
                    acc[mt][nt][c] += red[idx*128 + pairIdx*32 + lane];
                }

        #pragma unroll
        for (int mt = 0; mt < 4; mt++) {
            #pragma unroll
            for (int nt = 0; nt < 4; nt++) {
                int mbase = m0 + wm*64 + mt*16 + g;
                int nbase = n0 + wn*32 + nt*8 + (tk << 1);
                #pragma unroll
                for (int c = 0; c < 4; c++) {
                    int m = mbase + ((c >> 1) << 3);
                    int n = nbase + (c & 1);
                    if (m >= M) continue;
                    float v = acc[mt][nt][c];
                    if (bias) v += bias[n];
                    if (mode == 0) {
                        size_t idx = (size_t)m*N + n;
                        if (res) v += res[idx];
                        C[idx] = v;
                    } else {
                        size_t idx = ((size_t)(m >> 10)*CC + n)*HWP + (m & 1023);
                        C[idx] = v + res[idx];
                    }
                }
            }
        }
    }
}

// ---------------- flash-style masked self-attention (tf32 MMA, raw fp32 bits) ----------------
#define AT_TQ 64
#define AT_TK 64
#define KV_PAD 44
#define PS_PAD 68

__global__ __launch_bounds__(256) void self_attn_mma_kernel(
    const float* __restrict__ Q, const float* __restrict__ K,
    const float* __restrict__ V, const unsigned int* __restrict__ mask,
    float* __restrict__ O)
{
    __shared__ uint32_t Ks[AT_TK][KV_PAD];
    __shared__ uint32_t Vs[AT_TK][KV_PAD];
    __shared__ uint32_t Ps[AT_TQ][PS_PAD];
    __shared__ float sm_m[64], sm_l[64], sm_alpha[64];
    __shared__ float smx[2][64], ssum[2][64];

    int b = blockIdx.z, h = blockIdx.y, q0 = blockIdx.x * AT_TQ;
    int tid = threadIdx.x, lane = tid & 31, w = tid >> 5;
    int wm = w >> 1, wn = w & 1;
    int g = lane >> 2, tk = lane & 3;
    int r_lo = wm*16 + g, r_hi = r_lo + 8;

    const float scale = rsqrtf((float)DHEAD);

    for (int i = tid; i < AT_TQ*DHEAD; i += 256) {
        int r = i / DHEAD, c = i % DHEAD;
        Ps[r][c] = __float_as_uint(Q[((size_t)b*HWP + q0 + r)*CC + h*DHEAD + c] * scale);
    }
    if (tid < 64) { sm_m[tid] = NEGMAX; sm_l[tid] = 0.f; }
    __syncthreads();

    uint32_t aq[5][4];
    #pragma unroll
    for (int kk = 0; kk < 5; kk++) {
        int kc = kk*8 + tk;
        aq[kk][0] = Ps[r_lo][kc];
        aq[kk][1] = Ps[r_hi][kc];
        aq[kk][2] = Ps[r_lo][kc+4];
        aq[kk][3] = Ps[r_hi][kc+4];
    }

    float o[5][4] = {};

    for (int jt = 0; jt < HWP/AT_TK; jt++) {
        __syncthreads();
        for (int i = tid; i < AT_TK*DHEAD; i += 256) {
            int j = i / DHEAD, c = i % DHEAD;
            size_t base = ((size_t)b*HWP + jt*AT_TK + j)*CC + h*DHEAD + c;
            Ks[j][c] = __float_as_uint(K[base]);
            Vs[j][c] = __float_as_uint(V[base]);
        }
        __syncthreads();

        float s_[4][4] = {};
        #pragma unroll
        for (int kk = 0; kk < 5; kk++) {
            int kc = kk*8 + tk;
            #pragma unroll
            for (int nt = 0; nt < 4; nt++) {
                int jn = wn*32 + nt*8 + g;
                mma_tf32(s_[nt], aq[kk][0], aq[kk][1], aq[kk][2], aq[kk][3],
                         Ks[jn][kc], Ks[jn][kc+4]);
            }
        }

        const unsigned int* mlo_p = mask + ((size_t)b*HWP + q0 + r_lo)*HWP + (size_t)jt*AT_TK;
        const unsigned int* mhi_p = mask + ((size_t)b*HWP + q0 + r_hi)*HWP + (size_t)jt*AT_TK;
        float mlo = NEGMAX, mhi = NEGMAX;
        #pragma unroll
        for (int nt = 0; nt < 4; nt++) {
            int col = wn*32 + nt*8 + tk*2;
            uint2 m0 = *(const uint2*)(mlo_p + col);
            uint2 m1 = *(const uint2*)(mhi_p + col);
            s_[nt][0] = m0.x ? s_[nt][0] : NEGMAX;
            s_[nt][1] = m0.y ? s_[nt][1] : NEGMAX;
            s_[nt][2] = m1.x ? s_[nt][2] : NEGMAX;
            s_[nt][3] = m1.y ? s_[nt][3] : NEGMAX;
            mlo = fmaxf(mlo, fmaxf(s_[nt][0], s_[nt][1]));
            mhi = fmaxf(mhi, fmaxf(s_[nt][2], s_[nt][3]));
        }
        mlo = fmaxf(mlo, __shfl_xor_sync(0xffffffffu, mlo, 1));
        mlo = fmaxf(mlo, __shfl_xor_sync(0xffffffffu, mlo, 2));
        mhi = fmaxf(mhi, __shfl_xor_sync(0xffffffffu, mhi, 1));
        mhi = fmaxf(mhi, __shfl_xor_sync(0xffffffffu, mhi, 2));
        if (tk == 0) { smx[wn][r_lo] = mlo; smx[wn][r_hi] = mhi; }
        __syncthreads();

        if (tid < 64) {
            float mo = sm_m[tid];
            float mn = fmaxf(mo, fmaxf(smx[0][tid], smx[1][tid]));
            sm_m[tid] = mn;
            sm_alpha[tid] = __expf(mo - mn);
        }
        __syncthreads();

        float mn_lo = sm_m[r_lo], mn_hi = sm_m[r_hi];
        float slo = 0.f, shi = 0.f;
        #pragma unroll
        for (int nt = 0; nt < 4; nt++) {
            int col = wn*32 + nt*8 + tk*2;
            float p0 = __expf(s_[nt][0] - mn_lo);
            float p1 = __expf(s_[nt][1] - mn_lo);
            float p2 = __expf(s_[nt][2] - mn_hi);
            float p3 = __expf(s_[nt][3] - mn_hi);
            slo += p0 + p1; shi += p2 + p3;
            uint2 wlo; wlo.x = __float_as_uint(p0); wlo.y = __float_as_uint(p1);
            uint2 whi; whi.x = __float_as_uint(p2); whi.y = __float_as_uint(p3);
            *(uint2*)&Ps[r_lo][col] = wlo;
            *(uint2*)&Ps[r_hi][col] = whi;
        }
        slo += __shfl_xor_sync(0xffffffffu, slo, 1);
        slo += __shfl_xor_sync(0xffffffffu, slo, 2);
        shi += __shfl_xor_sync(0xffffffffu, shi, 1);
        shi += __shfl_xor_sync(0xffffffffu, shi, 2);
        if (tk == 0) { ssum[wn][r_lo] = slo; ssum[wn][r_hi] = shi; }

        float alo = sm_alpha[r_lo], ahi = sm_alpha[r_hi];
        #pragma unroll
        for (int nt = 0; nt < 5; nt++) {
            o[nt][0] *= alo; o[nt][1] *= alo;
            o[nt][2] *= ahi; o[nt][3] *= ahi;
        }
        __syncthreads();

        if (tid < 64)
            sm_l[tid] = sm_alpha[tid]*sm_l[tid] + ssum[0][tid] + ssum[1][tid];

        #pragma unroll
        for (int kk = 0; kk < 4; kk++) {
            int kb = wn*32 + kk*8;
            uint32_t a0 = Ps[r_lo][kb+tk];
            uint32_t a1 = Ps[r_hi][kb+tk];
            uint32_t a2 = Ps[r_lo][kb+4+tk];
            uint32_t a3 = Ps[r_hi][kb+4+tk];
            #pragma unroll
            for (int nt = 0; nt < 5; nt++) {
                mma_tf32(o[nt], a0, a1, a2, a3,
                         Vs[kb+tk][nt*8+g], Vs[kb+4+tk][nt*8+g]);
            }
        }
    }
    __syncthreads();

    if (wn == 1) {
        #pragma unroll
        for (int nt = 0; nt < 5; nt++) {
            int c = nt*8 + tk*2;
            Ps[r_lo][c]   = __float_as_uint(o[nt][0]);
            Ps[r_lo][c+1] = __float_as_uint(o[nt][1]);
            Ps[r_hi][c]   = __float_as_uint(o[nt][2]);
            Ps[r_hi][c+1] = __float_as_uint(o[nt][3]);
        }
    }
    __syncthreads();
    if (wn == 0) {
        float il_lo = 1.f / sm_l[r_lo];
        float il_hi = 1.f / sm_l[r_hi];
        float* out_lo = O + ((size_t)b*HWP + q0 + r_lo)*CC + h*DHEAD;
        float* out_hi = O + ((size_t)b*HWP + q0 + r_hi)*CC + h*DHEAD;
        #pragma unroll
        for (int nt = 0; nt < 5; nt++) {
            int c = nt*8 + tk*2;
            out_lo[c]   = (o[nt][0] + __uint_as_float(Ps[r_lo][c]))   * il_lo;
            out_lo[c+1] = (o[nt][1] + __uint_as_float(Ps[r_lo][c+1])) * il_lo;
            out_hi[c]   = (o[nt][2] + __uint_as_float(Ps[r_hi][c]))   * il_hi;
            out_hi[c+1] = (o[nt][3] + __uint_as_float(Ps[r_hi][c+1])) * il_hi;
        }
    }
}

// ---------------- masked cross-attention (keys = 77, K/V resident in SMEM) ----------------
#define QT2 16
__global__ __launch_bounds__(256) void cross_attn_kernel(
    const float* __restrict__ Q, const float* __restrict__ Kc,
    const float* __restrict__ Vc, const unsigned int* __restrict__ mask,
    float* __restrict__ O)
{
    __shared__ float sk[CTX][DHEAD];
    __shared__ float sv[CTX][DHEAD];
    __shared__ float sq[QT2][DHEAD];
    __shared__ float sc[QT2][CTX+3];
    int b = blockIdx.z, h = blockIdx.y, q0 = blockIdx.x * QT2;
    int tid = threadIdx.x;

    for (int i = tid; i < CTX*DHEAD; i += 256) {
        int r = i / DHEAD, d = i % DHEAD;
        sk[r][d] = Kc[((size_t)b*CTX + r)*CC + h*DHEAD + d];
        sv[r][d] = Vc[((size_t)b*CTX + r)*CC + h*DHEAD + d];
    }
    for (int i = tid; i < QT2*DHEAD; i += 256) {
        int r = i / DHEAD, d = i % DHEAD;
        sq[r][d] = Q[((size_t)b*HWP + q0 + r)*CC + h*DHEAD + d];
    }
    __syncthreads();

    const float scale = rsqrtf((float)DHEAD);
    for (int idx = tid; idx < QT2*CTX; idx += 256) {
        int qi = idx / CTX, j = idx % CTX;
        float s = 0.f;
        #pragma unroll
        for (int d = 0; d < DHEAD; d++) s += sq[qi][d]*sk[j][d];
        unsigned int m = mask[((size_t)b*HWP + q0 + qi)*CTX + j];
        sc[qi][j] = (m != 0u) ? s*scale : NEGMAX;
    }
    __syncthreads();

    if (tid < QT2) {
        int qi = tid;
        float mx = NEGMAX;
        for (int j = 0; j < CTX; j++) mx = fmaxf(mx, sc[qi][j]);
        float sum = 0.f;
        for (int j = 0; j < CTX; j++) { float e = __expf(sc[qi][j]-mx); sc[qi][j] = e; sum += e; }
        float inv = 1.f/sum;
        for (int j = 0; j < CTX; j++) sc[qi][j] *= inv;
    }
    __syncthreads();

    for (int idx = tid; idx < QT2*DHEAD; idx += 256) {
        int qi = idx / DHEAD, d = idx % DHEAD;
        float s = 0.f;
        #pragma unroll
        for (int j = 0; j < CTX; j++) s += sc[qi][j]*sv[j][d];
        O[((size_t)b*HWP + q0 + qi)*CC + h*DHEAD + d] = s;
    }
}

// ---------------- GEGLU: u = a * gelu_exact(g) ----------------
__global__ __launch_bounds__(256) void geglu_kernel(
    const float* __restrict__ Y, float* __restrict__ U)
{
    size_t i = (size_t)blockIdx.x*256 + threadIdx.x;
    if (i >= (size_t)MROWS*FFI) return;
    size_t m = i / FFI, c = i % FFI;
    float a = Y[m*2*FFI + c];
    float g = Y[m*2*FFI + FFI + c];
    float ge = 0.5f * g * (1.f + erff(g * 0.70710678118654752f));
    U[i] = a * ge;
}

// ---------------- host orchestration ----------------
static inline void run_gemm1(const float* A, const float* B, const float* bias,
                             const float* res, float* C, int M, int N, int K, int mode)
{
    int nblk = N / GBN;
    dim3 grid(nblk, (M + GBM - 1) / GBM);
    mma_gemm_kernel<<<grid, 256, GEMM_SMEM_BYTES>>>(
        A, B, nullptr, nullptr, bias, res, C, nullptr, nullptr, M, N, K, mode, nblk);
}

static inline void run_gemm3(const float* A,
                             const float* B0, const float* B1, const float* B2,
                             float* C0, float* C1, float* C2,
                             int M, int N, int K, int nmat)
{
    int nblk = N / GBN;
    dim3 grid(nblk * nmat, (M + GBM - 1) / GBM);
    mma_gemm_kernel<<<grid, 256, GEMM_SMEM_BYTES>>>(
        A, B0, B1, B2, nullptr, nullptr, C0, C1, C2, M, N, K, 0, nblk);
}

extern "C" void kernel_launch(void* const* d_in, const int* in_sizes, int n_in,
                              void* d_out, int out_size)
{
    const float* x         = (const float*)d_in[0];
    const float* context   = (const float*)d_in[1];
    const unsigned int* vis_mask = (const unsigned int*)d_in[2];
    const unsigned int* v2t_mask = (const unsigned int*)d_in[3];
    const float* gn_scale  = (const float*)d_in[4];
    const float* gn_bias   = (const float*)d_in[5];
    const float* proj_in_w = (const float*)d_in[6];
    const float* proj_in_b = (const float*)d_in[7];
    const float* n1_s = (const float*)d_in[8];
    const float* n1_b = (const float*)d_in[9];
    const float* wq1  = (const float*)d_in[10];
    const float* wk1  = (const float*)d_in[11];
    const float* wv1  = (const float*)d_in[12];
    const float* wo1  = (const float*)d_in[13];
    const float* bo1  = (const float*)d_in[14];
    const float* n2_s = (const float*)d_in[15];
    const float* n2_b = (const float*)d_in[16];
    const float* wq2  = (const float*)d_in[17];
    const float* wk2  = (const float*)d_in[18];
    const float* wv2  = (const float*)d_in[19];
    const float* wo2  = (const float*)d_in[20];
    const float* bo2  = (const float*)d_in[21];
    const float* n3_s = (const float*)d_in[22];
    const float* n3_b = (const float*)d_in[23];
    const float* ff_w1 = (const float*)d_in[24];
    const float* ff_b1 = (const float*)d_in[25];
    const float* ff_w2 = (const float*)d_in[26];
    const float* ff_b2 = (const float*)d_in[27];
    const float* proj_out_w = (const float*)d_in[28];
    const float* proj_out_b = (const float*)d_in[29];
    float* out = (float*)d_out;

    cudaFuncSetAttribute(mma_gemm_kernel,
                         cudaFuncAttributeMaxDynamicSharedMemorySize, GEMM_SMEM_BYTES);

    float *gn, *h, *ln, *q, *k, *v, *ao, *ff1, *ffu;
    cudaGetSymbolAddress((void**)&gn,  g_gn);
    cudaGetSymbolAddress((void**)&h,   g_h);
    cudaGetSymbolAddress((void**)&ln,  g_ln);
    cudaGetSymbolAddress((void**)&q,   g_q);
    cudaGetSymbolAddress((void**)&k,   g_k);
    cudaGetSymbolAddress((void**)&v,   g_v);
    cudaGetSymbolAddress((void**)&ao,  g_ao);
    cudaGetSymbolAddress((void**)&ff1, g_ff1);
    cudaGetSymbolAddress((void**)&ffu, g_ffu);

    // 1. GroupNorm + transpose to [B, HW, C]
    groupnorm_kernel<<<BB*32, 256>>>(x, gn_scale, gn_bias, gn);
    // 2. proj_in
    run_gemm1(gn, proj_in_w, proj_in_b, nullptr, h, MROWS, CC, CC, 0);
    // 3. LN1
    layernorm_kernel<<<MROWS, CC>>>(h, n1_s, n1_b, ln);
    // 4. fused q,k,v (self)
    run_gemm3(ln, wq1, wk1, wv1, q, k, v, MROWS, CC, CC, 3);
    // 5. masked self-attention (flash tf32 MMA)
    {
        dim3 grid(HWP/AT_TQ, NHEADS, BB);
        self_attn_mma_kernel<<<grid, 256>>>(q, k, v, vis_mask, ao);
    }
    // 6. out-proj + residual
    run_gemm1(ao, wo1, bo1, h, h, MROWS, CC, CC, 0);
    // 7. LN2
    layernorm_kernel<<<MROWS, CC>>>(h, n2_s, n2_b, ln);
    // 8. q (cross)
    run_gemm1(ln, wq2, nullptr, nullptr, q, MROWS, CC, CC, 0);
    // 9. fused k,v from context
    run_gemm3(context, wk2, wv2, nullptr, k, v, nullptr, BB*CTX, CC, CTXD, 2);
    // 10. masked cross-attention
    {
        dim3 grid(HWP/QT2, NHEADS, BB);
        cross_attn_kernel<<<grid, 256>>>(q, k, v, v2t_mask, ao);
    }
    // 11. out-proj + residual
    run_gemm1(ao, wo2, bo2, h, h, MROWS, CC, CC, 0);
    // 12. LN3
    layernorm_kernel<<<MROWS, CC>>>(h, n3_s, n3_b, ln);
    // 13. FF up (GEGLU input)
    run_gemm1(ln, ff_w1, ff_b1, nullptr, ff1, MROWS, 2*FFI, CC, 0);
    // 14. GEGLU
    {
        size_t n = (size_t)MROWS*FFI;
        geglu_kernel<<<(unsigned)((n + 255)/256), 256>>>(ff1, ffu);
    }
    // 15. FF down + residual
    run_gemm1(ffu, ff_w2, ff_b2, h, h, MROWS, CC, FFI, 0);
    // 16. proj_out + transpose back to [B,C,H,W] + input residual
    run_gemm1(h, proj_out_w, proj_out_b, x, out, MROWS, CC, CC, 1);
}

// round 9
// speedup vs baseline: 4.2049x; 1.1730x over previous
#include <cuda_runtime.h>
#include <cuda_fp16.h>
#include <math.h>
#include <stdint.h>

// ---------------- problem constants ----------------
#define BB      8
#define CC      320
#define HWP     1024
#define NHEADS  8
#define DHEAD   40
#define CTX     77
#define CTXD    768
#define FFI     1280          // FF_INNER
#define MROWS   (BB*HWP)      // 8192
#define NEGMAX  (-3.402823466e38f)

// ---------------- scratch (device globals; no runtime allocs) ----------------
__device__ float  g_h  [MROWS*CC];
__device__ float  g_q  [MROWS*CC];
__device__ float  g_k  [MROWS*CC];
__device__ float  g_v  [MROWS*CC];
__device__ float  g_ff1[MROWS*2*FFI];
__device__ __half g_gn16 [MROWS*CC];
__device__ __half g_ln16 [MROWS*CC];
__device__ __half g_ao16 [MROWS*CC];
__device__ __half g_ffu16[(size_t)MROWS*FFI];
__device__ __half g_ctx16[BB*CTX*CTXD];
__device__ __half g_h16  [MROWS*CC];
__device__ __half g_wt16 [2539520];        // transposed weights [N][K], fp16

// offsets into g_wt16 (halves)
#define OFF_PIN  0
#define OFF_Q1   102400
#define OFF_K1   204800
#define OFF_V1   307200
#define OFF_O1   409600
#define OFF_Q2   512000
#define OFF_O2   614400
#define OFF_POUT 716800
#define OFF_K2   819200
#define OFF_V2   1064960
#define OFF_FF1  1310720
#define OFF_FF2  2129920

// ---------------- block reductions ----------------
__device__ __forceinline__ float blockReduceSum(float v, float* scratch) {
    int lane = threadIdx.x & 31, wid = threadIdx.x >> 5;
    #pragma unroll
    for (int o = 16; o > 0; o >>= 1) v += __shfl_down_sync(0xffffffffu, v, o);
    if (lane == 0) scratch[wid] = v;
    __syncthreads();
    int nw = (blockDim.x + 31) >> 5;
    v = (threadIdx.x < nw) ? scratch[threadIdx.x] : 0.f;
    if (wid == 0) {
        #pragma unroll
        for (int o = 16; o > 0; o >>= 1) v += __shfl_down_sync(0xffffffffu, v, o);
        if (lane == 0) scratch[0] = v;
    }
    __syncthreads();
    v = scratch[0];
    __syncthreads();
    return v;
}

// ---------------- GroupNorm -> fp16 [B,HW,C] ----------------
__global__ __launch_bounds__(256) void groupnorm_kernel(
    const float* __restrict__ x, const float* __restrict__ scale,
    const float* __restrict__ bias, __half* __restrict__ out)
{
    __shared__ float scratch[32];
    __shared__ float s_mu, s_inv;
    int b = blockIdx.x >> 5, g = blockIdx.x & 31;
    const float* xp = x + ((size_t)b*CC + g*10) * HWP;
    float sum = 0.f, sq = 0.f;
    for (int i = threadIdx.x; i < 10*HWP; i += 256) { float v = xp[i]; sum += v; sq += v*v; }
    sum = blockReduceSum(sum, scratch);
    sq  = blockReduceSum(sq,  scratch);
    if (threadIdx.x == 0) {
        float mu  = sum * (1.f/10240.f);
        float var = sq * (1.f/10240.f) - mu*mu;
        s_mu = mu; s_inv = rsqrtf(var + 1e-6f);
    }
    __syncthreads();
    float mu = s_mu, inv = s_inv;
    for (int i = threadIdx.x; i < 10*HWP; i += 256) {
        int cl = i >> 10, p = i & 1023;
        int c = g*10 + cl;
        float xn = (xp[i] - mu) * inv;
        out[((size_t)b*HWP + p)*CC + c] = __float2half(xn * scale[c] + bias[c]);
    }
}

// ---------------- LayerNorm over last dim = 320 -> fp16 ----------------
__global__ __launch_bounds__(CC) void layernorm_kernel(
    const float* __restrict__ X, const float* __restrict__ s,
    const float* __restrict__ bpar, __half* __restrict__ Y)
{
    __shared__ float scratch[32];
    int row = blockIdx.x, t = threadIdx.x;
    float v = X[(size_t)row*CC + t];
    float mu = blockReduceSum(v, scratch) * (1.f/CC);
    float d = v - mu;
    float var = blockReduceSum(d*d, scratch) * (1.f/CC);
    Y[(size_t)row*CC + t] = __float2half(d * rsqrtf(var + 1e-5f) * s[t] + bpar[t]);
}

// ---------------- weight transpose to fp16 [N][K] ----------------
struct TransDesc {
    const float* src[12];
    __half* dst[12];
    int K[12], N[12];
    int start[13];
};

__global__ __launch_bounds__(256) void transpose_all_kernel(TransDesc p) {
    __shared__ float t[32][33];
    int bid = blockIdx.x;
    int i = 0;
    while (bid >= p.start[i+1]) i++;
    const float* src = p.src[i];
    __half* dst = p.dst[i];
    int K = p.K[i], N = p.N[i];
    int lt = bid - p.start[i];
    int tiles_n = N >> 5;
    int tk = lt / tiles_n, tn = lt - tk*tiles_n;
    int tx = threadIdx.x & 31, ty = threadIdx.x >> 5;   // 32 x 8
    #pragma unroll
    for (int j = 0; j < 32; j += 8)
        t[ty+j][tx] = src[(size_t)(tk*32+ty+j)*N + tn*32 + tx];
    __syncthreads();
    #pragma unroll
    for (int j = 0; j < 32; j += 8)
        dst[(size_t)(tn*32+ty+j)*K + tk*32 + tx] = __float2half(t[tx][ty+j]);
}

// ---------------- context -> fp16 ----------------
__global__ __launch_bounds__(256) void f2h_kernel(
    const float* __restrict__ src, __half* __restrict__ dst, int n)
{
    int i = blockIdx.x*256 + threadIdx.x;
    if (i < n) dst[i] = __float2half(src[i]);
}

// ---------------- mma helpers ----------------
__device__ __forceinline__ void mma_f16(float c[4], uint32_t a0, uint32_t a1,
                                        uint32_t a2, uint32_t a3,
                                        uint32_t b0, uint32_t b1) {
    asm volatile(
        "mma.sync.aligned.m16n8k16.row.col.f32.f16.f16.f32 "
        "{%0,%1,%2,%3}, {%4,%5,%6,%7}, {%8,%9}, {%0,%1,%2,%3};"
        : "+f"(c[0]), "+f"(c[1]), "+f"(c[2]), "+f"(c[3])
        : "r"(a0), "r"(a1), "r"(a2), "r"(a3), "r"(b0), "r"(b1));
}

__device__ __forceinline__ void mma_tf32(float c[4], uint32_t a0, uint32_t a1,
                                         uint32_t a2, uint32_t a3,
                                         uint32_t b0, uint32_t b1) {
    asm volatile(
        "mma.sync.aligned.m16n8k8.row.col.f32.tf32.tf32.f32 "
        "{%0,%1,%2,%3}, {%4,%5,%6,%7}, {%8,%9}, {%0,%1,%2,%3};"
        : "+f"(c[0]), "+f"(c[1]), "+f"(c[2]), "+f"(c[3])
        : "r"(a0), "r"(a1), "r"(a2), "r"(a3), "r"(b0), "r"(b1));
}

__device__ __forceinline__ void cp_async16(void* smem_dst, const void* gsrc, int src_bytes) {
    uint32_t s = (uint32_t)__cvta_generic_to_shared(smem_dst);
    asm volatile("cp.async.cg.shared.global [%0], [%1], 16, %2;"
                 :: "r"(s), "l"(gsrc), "r"(src_bytes));
}
#define CP_COMMIT()  asm volatile("cp.async.commit_group;")
#define CP_WAIT1()   asm volatile("cp.async.wait_group 1;")

// ---------------- fp16 tensor-core GEMM (cp.async 3-stage, 2x2x2 k-split) ----------------
// C[mat] = A16 @ Bt16[mat]^T (+bias) (+res). A16 [M][K] fp16, Bt16 [N][K] fp16.
// N%64==0, K%64==0; M arbitrary. mode 0: normal (+optional fp16 copy C16); mode 1: final store.
#define GBM 128
#define GBN 64
#define GBK 64
#define A_P16 36      // uint32 words per A row (32 pairs + pad), 144B (16B aligned)
#define B_P16 36
#define STAGES 3
#define GEMM_SMEM_BYTES ((STAGES*(GBM*A_P16 + GBN*B_P16))*4)

__global__ __launch_bounds__(256, 2) void mma_gemm_kernel(
    const __half* __restrict__ A,
    const __half* __restrict__ B0, const __half* __restrict__ B1, const __half* __restrict__ B2,
    const float* __restrict__ bias, const float* __restrict__ res,
    float* __restrict__ C0, float* __restrict__ C1, float* __restrict__ C2,
    __half* __restrict__ C16,
    int M, int N, int K, int mode, int nblk)
{
    extern __shared__ uint32_t dynsmem[];
    uint32_t* AsBase = dynsmem;                          // STAGES x GBM x A_P16
    uint32_t* BsBase = dynsmem + STAGES*GBM*A_P16;       // STAGES x GBN x B_P16

    int mat = blockIdx.x / nblk;
    const __half* B = (mat == 0) ? B0 : ((mat == 1) ? B1 : B2);
    float* C        = (mat == 0) ? C0 : ((mat == 1) ? C1 : C2);
    int n0 = (blockIdx.x - mat*nblk) * GBN;

    int tid = threadIdx.x;
    int lane = tid & 31, warp = tid >> 5;
    int wm = (warp >> 2) & 1, wn = (warp >> 1) & 1, wk = warp & 1;
    int m0 = blockIdx.y * GBM;

    float acc[4][4][4];
    #pragma unroll
    for (int i = 0; i < 4; i++)
        #pragma unroll
        for (int j = 0; j < 4; j++)
            #pragma unroll
            for (int c = 0; c < 4; c++) acc[i][j][c] = 0.f;

    int g = lane >> 2, tk = lane & 3;

    // loader coords: A 1024 16B-chunks (4/thr), B 512 chunks (2/thr); 8 chunks/row
    int a_row = tid >> 3, a_ch = tid & 7;     // + j*32 rows
    int b_row = tid >> 3, b_ch = tid & 7;     // + j*32 rows

    int KT = K / GBK;

    auto prefetch = [&](int kt, int buf) {
        uint32_t* As = AsBase + buf*GBM*A_P16;
        uint32_t* Bs = BsBase + buf*GBN*B_P16;
        int k0 = kt * GBK;
        #pragma unroll
        for (int j = 0; j < 4; j++) {
            int row = a_row + j*32;
            int gr = m0 + row;
            const __half* src = A + ((gr < M) ? ((size_t)gr*K + k0 + a_ch*8) : 0);
            cp_async16(&As[row*A_P16 + a_ch*4], src, (gr < M) ? 16 : 0);
        }
        #pragma unroll
        for (int j = 0; j < 2; j++) {
            int row = b_row + j*32;
            cp_async16(&Bs[row*B_P16 + b_ch*4],
                       B + (size_t)(n0 + row)*K + k0 + b_ch*8, 16);
        }
        CP_COMMIT();
    };

    prefetch(0, 0);
    prefetch(1, 1);

    for (int kt = 0; kt < KT; kt++) {
        CP_WAIT1();
        __syncthreads();
        if (kt + 2 < KT) prefetch(kt+2, (kt+2) % STAGES);
        else CP_COMMIT();

        int buf = kt % STAGES;
        uint32_t* As = AsBase + buf*GBM*A_P16;
        uint32_t* Bs = BsBase + buf*GBN*B_P16;

        #pragma unroll
        for (int s = 0; s < 2; s++) {                    // two k16 steps per wk half
            int p0 = wk*16 + s*8;                        // pair index base (k/2)
            uint32_t a[4][4];
            #pragma unroll
            for (int mt = 0; mt < 4; mt++) {
                int r0 = wm*64 + mt*16 + g;
                a[mt][0] = As[r0*A_P16 + p0 + tk];
                a[mt][1] = As[(r0+8)*A_P16 + p0 + tk];
                a[mt][2] = As[r0*A_P16 + p0 + 4 + tk];
                a[mt][3] = As[(r0+8)*A_P16 + p0 + 4 + tk];
            }
            uint32_t b[4][2];
            #pragma unroll
            for (int nt = 0; nt < 4; nt++) {
                int col = wn*32 + nt*8 + g;
                b[nt][0] = Bs[col*B_P16 + p0 + tk];
                b[nt][1] = Bs[col*B_P16 + p0 + 4 + tk];
            }
            #pragma unroll
            for (int mt = 0; mt < 4; mt++)
                #pragma unroll
                for (int nt = 0; nt < 4; nt++)
                    mma_f16(acc[mt][nt], a[mt][0], a[mt][1], a[mt][2], a[mt][3],
                            b[nt][0], b[nt][1]);
        }
    }

    // ---- k-split reduction: wk=1 partials -> wk=0 via SMEM ----
    __syncthreads();
    float* red = (float*)dynsmem;     // [64 idx][4 pairs * 32 lanes] = 32 KB
    int pairIdx = wm*2 + wn;
    if (wk == 1) {
        #pragma unroll
        for (int mt = 0; mt < 4; mt++)
            #pragma unroll
            for (int nt = 0; nt < 4; nt++)
                #pragma unroll
                for (int c = 0; c < 4; c++) {
                    int idx = (mt*4 + nt)*4 + c;
                    red[idx*128 + pairIdx*32 + lane] = acc[mt][nt][c];
                }
    }
    __syncthreads();
    if (wk == 0) {
        #pragma unroll
        for (int mt = 0; mt < 4; mt++)
            #pragma unroll
            for (int nt = 0; nt < 4; nt++)
                #pragma unroll
                for (int c = 0; c < 4; c++) {
                    int idx = (mt*4 + nt)*4 + c;
                    acc[mt][nt][c] += red[idx*128 + pairIdx*32 + lane];
                }

        #pragma unroll
        for (int mt = 0; mt < 4; mt++) {
            #pragma unroll
            for (int nt = 0; nt < 4; nt++) {
                int mbase = m0 + wm*64 + mt*16 + g;
                int nbase = n0 + wn*32 + nt*8 + (tk << 1);
                #pragma unroll
                for (int c = 0; c < 4; c++) {
                    int m = mbase + ((c >> 1) << 3);
                    int n = nbase + (c & 1);
                    if (m >= M) continue;
                    float v = acc[mt][nt][c];
                    if (bias) v += bias[n];
                    if (mode == 0) {
                        size_t idx = (size_t)m*N + n;
                        if (res) v += res[idx];
                        C[idx] = v;
                        if (C16) C16[idx] = __float2half(v);
                    } else {
                        size_t idx = ((size_t)(m >> 10)*CC + n)*HWP + (m & 1023);
                        C[idx] = v + res[idx];
                    }
                }
            }
        }
    }
}

// ---------------- flash-style masked self-attention (tf32 MMA, fp16 output) ----------------
#define AT_TQ 64
#define AT_TK 64
#define KV_PAD 44
#define PS_PAD 68

__global__ __launch_bounds__(256) void self_attn_mma_kernel(
    const float* __restrict__ Q, const float* __restrict__ K,
    const float* __restrict__ V, const unsigned int* __restrict__ mask,
    __half* __restrict__ O)
{
    __shared__ uint32_t Ks[AT_TK][KV_PAD];
    __shared__ uint32_t Vs[AT_TK][KV_PAD];
    __shared__ uint32_t Ps[AT_TQ][PS_PAD];
    __shared__ float sm_m[64], sm_l[64], sm_alpha[64];
    __shared__ float smx[2][64], ssum[2][64];

    int b = blockIdx.z, h = blockIdx.y, q0 = blockIdx.x * AT_TQ;
    int tid = threadIdx.x, lane = tid & 31, w = tid >> 5;
    int wm = w >> 1, wn = w & 1;
    int g = lane >> 2, tk = lane & 3;
    int r_lo = wm*16 + g, r_hi = r_lo + 8;

    const float scale = rsqrtf((float)DHEAD);

    for (int i = tid; i < AT_TQ*DHEAD; i += 256) {
        int r = i / DHEAD, c = i % DHEAD;
        Ps[r][c] = __float_as_uint(Q[((size_t)b*HWP + q0 + r)*CC + h*DHEAD + c] * scale);
    }
    if (tid < 64) { sm_m[tid] = NEGMAX; sm_l[tid] = 0.f; }
    __syncthreads();

    uint32_t aq[5][4];
    #pragma unroll
    for (int kk = 0; kk < 5; kk++) {
        int kc = kk*8 + tk;
        aq[kk][0] = Ps[r_lo][kc];
        aq[kk][1] = Ps[r_hi][kc];
        aq[kk][2] = Ps[r_lo][kc+4];
        aq[kk][3] = Ps[r_hi][kc+4];
    }

    float o[5][4] = {};

    for (int jt = 0; jt < HWP/AT_TK; jt++) {
        __syncthreads();
        for (int i = tid; i < AT_TK*DHEAD; i += 256) {
            int j = i / DHEAD, c = i % DHEAD;
            size_t base = ((size_t)b*HWP + jt*AT_TK + j)*CC + h*DHEAD + c;
            Ks[j][c] = __float_as_uint(K[base]);
            Vs[j][c] = __float_as_uint(V[base]);
        }
        __syncthreads();

        float s_[4][4] = {};
        #pragma unroll
        for (int kk = 0; kk < 5; kk++) {
            int kc = kk*8 + tk;
            #pragma unroll
            for (int nt = 0; nt < 4; nt++) {
                int jn = wn*32 + nt*8 + g;
                mma_tf32(s_[nt], aq[kk][0], aq[kk][1], aq[kk][2], aq[kk][3],
                         Ks[jn][kc], Ks[jn][kc+4]);
            }
        }

        const unsigned int* mlo_p = mask + ((size_t)b*HWP + q0 + r_lo)*HWP + (size_t)jt*AT_TK;
        const unsigned int* mhi_p = mask + ((size_t)b*HWP + q0 + r_hi)*HWP + (size_t)jt*AT_TK;
        float mlo = NEGMAX, mhi = NEGMAX;
        #pragma unroll
        for (int nt = 0; nt < 4; nt++) {
            int col = wn*32 + nt*8 + tk*2;
            uint2 m0v = *(const uint2*)(mlo_p + col);
            uint2 m1v = *(const uint2*)(mhi_p + col);
            s_[nt][0] = m0v.x ? s_[nt][0] : NEGMAX;
            s_[nt][1] = m0v.y ? s_[nt][1] : NEGMAX;
            s_[nt][2] = m1v.x ? s_[nt][2] : NEGMAX;
            s_[nt][3] = m1v.y ? s_[nt][3] : NEGMAX;
            mlo = fmaxf(mlo, fmaxf(s_[nt][0], s_[nt][1]));
            mhi = fmaxf(mhi, fmaxf(s_[nt][2], s_[nt][3]));
        }
        mlo = fmaxf(mlo, __shfl_xor_sync(0xffffffffu, mlo, 1));
        mlo = fmaxf(mlo, __shfl_xor_sync(0xffffffffu, mlo, 2));
        mhi = fmaxf(mhi, __shfl_xor_sync(0xffffffffu, mhi, 1));
        mhi = fmaxf(mhi, __shfl_xor_sync(0xffffffffu, mhi, 2));
        if (tk == 0) { smx[wn][r_lo] = mlo; smx[wn][r_hi] = mhi; }
        __syncthreads();

        if (tid < 64) {
            float mo = sm_m[tid];
            float mn = fmaxf(mo, fmaxf(smx[0][tid], smx[1][tid]));
            sm_m[tid] = mn;
            sm_alpha[tid] = __expf(mo - mn);
        }
        __syncthreads();

        float mn_lo = sm_m[r_lo], mn_hi = sm_m[r_hi];
        float slo = 0.f, shi = 0.f;
        #pragma unroll
        for (int nt = 0; nt < 4; nt++) {
            int col = wn*32 + nt*8 + tk*2;
            float p0 = __expf(s_[nt][0] - mn_lo);
            float p1 = __expf(s_[nt][1] - mn_lo);
            float p2 = __expf(s_[nt][2] - mn_hi);
            float p3 = __expf(s_[nt][3] - mn_hi);
            slo += p0 + p1; shi += p2 + p3;
            uint2 wlo; wlo.x = __float_as_uint(p0); wlo.y = __float_as_uint(p1);
            uint2 whi; whi.x = __float_as_uint(p2); whi.y = __float_as_uint(p3);
            *(uint2*)&Ps[r_lo][col] = wlo;
            *(uint2*)&Ps[r_hi][col] = whi;
        }
        slo += __shfl_xor_sync(0xffffffffu, slo, 1);
        slo += __shfl_xor_sync(0xffffffffu, slo, 2);
        shi += __shfl_xor_sync(0xffffffffu, shi, 1);
        shi += __shfl_xor_sync(0xffffffffu, shi, 2);
        if (tk == 0) { ssum[wn][r_lo] = slo; ssum[wn][r_hi] = shi; }

        float alo = sm_alpha[r_lo], ahi = sm_alpha[r_hi];
        #pragma unroll
        for (int nt = 0; nt < 5; nt++) {
            o[nt][0] *= alo; o[nt][1] *= alo;
            o[nt][2] *= ahi; o[nt][3] *= ahi;
        }
        __syncthreads();

        if (tid < 64)
            sm_l[tid] = sm_alpha[tid]*sm_l[tid] + ssum[0][tid] + ssum[1][tid];

        #pragma unroll
        for (int kk = 0; kk < 4; kk++) {
            int kb = wn*32 + kk*8;
            uint32_t a0 = Ps[r_lo][kb+tk];
            uint32_t a1 = Ps[r_hi][kb+tk];
            uint32_t a2 = Ps[r_lo][kb+4+tk];
            uint32_t a3 = Ps[r_hi][kb+4+tk];
            #pragma unroll
            for (int nt = 0; nt < 5; nt++) {
                mma_tf32(o[nt], a0, a1, a2, a3,
                         Vs[kb+tk][nt*8+g], Vs[kb+4+tk][nt*8+g]);
            }
        }
    }
    __syncthreads();

    if (wn == 1) {
        #pragma unroll
        for (int nt = 0; nt < 5; nt++) {
            int c = nt*8 + tk*2;
            Ps[r_lo][c]   = __float_as_uint(o[nt][0]);
            Ps[r_lo][c+1] = __float_as_uint(o[nt][1]);
            Ps[r_hi][c]   = __float_as_uint(o[nt][2]);
            Ps[r_hi][c+1] = __float_as_uint(o[nt][3]);
        }
    }
    __syncthreads();
    if (wn == 0) {
        float il_lo = 1.f / sm_l[r_lo];
        float il_hi = 1.f / sm_l[r_hi];
        __half* out_lo = O + ((size_t)b*HWP + q0 + r_lo)*CC + h*DHEAD;
        __half* out_hi = O + ((size_t)b*HWP + q0 + r_hi)*CC + h*DHEAD;
        #pragma unroll
        for (int nt = 0; nt < 5; nt++) {
            int c = nt*8 + tk*2;
            float v0 = (o[nt][0] + __uint_as_float(Ps[r_lo][c]))   * il_lo;
            float v1 = (o[nt][1] + __uint_as_float(Ps[r_lo][c+1])) * il_lo;
            float v2 = (o[nt][2] + __uint_as_float(Ps[r_hi][c]))   * il_hi;
            float v3 = (o[nt][3] + __uint_as_float(Ps[r_hi][c+1])) * il_hi;
            *(__half2*)(out_lo + c) = __floats2half2_rn(v0, v1);
            *(__half2*)(out_hi + c) = __floats2half2_rn(v2, v3);
        }
    }
}

// ---------------- masked cross-attention (keys = 77, fp16 output) ----------------
#define QT2 16
__global__ __launch_bounds__(256) void cross_attn_kernel(
    const float* __restrict__ Q, const float* __restrict__ Kc,
    const float* __restrict__ Vc, const unsigned int* __restrict__ mask,
    __half* __restrict__ O)
{
    __shared__ float sk[CTX][DHEAD];
    __shared__ float sv[CTX][DHEAD];
    __shared__ float sq[QT2][DHEAD];
    __shared__ float sc[QT2][CTX+3];
    int b = blockIdx.z, h = blockIdx.y, q0 = blockIdx.x * QT2;
    int tid = threadIdx.x;

    for (int i = tid; i < CTX*DHEAD; i += 256) {
        int r = i / DHEAD, d = i % DHEAD;
        sk[r][d] = Kc[((size_t)b*CTX + r)*CC + h*DHEAD + d];
        sv[r][d] = Vc[((size_t)b*CTX + r)*CC + h*DHEAD + d];
    }
    for (int i = tid; i < QT2*DHEAD; i += 256) {
        int r = i / DHEAD, d = i % DHEAD;
        sq[r][d] = Q[((size_t)b*HWP + q0 + r)*CC + h*DHEAD + d];
    }
    __syncthreads();

    const float scale = rsqrtf((float)DHEAD);
    for (int idx = tid; idx < QT2*CTX; idx += 256) {
        int qi = idx / CTX, j = idx % CTX;
        float s = 0.f;
        #pragma unroll
        for (int d = 0; d < DHEAD; d++) s += sq[qi][d]*sk[j][d];
        unsigned int m = mask[((size_t)b*HWP + q0 + qi)*CTX + j];
        sc[qi][j] = (m != 0u) ? s*scale : NEGMAX;
    }
    __syncthreads();

    if (tid < QT2) {
        int qi = tid;
        float mx = NEGMAX;
        for (int j = 0; j < CTX; j++) mx = fmaxf(mx, sc[qi][j]);
        float sum = 0.f;
        for (int j = 0; j < CTX; j++) { float e = __expf(sc[qi][j]-mx); sc[qi][j] = e; sum += e; }
        float inv = 1.f/sum;
        for (int j = 0; j < CTX; j++) sc[qi][j] *= inv;
    }
    __syncthreads();

    for (int idx = tid; idx < QT2*DHEAD; idx += 256) {
        int qi = idx / DHEAD, d = idx % DHEAD;
        float s = 0.f;
        #pragma unroll
        for (int j = 0; j < CTX; j++) s += sc[qi][j]*sv[j][d];
        O[((size_t)b*HWP + q0 + qi)*CC + h*DHEAD + d] = __float2half(s);
    }
}

// ---------------- GEGLU: u = a * gelu_exact(g) -> fp16 ----------------
__global__ __launch_bounds__(256) void geglu_kernel(
    const float* __restrict__ Y, __half* __restrict__ U)
{
    size_t i = (size_t)blockIdx.x*256 + threadIdx.x;
    if (i >= (size_t)MROWS*FFI) return;
    size_t m = i / FFI, c = i % FFI;
    float a = Y[m*2*FFI + c];
    float g = Y[m*2*FFI + FFI + c];
    float ge = 0.5f * g * (1.f + erff(g * 0.70710678118654752f));
    U[i] = __float2half(a * ge);
}

// ---------------- host orchestration ----------------
static inline void run_gemm1(const __half* A, const __half* B, const float* bias,
                             const float* res, float* C, __half* C16,
                             int M, int N, int K, int mode)
{
    int nblk = N / GBN;
    dim3 grid(nblk, (M + GBM - 1) / GBM);
    mma_gemm_kernel<<<grid, 256, GEMM_SMEM_BYTES>>>(
        A, B, nullptr, nullptr, bias, res, C, nullptr, nullptr, C16, M, N, K, mode, nblk);
}

static inline void run_gemm3(const __half* A,
                             const __half* B0, const __half* B1, const __half* B2,
                             float* C0, float* C1, float* C2,
                             int M, int N, int K, int nmat)
{
    int nblk = N / GBN;
    dim3 grid(nblk * nmat, (M + GBM - 1) / GBM);
    mma_gemm_kernel<<<grid, 256, GEMM_SMEM_BYTES>>>(
        A, B0, B1, B2, nullptr, nullptr, C0, C1, C2, nullptr, M, N, K, 0, nblk);
}

extern "C" void kernel_launch(void* const* d_in, const int* in_sizes, int n_in,
                              void* d_out, int out_size)
{
    const float* x         = (const float*)d_in[0];
    const float* context   = (const float*)d_in[1];
    const unsigned int* vis_mask = (const unsigned int*)d_in[2];
    const unsigned int* v2t_mask = (const unsigned int*)d_in[3];
    const float* gn_scale  = (const float*)d_in[4];
    const float* gn_bias   = (const float*)d_in[5];
    const float* proj_in_w = (const float*)d_in[6];
    const float* proj_in_b = (const float*)d_in[7];
    const float* n1_s = (const float*)d_in[8];
    const float* n1_b = (const float*)d_in[9];
    const float* wq1  = (const float*)d_in[10];
    const float* wk1  = (const float*)d_in[11];
    const float* wv1  = (const float*)d_in[12];
    const float* wo1  = (const float*)d_in[13];
    const float* bo1  = (const float*)d_in[14];
    const float* n2_s = (const float*)d_in[15];
    const float* n2_b = (const float*)d_in[16];
    const float* wq2  = (const float*)d_in[17];
    const float* wk2  = (const float*)d_in[18];
    const float* wv2  = (const float*)d_in[19];
    const float* wo2  = (const float*)d_in[20];
    const float* bo2  = (const float*)d_in[21];
    const float* n3_s = (const float*)d_in[22];
    const float* n3_b = (const float*)d_in[23];
    const float* ff_w1 = (const float*)d_in[24];
    const float* ff_b1 = (const float*)d_in[25];
    const float* ff_w2 = (const float*)d_in[26];
    const float* ff_b2 = (const float*)d_in[27];
    const float* proj_out_w = (const float*)d_in[28];
    const float* proj_out_b = (const float*)d_in[29];
    float* out = (float*)d_out;

    cudaFuncSetAttribute(mma_gemm_kernel,
                         cudaFuncAttributeMaxDynamicSharedMemorySize, GEMM_SMEM_BYTES);

    float *h, *q, *k, *v, *ff1;
    __half *gn16, *ln16, *ao16, *ffu16, *ctx16, *h16, *wt16;
    cudaGetSymbolAddress((void**)&h,    g_h);
    cudaGetSymbolAddress((void**)&q,    g_q);
    cudaGetSymbolAddress((void**)&k,    g_k);
    cudaGetSymbolAddress((void**)&v,    g_v);
    cudaGetSymbolAddress((void**)&ff1,  g_ff1);
    cudaGetSymbolAddress((void**)&gn16, g_gn16);
    cudaGetSymbolAddress((void**)&ln16, g_ln16);
    cudaGetSymbolAddress((void**)&ao16, g_ao16);
    cudaGetSymbolAddress((void**)&ffu16,g_ffu16);
    cudaGetSymbolAddress((void**)&ctx16,g_ctx16);
    cudaGetSymbolAddress((void**)&h16,  g_h16);
    cudaGetSymbolAddress((void**)&wt16, g_wt16);

    // 0a. transpose all weight matrices to fp16 [N][K]
    {
        TransDesc td;
        const float* srcs[12] = {proj_in_w, wq1, wk1, wv1, wo1, wq2, wo2, proj_out_w,
                                 wk2, wv2, ff_w1, ff_w2};
        __half* dsts[12] = {wt16+OFF_PIN, wt16+OFF_Q1, wt16+OFF_K1, wt16+OFF_V1, wt16+OFF_O1,
                            wt16+OFF_Q2, wt16+OFF_O2, wt16+OFF_POUT, wt16+OFF_K2, wt16+OFF_V2,
                            wt16+OFF_FF1, wt16+OFF_FF2};
        int Ks[12] = {CC,CC,CC,CC,CC,CC,CC,CC, CTXD,CTXD, CC, FFI};
        int Ns[12] = {CC,CC,CC,CC,CC,CC,CC,CC, CC,CC, 2*FFI, CC};
        int acc = 0;
        for (int i = 0; i < 12; i++) {
            td.src[i] = srcs[i]; td.dst[i] = dsts[i];
            td.K[i] = Ks[i]; td.N[i] = Ns[i];
            td.start[i] = acc;
            acc += (Ks[i]/32) * (Ns[i]/32);
        }
        td.start[12] = acc;
        transpose_all_kernel<<<acc, 256>>>(td);
    }
    // 0b. context -> fp16
    {
        int n = BB*CTX*CTXD;
        f2h_kernel<<<(n + 255)/256, 256>>>(context, ctx16, n);
    }

    // 1. GroupNorm + transpose to [B, HW, C] (fp16)
    groupnorm_kernel<<<BB*32, 256>>>(x, gn_scale, gn_bias, gn16);
    // 2. proj_in
    run_gemm1(gn16, wt16+OFF_PIN, proj_in_b, nullptr, h, nullptr, MROWS, CC, CC, 0);
    // 3. LN1 (fp16 out)
    layernorm_kernel<<<MROWS, CC>>>(h, n1_s, n1_b, ln16);
    // 4. fused q,k,v (self)
    run_gemm3(ln16, wt16+OFF_Q1, wt16+OFF_K1, wt16+OFF_V1, q, k, v, MROWS, CC, CC, 3);
    // 5. masked self-attention (flash tf32 MMA, fp16 out)
    {
        dim3 grid(HWP/AT_TQ, NHEADS, BB);
        self_attn_mma_kernel<<<grid, 256>>>(q, k, v, vis_mask, ao16);
    }
    // 6. out-proj + residual
    run_gemm1(ao16, wt16+OFF_O1, bo1, h, h, nullptr, MROWS, CC, CC, 0);
    // 7. LN2
    layernorm_kernel<<<MROWS, CC>>>(h, n2_s, n2_b, ln16);
    // 8. q (cross)
    run_gemm1(ln16, wt16+OFF_Q2, nullptr, nullptr, q, nullptr, MROWS, CC, CC, 0);
    // 9. fused k,v from context
    run_gemm3(ctx16, wt16+OFF_K2, wt16+OFF_V2, nullptr, k, v, nullptr, BB*CTX, CC, CTXD, 2);
    // 10. masked cross-attention (fp16 out)
    {
        dim3 grid(HWP/QT2, NHEADS, BB);
        cross_attn_kernel<<<grid, 256>>>(q, k, v, v2t_mask, ao16);
    }
    // 11. out-proj + residual
    run_gemm1(ao16, wt16+OFF_O2, bo2, h, h, nullptr, MROWS, CC, CC, 0);
    // 12. LN3
    layernorm_kernel<<<MROWS, CC>>>(h, n3_s, n3_b, ln16);
    // 13. FF up (GEGLU input)
    run_gemm1(ln16, wt16+OFF_FF1, ff_b1, nullptr, ff1, nullptr, MROWS, 2*FFI, CC, 0);
    // 14. GEGLU (fp16 out)
    {
        size_t n = (size_t)MROWS*FFI;
        geglu_kernel<<<(unsigned)((n + 255)/256), 256>>>(ff1, ffu16);
    }
    // 15. FF down + residual (also emit fp16 copy of h for final proj)
    run_gemm1(ffu16, wt16+OFF_FF2, ff_b2, h, h, h16, MROWS, CC, FFI, 0);
    // 16. proj_out + transpose back to [B,C,H,W] + input residual
    run_gemm1(h16, wt16+OFF_POUT, proj_out_b, x, out, nullptr, MROWS, CC, CC, 1);
}

// round 11
// speedup vs baseline: 4.2589x; 1.0129x over previous
#include <cuda_runtime.h>
#include <cuda_fp16.h>
#include <math.h>
#include <stdint.h>

// ---------------- problem constants ----------------
#define BB      8
#define CC      320
#define HWP     1024
#define NHEADS  8
#define DHEAD   40
#define CTX     77
#define CTXD    768
#define FFI     1280          // FF_INNER
#define MROWS   (BB*HWP)      // 8192
#define NEGMAX  (-3.402823466e38f)

// ---------------- scratch (device globals; no runtime allocs) ----------------
__device__ float  g_h  [MROWS*CC];
__device__ float  g_q  [MROWS*CC];
__device__ float  g_k  [MROWS*CC];
__device__ float  g_v  [MROWS*CC];
__device__ float  g_ff1[MROWS*2*FFI];
__device__ __half g_gn16 [MROWS*CC];
__device__ __half g_ln16 [MROWS*CC];
__device__ __half g_ao16 [MROWS*CC];
__device__ __half g_ffu16[(size_t)MROWS*FFI];
__device__ __half g_ctx16[BB*CTX*CTXD];
__device__ __half g_h16  [MROWS*CC];
__device__ __half g_wt16 [2539520];        // transposed weights [N][K], fp16

// offsets into g_wt16 (halves)
#define OFF_PIN  0
#define OFF_Q1   102400
#define OFF_K1   204800
#define OFF_V1   307200
#define OFF_O1   409600
#define OFF_Q2   512000
#define OFF_O2   614400
#define OFF_POUT 716800
#define OFF_K2   819200
#define OFF_V2   1064960
#define OFF_FF1  1310720
#define OFF_FF2  2129920

__device__ __forceinline__ uint32_t h2_to_u32(__half2 h) {
    union { __half2 h2; uint32_t u; } cvt;
    cvt.h2 = h;
    return cvt.u;
}

// ---------------- block reductions ----------------
__device__ __forceinline__ float blockReduceSum(float v, float* scratch) {
    int lane = threadIdx.x & 31, wid = threadIdx.x >> 5;
    #pragma unroll
    for (int o = 16; o > 0; o >>= 1) v += __shfl_down_sync(0xffffffffu, v, o);
    if (lane == 0) scratch[wid] = v;
    __syncthreads();
    int nw = (blockDim.x + 31) >> 5;
    v = (threadIdx.x < nw) ? scratch[threadIdx.x] : 0.f;
    if (wid == 0) {
        #pragma unroll
        for (int o = 16; o > 0; o >>= 1) v += __shfl_down_sync(0xffffffffu, v, o);
        if (lane == 0) scratch[0] = v;
    }
    __syncthreads();
    v = scratch[0];
    __syncthreads();
    return v;
}

// ---------------- GroupNorm -> fp16 [B,HW,C] ----------------
__global__ __launch_bounds__(256) void groupnorm_kernel(
    const float* __restrict__ x, const float* __restrict__ scale,
    const float* __restrict__ bias, __half* __restrict__ out)
{
    __shared__ float scratch[32];
    __shared__ float s_mu, s_inv;
    int b = blockIdx.x >> 5, g = blockIdx.x & 31;
    const float* xp = x + ((size_t)b*CC + g*10) * HWP;
    float sum = 0.f, sq = 0.f;
    for (int i = threadIdx.x; i < 10*HWP; i += 256) { float v = xp[i]; sum += v; sq += v*v; }
    sum = blockReduceSum(sum, scratch);
    sq  = blockReduceSum(sq,  scratch);
    if (threadIdx.x == 0) {
        float mu  = sum * (1.f/10240.f);
        float var = sq * (1.f/10240.f) - mu*mu;
        s_mu = mu; s_inv = rsqrtf(var + 1e-6f);
    }
    __syncthreads();
    float mu = s_mu, inv = s_inv;
    for (int i = threadIdx.x; i < 10*HWP; i += 256) {
        int cl = i >> 10, p = i & 1023;
        int c = g*10 + cl;
        float xn = (xp[i] - mu) * inv;
        out[((size_t)b*HWP + p)*CC + c] = __float2half(xn * scale[c] + bias[c]);
    }
}

// ---------------- LayerNorm over last dim = 320 -> fp16 ----------------
__global__ __launch_bounds__(CC) void layernorm_kernel(
    const float* __restrict__ X, const float* __restrict__ s,
    const float* __restrict__ bpar, __half* __restrict__ Y)
{
    __shared__ float scratch[32];
    int row = blockIdx.x, t = threadIdx.x;
    float v = X[(size_t)row*CC + t];
    float mu = blockReduceSum(v, scratch) * (1.f/CC);
    float d = v - mu;
    float var = blockReduceSum(d*d, scratch) * (1.f/CC);
    Y[(size_t)row*CC + t] = __float2half(d * rsqrtf(var + 1e-5f) * s[t] + bpar[t]);
}

// ---------------- weight transpose to fp16 [N][K] (with optional scale) ----------------
struct TransDesc {
    const float* src[12];
    __half* dst[12];
    float scl[12];
    int K[12], N[12];
    int start[13];
};

__global__ __launch_bounds__(256) void transpose_all_kernel(TransDesc p) {
    __shared__ float t[32][33];
    int bid = blockIdx.x;
    int i = 0;
    while (bid >= p.start[i+1]) i++;
    const float* src = p.src[i];
    __half* dst = p.dst[i];
    float scl = p.scl[i];
    int K = p.K[i], N = p.N[i];
    int lt = bid - p.start[i];
    int tiles_n = N >> 5;
    int tk = lt / tiles_n, tn = lt - tk*tiles_n;
    int tx = threadIdx.x & 31, ty = threadIdx.x >> 5;   // 32 x 8
    #pragma unroll
    for (int j = 0; j < 32; j += 8)
        t[ty+j][tx] = src[(size_t)(tk*32+ty+j)*N + tn*32 + tx];
    __syncthreads();
    #pragma unroll
    for (int j = 0; j < 32; j += 8)
        dst[(size_t)(tn*32+ty+j)*K + tk*32 + tx] = __float2half(t[tx][ty+j] * scl);
}

// ---------------- context -> fp16 ----------------
__global__ __launch_bounds__(256) void f2h_kernel(
    const float* __restrict__ src, __half* __restrict__ dst, int n)
{
    int i = blockIdx.x*256 + threadIdx.x;
    if (i < n) dst[i] = __float2half(src[i]);
}

// ---------------- mma helpers ----------------
__device__ __forceinline__ void mma_f16(float c[4], uint32_t a0, uint32_t a1,
                                        uint32_t a2, uint32_t a3,
                                        uint32_t b0, uint32_t b1) {
    asm volatile(
        "mma.sync.aligned.m16n8k16.row.col.f32.f16.f16.f32 "
        "{%0,%1,%2,%3}, {%4,%5,%6,%7}, {%8,%9}, {%0,%1,%2,%3};"
        : "+f"(c[0]), "+f"(c[1]), "+f"(c[2]), "+f"(c[3])
        : "r"(a0), "r"(a1), "r"(a2), "r"(a3), "r"(b0), "r"(b1));
}

__device__ __forceinline__ void cp_async16(void* smem_dst, const void* gsrc, int src_bytes) {
    uint32_t s = (uint32_t)__cvta_generic_to_shared(smem_dst);
    asm volatile("cp.async.cg.shared.global [%0], [%1], 16, %2;"
                 :: "r"(s), "l"(gsrc), "r"(src_bytes));
}
#define CP_COMMIT()  asm volatile("cp.async.commit_group;")
#define CP_WAIT1()   asm volatile("cp.async.wait_group 1;")

// ---------------- fp16 tensor-core GEMM (cp.async 3-stage, 2x2x2 k-split) ----------------
// C[mat] = A16 @ Bt16[mat]^T (+bias) (+res). A16 [M][K] fp16, Bt16 [N][K] fp16.
// N%64==0, K%64==0; M arbitrary.
// mode 0: fp32 out (+optional fp16 copy C16); mode 1: final transposed store; mode 2: fp16-only out (C reinterpreted).
#define GBM 128
#define GBN 64
#define GBK 64
#define A_P16 36
#define B_P16 36
#define STAGES 3
#define GEMM_SMEM_BYTES ((STAGES*(GBM*A_P16 + GBN*B_P16))*4)

__global__ __launch_bounds__(256, 2) void mma_gemm_kernel(
    const __half* __restrict__ A,
    const __half* __restrict__ B0, const __half* __restrict__ B1, const __half* __restrict__ B2,
    const float* __restrict__ bias, const float* __restrict__ res,
    float* __restrict__ C0, float* __restrict__ C1, float* __restrict__ C2,
    __half* __restrict__ C16,
    int M, int N, int K, int mode, int nblk)
{
    extern __shared__ uint32_t dynsmem[];
    uint32_t* AsBase = dynsmem;
    uint32_t* BsBase = dynsmem + STAGES*GBM*A_P16;

    int mat = blockIdx.x / nblk;
    const __half* B = (mat == 0) ? B0 : ((mat == 1) ? B1 : B2);
    float* C        = (mat == 0) ? C0 : ((mat == 1) ? C1 : C2);
    int n0 = (blockIdx.x - mat*nblk) * GBN;

    int tid = threadIdx.x;
    int lane = tid & 31, warp = tid >> 5;
    int wm = (warp >> 2) & 1, wn = (warp >> 1) & 1, wk = warp & 1;
    int m0 = blockIdx.y * GBM;

    float acc[4][4][4];
    #pragma unroll
    for (int i = 0; i < 4; i++)
        #pragma unroll
        for (int j = 0; j < 4; j++)
            #pragma unroll
            for (int c = 0; c < 4; c++) acc[i][j][c] = 0.f;

    int g = lane >> 2, tk = lane & 3;

    int a_row = tid >> 3, a_ch = tid & 7;
    int b_row = tid >> 3, b_ch = tid & 7;

    int KT = K / GBK;

    auto prefetch = [&](int kt, int buf) {
        uint32_t* As = AsBase + buf*GBM*A_P16;
        uint32_t* Bs = BsBase + buf*GBN*B_P16;
        int k0 = kt * GBK;
        #pragma unroll
        for (int j = 0; j < 4; j++) {
            int row = a_row + j*32;
            int gr = m0 + row;
            const __half* src = A + ((gr < M) ? ((size_t)gr*K + k0 + a_ch*8) : 0);
            cp_async16(&As[row*A_P16 + a_ch*4], src, (gr < M) ? 16 : 0);
        }
        #pragma unroll
        for (int j = 0; j < 2; j++) {
            int row = b_row + j*32;
            cp_async16(&Bs[row*B_P16 + b_ch*4],
                       B + (size_t)(n0 + row)*K + k0 + b_ch*8, 16);
        }
        CP_COMMIT();
    };

    prefetch(0, 0);
    prefetch(1, 1);

    for (int kt = 0; kt < KT; kt++) {
        CP_WAIT1();
        __syncthreads();
        if (kt + 2 < KT) prefetch(kt+2, (kt+2) % STAGES);
        else CP_COMMIT();

        int buf = kt % STAGES;
        uint32_t* As = AsBase + buf*GBM*A_P16;
        uint32_t* Bs = BsBase + buf*GBN*B_P16;

        #pragma unroll
        for (int s = 0; s < 2; s++) {
            int p0 = wk*16 + s*8;
            uint32_t a[4][4];
            #pragma unroll
            for (int mt = 0; mt < 4; mt++) {
                int r0 = wm*64 + mt*16 + g;
                a[mt][0] = As[r0*A_P16 + p0 + tk];
                a[mt][1] = As[(r0+8)*A_P16 + p0 + tk];
                a[mt][2] = As[r0*A_P16 + p0 + 4 + tk];
                a[mt][3] = As[(r0+8)*A_P16 + p0 + 4 + tk];
            }
            uint32_t b[4][2];
            #pragma unroll
            for (int nt = 0; nt < 4; nt++) {
                int col = wn*32 + nt*8 + g;
                b[nt][0] = Bs[col*B_P16 + p0 + tk];
                b[nt][1] = Bs[col*B_P16 + p0 + 4 + tk];
            }
            #pragma unroll
            for (int mt = 0; mt < 4; mt++)
                #pragma unroll
                for (int nt = 0; nt < 4; nt++)
                    mma_f16(acc[mt][nt], a[mt][0], a[mt][1], a[mt][2], a[mt][3],
                            b[nt][0], b[nt][1]);
        }
    }

    __syncthreads();
    float* red = (float*)dynsmem;
    int pairIdx = wm*2 + wn;
    if (wk == 1) {
        #pragma unroll
        for (int mt = 0; mt < 4; mt++)
            #pragma unroll
            for (int nt = 0; nt < 4; nt++)
                #pragma unroll
                for (int c = 0; c < 4; c++) {
                    int idx = (mt*4 + nt)*4 + c;
                    red[idx*128 + pairIdx*32 + lane] = acc[mt][nt][c];
                }
    }
    __syncthreads();
    if (wk == 0) {
        #pragma unroll
        for (int mt = 0; mt < 4; mt++)
            #pragma unroll
            for (int nt = 0; nt < 4; nt++)
                #pragma unroll
                for (int c = 0; c < 4; c++) {
                    int idx = (mt*4 + nt)*4 + c;
                    acc[mt][nt][c] += red[idx*128 + pairIdx*32 + lane];
                }

        #pragma unroll
        for (int mt = 0; mt < 4; mt++) {
            #pragma unroll
            for (int nt = 0; nt < 4; nt++) {
                int mbase = m0 + wm*64 + mt*16 + g;
                int nbase = n0 + wn*32 + nt*8 + (tk << 1);
                #pragma unroll
                for (int c = 0; c < 4; c++) {
                    int m = mbase + ((c >> 1) << 3);
                    int n = nbase + (c & 1);
                    if (m >= M) continue;
                    float v = acc[mt][nt][c];
                    if (bias) v += bias[n];
                    if (mode == 0) {
                        size_t idx = (size_t)m*N + n;
                        if (res) v += res[idx];
                        C[idx] = v;
                        if (C16) C16[idx] = __float2half(v);
                    } else if (mode == 2) {
                        ((__half*)C)[(size_t)m*N + n] = __float2half(v);
                    } else {
                        size_t idx = ((size_t)(m >> 10)*CC + n)*HWP + (m & 1023);
                        C[idx] = v + res[idx];
                    }
                }
            }
        }
    }
}

// ---------------- flash-style masked self-attention (fp16 MMA m16n8k16) ----------------
// Q pre-scaled (scale folded into wq1). Q,K,V fp16 [row][CC] slices per head.
#define AQ_PAD 28   // uint32 pairs per Q/K row (20 real + 8 zero-pad)
#define AV_PAD 36   // uint32 pairs per V^T row (32 real + 4 pad)
#define AP_PAD 36   // uint32 pairs per P row (32 real + 4 pad)

__global__ __launch_bounds__(256) void self_attn_f16_kernel(
    const __half* __restrict__ Q, const __half* __restrict__ K,
    const __half* __restrict__ V, const unsigned int* __restrict__ mask,
    __half* __restrict__ O)
{
    __shared__ uint32_t Qs[64][AQ_PAD];
    __shared__ uint32_t Ks[64][AQ_PAD];
    __shared__ uint32_t Vs[DHEAD][AV_PAD];   // V^T: [dhead][keys] halves
    __shared__ uint32_t Ps[64][AP_PAD];
    __shared__ float comb[64][41];
    __shared__ float sm_m[64], sm_l[64], sm_alpha[64];
    __shared__ float smx[2][64], ssum[2][64];

    int b = blockIdx.z, h = blockIdx.y, q0 = blockIdx.x * 64;
    int tid = threadIdx.x, lane = tid & 31, w = tid >> 5;
    int wm = w >> 1, wn = w & 1;
    int g = lane >> 2, tk = lane & 3;
    int r_lo = wm*16 + g, r_hi = r_lo + 8;

    // zero Q/K tiles (pads persist as zero)
    for (int i = tid; i < 64*AQ_PAD; i += 256) {
        Qs[i/AQ_PAD][i%AQ_PAD] = 0;
        Ks[i/AQ_PAD][i%AQ_PAD] = 0;
    }
    // stage Q (already scaled): 20 u32 pairs per row
    {
        const uint32_t* qb = (const uint32_t*)Q;
        for (int i = tid; i < 64*20; i += 256) {
            int r = i/20, p = i%20;
            Qs[r][p] = qb[(((size_t)b*HWP + q0 + r)*CC + h*DHEAD)/2 + p];
        }
    }
    if (tid < 64) { sm_m[tid] = NEGMAX; sm_l[tid] = 0.f; }
    __syncthreads();

    uint32_t aq[3][4];
    #pragma unroll
    for (int s = 0; s < 3; s++) {
        aq[s][0] = Qs[r_lo][s*8 + tk];
        aq[s][1] = Qs[r_hi][s*8 + tk];
        aq[s][2] = Qs[r_lo][s*8 + 4 + tk];
        aq[s][3] = Qs[r_hi][s*8 + 4 + tk];
    }

    float o[5][4] = {};

    for (int jt = 0; jt < HWP/64; jt++) {
        __syncthreads();
        {
            const uint32_t* kb = (const uint32_t*)K;
            for (int i = tid; i < 64*20; i += 256) {
                int j = i/20, p = i%20;
                Ks[j][p] = kb[(((size_t)b*HWP + jt*64 + j)*CC + h*DHEAD)/2 + p];
            }
            const __half* vb = V + ((size_t)b*HWP + jt*64)*CC + h*DHEAD;
            __half* vsh = (__half*)Vs;
            for (int i = tid; i < 64*DHEAD; i += 256) {
                int j = i/DHEAD, c = i%DHEAD;
                vsh[c*(2*AV_PAD) + j] = vb[(size_t)j*CC + c];
            }
        }
        __syncthreads();

        // S = Q K^T (3 k16 steps)
        float s_[4][4] = {};
        #pragma unroll
        for (int s = 0; s < 3; s++) {
            #pragma unroll
            for (int nt = 0; nt < 4; nt++) {
                int jn = wn*32 + nt*8 + g;
                mma_f16(s_[nt], aq[s][0], aq[s][1], aq[s][2], aq[s][3],
                        Ks[jn][s*8 + tk], Ks[jn][s*8 + 4 + tk]);
            }
        }

        // mask + row max
        const unsigned int* mlo_p = mask + ((size_t)b*HWP + q0 + r_lo)*HWP + (size_t)jt*64;
        const unsigned int* mhi_p = mask + ((size_t)b*HWP + q0 + r_hi)*HWP + (size_t)jt*64;
        float mlo = NEGMAX, mhi = NEGMAX;
        #pragma unroll
        for (int nt = 0; nt < 4; nt++) {
            int col = wn*32 + nt*8 + tk*2;
            uint2 m0v = *(const uint2*)(mlo_p + col);
            uint2 m1v = *(const uint2*)(mhi_p + col);
            s_[nt][0] = m0v.x ? s_[nt][0] : NEGMAX;
            s_[nt][1] = m0v.y ? s_[nt][1] : NEGMAX;
            s_[nt][2] = m1v.x ? s_[nt][2] : NEGMAX;
            s_[nt][3] = m1v.y ? s_[nt][3] : NEGMAX;
            mlo = fmaxf(mlo, fmaxf(s_[nt][0], s_[nt][1]));
            mhi = fmaxf(mhi, fmaxf(s_[nt][2], s_[nt][3]));
        }
        mlo = fmaxf(mlo, __shfl_xor_sync(0xffffffffu, mlo, 1));
        mlo = fmaxf(mlo, __shfl_xor_sync(0xffffffffu, mlo, 2));
        mhi = fmaxf(mhi, __shfl_xor_sync(0xffffffffu, mhi, 1));
        mhi = fmaxf(mhi, __shfl_xor_sync(0xffffffffu, mhi, 2));
        if (tk == 0) { smx[wn][r_lo] = mlo; smx[wn][r_hi] = mhi; }
        __syncthreads();

        if (tid < 64) {
            float mo = sm_m[tid];
            float mn = fmaxf(mo, fmaxf(smx[0][tid], smx[1][tid]));
            sm_m[tid] = mn;
            sm_alpha[tid] = __expf(mo - mn);
        }
        __syncthreads();

        // P = exp(S - m) (fp32), write half2 pairs, row sums
        float mn_lo = sm_m[r_lo], mn_hi = sm_m[r_hi];
        float slo = 0.f, shi = 0.f;
        #pragma unroll
        for (int nt = 0; nt < 4; nt++) {
            int pr = wn*16 + nt*4 + tk;   // pair index
            float p0 = __expf(s_[nt][0] - mn_lo);
            float p1 = __expf(s_[nt][1] - mn_lo);
            float p2 = __expf(s_[nt][2] - mn_hi);
            float p3 = __expf(s_[nt][3] - mn_hi);
            slo += p0 + p1; shi += p2 + p3;
            Ps[r_lo][pr] = h2_to_u32(__floats2half2_rn(p0, p1));
            Ps[r_hi][pr] = h2_to_u32(__floats2half2_rn(p2, p3));
        }
        slo += __shfl_xor_sync(0xffffffffu, slo, 1);
        slo += __shfl_xor_sync(0xffffffffu, slo, 2);
        shi += __shfl_xor_sync(0xffffffffu, shi, 1);
        shi += __shfl_xor_sync(0xffffffffu, shi, 2);
        if (tk == 0) { ssum[wn][r_lo] = slo; ssum[wn][r_hi] = shi; }

        float alo = sm_alpha[r_lo], ahi = sm_alpha[r_hi];
        #pragma unroll
        for (int nt = 0; nt < 5; nt++) {
            o[nt][0] *= alo; o[nt][1] *= alo;
            o[nt][2] *= ahi; o[nt][3] *= ahi;
        }
        __syncthreads();

        if (tid < 64)
            sm_l[tid] = sm_alpha[tid]*sm_l[tid] + ssum[0][tid] + ssum[1][tid];

        // O += P V (2 k16 steps per wn half)
        #pragma unroll
        for (int s2 = 0; s2 < 2; s2++) {
            int pb = wn*16 + s2*8;
            uint32_t a0 = Ps[r_lo][pb + tk];
            uint32_t a1 = Ps[r_hi][pb + tk];
            uint32_t a2 = Ps[r_lo][pb + 4 + tk];
            uint32_t a3 = Ps[r_hi][pb + 4 + tk];
            #pragma unroll
            for (int nt = 0; nt < 5; nt++) {
                int n = nt*8 + g;
                mma_f16(o[nt], a0, a1, a2, a3,
                        Vs[n][pb + tk], Vs[n][pb + 4 + tk]);
            }
        }
    }
    __syncthreads();

    // combine wn halves, normalize, write fp16
    if (wn == 1) {
        #pragma unroll
        for (int nt = 0; nt < 5; nt++) {
            int c = nt*8 + tk*2;
            comb[r_lo][c]   = o[nt][0];
            comb[r_lo][c+1] = o[nt][1];
            comb[r_hi][c]   = o[nt][2];
            comb[r_hi][c+1] = o[nt][3];
        }
    }
    __syncthreads();
    if (wn == 0) {
        float il_lo = 1.f / sm_l[r_lo];
        float il_hi = 1.f / sm_l[r_hi];
        __half* out_lo = O + ((size_t)b*HWP + q0 + r_lo)*CC + h*DHEAD;
        __half* out_hi = O + ((size_t)b*HWP + q0 + r_hi)*CC + h*DHEAD;
        #pragma unroll
        for (int nt = 0; nt < 5; nt++) {
            int c = nt*8 + tk*2;
            float v0 = (o[nt][0] + comb[r_lo][c])   * il_lo;
            float v1 = (o[nt][1] + comb[r_lo][c+1]) * il_lo;
            float v2 = (o[nt][2] + comb[r_hi][c])   * il_hi;
            float v3 = (o[nt][3] + comb[r_hi][c+1]) * il_hi;
            *(__half2*)(out_lo + c) = __floats2half2_rn(v0, v1);
            *(__half2*)(out_hi + c) = __floats2half2_rn(v2, v3);
        }
    }
}

// ---------------- masked cross-attention (keys = 77, fp16 output) ----------------
#define QT2 16
__global__ __launch_bounds__(256) void cross_attn_kernel(
    const float* __restrict__ Q, const float* __restrict__ Kc,
    const float* __restrict__ Vc, const unsigned int* __restrict__ mask,
    __half* __restrict__ O)
{
    __shared__ float sk[CTX][DHEAD];
    __shared__ float sv[CTX][DHEAD];
    __shared__ float sq[QT2][DHEAD];
    __shared__ float sc[QT2][CTX+3];
    int b = blockIdx.z, h = blockIdx.y, q0 = blockIdx.x * QT2;
    int tid = threadIdx.x;

    for (int i = tid; i < CTX*DHEAD; i += 256) {
        int r = i / DHEAD, d = i % DHEAD;
        sk[r][d] = Kc[((size_t)b*CTX + r)*CC + h*DHEAD + d];
        sv[r][d] = Vc[((size_t)b*CTX + r)*CC + h*DHEAD + d];
    }
    for (int i = tid; i < QT2*DHEAD; i += 256) {
        int r = i / DHEAD, d = i % DHEAD;
        sq[r][d] = Q[((size_t)b*HWP + q0 + r)*CC + h*DHEAD + d];
    }
    __syncthreads();

    const float scale = rsqrtf((float)DHEAD);
    for (int idx = tid; idx < QT2*CTX; idx += 256) {
        int qi = idx / CTX, j = idx % CTX;
        float s = 0.f;
        #pragma unroll
        for (int d = 0; d < DHEAD; d++) s += sq[qi][d]*sk[j][d];
        unsigned int m = mask[((size_t)b*HWP + q0 + qi)*CTX + j];
        sc[qi][j] = (m != 0u) ? s*scale : NEGMAX;
    }
    __syncthreads();

    if (tid < QT2) {
        int qi = tid;
        float mx = NEGMAX;
        for (int j = 0; j < CTX; j++) mx = fmaxf(mx, sc[qi][j]);
        float sum = 0.f;
        for (int j = 0; j < CTX; j++) { float e = __expf(sc[qi][j]-mx); sc[qi][j] = e; sum += e; }
        float inv = 1.f/sum;
        for (int j = 0; j < CTX; j++) sc[qi][j] *= inv;
    }
    __syncthreads();

    for (int idx = tid; idx < QT2*DHEAD; idx += 256) {
        int qi = idx / DHEAD, d = idx % DHEAD;
        float s = 0.f;
        #pragma unroll
        for (int j = 0; j < CTX; j++) s += sc[qi][j]*sv[j][d];
        O[((size_t)b*HWP + q0 + qi)*CC + h*DHEAD + d] = __float2half(s);
    }
}

// ---------------- GEGLU: u = a * gelu_exact(g) -> fp16 ----------------
__global__ __launch_bounds__(256) void geglu_kernel(
    const float* __restrict__ Y, __half* __restrict__ U)
{
    size_t i = (size_t)blockIdx.x*256 + threadIdx.x;
    if (i >= (size_t)MROWS*FFI) return;
    size_t m = i / FFI, c = i % FFI;
    float a = Y[m*2*FFI + c];
    float g = Y[m*2*FFI + FFI + c];
    float ge = 0.5f * g * (1.f + erff(g * 0.70710678118654752f));
    U[i] = __float2half(a * ge);
}

// ---------------- host orchestration ----------------
static inline void run_gemm1(const __half* A, const __half* B, const float* bias,
                             const float* res, float* C, __half* C16,
                             int M, int N, int K, int mode)
{
    int nblk = N / GBN;
    dim3 grid(nblk, (M + GBM - 1) / GBM);
    mma_gemm_kernel<<<grid, 256, GEMM_SMEM_BYTES>>>(
        A, B, nullptr, nullptr, bias, res, C, nullptr, nullptr, C16, M, N, K, mode, nblk);
}

static inline void run_gemm3(const __half* A,
                             const __half* B0, const __half* B1, const __half* B2,
                             float* C0, float* C1, float* C2,
                             int M, int N, int K, int nmat, int mode)
{
    int nblk = N / GBN;
    dim3 grid(nblk * nmat, (M + GBM - 1) / GBM);
    mma_gemm_kernel<<<grid, 256, GEMM_SMEM_BYTES>>>(
        A, B0, B1, B2, nullptr, nullptr, C0, C1, C2, nullptr, M, N, K, mode, nblk);
}

extern "C" void kernel_launch(void* const* d_in, const int* in_sizes, int n_in,
                              void* d_out, int out_size)
{
    const float* x         = (const float*)d_in[0];
    const float* context   = (const float*)d_in[1];
    const unsigned int* vis_mask = (const unsigned int*)d_in[2];
    const unsigned int* v2t_mask = (const unsigned int*)d_in[3];
    const float* gn_scale  = (const float*)d_in[4];
    const float* gn_bias   = (const float*)d_in[5];
    const float* proj_in_w = (const float*)d_in[6];
    const float* proj_in_b = (const float*)d_in[7];
    const float* n1_s = (const float*)d_in[8];
    const float* n1_b = (const float*)d_in[9];
    const float* wq1  = (const float*)d_in[10];
    const float* wk1  = (const float*)d_in[11];
    const float* wv1  = (const float*)d_in[12];
    const float* wo1  = (const float*)d_in[13];
    const float* bo1  = (const float*)d_in[14];
    const float* n2_s = (const float*)d_in[15];
    const float* n2_b = (const float*)d_in[16];
    const float* wq2  = (const float*)d_in[17];
    const float* wk2  = (const float*)d_in[18];
    const float* wv2  = (const float*)d_in[19];
    const float* wo2  = (const float*)d_in[20];
    const float* bo2  = (const float*)d_in[21];
    const float* n3_s = (const float*)d_in[22];
    const float* n3_b = (const float*)d_in[23];
    const float* ff_w1 = (const float*)d_in[24];
    const float* ff_b1 = (const float*)d_in[25];
    const float* ff_w2 = (const float*)d_in[26];
    const float* ff_b2 = (const float*)d_in[27];
    const float* proj_out_w = (const float*)d_in[28];
    const float* proj_out_b = (const float*)d_in[29];
    float* out = (float*)d_out;

    cudaFuncSetAttribute(mma_gemm_kernel,
                         cudaFuncAttributeMaxDynamicSharedMemorySize, GEMM_SMEM_BYTES);

    float *h, *q, *k, *v, *ff1;
    __half *gn16, *ln16, *ao16, *ffu16, *ctx16, *h16, *wt16;
    cudaGetSymbolAddress((void**)&h,    g_h);
    cudaGetSymbolAddress((void**)&q,    g_q);
    cudaGetSymbolAddress((void**)&k,    g_k);
    cudaGetSymbolAddress((void**)&v,    g_v);
    cudaGetSymbolAddress((void**)&ff1,  g_ff1);
    cudaGetSymbolAddress((void**)&gn16, g_gn16);
    cudaGetSymbolAddress((void**)&ln16, g_ln16);
    cudaGetSymbolAddress((void**)&ao16, g_ao16);
    cudaGetSymbolAddress((void**)&ffu16,g_ffu16);
    cudaGetSymbolAddress((void**)&ctx16,g_ctx16);
    cudaGetSymbolAddress((void**)&h16,  g_h16);
    cudaGetSymbolAddress((void**)&wt16, g_wt16);

    // 0a. transpose all weight matrices to fp16 [N][K]; fold 1/sqrt(DHEAD) into wq1
    {
        TransDesc td;
        const float* srcs[12] = {proj_in_w, wq1, wk1, wv1, wo1, wq2, wo2, proj_out_w,
                                 wk2, wv2, ff_w1, ff_w2};
        __half* dsts[12] = {wt16+OFF_PIN, wt16+OFF_Q1, wt16+OFF_K1, wt16+OFF_V1, wt16+OFF_O1,
                            wt16+OFF_Q2, wt16+OFF_O2, wt16+OFF_POUT, wt16+OFF_K2, wt16+OFF_V2,
                            wt16+OFF_FF1, wt16+OFF_FF2};
        int Ks[12] = {CC,CC,CC,CC,CC,CC,CC,CC, CTXD,CTXD, CC, FFI};
        int Ns[12] = {CC,CC,CC,CC,CC,CC,CC,CC, CC,CC, 2*FFI, CC};
        int acc = 0;
        float qs = rsqrtf((float)DHEAD);
        for (int i = 0; i < 12; i++) {
            td.src[i] = srcs[i]; td.dst[i] = dsts[i];
            td.scl[i] = (i == 1) ? qs : 1.f;
            td.K[i] = Ks[i]; td.N[i] = Ns[i];
            td.start[i] = acc;
            acc += (Ks[i]/32) * (Ns[i]/32);
        }
        td.start[12] = acc;
        transpose_all_kernel<<<acc, 256>>>(td);
    }
    // 0b. context -> fp16
    {
        int n = BB*CTX*CTXD;
        f2h_kernel<<<(n + 255)/256, 256>>>(context, ctx16, n);
    }

    // 1. GroupNorm + transpose to [B, HW, C] (fp16)
    groupnorm_kernel<<<BB*32, 256>>>(x, gn_scale, gn_bias, gn16);
    // 2. proj_in
    run_gemm1(gn16, wt16+OFF_PIN, proj_in_b, nullptr, h, nullptr, MROWS, CC, CC, 0);
    // 3. LN1 (fp16 out)
    layernorm_kernel<<<MROWS, CC>>>(h, n1_s, n1_b, ln16);
    // 4. fused q,k,v (self) -> fp16 (q pre-scaled via wq1)
    run_gemm3(ln16, wt16+OFF_Q1, wt16+OFF_K1, wt16+OFF_V1, q, k, v, MROWS, CC, CC, 3, 2);
    // 5. masked self-attention (fp16 MMA)
    {
        dim3 grid(HWP/64, NHEADS, BB);
        self_attn_f16_kernel<<<grid, 256>>>((const __half*)q, (const __half*)k,
                                            (const __half*)v, vis_mask, ao16);
    }
    // 6. out-proj + residual
    run_gemm1(ao16, wt16+OFF_O1, bo1, h, h, nullptr, MROWS, CC, CC, 0);
    // 7. LN2
    layernorm_kernel<<<MROWS, CC>>>(h, n2_s, n2_b, ln16);
    // 8. q (cross) -> fp32
    run_gemm1(ln16, wt16+OFF_Q2, nullptr, nullptr, q, nullptr, MROWS, CC, CC, 0);
    // 9. fused k,v from context -> fp32
    run_gemm3(ctx16, wt16+OFF_K2, wt16+OFF_V2, nullptr, k, v, nullptr, BB*CTX, CC, CTXD, 2, 0);
    // 10. masked cross-attention (fp16 out)
    {
        dim3 grid(HWP/QT2, NHEADS, BB);
        cross_attn_kernel<<<grid, 256>>>(q, k, v, v2t_mask, ao16);
    }
    // 11. out-proj + residual
    run_gemm1(ao16, wt16+OFF_O2, bo2, h, h, nullptr, MROWS, CC, CC, 0);
    // 12. LN3
    layernorm_kernel<<<MROWS, CC>>>(h, n3_s, n3_b, ln16);
    // 13. FF up (GEGLU input)
    run_gemm1(ln16, wt16+OFF_FF1, ff_b1, nullptr, ff1, nullptr, MROWS, 2*FFI, CC, 0);
    // 14. GEGLU (fp16 out)
    {
        size_t n = (size_t)MROWS*FFI;
        geglu_kernel<<<(unsigned)((n + 255)/256), 256>>>(ff1, ffu16);
    }
    // 15. FF down + residual (emit fp16 copy for final proj)
    run_gemm1(ffu16, wt16+OFF_FF2, ff_b2, h, h, h16, MROWS, CC, FFI, 0);
    // 16. proj_out + transpose back to [B,C,H,W] + input residual
    run_gemm1(h16, wt16+OFF_POUT, proj_out_b, x, out, nullptr, MROWS, CC, CC, 1);
}

// round 12
// speedup vs baseline: 4.2603x; 1.0003x over previous
#include <cuda_runtime.h>
#include <cuda_fp16.h>
#include <math.h>
#include <stdint.h>

// ---------------- problem constants ----------------
#define BB      8
#define CC      320
#define HWP     1024
#define NHEADS  8
#define DHEAD   40
#define CTX     77
#define CTXD    768
#define FFI     1280          // FF_INNER
#define MROWS   (BB*HWP)      // 8192
#define NEGMAX  (-3.402823466e38f)

// ---------------- scratch (device globals; no runtime allocs) ----------------
__device__ float  g_h  [MROWS*CC];
__device__ float  g_q  [MROWS*CC];
__device__ float  g_k  [MROWS*CC];
__device__ float  g_v  [MROWS*CC];
__device__ float  g_ff1[MROWS*2*FFI];
__device__ __half g_gn16 [MROWS*CC];
__device__ __half g_ln16 [MROWS*CC];
__device__ __half g_ao16 [MROWS*CC];
__device__ __half g_ffu16[(size_t)MROWS*FFI];
__device__ __half g_ctx16[BB*CTX*CTXD];
__device__ __half g_h16  [MROWS*CC];
__device__ __half g_wt16 [2539520];        // transposed weights [N][K], fp16

// offsets into g_wt16 (halves)
#define OFF_PIN  0
#define OFF_Q1   102400
#define OFF_K1   204800
#define OFF_V1   307200
#define OFF_O1   409600
#define OFF_Q2   512000
#define OFF_O2   614400
#define OFF_POUT 716800
#define OFF_K2   819200
#define OFF_V2   1064960
#define OFF_FF1  1310720
#define OFF_FF2  2129920

__device__ __forceinline__ uint32_t h2_to_u32(__half2 h) {
    union { __half2 h2; uint32_t u; } cvt;
    cvt.h2 = h;
    return cvt.u;
}

// ---------------- block reductions ----------------
__device__ __forceinline__ float blockReduceSum(float v, float* scratch) {
    int lane = threadIdx.x & 31, wid = threadIdx.x >> 5;
    #pragma unroll
    for (int o = 16; o > 0; o >>= 1) v += __shfl_down_sync(0xffffffffu, v, o);
    if (lane == 0) scratch[wid] = v;
    __syncthreads();
    int nw = (blockDim.x + 31) >> 5;
    v = (threadIdx.x < nw) ? scratch[threadIdx.x] : 0.f;
    if (wid == 0) {
        #pragma unroll
        for (int o = 16; o > 0; o >>= 1) v += __shfl_down_sync(0xffffffffu, v, o);
        if (lane == 0) scratch[0] = v;
    }
    __syncthreads();
    v = scratch[0];
    __syncthreads();
    return v;
}

// ---------------- GroupNorm -> fp16 [B,HW,C] ----------------
__global__ __launch_bounds__(256) void groupnorm_kernel(
    const float* __restrict__ x, const float* __restrict__ scale,
    const float* __restrict__ bias, __half* __restrict__ out)
{
    __shared__ float scratch[32];
    __shared__ float s_mu, s_inv;
    int b = blockIdx.x >> 5, g = blockIdx.x & 31;
    const float* xp = x + ((size_t)b*CC + g*10) * HWP;
    float sum = 0.f, sq = 0.f;
    for (int i = threadIdx.x; i < 10*HWP; i += 256) { float v = xp[i]; sum += v; sq += v*v; }
    sum = blockReduceSum(sum, scratch);
    sq  = blockReduceSum(sq,  scratch);
    if (threadIdx.x == 0) {
        float mu  = sum * (1.f/10240.f);
        float var = sq * (1.f/10240.f) - mu*mu;
        s_mu = mu; s_inv = rsqrtf(var + 1e-6f);
    }
    __syncthreads();
    float mu = s_mu, inv = s_inv;
    for (int i = threadIdx.x; i < 10*HWP; i += 256) {
        int cl = i >> 10, p = i & 1023;
        int c = g*10 + cl;
        float xn = (xp[i] - mu) * inv;
        out[((size_t)b*HWP + p)*CC + c] = __float2half(xn * scale[c] + bias[c]);
    }
}

// ---------------- LayerNorm over last dim = 320 -> fp16 ----------------
__global__ __launch_bounds__(CC) void layernorm_kernel(
    const float* __restrict__ X, const float* __restrict__ s,
    const float* __restrict__ bpar, __half* __restrict__ Y)
{
    __shared__ float scratch[32];
    int row = blockIdx.x, t = threadIdx.x;
    float v = X[(size_t)row*CC + t];
    float mu = blockReduceSum(v, scratch) * (1.f/CC);
    float d = v - mu;
    float var = blockReduceSum(d*d, scratch) * (1.f/CC);
    Y[(size_t)row*CC + t] = __float2half(d * rsqrtf(var + 1e-5f) * s[t] + bpar[t]);
}

// ---------------- weight transpose to fp16 [N][K] (with optional scale) ----------------
struct TransDesc {
    const float* src[12];
    __half* dst[12];
    float scl[12];
    int K[12], N[12];
    int start[13];
};

__global__ __launch_bounds__(256) void transpose_all_kernel(TransDesc p) {
    __shared__ float t[32][33];
    int bid = blockIdx.x;
    int i = 0;
    while (bid >= p.start[i+1]) i++;
    const float* src = p.src[i];
    __half* dst = p.dst[i];
    float scl = p.scl[i];
    int K = p.K[i], N = p.N[i];
    int lt = bid - p.start[i];
    int tiles_n = N >> 5;
    int tk = lt / tiles_n, tn = lt - tk*tiles_n;
    int tx = threadIdx.x & 31, ty = threadIdx.x >> 5;   // 32 x 8
    #pragma unroll
    for (int j = 0; j < 32; j += 8)
        t[ty+j][tx] = src[(size_t)(tk*32+ty+j)*N + tn*32 + tx];
    __syncthreads();
    #pragma unroll
    for (int j = 0; j < 32; j += 8)
        dst[(size_t)(tn*32+ty+j)*K + tk*32 + tx] = __float2half(t[tx][ty+j] * scl);
}

// ---------------- context -> fp16 ----------------
__global__ __launch_bounds__(256) void f2h_kernel(
    const float* __restrict__ src, __half* __restrict__ dst, int n)
{
    int i = blockIdx.x*256 + threadIdx.x;
    if (i < n) dst[i] = __float2half(src[i]);
}

// ---------------- mma helpers ----------------
__device__ __forceinline__ void mma_f16(float c[4], uint32_t a0, uint32_t a1,
                                        uint32_t a2, uint32_t a3,
                                        uint32_t b0, uint32_t b1) {
    asm volatile(
        "mma.sync.aligned.m16n8k16.row.col.f32.f16.f16.f32 "
        "{%0,%1,%2,%3}, {%4,%5,%6,%7}, {%8,%9}, {%0,%1,%2,%3};"
        : "+f"(c[0]), "+f"(c[1]), "+f"(c[2]), "+f"(c[3])
        : "r"(a0), "r"(a1), "r"(a2), "r"(a3), "r"(b0), "r"(b1));
}

__device__ __forceinline__ void cp_async16(void* smem_dst, const void* gsrc, int src_bytes) {
    uint32_t s = (uint32_t)__cvta_generic_to_shared(smem_dst);
    asm volatile("cp.async.cg.shared.global [%0], [%1], 16, %2;"
                 :: "r"(s), "l"(gsrc), "r"(src_bytes));
}
#define CP_COMMIT()  asm volatile("cp.async.commit_group;")
#define CP_WAIT2()   asm volatile("cp.async.wait_group 2;")

// ---------------- fp16 tensor-core GEMM (cp.async 4-stage, 2x2x2 k-split) ----------------
// C[mat] = A16 @ Bt16[mat]^T (+bias) (+res). A16 [M][K] fp16, Bt16 [N][K] fp16.
// N%64==0, K%64==0; M arbitrary.
// mode 0: fp32 out (+optional fp16 copy C16); mode 1: final transposed store; mode 2: fp16-only out.
#define GBM 128
#define GBN 64
#define GBK 64
#define A_P16 36
#define B_P16 36
#define STAGES 4
#define GEMM_SMEM_BYTES ((STAGES*(GBM*A_P16 + GBN*B_P16))*4)

__global__ __launch_bounds__(256, 2) void mma_gemm_kernel(
    const __half* __restrict__ A,
    const __half* __restrict__ B0, const __half* __restrict__ B1, const __half* __restrict__ B2,
    const float* __restrict__ bias, const float* __restrict__ res,
    float* __restrict__ C0, float* __restrict__ C1, float* __restrict__ C2,
    __half* __restrict__ C16,
    int M, int N, int K, int mode, int nblk)
{
    extern __shared__ uint32_t dynsmem[];
    uint32_t* AsBase = dynsmem;
    uint32_t* BsBase = dynsmem + STAGES*GBM*A_P16;

    int mat = blockIdx.x / nblk;
    const __half* B = (mat == 0) ? B0 : ((mat == 1) ? B1 : B2);
    float* C        = (mat == 0) ? C0 : ((mat == 1) ? C1 : C2);
    int n0 = (blockIdx.x - mat*nblk) * GBN;

    int tid = threadIdx.x;
    int lane = tid & 31, warp = tid >> 5;
    int wm = (warp >> 2) & 1, wn = (warp >> 1) & 1, wk = warp & 1;
    int m0 = blockIdx.y * GBM;

    float acc[4][4][4];
    #pragma unroll
    for (int i = 0; i < 4; i++)
        #pragma unroll
        for (int j = 0; j < 4; j++)
            #pragma unroll
            for (int c = 0; c < 4; c++) acc[i][j][c] = 0.f;

    int g = lane >> 2, tk = lane & 3;

    int a_row = tid >> 3, a_ch = tid & 7;
    int b_row = tid >> 3, b_ch = tid & 7;

    int KT = K / GBK;

    auto prefetch = [&](int kt, int buf) {
        uint32_t* As = AsBase + buf*GBM*A_P16;
        uint32_t* Bs = BsBase + buf*GBN*B_P16;
        int k0 = kt * GBK;
        #pragma unroll
        for (int j = 0; j < 4; j++) {
            int row = a_row + j*32;
            int gr = m0 + row;
            const __half* src = A + ((gr < M) ? ((size_t)gr*K + k0 + a_ch*8) : 0);
            cp_async16(&As[row*A_P16 + a_ch*4], src, (gr < M) ? 16 : 0);
        }
        #pragma unroll
        for (int j = 0; j < 2; j++) {
            int row = b_row + j*32;
            cp_async16(&Bs[row*B_P16 + b_ch*4],
                       B + (size_t)(n0 + row)*K + k0 + b_ch*8, 16);
        }
        CP_COMMIT();
    };

    prefetch(0, 0);
    if (KT > 1) prefetch(1, 1); else CP_COMMIT();
    if (KT > 2) prefetch(2, 2); else CP_COMMIT();

    for (int kt = 0; kt < KT; kt++) {
        CP_WAIT2();            // group kt complete (kt+1, kt+2 may be in flight)
        __syncthreads();       // protects buffer (kt+3)%4 from early overwrite
        if (kt + 3 < KT) prefetch(kt+3, (kt+3) % STAGES);
        else CP_COMMIT();      // keep one-group-per-iter accounting

        int buf = kt % STAGES;
        uint32_t* As = AsBase + buf*GBM*A_P16;
        uint32_t* Bs = BsBase + buf*GBN*B_P16;

        #pragma unroll
        for (int s = 0; s < 2; s++) {
            int p0 = wk*16 + s*8;
            uint32_t a[4][4];
            #pragma unroll
            for (int mt = 0; mt < 4; mt++) {
                int r0 = wm*64 + mt*16 + g;
                a[mt][0] = As[r0*A_P16 + p0 + tk];
                a[mt][1] = As[(r0+8)*A_P16 + p0 + tk];
                a[mt][2] = As[r0*A_P16 + p0 + 4 + tk];
                a[mt][3] = As[(r0+8)*A_P16 + p0 + 4 + tk];
            }
            uint32_t b[4][2];
            #pragma unroll
            for (int nt = 0; nt < 4; nt++) {
                int col = wn*32 + nt*8 + g;
                b[nt][0] = Bs[col*B_P16 + p0 + tk];
                b[nt][1] = Bs[col*B_P16 + p0 + 4 + tk];
            }
            #pragma unroll
            for (int mt = 0; mt < 4; mt++)
                #pragma unroll
                for (int nt = 0; nt < 4; nt++)
                    mma_f16(acc[mt][nt], a[mt][0], a[mt][1], a[mt][2], a[mt][3],
                            b[nt][0], b[nt][1]);
        }
    }

    __syncthreads();
    float* red = (float*)dynsmem;
    int pairIdx = wm*2 + wn;
    if (wk == 1) {
        #pragma unroll
        for (int mt = 0; mt < 4; mt++)
            #pragma unroll
            for (int nt = 0; nt < 4; nt++)
                #pragma unroll
                for (int c = 0; c < 4; c++) {
                    int idx = (mt*4 + nt)*4 + c;
                    red[idx*128 + pairIdx*32 + lane] = acc[mt][nt][c];
                }
    }
    __syncthreads();
    if (wk == 0) {
        #pragma unroll
        for (int mt = 0; mt < 4; mt++)
            #pragma unroll
            for (int nt = 0; nt < 4; nt++)
                #pragma unroll
                for (int c = 0; c < 4; c++) {
                    int idx = (mt*4 + nt)*4 + c;
                    acc[mt][nt][c] += red[idx*128 + pairIdx*32 + lane];
                }

        #pragma unroll
        for (int mt = 0; mt < 4; mt++) {
            #pragma unroll
            for (int nt = 0; nt < 4; nt++) {
                int mbase = m0 + wm*64 + mt*16 + g;
                int nbase = n0 + wn*32 + nt*8 + (tk << 1);
                #pragma unroll
                for (int c = 0; c < 4; c++) {
                    int m = mbase + ((c >> 1) << 3);
                    int n = nbase + (c & 1);
                    if (m >= M) continue;
                    float v = acc[mt][nt][c];
                    if (bias) v += bias[n];
                    if (mode == 0) {
                        size_t idx = (size_t)m*N + n;
                        if (res) v += res[idx];
                        C[idx] = v;
                        if (C16) C16[idx] = __float2half(v);
                    } else if (mode == 2) {
                        ((__half*)C)[(size_t)m*N + n] = __float2half(v);
                    } else {
                        size_t idx = ((size_t)(m >> 10)*CC + n)*HWP + (m & 1023);
                        C[idx] = v + res[idx];
                    }
                }
            }
        }
    }
}

// ---------------- flash-style masked self-attention (fp16 MMA m16n8k16) ----------------
// Q pre-scaled (scale folded into wq1). Q,K,V fp16 [row][CC] slices per head.
#define AQ_PAD 28   // uint32 pairs per Q/K row (20 real + 8 zero-pad)
#define AV_PAD 36   // uint32 pairs per V^T row (32 real + 4 pad)
#define AP_PAD 36   // uint32 pairs per P row (32 real + 4 pad)

__global__ __launch_bounds__(256) void self_attn_f16_kernel(
    const __half* __restrict__ Q, const __half* __restrict__ K,
    const __half* __restrict__ V, const unsigned int* __restrict__ mask,
    __half* __restrict__ O)
{
    __shared__ uint32_t Qs[64][AQ_PAD];
    __shared__ uint32_t Ks[64][AQ_PAD];
    __shared__ uint32_t Vs[DHEAD][AV_PAD];   // V^T: [dhead][keys] halves
    __shared__ uint32_t Ps[64][AP_PAD];
    __shared__ float comb[64][41];
    __shared__ float sm_m[64], sm_l[64], sm_alpha[64];
    __shared__ float smx[2][64], ssum[2][64];

    int b = blockIdx.z, h = blockIdx.y, q0 = blockIdx.x * 64;
    int tid = threadIdx.x, lane = tid & 31, w = tid >> 5;
    int wm = w >> 1, wn = w & 1;
    int g = lane >> 2, tk = lane & 3;
    int r_lo = wm*16 + g, r_hi = r_lo + 8;

    // zero Q/K tiles (pads persist as zero)
    for (int i = tid; i < 64*AQ_PAD; i += 256) {
        Qs[i/AQ_PAD][i%AQ_PAD] = 0;
        Ks[i/AQ_PAD][i%AQ_PAD] = 0;
    }
    // stage Q (already scaled): 20 u32 pairs per row
    {
        const uint32_t* qb = (const uint32_t*)Q;
        for (int i = tid; i < 64*20; i += 256) {
            int r = i/20, p = i%20;
            Qs[r][p] = qb[(((size_t)b*HWP + q0 + r)*CC + h*DHEAD)/2 + p];
        }
    }
    if (tid < 64) { sm_m[tid] = NEGMAX; sm_l[tid] = 0.f; }
    __syncthreads();

    uint32_t aq[3][4];
    #pragma unroll
    for (int s = 0; s < 3; s++) {
        aq[s][0] = Qs[r_lo][s*8 + tk];
        aq[s][1] = Qs[r_hi][s*8 + tk];
        aq[s][2] = Qs[r_lo][s*8 + 4 + tk];
        aq[s][3] = Qs[r_hi][s*8 + 4 + tk];
    }

    float o[5][4] = {};

    for (int jt = 0; jt < HWP/64; jt++) {
        __syncthreads();
        {
            const uint32_t* kb = (const uint32_t*)K;
            for (int i = tid; i < 64*20; i += 256) {
                int j = i/20, p = i%20;
                Ks[j][p] = kb[(((size_t)b*HWP + jt*64 + j)*CC + h*DHEAD)/2 + p];
            }
            const __half* vb = V + ((size_t)b*HWP + jt*64)*CC + h*DHEAD;
            __half* vsh = (__half*)Vs;
            for (int i = tid; i < 64*DHEAD; i += 256) {
                int j = i/DHEAD, c = i%DHEAD;
                vsh[c*(2*AV_PAD) + j] = vb[(size_t)j*CC + c];
            }
        }
        __syncthreads();

        // S = Q K^T (3 k16 steps)
        float s_[4][4] = {};
        #pragma unroll
        for (int s = 0; s < 3; s++) {
            #pragma unroll
            for (int nt = 0; nt < 4; nt++) {
                int jn = wn*32 + nt*8 + g;
                mma_f16(s_[nt], aq[s][0], aq[s][1], aq[s][2], aq[s][3],
                        Ks[jn][s*8 + tk], Ks[jn][s*8 + 4 + tk]);
            }
        }

        // mask + row max
        const unsigned int* mlo_p = mask + ((size_t)b*HWP + q0 + r_lo)*HWP + (size_t)jt*64;
        const unsigned int* mhi_p = mask + ((size_t)b*HWP + q0 + r_hi)*HWP + (size_t)jt*64;
        float mlo = NEGMAX, mhi = NEGMAX;
        #pragma unroll
        for (int nt = 0; nt < 4; nt++) {
            int col = wn*32 + nt*8 + tk*2;
            uint2 m0v = *(const uint2*)(mlo_p + col);
            uint2 m1v = *(const uint2*)(mhi_p + col);
            s_[nt][0] = m0v.x ? s_[nt][0] : NEGMAX;
            s_[nt][1] = m0v.y ? s_[nt][1] : NEGMAX;
            s_[nt][2] = m1v.x ? s_[nt][2] : NEGMAX;
            s_[nt][3] = m1v.y ? s_[nt][3] : NEGMAX;
            mlo = fmaxf(mlo, fmaxf(s_[nt][0], s_[nt][1]));
            mhi = fmaxf(mhi, fmaxf(s_[nt][2], s_[nt][3]));
        }
        mlo = fmaxf(mlo, __shfl_xor_sync(0xffffffffu, mlo, 1));
        mlo = fmaxf(mlo, __shfl_xor_sync(0xffffffffu, mlo, 2));
        mhi = fmaxf(mhi, __shfl_xor_sync(0xffffffffu, mhi, 1));
        mhi = fmaxf(mhi, __shfl_xor_sync(0xffffffffu, mhi, 2));
        if (tk == 0) { smx[wn][r_lo] = mlo; smx[wn][r_hi] = mhi; }
        __syncthreads();

        if (tid < 64) {
            float mo = sm_m[tid];
            float mn = fmaxf(mo, fmaxf(smx[0][tid], smx[1][tid]));
            sm_m[tid] = mn;
            sm_alpha[tid] = __expf(mo - mn);
        }
        __syncthreads();

        // P = exp(S - m) (fp32), write half2 pairs, row sums
        float mn_lo = sm_m[r_lo], mn_hi = sm_m[r_hi];
        float slo = 0.f, shi = 0.f;
        #pragma unroll
        for (int nt = 0; nt < 4; nt++) {
            int pr = wn*16 + nt*4 + tk;   // pair index
            float p0 = __expf(s_[nt][0] - mn_lo);
            float p1 = __expf(s_[nt][1] - mn_lo);
            float p2 = __expf(s_[nt][2] - mn_hi);
            float p3 = __expf(s_[nt][3] - mn_hi);
            slo += p0 + p1; shi += p2 + p3;
            Ps[r_lo][pr] = h2_to_u32(__floats2half2_rn(p0, p1));
            Ps[r_hi][pr] = h2_to_u32(__floats2half2_rn(p2, p3));
        }
        slo += __shfl_xor_sync(0xffffffffu, slo, 1);
        slo += __shfl_xor_sync(0xffffffffu, slo, 2);
        shi += __shfl_xor_sync(0xffffffffu, shi, 1);
        shi += __shfl_xor_sync(0xffffffffu, shi, 2);
        if (tk == 0) { ssum[wn][r_lo] = slo; ssum[wn][r_hi] = shi; }

        float alo = sm_alpha[r_lo], ahi = sm_alpha[r_hi];
        #pragma unroll
        for (int nt = 0; nt < 5; nt++) {
            o[nt][0] *= alo; o[nt][1] *= alo;
            o[nt][2] *= ahi; o[nt][3] *= ahi;
        }
        __syncthreads();

        if (tid < 64)
            sm_l[tid] = sm_alpha[tid]*sm_l[tid] + ssum[0][tid] + ssum[1][tid];

        // O += P V (2 k16 steps per wn half)
        #pragma unroll
        for (int s2 = 0; s2 < 2; s2++) {
            int pb = wn*16 + s2*8;
            uint32_t a0 = Ps[r_lo][pb + tk];
            uint32_t a1 = Ps[r_hi][pb + tk];
            uint32_t a2 = Ps[r_lo][pb + 4 + tk];
            uint32_t a3 = Ps[r_hi][pb + 4 + tk];
            #pragma unroll
            for (int nt = 0; nt < 5; nt++) {
                int n = nt*8 + g;
                mma_f16(o[nt], a0, a1, a2, a3,
                        Vs[n][pb + tk], Vs[n][pb + 4 + tk]);
            }
        }
    }
    __syncthreads();

    // combine wn halves, normalize, write fp16
    if (wn == 1) {
        #pragma unroll
        for (int nt = 0; nt < 5; nt++) {
            int c = nt*8 + tk*2;
            comb[r_lo][c]   = o[nt][0];
            comb[r_lo][c+1] = o[nt][1];
            comb[r_hi][c]   = o[nt][2];
            comb[r_hi][c+1] = o[nt][3];
        }
    }
    __syncthreads();
    if (wn == 0) {
        float il_lo = 1.f / sm_l[r_lo];
        float il_hi = 1.f / sm_l[r_hi];
        __half* out_lo = O + ((size_t)b*HWP + q0 + r_lo)*CC + h*DHEAD;
        __half* out_hi = O + ((size_t)b*HWP + q0 + r_hi)*CC + h*DHEAD;
        #pragma unroll
        for (int nt = 0; nt < 5; nt++) {
            int c = nt*8 + tk*2;
            float v0 = (o[nt][0] + comb[r_lo][c])   * il_lo;
            float v1 = (o[nt][1] + comb[r_lo][c+1]) * il_lo;
            float v2 = (o[nt][2] + comb[r_hi][c])   * il_hi;
            float v3 = (o[nt][3] + comb[r_hi][c+1]) * il_hi;
            *(__half2*)(out_lo + c) = __floats2half2_rn(v0, v1);
            *(__half2*)(out_hi + c) = __floats2half2_rn(v2, v3);
        }
    }
}

// ---------------- masked cross-attention (keys = 77, fp16 output) ----------------
#define QT2 16
__global__ __launch_bounds__(256) void cross_attn_kernel(
    const float* __restrict__ Q, const float* __restrict__ Kc,
    const float* __restrict__ Vc, const unsigned int* __restrict__ mask,
    __half* __restrict__ O)
{
    __shared__ float sk[CTX][DHEAD];
    __shared__ float sv[CTX][DHEAD];
    __shared__ float sq[QT2][DHEAD];
    __shared__ float sc[QT2][CTX+3];
    int b = blockIdx.z, h = blockIdx.y, q0 = blockIdx.x * QT2;
    int tid = threadIdx.x;

    for (int i = tid; i < CTX*DHEAD; i += 256) {
        int r = i / DHEAD, d = i % DHEAD;
        sk[r][d] = Kc[((size_t)b*CTX + r)*CC + h*DHEAD + d];
        sv[r][d] = Vc[((size_t)b*CTX + r)*CC + h*DHEAD + d];
    }
    for (int i = tid; i < QT2*DHEAD; i += 256) {
        int r = i / DHEAD, d = i % DHEAD;
        sq[r][d] = Q[((size_t)b*HWP + q0 + r)*CC + h*DHEAD + d];
    }
    __syncthreads();

    const float scale = rsqrtf((float)DHEAD);
    for (int idx = tid; idx < QT2*CTX; idx += 256) {
        int qi = idx / CTX, j = idx % CTX;
        float s = 0.f;
        #pragma unroll
        for (int d = 0; d < DHEAD; d++) s += sq[qi][d]*sk[j][d];
        unsigned int m = mask[((size_t)b*HWP + q0 + qi)*CTX + j];
        sc[qi][j] = (m != 0u) ? s*scale : NEGMAX;
    }
    __syncthreads();

    if (tid < QT2) {
        int qi = tid;
        float mx = NEGMAX;
        for (int j = 0; j < CTX; j++) mx = fmaxf(mx, sc[qi][j]);
        float sum = 0.f;
        for (int j = 0; j < CTX; j++) { float e = __expf(sc[qi][j]-mx); sc[qi][j] = e; sum += e; }
        float inv = 1.f/sum;
        for (int j = 0; j < CTX; j++) sc[qi][j] *= inv;
    }
    __syncthreads();

    for (int idx = tid; idx < QT2*DHEAD; idx += 256) {
        int qi = idx / DHEAD, d = idx % DHEAD;
        float s = 0.f;
        #pragma unroll
        for (int j = 0; j < CTX; j++) s += sc[qi][j]*sv[j][d];
        O[((size_t)b*HWP + q0 + qi)*CC + h*DHEAD + d] = __float2half(s);
    }
}

// ---------------- GEGLU: u = a * gelu_exact(g) -> fp16 ----------------
__global__ __launch_bounds__(256) void geglu_kernel(
    const float* __restrict__ Y, __half* __restrict__ U)
{
    size_t i = (size_t)blockIdx.x*256 + threadIdx.x;
    if (i >= (size_t)MROWS*FFI) return;
    size_t m = i / FFI, c = i % FFI;
    float a = Y[m*2*FFI + c];
    float g = Y[m*2*FFI + FFI + c];
    float ge = 0.5f * g * (1.f + erff(g * 0.70710678118654752f));
    U[i] = __float2half(a * ge);
}

// ---------------- host orchestration ----------------
static inline void run_gemm1(const __half* A, const __half* B, const float* bias,
                             const float* res, float* C, __half* C16,
                             int M, int N, int K, int mode)
{
    int nblk = N / GBN;
    dim3 grid(nblk, (M + GBM - 1) / GBM);
    mma_gemm_kernel<<<grid, 256, GEMM_SMEM_BYTES>>>(
        A, B, nullptr, nullptr, bias, res, C, nullptr, nullptr, C16, M, N, K, mode, nblk);
}

static inline void run_gemm3(const __half* A,
                             const __half* B0, const __half* B1, const __half* B2,
                             float* C0, float* C1, float* C2,
                             int M, int N, int K, int nmat, int mode)
{
    int nblk = N / GBN;
    dim3 grid(nblk * nmat, (M + GBM - 1) / GBM);
    mma_gemm_kernel<<<grid, 256, GEMM_SMEM_BYTES>>>(
        A, B0, B1, B2, nullptr, nullptr, C0, C1, C2, nullptr, M, N, K, mode, nblk);
}

extern "C" void kernel_launch(void* const* d_in, const int* in_sizes, int n_in,
                              void* d_out, int out_size)
{
    const float* x         = (const float*)d_in[0];
    const float* context   = (const float*)d_in[1];
    const unsigned int* vis_mask = (const unsigned int*)d_in[2];
    const unsigned int* v2t_mask = (const unsigned int*)d_in[3];
    const float* gn_scale  = (const float*)d_in[4];
    const float* gn_bias   = (const float*)d_in[5];
    const float* proj_in_w = (const float*)d_in[6];
    const float* proj_in_b = (const float*)d_in[7];
    const float* n1_s = (const float*)d_in[8];
    const float* n1_b = (const float*)d_in[9];
    const float* wq1  = (const float*)d_in[10];
    const float* wk1  = (const float*)d_in[11];
    const float* wv1  = (const float*)d_in[12];
    const float* wo1  = (const float*)d_in[13];
    const float* bo1  = (const float*)d_in[14];
    const float* n2_s = (const float*)d_in[15];
    const float* n2_b = (const float*)d_in[16];
    const float* wq2  = (const float*)d_in[17];
    const float* wk2  = (const float*)d_in[18];
    const float* wv2  = (const float*)d_in[19];
    const float* wo2  = (const float*)d_in[20];
    const float* bo2  = (const float*)d_in[21];
    const float* n3_s = (const float*)d_in[22];
    const float* n3_b = (const float*)d_in[23];
    const float* ff_w1 = (const float*)d_in[24];
    const float* ff_b1 = (const float*)d_in[25];
    const float* ff_w2 = (const float*)d_in[26];
    const float* ff_b2 = (const float*)d_in[27];
    const float* proj_out_w = (const float*)d_in[28];
    const float* proj_out_b = (const float*)d_in[29];
    float* out = (float*)d_out;

    cudaFuncSetAttribute(mma_gemm_kernel,
                         cudaFuncAttributeMaxDynamicSharedMemorySize, GEMM_SMEM_BYTES);

    float *h, *q, *k, *v, *ff1;
    __half *gn16, *ln16, *ao16, *ffu16, *ctx16, *h16, *wt16;
    cudaGetSymbolAddress((void**)&h,    g_h);
    cudaGetSymbolAddress((void**)&q,    g_q);
    cudaGetSymbolAddress((void**)&k,    g_k);
    cudaGetSymbolAddress((void**)&v,    g_v);
    cudaGetSymbolAddress((void**)&ff1,  g_ff1);
    cudaGetSymbolAddress((void**)&gn16, g_gn16);
    cudaGetSymbolAddress((void**)&ln16, g_ln16);
    cudaGetSymbolAddress((void**)&ao16, g_ao16);
    cudaGetSymbolAddress((void**)&ffu16,g_ffu16);
    cudaGetSymbolAddress((void**)&ctx16,g_ctx16);
    cudaGetSymbolAddress((void**)&h16,  g_h16);
    cudaGetSymbolAddress((void**)&wt16, g_wt16);

    // 0a. transpose all weight matrices to fp16 [N][K]; fold 1/sqrt(DHEAD) into wq1
    {
        TransDesc td;
        const float* srcs[12] = {proj_in_w, wq1, wk1, wv1, wo1, wq2, wo2, proj_out_w,
                                 wk2, wv2, ff_w1, ff_w2};
        __half* dsts[12] = {wt16+OFF_PIN, wt16+OFF_Q1, wt16+OFF_K1, wt16+OFF_V1, wt16+OFF_O1,
                            wt16+OFF_Q2, wt16+OFF_O2, wt16+OFF_POUT, wt16+OFF_K2, wt16+OFF_V2,
                            wt16+OFF_FF1, wt16+OFF_FF2};
        int Ks[12] = {CC,CC,CC,CC,CC,CC,CC,CC, CTXD,CTXD, CC, FFI};
        int Ns[12] = {CC,CC,CC,CC,CC,CC,CC,CC, CC,CC, 2*FFI, CC};
        int acc = 0;
        float qs = rsqrtf((float)DHEAD);
        for (int i = 0; i < 12; i++) {
            td.src[i] = srcs[i]; td.dst[i] = dsts[i];
            td.scl[i] = (i == 1) ? qs : 1.f;
            td.K[i] = Ks[i]; td.N[i] = Ns[i];
            td.start[i] = acc;
            acc += (Ks[i]/32) * (Ns[i]/32);
        }
        td.start[12] = acc;
        transpose_all_kernel<<<acc, 256>>>(td);
    }
    // 0b. context -> fp16
    {
        int n = BB*CTX*CTXD;
        f2h_kernel<<<(n + 255)/256, 256>>>(context, ctx16, n);
    }

    // 1. GroupNorm + transpose to [B, HW, C] (fp16)
    groupnorm_kernel<<<BB*32, 256>>>(x, gn_scale, gn_bias, gn16);
    // 2. proj_in
    run_gemm1(gn16, wt16+OFF_PIN, proj_in_b, nullptr, h, nullptr, MROWS, CC, CC, 0);
    // 3. LN1 (fp16 out)
    layernorm_kernel<<<MROWS, CC>>>(h, n1_s, n1_b, ln16);
    // 4. fused q,k,v (self) -> fp16 (q pre-scaled via wq1)
    run_gemm3(ln16, wt16+OFF_Q1, wt16+OFF_K1, wt16+OFF_V1, q, k, v, MROWS, CC, CC, 3, 2);
    // 5. masked self-attention (fp16 MMA)
    {
        dim3 grid(HWP/64, NHEADS, BB);
        self_attn_f16_kernel<<<grid, 256>>>((const __half*)q, (const __half*)k,
                                            (const __half*)v, vis_mask, ao16);
    }
    // 6. out-proj + residual
    run_gemm1(ao16, wt16+OFF_O1, bo1, h, h, nullptr, MROWS, CC, CC, 0);
    // 7. LN2
    layernorm_kernel<<<MROWS, CC>>>(h, n2_s, n2_b, ln16);
    // 8. q (cross) -> fp32
    run_gemm1(ln16, wt16+OFF_Q2, nullptr, nullptr, q, nullptr, MROWS, CC, CC, 0);
    // 9. fused k,v from context -> fp32
    run_gemm3(ctx16, wt16+OFF_K2, wt16+OFF_V2, nullptr, k, v, nullptr, BB*CTX, CC, CTXD, 2, 0);
    // 10. masked cross-attention (fp16 out)
    {
        dim3 grid(HWP/QT2, NHEADS, BB);
        cross_attn_kernel<<<grid, 256>>>(q, k, v, v2t_mask, ao16);
    }
    // 11. out-proj + residual
    run_gemm1(ao16, wt16+OFF_O2, bo2, h, h, nullptr, MROWS, CC, CC, 0);
    // 12. LN3
    layernorm_kernel<<<MROWS, CC>>>(h, n3_s, n3_b, ln16);
    // 13. FF up (GEGLU input)
    run_gemm1(ln16, wt16+OFF_FF1, ff_b1, nullptr, ff1, nullptr, MROWS, 2*FFI, CC, 0);
    // 14. GEGLU (fp16 out)
    {
        size_t n = (size_t)MROWS*FFI;
        geglu_kernel<<<(unsigned)((n + 255)/256), 256>>>(ff1, ffu16);
    }
    // 15. FF down + residual (emit fp16 copy for final proj)
    run_gemm1(ffu16, wt16+OFF_FF2, ff_b2, h, h, h16, MROWS, CC, FFI, 0);
    // 16. proj_out + transpose back to [B,C,H,W] + input residual
    run_gemm1(h16, wt16+OFF_POUT, proj_out_b, x, out, nullptr, MROWS, CC, CC, 1);
}

// round 13
// speedup vs baseline: 4.4246x; 1.0386x over previous
#include <cuda_runtime.h>
#include <cuda_fp16.h>
#include <math.h>
#include <stdint.h>

// ---------------- problem constants ----------------
#define BB      8
#define CC      320
#define HWP     1024
#define NHEADS  8
#define DHEAD   40
#define CTX     77
#define CTXD    768
#define FFI     1280          // FF_INNER
#define MROWS   (BB*HWP)      // 8192
#define NEGMAX  (-3.402823466e38f)

// ---------------- scratch (device globals; no runtime allocs) ----------------
__device__ float  g_h  [MROWS*CC];
__device__ float  g_q  [MROWS*CC];
__device__ float  g_k  [MROWS*CC];
__device__ float  g_v  [MROWS*CC];
__device__ float  g_ff1[MROWS*2*FFI];
__device__ __half g_gn16 [MROWS*CC];
__device__ __half g_ln16 [MROWS*CC];
__device__ __half g_ao16 [MROWS*CC];
__device__ __half g_ffu16[(size_t)MROWS*FFI];
__device__ __half g_ctx16[BB*CTX*CTXD];
__device__ __half g_h16  [MROWS*CC];
__device__ __half g_wt16 [2539520];        // transposed weights [N][K], fp16

// offsets into g_wt16 (halves)
#define OFF_PIN  0
#define OFF_Q1   102400
#define OFF_K1   204800
#define OFF_V1   307200
#define OFF_O1   409600
#define OFF_Q2   512000
#define OFF_O2   614400
#define OFF_POUT 716800
#define OFF_K2   819200
#define OFF_V2   1064960
#define OFF_FF1  1310720
#define OFF_FF2  2129920

__device__ __forceinline__ uint32_t h2_to_u32(__half2 h) {
    union { __half2 h2; uint32_t u; } cvt;
    cvt.h2 = h;
    return cvt.u;
}

// ---------------- block reductions ----------------
__device__ __forceinline__ float blockReduceSum(float v, float* scratch) {
    int lane = threadIdx.x & 31, wid = threadIdx.x >> 5;
    #pragma unroll
    for (int o = 16; o > 0; o >>= 1) v += __shfl_down_sync(0xffffffffu, v, o);
    if (lane == 0) scratch[wid] = v;
    __syncthreads();
    int nw = (blockDim.x + 31) >> 5;
    v = (threadIdx.x < nw) ? scratch[threadIdx.x] : 0.f;
    if (wid == 0) {
        #pragma unroll
        for (int o = 16; o > 0; o >>= 1) v += __shfl_down_sync(0xffffffffu, v, o);
        if (lane == 0) scratch[0] = v;
    }
    __syncthreads();
    v = scratch[0];
    __syncthreads();
    return v;
}

// ---------------- GroupNorm -> fp16 [B,HW,C] ----------------
__global__ __launch_bounds__(256) void groupnorm_kernel(
    const float* __restrict__ x, const float* __restrict__ scale,
    const float* __restrict__ bias, __half* __restrict__ out)
{
    __shared__ float scratch[32];
    __shared__ float s_mu, s_inv;
    int b = blockIdx.x >> 5, g = blockIdx.x & 31;
    const float* xp = x + ((size_t)b*CC + g*10) * HWP;
    float sum = 0.f, sq = 0.f;
    for (int i = threadIdx.x; i < 10*HWP; i += 256) { float v = xp[i]; sum += v; sq += v*v; }
    sum = blockReduceSum(sum, scratch);
    sq  = blockReduceSum(sq,  scratch);
    if (threadIdx.x == 0) {
        float mu  = sum * (1.f/10240.f);
        float var = sq * (1.f/10240.f) - mu*mu;
        s_mu = mu; s_inv = rsqrtf(var + 1e-6f);
    }
    __syncthreads();
    float mu = s_mu, inv = s_inv;
    for (int i = threadIdx.x; i < 10*HWP; i += 256) {
        int cl = i >> 10, p = i & 1023;
        int c = g*10 + cl;
        float xn = (xp[i] - mu) * inv;
        out[((size_t)b*HWP + p)*CC + c] = __float2half(xn * scale[c] + bias[c]);
    }
}

// ---------------- LayerNorm over last dim = 320 -> fp16 ----------------
__global__ __launch_bounds__(CC) void layernorm_kernel(
    const float* __restrict__ X, const float* __restrict__ s,
    const float* __restrict__ bpar, __half* __restrict__ Y)
{
    __shared__ float scratch[32];
    int row = blockIdx.x, t = threadIdx.x;
    float v = X[(size_t)row*CC + t];
    float mu = blockReduceSum(v, scratch) * (1.f/CC);
    float d = v - mu;
    float var = blockReduceSum(d*d, scratch) * (1.f/CC);
    Y[(size_t)row*CC + t] = __float2half(d * rsqrtf(var + 1e-5f) * s[t] + bpar[t]);
}

// ---------------- weight transpose to fp16 [N][K] (with optional scale) ----------------
struct TransDesc {
    const float* src[12];
    __half* dst[12];
    float scl[12];
    int K[12], N[12];
    int start[13];
};

__global__ __launch_bounds__(256) void transpose_all_kernel(TransDesc p) {
    __shared__ float t[32][33];
    int bid = blockIdx.x;
    int i = 0;
    while (bid >= p.start[i+1]) i++;
    const float* src = p.src[i];
    __half* dst = p.dst[i];
    float scl = p.scl[i];
    int K = p.K[i], N = p.N[i];
    int lt = bid - p.start[i];
    int tiles_n = N >> 5;
    int tk = lt / tiles_n, tn = lt - tk*tiles_n;
    int tx = threadIdx.x & 31, ty = threadIdx.x >> 5;   // 32 x 8
    #pragma unroll
    for (int j = 0; j < 32; j += 8)
        t[ty+j][tx] = src[(size_t)(tk*32+ty+j)*N + tn*32 + tx];
    __syncthreads();
    #pragma unroll
    for (int j = 0; j < 32; j += 8)
        dst[(size_t)(tn*32+ty+j)*K + tk*32 + tx] = __float2half(t[tx][ty+j] * scl);
}

// ---------------- context -> fp16 ----------------
__global__ __launch_bounds__(256) void f2h_kernel(
    const float* __restrict__ src, __half* __restrict__ dst, int n)
{
    int i = blockIdx.x*256 + threadIdx.x;
    if (i < n) dst[i] = __float2half(src[i]);
}

// ---------------- mma / ldmatrix helpers ----------------
__device__ __forceinline__ void mma_f16(float c[4], uint32_t a0, uint32_t a1,
                                        uint32_t a2, uint32_t a3,
                                        uint32_t b0, uint32_t b1) {
    asm volatile(
        "mma.sync.aligned.m16n8k16.row.col.f32.f16.f16.f32 "
        "{%0,%1,%2,%3}, {%4,%5,%6,%7}, {%8,%9}, {%0,%1,%2,%3};"
        : "+f"(c[0]), "+f"(c[1]), "+f"(c[2]), "+f"(c[3])
        : "r"(a0), "r"(a1), "r"(a2), "r"(a3), "r"(b0), "r"(b1));
}

__device__ __forceinline__ void ldmatrix_x4(uint32_t& d0, uint32_t& d1,
                                            uint32_t& d2, uint32_t& d3, uint32_t addr) {
    asm volatile("ldmatrix.sync.aligned.m8n8.x4.shared.b16 {%0,%1,%2,%3}, [%4];"
                 : "=r"(d0), "=r"(d1), "=r"(d2), "=r"(d3) : "r"(addr));
}
__device__ __forceinline__ void ldmatrix_x2(uint32_t& d0, uint32_t& d1, uint32_t addr) {
    asm volatile("ldmatrix.sync.aligned.m8n8.x2.shared.b16 {%0,%1}, [%2];"
                 : "=r"(d0), "=r"(d1) : "r"(addr));
}

__device__ __forceinline__ void cp_async16_s(uint32_t saddr, const void* gsrc, int src_bytes) {
    asm volatile("cp.async.cg.shared.global [%0], [%1], 16, %2;"
                 :: "r"(saddr), "l"(gsrc), "r"(src_bytes));
}
#define CP_COMMIT()  asm volatile("cp.async.commit_group;")
#define CP_WAIT1()   asm volatile("cp.async.wait_group 1;")

// ---------------- fp16 tensor-core GEMM (ldmatrix + XOR swizzle, 3-stage, 2x2x2) --------
// C[mat] = A16 @ Bt16[mat]^T (+bias) (+res). A16 [M][K] fp16, Bt16 [N][K] fp16.
// N%64==0, K%64==0; M arbitrary.
// SMEM tiles: 16B chunks, chunk' = chunk ^ (row & 7)  -> conflict-free ldmatrix.
// mode 0: fp32 out (+optional fp16 copy C16); mode 1: final transposed store; mode 2: fp16-only.
#define GBM 128
#define GBN 64
#define GBK 64
#define NCH 8                    // 8 chunks of 16B per row (64 halves)
#define STAGES 3
#define A_STAGE_B (GBM*NCH*16)   // 16384
#define B_STAGE_B (GBN*NCH*16)   // 8192
#define GEMM_SMEM_BYTES (STAGES*(A_STAGE_B + B_STAGE_B))   // 73728

__global__ __launch_bounds__(256, 2) void mma_gemm_kernel(
    const __half* __restrict__ A,
    const __half* __restrict__ B0, const __half* __restrict__ B1, const __half* __restrict__ B2,
    const float* __restrict__ bias, const float* __restrict__ res,
    float* __restrict__ C0, float* __restrict__ C1, float* __restrict__ C2,
    __half* __restrict__ C16,
    int M, int N, int K, int mode, int nblk)
{
    extern __shared__ __align__(16) char smemraw[];
    uint32_t sbase = (uint32_t)__cvta_generic_to_shared(smemraw);
    uint32_t bbase0 = sbase + STAGES*A_STAGE_B;

    int mat = blockIdx.x / nblk;
    const __half* B = (mat == 0) ? B0 : ((mat == 1) ? B1 : B2);
    float* C        = (mat == 0) ? C0 : ((mat == 1) ? C1 : C2);
    int n0 = (blockIdx.x - mat*nblk) * GBN;

    int tid = threadIdx.x;
    int lane = tid & 31, warp = tid >> 5;
    int wm = (warp >> 2) & 1, wn = (warp >> 1) & 1, wk = warp & 1;
    int m0 = blockIdx.y * GBM;

    float acc[4][4][4];
    #pragma unroll
    for (int i = 0; i < 4; i++)
        #pragma unroll
        for (int j = 0; j < 4; j++)
            #pragma unroll
            for (int c = 0; c < 4; c++) acc[i][j][c] = 0.f;

    int g = lane >> 2, tk = lane & 3;

    // loader coords: one 16B chunk per (row, ch)
    int a_row = tid >> 3, a_ch = tid & 7;
    int b_row = tid >> 3, b_ch = tid & 7;

    // ldmatrix lane-address components
    int sub = lane >> 3, lr = lane & 7;          // A x4: 4 mats
    int lrB = lane & 7, subB = (lane >> 3) & 1;  // B x2: 2 mats (lanes 0..15)

    int KT = K / GBK;

    auto prefetch = [&](int kt, int buf) {
        uint32_t abase = sbase + buf*A_STAGE_B;
        uint32_t bbase = bbase0 + buf*B_STAGE_B;
        int k0 = kt * GBK;
        #pragma unroll
        for (int j = 0; j < 4; j++) {
            int row = a_row + j*32;
            int gr = m0 + row;
            int ch = a_ch ^ (row & 7);
            const __half* src = A + ((gr < M) ? ((size_t)gr*K + k0 + a_ch*8) : 0);
            cp_async16_s(abase + (row*NCH + ch)*16, src, (gr < M) ? 16 : 0);
        }
        #pragma unroll
        for (int j = 0; j < 2; j++) {
            int row = b_row + j*32;
            int ch = b_ch ^ (row & 7);
            cp_async16_s(bbase + (row*NCH + ch)*16,
                         B + (size_t)(n0 + row)*K + k0 + b_ch*8, 16);
        }
        CP_COMMIT();
    };

    prefetch(0, 0);
    if (KT > 1) prefetch(1, 1); else CP_COMMIT();

    for (int kt = 0; kt < KT; kt++) {
        CP_WAIT1();
        __syncthreads();
        if (kt + 2 < KT) prefetch(kt+2, (kt+2) % STAGES);
        else CP_COMMIT();

        int buf = kt % STAGES;
        uint32_t abase = sbase + buf*A_STAGE_B;
        uint32_t bbase = bbase0 + buf*B_STAGE_B;

        #pragma unroll
        for (int s = 0; s < 2; s++) {
            int c0 = wk*4 + s*2;                 // chunk base for this k16 step
            // A fragments via ldmatrix.x4
            uint32_t a[4][4];
            #pragma unroll
            for (int mt = 0; mt < 4; mt++) {
                int r = wm*64 + mt*16 + lr + (sub & 1)*8;
                int ch = (c0 + (sub >> 1)) ^ (r & 7);
                ldmatrix_x4(a[mt][0], a[mt][1], a[mt][2], a[mt][3],
                            abase + (r*NCH + ch)*16);
            }
            // B fragments via ldmatrix.x2
            uint32_t b[4][2];
            #pragma unroll
            for (int nt = 0; nt < 4; nt++) {
                int rn = wn*32 + nt*8 + lrB;
                int ch = (c0 + subB) ^ (rn & 7);
                ldmatrix_x2(b[nt][0], b[nt][1], bbase + (rn*NCH + ch)*16);
            }
            #pragma unroll
            for (int mt = 0; mt < 4; mt++)
                #pragma unroll
                for (int nt = 0; nt < 4; nt++)
                    mma_f16(acc[mt][nt], a[mt][0], a[mt][1], a[mt][2], a[mt][3],
                            b[nt][0], b[nt][1]);
        }
    }

    // ---- k-split reduction: wk=1 partials -> wk=0 via SMEM ----
    __syncthreads();
    float* red = (float*)smemraw;
    int pairIdx = wm*2 + wn;
    if (wk == 1) {
        #pragma unroll
        for (int mt = 0; mt < 4; mt++)
            #pragma unroll
            for (int nt = 0; nt < 4; nt++)
                #pragma unroll
                for (int c = 0; c < 4; c++) {
                    int idx = (mt*4 + nt)*4 + c;
                    red[idx*128 + pairIdx*32 + lane] = acc[mt][nt][c];
                }
    }
    __syncthreads();
    if (wk == 0) {
        #pragma unroll
        for (int mt = 0; mt < 4; mt++)
            #pragma unroll
            for (int nt = 0; nt < 4; nt++)
                #pragma unroll
                for (int c = 0; c < 4; c++) {
                    int idx = (mt*4 + nt)*4 + c;
                    acc[mt][nt][c] += red[idx*128 + pairIdx*32 + lane];
                }

        #pragma unroll
        for (int mt = 0; mt < 4; mt++) {
            #pragma unroll
            for (int nt = 0; nt < 4; nt++) {
                int mbase = m0 + wm*64 + mt*16 + g;
                int nbase = n0 + wn*32 + nt*8 + (tk << 1);
                #pragma unroll
                for (int c = 0; c < 4; c++) {
                    int m = mbase + ((c >> 1) << 3);
                    int n = nbase + (c & 1);
                    if (m >= M) continue;
                    float v = acc[mt][nt][c];
                    if (bias) v += bias[n];
                    if (mode == 0) {
                        size_t idx = (size_t)m*N + n;
                        if (res) v += res[idx];
                        C[idx] = v;
                        if (C16) C16[idx] = __float2half(v);
                    } else if (mode == 2) {
                        ((__half*)C)[(size_t)m*N + n] = __float2half(v);
                    } else {
                        size_t idx = ((size_t)(m >> 10)*CC + n)*HWP + (m & 1023);
                        C[idx] = v + res[idx];
                    }
                }
            }
        }
    }
}

// ---------------- flash-style masked self-attention (fp16 MMA m16n8k16) ----------------
// Q pre-scaled (scale folded into wq1). Q,K,V fp16 [row][CC] slices per head.
#define AQ_PAD 28   // uint32 pairs per Q/K row (20 real + 8 zero-pad)
#define AV_PAD 36   // uint32 pairs per V^T row (32 real + 4 pad)
#define AP_PAD 36   // uint32 pairs per P row (32 real + 4 pad)

__global__ __launch_bounds__(256) void self_attn_f16_kernel(
    const __half* __restrict__ Q, const __half* __restrict__ K,
    const __half* __restrict__ V, const unsigned int* __restrict__ mask,
    __half* __restrict__ O)
{
    __shared__ uint32_t Qs[64][AQ_PAD];
    __shared__ uint32_t Ks[64][AQ_PAD];
    __shared__ uint32_t Vs[DHEAD][AV_PAD];   // V^T: [dhead][keys] halves
    __shared__ uint32_t Ps[64][AP_PAD];
    __shared__ float comb[64][41];
    __shared__ float sm_m[64], sm_l[64], sm_alpha[64];
    __shared__ float smx[2][64], ssum[2][64];

    int b = blockIdx.z, h = blockIdx.y, q0 = blockIdx.x * 64;
    int tid = threadIdx.x, lane = tid & 31, w = tid >> 5;
    int wm = w >> 1, wn = w & 1;
    int g = lane >> 2, tk = lane & 3;
    int r_lo = wm*16 + g, r_hi = r_lo + 8;

    for (int i = tid; i < 64*AQ_PAD; i += 256) {
        Qs[i/AQ_PAD][i%AQ_PAD] = 0;
        Ks[i/AQ_PAD][i%AQ_PAD] = 0;
    }
    {
        const uint32_t* qb = (const uint32_t*)Q;
        for (int i = tid; i < 64*20; i += 256) {
            int r = i/20, p = i%20;
            Qs[r][p] = qb[(((size_t)b*HWP + q0 + r)*CC + h*DHEAD)/2 + p];
        }
    }
    if (tid < 64) { sm_m[tid] = NEGMAX; sm_l[tid] = 0.f; }
    __syncthreads();

    uint32_t aq[3][4];
    #pragma unroll
    for (int s = 0; s < 3; s++) {
        aq[s][0] = Qs[r_lo][s*8 + tk];
        aq[s][1] = Qs[r_hi][s*8 + tk];
        aq[s][2] = Qs[r_lo][s*8 + 4 + tk];
        aq[s][3] = Qs[r_hi][s*8 + 4 + tk];
    }

    float o[5][4] = {};

    for (int jt = 0; jt < HWP/64; jt++) {
        __syncthreads();
        {
            const uint32_t* kb = (const uint32_t*)K;
            for (int i = tid; i < 64*20; i += 256) {
                int j = i/20, p = i%20;
                Ks[j][p] = kb[(((size_t)b*HWP + jt*64 + j)*CC + h*DHEAD)/2 + p];
            }
            const __half* vb = V + ((size_t)b*HWP + jt*64)*CC + h*DHEAD;
            __half* vsh = (__half*)Vs;
            for (int i = tid; i < 64*DHEAD; i += 256) {
                int j = i/DHEAD, c = i%DHEAD;
                vsh[c*(2*AV_PAD) + j] = vb[(size_t)j*CC + c];
            }
        }
        __syncthreads();

        float s_[4][4] = {};
        #pragma unroll
        for (int s = 0; s < 3; s++) {
            #pragma unroll
            for (int nt = 0; nt < 4; nt++) {
                int jn = wn*32 + nt*8 + g;
                mma_f16(s_[nt], aq[s][0], aq[s][1], aq[s][2], aq[s][3],
                        Ks[jn][s*8 + tk], Ks[jn][s*8 + 4 + tk]);
            }
        }

        const unsigned int* mlo_p = mask + ((size_t)b*HWP + q0 + r_lo)*HWP + (size_t)jt*64;
        const unsigned int* mhi_p = mask + ((size_t)b*HWP + q0 + r_hi)*HWP + (size_t)jt*64;
        float mlo = NEGMAX, mhi = NEGMAX;
        #pragma unroll
        for (int nt = 0; nt < 4; nt++) {
            int col = wn*32 + nt*8 + tk*2;
            uint2 m0v = *(const uint2*)(mlo_p + col);
            uint2 m1v = *(const uint2*)(mhi_p + col);
            s_[nt][0] = m0v.x ? s_[nt][0] : NEGMAX;
            s_[nt][1] = m0v.y ? s_[nt][1] : NEGMAX;
            s_[nt][2] = m1v.x ? s_[nt][2] : NEGMAX;
            s_[nt][3] = m1v.y ? s_[nt][3] : NEGMAX;
            mlo = fmaxf(mlo, fmaxf(s_[nt][0], s_[nt][1]));
            mhi = fmaxf(mhi, fmaxf(s_[nt][2], s_[nt][3]));
        }
        mlo = fmaxf(mlo, __shfl_xor_sync(0xffffffffu, mlo, 1));
        mlo = fmaxf(mlo, __shfl_xor_sync(0xffffffffu, mlo, 2));
        mhi = fmaxf(mhi, __shfl_xor_sync(0xffffffffu, mhi, 1));
        mhi = fmaxf(mhi, __shfl_xor_sync(0xffffffffu, mhi, 2));
        if (tk == 0) { smx[wn][r_lo] = mlo; smx[wn][r_hi] = mhi; }
        __syncthreads();

        if (tid < 64) {
            float mo = sm_m[tid];
            float mn = fmaxf(mo, fmaxf(smx[0][tid], smx[1][tid]));
            sm_m[tid] = mn;
            sm_alpha[tid] = __expf(mo - mn);
        }
        __syncthreads();

        float mn_lo = sm_m[r_lo], mn_hi = sm_m[r_hi];
        float slo = 0.f, shi = 0.f;
        #pragma unroll
        for (int nt = 0; nt < 4; nt++) {
            int pr = wn*16 + nt*4 + tk;
            float p0 = __expf(s_[nt][0] - mn_lo);
            float p1 = __expf(s_[nt][1] - mn_lo);
            float p2 = __expf(s_[nt][2] - mn_hi);
            float p3 = __expf(s_[nt][3] - mn_hi);
            slo += p0 + p1; shi += p2 + p3;
            Ps[r_lo][pr] = h2_to_u32(__floats2half2_rn(p0, p1));
            Ps[r_hi][pr] = h2_to_u32(__floats2half2_rn(p2, p3));
        }
        slo += __shfl_xor_sync(0xffffffffu, slo, 1);
        slo += __shfl_xor_sync(0xffffffffu, slo, 2);
        shi += __shfl_xor_sync(0xffffffffu, shi, 1);
        shi += __shfl_xor_sync(0xffffffffu, shi, 2);
        if (tk == 0) { ssum[wn][r_lo] = slo; ssum[wn][r_hi] = shi; }

        float alo = sm_alpha[r_lo], ahi = sm_alpha[r_hi];
        #pragma unroll
        for (int nt = 0; nt < 5; nt++) {
            o[nt][0] *= alo; o[nt][1] *= alo;
            o[nt][2] *= ahi; o[nt][3] *= ahi;
        }
        __syncthreads();

        if (tid < 64)
            sm_l[tid] = sm_alpha[tid]*sm_l[tid] + ssum[0][tid] + ssum[1][tid];

        #pragma unroll
        for (int s2 = 0; s2 < 2; s2++) {
            int pb = wn*16 + s2*8;
            uint32_t a0 = Ps[r_lo][pb + tk];
            uint32_t a1 = Ps[r_hi][pb + tk];
            uint32_t a2 = Ps[r_lo][pb + 4 + tk];
            uint32_t a3 = Ps[r_hi][pb + 4 + tk];
            #pragma unroll
            for (int nt = 0; nt < 5; nt++) {
                int n = nt*8 + g;
                mma_f16(o[nt], a0, a1, a2, a3,
                        Vs[n][pb + tk], Vs[n][pb + 4 + tk]);
            }
        }
    }
    __syncthreads();

    if (wn == 1) {
        #pragma unroll
        for (int nt = 0; nt < 5; nt++) {
            int c = nt*8 + tk*2;
            comb[r_lo][c]   = o[nt][0];
            comb[r_lo][c+1] = o[nt][1];
            comb[r_hi][c]   = o[nt][2];
            comb[r_hi][c+1] = o[nt][3];
        }
    }
    __syncthreads();
    if (wn == 0) {
        float il_lo = 1.f / sm_l[r_lo];
        float il_hi = 1.f / sm_l[r_hi];
        __half* out_lo = O + ((size_t)b*HWP + q0 + r_lo)*CC + h*DHEAD;
        __half* out_hi = O + ((size_t)b*HWP + q0 + r_hi)*CC + h*DHEAD;
        #pragma unroll
        for (int nt = 0; nt < 5; nt++) {
            int c = nt*8 + tk*2;
            float v0 = (o[nt][0] + comb[r_lo][c])   * il_lo;
            float v1 = (o[nt][1] + comb[r_lo][c+1]) * il_lo;
            float v2 = (o[nt][2] + comb[r_hi][c])   * il_hi;
            float v3 = (o[nt][3] + comb[r_hi][c+1]) * il_hi;
            *(__half2*)(out_lo + c) = __floats2half2_rn(v0, v1);
            *(__half2*)(out_hi + c) = __floats2half2_rn(v2, v3);
        }
    }
}

// ---------------- masked cross-attention (keys = 77, fp16 output) ----------------
#define QT2 16
__global__ __launch_bounds__(256) void cross_attn_kernel(
    const float* __restrict__ Q, const float* __restrict__ Kc,
    const float* __restrict__ Vc, const unsigned int* __restrict__ mask,
    __half* __restrict__ O)
{
    __shared__ float sk[CTX][DHEAD];
    __shared__ float sv[CTX][DHEAD];
    __shared__ float sq[QT2][DHEAD];
    __shared__ float sc[QT2][CTX+3];
    int b = blockIdx.z, h = blockIdx.y, q0 = blockIdx.x * QT2;
    int tid = threadIdx.x;

    for (int i = tid; i < CTX*DHEAD; i += 256) {
        int r = i / DHEAD, d = i % DHEAD;
        sk[r][d] = Kc[((size_t)b*CTX + r)*CC + h*DHEAD + d];
        sv[r][d] = Vc[((size_t)b*CTX + r)*CC + h*DHEAD + d];
    }
    for (int i = tid; i < QT2*DHEAD; i += 256) {
        int r = i / DHEAD, d = i % DHEAD;
        sq[r][d] = Q[((size_t)b*HWP + q0 + r)*CC + h*DHEAD + d];
    }
    __syncthreads();

    const float scale = rsqrtf((float)DHEAD);
    for (int idx = tid; idx < QT2*CTX; idx += 256) {
        int qi = idx / CTX, j = idx % CTX;
        float s = 0.f;
        #pragma unroll
        for (int d = 0; d < DHEAD; d++) s += sq[qi][d]*sk[j][d];
        unsigned int m = mask[((size_t)b*HWP + q0 + qi)*CTX + j];
        sc[qi][j] = (m != 0u) ? s*scale : NEGMAX;
    }
    __syncthreads();

    if (tid < QT2) {
        int qi = tid;
        float mx = NEGMAX;
        for (int j = 0; j < CTX; j++) mx = fmaxf(mx, sc[qi][j]);
        float sum = 0.f;
        for (int j = 0; j < CTX; j++) { float e = __expf(sc[qi][j]-mx); sc[qi][j] = e; sum += e; }
        float inv = 1.f/sum;
        for (int j = 0; j < CTX; j++) sc[qi][j] *= inv;
    }
    __syncthreads();

    for (int idx = tid; idx < QT2*DHEAD; idx += 256) {
        int qi = idx / DHEAD, d = idx % DHEAD;
        float s = 0.f;
        #pragma unroll
        for (int j = 0; j < CTX; j++) s += sc[qi][j]*sv[j][d];
        O[((size_t)b*HWP + q0 + qi)*CC + h*DHEAD + d] = __float2half(s);
    }
}

// ---------------- GEGLU: u = a * gelu_exact(g) -> fp16 ----------------
__global__ __launch_bounds__(256) void geglu_kernel(
    const float* __restrict__ Y, __half* __restrict__ U)
{
    size_t i = (size_t)blockIdx.x*256 + threadIdx.x;
    if (i >= (size_t)MROWS*FFI) return;
    size_t m = i / FFI, c = i % FFI;
    float a = Y[m*2*FFI + c];
    float g = Y[m*2*FFI + FFI + c];
    float ge = 0.5f * g * (1.f + erff(g * 0.70710678118654752f));
    U[i] = __float2half(a * ge);
}

// ---------------- host orchestration ----------------
static inline void run_gemm1(const __half* A, const __half* B, const float* bias,
                             const float* res, float* C, __half* C16,
                             int M, int N, int K, int mode)
{
    int nblk = N / GBN;
    dim3 grid(nblk, (M + GBM - 1) / GBM);
    mma_gemm_kernel<<<grid, 256, GEMM_SMEM_BYTES>>>(
        A, B, nullptr, nullptr, bias, res, C, nullptr, nullptr, C16, M, N, K, mode, nblk);
}

static inline void run_gemm3(const __half* A,
                             const __half* B0, const __half* B1, const __half* B2,
                             float* C0, float* C1, float* C2,
                             int M, int N, int K, int nmat, int mode)
{
    int nblk = N / GBN;
    dim3 grid(nblk * nmat, (M + GBM - 1) / GBM);
    mma_gemm_kernel<<<grid, 256, GEMM_SMEM_BYTES>>>(
        A, B0, B1, B2, nullptr, nullptr, C0, C1, C2, nullptr, M, N, K, mode, nblk);
}

extern "C" void kernel_launch(void* const* d_in, const int* in_sizes, int n_in,
                              void* d_out, int out_size)
{
    const float* x         = (const float*)d_in[0];
    const float* context   = (const float*)d_in[1];
    const unsigned int* vis_mask = (const unsigned int*)d_in[2];
    const unsigned int* v2t_mask = (const unsigned int*)d_in[3];
    const float* gn_scale  = (const float*)d_in[4];
    const float* gn_bias   = (const float*)d_in[5];
    const float* proj_in_w = (const float*)d_in[6];
    const float* proj_in_b = (const float*)d_in[7];
    const float* n1_s = (const float*)d_in[8];
    const float* n1_b = (const float*)d_in[9];
    const float* wq1  = (const float*)d_in[10];
    const float* wk1  = (const float*)d_in[11];
    const float* wv1  = (const float*)d_in[12];
    const float* wo1  = (const float*)d_in[13];
    const float* bo1  = (const float*)d_in[14];
    const float* n2_s = (const float*)d_in[15];
    const float* n2_b = (const float*)d_in[16];
    const float* wq2  = (const float*)d_in[17];
    const float* wk2  = (const float*)d_in[18];
    const float* wv2  = (const float*)d_in[19];
    const float* wo2  = (const float*)d_in[20];
    const float* bo2  = (const float*)d_in[21];
    const float* n3_s = (const float*)d_in[22];
    const float* n3_b = (const float*)d_in[23];
    const float* ff_w1 = (const float*)d_in[24];
    const float* ff_b1 = (const float*)d_in[25];
    const float* ff_w2 = (const float*)d_in[26];
    const float* ff_b2 = (const float*)d_in[27];
    const float* proj_out_w = (const float*)d_in[28];
    const float* proj_out_b = (const float*)d_in[29];
    float* out = (float*)d_out;

    cudaFuncSetAttribute(mma_gemm_kernel,
                         cudaFuncAttributeMaxDynamicSharedMemorySize, GEMM_SMEM_BYTES);

    float *h, *q, *k, *v, *ff1;
    __half *gn16, *ln16, *ao16, *ffu16, *ctx16, *h16, *wt16;
    cudaGetSymbolAddress((void**)&h,    g_h);
    cudaGetSymbolAddress((void**)&q,    g_q);
    cudaGetSymbolAddress((void**)&k,    g_k);
    cudaGetSymbolAddress((void**)&v,    g_v);
    cudaGetSymbolAddress((void**)&ff1,  g_ff1);
    cudaGetSymbolAddress((void**)&gn16, g_gn16);
    cudaGetSymbolAddress((void**)&ln16, g_ln16);
    cudaGetSymbolAddress((void**)&ao16, g_ao16);
    cudaGetSymbolAddress((void**)&ffu16,g_ffu16);
    cudaGetSymbolAddress((void**)&ctx16,g_ctx16);
    cudaGetSymbolAddress((void**)&h16,  g_h16);
    cudaGetSymbolAddress((void**)&wt16, g_wt16);

    // 0a. transpose all weight matrices to fp16 [N][K]; fold 1/sqrt(DHEAD) into wq1
    {
        TransDesc td;
        const float* srcs[12] = {proj_in_w, wq1, wk1, wv1, wo1, wq2, wo2, proj_out_w,
                                 wk2, wv2, ff_w1, ff_w2};
        __half* dsts[12] = {wt16+OFF_PIN, wt16+OFF_Q1, wt16+OFF_K1, wt16+OFF_V1, wt16+OFF_O1,
                            wt16+OFF_Q2, wt16+OFF_O2, wt16+OFF_POUT, wt16+OFF_K2, wt16+OFF_V2,
                            wt16+OFF_FF1, wt16+OFF_FF2};
        int Ks[12] = {CC,CC,CC,CC,CC,CC,CC,CC, CTXD,CTXD, CC, FFI};
        int Ns[12] = {CC,CC,CC,CC,CC,CC,CC,CC, CC,CC, 2*FFI, CC};
        int acc = 0;
        float qs = rsqrtf((float)DHEAD);
        for (int i = 0; i < 12; i++) {
            td.src[i] = srcs[i]; td.dst[i] = dsts[i];
            td.scl[i] = (i == 1) ? qs : 1.f;
            td.K[i] = Ks[i]; td.N[i] = Ns[i];
            td.start[i] = acc;
            acc += (Ks[i]/32) * (Ns[i]/32);
        }
        td.start[12] = acc;
        transpose_all_kernel<<<acc, 256>>>(td);
    }
    // 0b. context -> fp16
    {
        int n = BB*CTX*CTXD;
        f2h_kernel<<<(n + 255)/256, 256>>>(context, ctx16, n);
    }

    // 1. GroupNorm + transpose to [B, HW, C] (fp16)
    groupnorm_kernel<<<BB*32, 256>>>(x, gn_scale, gn_bias, gn16);
    // 2. proj_in
    run_gemm1(gn16, wt16+OFF_PIN, proj_in_b, nullptr, h, nullptr, MROWS, CC, CC, 0);
    // 3. LN1 (fp16 out)
    layernorm_kernel<<<MROWS, CC>>>(h, n1_s, n1_b, ln16);
    // 4. fused q,k,v (self) -> fp16 (q pre-scaled via wq1)
    run_gemm3(ln16, wt16+OFF_Q1, wt16+OFF_K1, wt16+OFF_V1, q, k, v, MROWS, CC, CC, 3, 2);
    // 5. masked self-attention (fp16 MMA)
    {
        dim3 grid(HWP/64, NHEADS, BB);
        self_attn_f16_kernel<<<grid, 256>>>((const __half*)q, (const __half*)k,
                                            (const __half*)v, vis_mask, ao16);
    }
    // 6. out-proj + residual
    run_gemm1(ao16, wt16+OFF_O1, bo1, h, h, nullptr, MROWS, CC, CC, 0);
    // 7. LN2
    layernorm_kernel<<<MROWS, CC>>>(h, n2_s, n2_b, ln16);
    // 8. q (cross) -> fp32
    run_gemm1(ln16, wt16+OFF_Q2, nullptr, nullptr, q, nullptr, MROWS, CC, CC, 0);
    // 9. fused k,v from context -> fp32
    run_gemm3(ctx16, wt16+OFF_K2, wt16+OFF_V2, nullptr, k, v, nullptr, BB*CTX, CC, CTXD, 2, 0);
    // 10. masked cross-attention (fp16 out)
    {
        dim3 grid(HWP/QT2, NHEADS, BB);
        cross_attn_kernel<<<grid, 256>>>(q, k, v, v2t_mask, ao16);
    }
    // 11. out-proj + residual
    run_gemm1(ao16, wt16+OFF_O2, bo2, h, h, nullptr, MROWS, CC, CC, 0);
    // 12. LN3
    layernorm_kernel<<<MROWS, CC>>>(h, n3_s, n3_b, ln16);
    // 13. FF up (GEGLU input)
    run_gemm1(ln16, wt16+OFF_FF1, ff_b1, nullptr, ff1, nullptr, MROWS, 2*FFI, CC, 0);
    // 14. GEGLU (fp16 out)
    {
        size_t n = (size_t)MROWS*FFI;
        geglu_kernel<<<(unsigned)((n + 255)/256), 256>>>(ff1, ffu16);
    }
    // 15. FF down + residual (emit fp16 copy for final proj)
    run_gemm1(ffu16, wt16+OFF_FF2, ff_b2, h, h, h16, MROWS, CC, FFI, 0);
    // 16. proj_out + transpose back to [B,C,H,W] + input residual
    run_gemm1(h16, wt16+OFF_POUT, proj_out_b, x, out, nullptr, MROWS, CC, CC, 1);
}

// round 14
// speedup vs baseline: 4.7407x; 1.0714x over previous
#include <cuda_runtime.h>
#include <cuda_fp16.h>
#include <math.h>
#include <stdint.h>

// ---------------- problem constants ----------------
#define BB      8
#define CC      320
#define HWP     1024
#define NHEADS  8
#define DHEAD   40
#define CTX     77
#define CTXD    768
#define FFI     1280          // FF_INNER
#define MROWS   (BB*HWP)      // 8192
#define NEGMAX  (-3.402823466e38f)

// ---------------- scratch (device globals; no runtime allocs) ----------------
__device__ float  g_h  [MROWS*CC];
__device__ float  g_q  [MROWS*CC];
__device__ float  g_k  [MROWS*CC];
__device__ float  g_v  [MROWS*CC];
__device__ float  g_ff1[MROWS*2*FFI];     // used as __half buffer for ff1 output
__device__ __half g_gn16 [MROWS*CC];
__device__ __half g_ln16 [MROWS*CC];
__device__ __half g_ao16 [MROWS*CC];
__device__ __half g_ffu16[(size_t)MROWS*FFI];
__device__ __half g_ctx16[BB*CTX*CTXD];
__device__ __half g_h16  [MROWS*CC];
__device__ __half g_wt16 [2539520];        // transposed weights [N][K], fp16

// offsets into g_wt16 (halves)
#define OFF_PIN  0
#define OFF_Q1   102400
#define OFF_K1   204800
#define OFF_V1   307200
#define OFF_O1   409600
#define OFF_Q2   512000
#define OFF_O2   614400
#define OFF_POUT 716800
#define OFF_K2   819200
#define OFF_V2   1064960
#define OFF_FF1  1310720
#define OFF_FF2  2129920

__device__ __forceinline__ uint32_t h2_to_u32(__half2 h) {
    union { __half2 h2; uint32_t u; } cvt;
    cvt.h2 = h;
    return cvt.u;
}

// ---------------- block reductions ----------------
__device__ __forceinline__ float blockReduceSum(float v, float* scratch) {
    int lane = threadIdx.x & 31, wid = threadIdx.x >> 5;
    #pragma unroll
    for (int o = 16; o > 0; o >>= 1) v += __shfl_down_sync(0xffffffffu, v, o);
    if (lane == 0) scratch[wid] = v;
    __syncthreads();
    int nw = (blockDim.x + 31) >> 5;
    v = (threadIdx.x < nw) ? scratch[threadIdx.x] : 0.f;
    if (wid == 0) {
        #pragma unroll
        for (int o = 16; o > 0; o >>= 1) v += __shfl_down_sync(0xffffffffu, v, o);
        if (lane == 0) scratch[0] = v;
    }
    __syncthreads();
    v = scratch[0];
    __syncthreads();
    return v;
}

// ---------------- GroupNorm -> fp16 [B,HW,C] ----------------
__global__ __launch_bounds__(256) void groupnorm_kernel(
    const float* __restrict__ x, const float* __restrict__ scale,
    const float* __restrict__ bias, __half* __restrict__ out)
{
    __shared__ float scratch[32];
    __shared__ float s_mu, s_inv;
    int b = blockIdx.x >> 5, g = blockIdx.x & 31;
    const float* xp = x + ((size_t)b*CC + g*10) * HWP;
    float sum = 0.f, sq = 0.f;
    for (int i = threadIdx.x; i < 10*HWP; i += 256) { float v = xp[i]; sum += v; sq += v*v; }
    sum = blockReduceSum(sum, scratch);
    sq  = blockReduceSum(sq,  scratch);
    if (threadIdx.x == 0) {
        float mu  = sum * (1.f/10240.f);
        float var = sq * (1.f/10240.f) - mu*mu;
        s_mu = mu; s_inv = rsqrtf(var + 1e-6f);
    }
    __syncthreads();
    float mu = s_mu, inv = s_inv;
    for (int i = threadIdx.x; i < 10*HWP; i += 256) {
        int cl = i >> 10, p = i & 1023;
        int c = g*10 + cl;
        float xn = (xp[i] - mu) * inv;
        out[((size_t)b*HWP + p)*CC + c] = __float2half(xn * scale[c] + bias[c]);
    }
}

// ---------------- LayerNorm over last dim = 320 -> fp16 ----------------
__global__ __launch_bounds__(CC) void layernorm_kernel(
    const float* __restrict__ X, const float* __restrict__ s,
    const float* __restrict__ bpar, __half* __restrict__ Y)
{
    __shared__ float scratch[32];
    int row = blockIdx.x, t = threadIdx.x;
    float v = X[(size_t)row*CC + t];
    float mu = blockReduceSum(v, scratch) * (1.f/CC);
    float d = v - mu;
    float var = blockReduceSum(d*d, scratch) * (1.f/CC);
    Y[(size_t)row*CC + t] = __float2half(d * rsqrtf(var + 1e-5f) * s[t] + bpar[t]);
}

// ---------------- weight transpose to fp16 [N][K] (with optional scale) ----------------
struct TransDesc {
    const float* src[12];
    __half* dst[12];
    float scl[12];
    int K[12], N[12];
    int start[13];
};

__global__ __launch_bounds__(256) void transpose_all_kernel(TransDesc p) {
    __shared__ float t[32][33];
    int bid = blockIdx.x;
    int i = 0;
    while (bid >= p.start[i+1]) i++;
    const float* src = p.src[i];
    __half* dst = p.dst[i];
    float scl = p.scl[i];
    int K = p.K[i], N = p.N[i];
    int lt = bid - p.start[i];
    int tiles_n = N >> 5;
    int tk = lt / tiles_n, tn = lt - tk*tiles_n;
    int tx = threadIdx.x & 31, ty = threadIdx.x >> 5;   // 32 x 8
    #pragma unroll
    for (int j = 0; j < 32; j += 8)
        t[ty+j][tx] = src[(size_t)(tk*32+ty+j)*N + tn*32 + tx];
    __syncthreads();
    #pragma unroll
    for (int j = 0; j < 32; j += 8)
        dst[(size_t)(tn*32+ty+j)*K + tk*32 + tx] = __float2half(t[tx][ty+j] * scl);
}

// ---------------- context -> fp16 ----------------
__global__ __launch_bounds__(256) void f2h_kernel(
    const float* __restrict__ src, __half* __restrict__ dst, int n)
{
    int i = blockIdx.x*256 + threadIdx.x;
    if (i < n) dst[i] = __float2half(src[i]);
}

// ---------------- mma / ldmatrix helpers ----------------
__device__ __forceinline__ void mma_f16(float c[4], uint32_t a0, uint32_t a1,
                                        uint32_t a2, uint32_t a3,
                                        uint32_t b0, uint32_t b1) {
    asm volatile(
        "mma.sync.aligned.m16n8k16.row.col.f32.f16.f16.f32 "
        "{%0,%1,%2,%3}, {%4,%5,%6,%7}, {%8,%9}, {%0,%1,%2,%3};"
        : "+f"(c[0]), "+f"(c[1]), "+f"(c[2]), "+f"(c[3])
        : "r"(a0), "r"(a1), "r"(a2), "r"(a3), "r"(b0), "r"(b1));
}

__device__ __forceinline__ void ldmatrix_x4(uint32_t& d0, uint32_t& d1,
                                            uint32_t& d2, uint32_t& d3, uint32_t addr) {
    asm volatile("ldmatrix.sync.aligned.m8n8.x4.shared.b16 {%0,%1,%2,%3}, [%4];"
                 : "=r"(d0), "=r"(d1), "=r"(d2), "=r"(d3) : "r"(addr));
}
__device__ __forceinline__ void ldmatrix_x2(uint32_t& d0, uint32_t& d1, uint32_t addr) {
    asm volatile("ldmatrix.sync.aligned.m8n8.x2.shared.b16 {%0,%1}, [%2];"
                 : "=r"(d0), "=r"(d1) : "r"(addr));
}

__device__ __forceinline__ void cp_async16_s(uint32_t saddr, const void* gsrc, int src_bytes) {
    asm volatile("cp.async.cg.shared.global [%0], [%1], 16, %2;"
                 :: "r"(saddr), "l"(gsrc), "r"(src_bytes));
}
#define CP_COMMIT()  asm volatile("cp.async.commit_group;")
#define CP_WAIT1()   asm volatile("cp.async.wait_group 1;")

// ---------------- fp16 tensor-core GEMM (64x64x64, 128 thr, ldmatrix swizzle) ----------
// C[mat] = A16 @ Bt16[mat]^T (+bias) (+res). A16 [M][K] fp16, Bt16 [N][K] fp16.
// N%64==0, K%64==0; M arbitrary.
// SMEM tiles: 16B chunks, chunk' = chunk ^ (row & 7)  -> conflict-free ldmatrix.
// mode 0: fp32 out (+optional fp16 copy C16); mode 1: final transposed store; mode 2: fp16-only.
#define GBM 64
#define GBN 64
#define GBK 64
#define NCH 8                    // 8 chunks of 16B per row (64 halves)
#define STAGES 3
#define A_STAGE_B (GBM*NCH*16)   // 8192
#define B_STAGE_B (GBN*NCH*16)   // 8192
#define GEMM_SMEM_BYTES (STAGES*(A_STAGE_B + B_STAGE_B))   // 49152

__global__ __launch_bounds__(128, 4) void mma_gemm_kernel(
    const __half* __restrict__ A,
    const __half* __restrict__ B0, const __half* __restrict__ B1, const __half* __restrict__ B2,
    const float* __restrict__ bias, const float* __restrict__ res,
    float* __restrict__ C0, float* __restrict__ C1, float* __restrict__ C2,
    __half* __restrict__ C16,
    int M, int N, int K, int mode, int nblk)
{
    extern __shared__ __align__(16) char smemraw[];
    uint32_t sbase = (uint32_t)__cvta_generic_to_shared(smemraw);
    uint32_t bbase0 = sbase + STAGES*A_STAGE_B;

    int mat = blockIdx.x / nblk;
    const __half* B = (mat == 0) ? B0 : ((mat == 1) ? B1 : B2);
    float* C        = (mat == 0) ? C0 : ((mat == 1) ? C1 : C2);
    int n0 = (blockIdx.x - mat*nblk) * GBN;

    int tid = threadIdx.x;
    int lane = tid & 31, warp = tid >> 5;
    int wm = warp >> 1, wn = warp & 1;             // 2 x 2 warps, warp tile 32x32
    int m0 = blockIdx.y * GBM;

    float acc[2][4][4];
    #pragma unroll
    for (int i = 0; i < 2; i++)
        #pragma unroll
        for (int j = 0; j < 4; j++)
            #pragma unroll
            for (int c = 0; c < 4; c++) acc[i][j][c] = 0.f;

    int g = lane >> 2, tk = lane & 3;

    // loader coords: one 16B chunk per (row, ch); 128 thr cover 16 rows/pass
    int l_row = tid >> 3, l_ch = tid & 7;

    // ldmatrix lane-address components
    int sub = lane >> 3, lr = lane & 7;          // A x4
    int lrB = lane & 7, subB = (lane >> 3) & 1;  // B x2

    int KT = K / GBK;

    auto prefetch = [&](int kt, int buf) {
        uint32_t abase = sbase + buf*A_STAGE_B;
        uint32_t bbase = bbase0 + buf*B_STAGE_B;
        int k0 = kt * GBK;
        #pragma unroll
        for (int j = 0; j < 4; j++) {
            int row = l_row + j*16;
            int gr = m0 + row;
            int ch = l_ch ^ (row & 7);
            const __half* src = A + ((gr < M) ? ((size_t)gr*K + k0 + l_ch*8) : 0);
            cp_async16_s(abase + (row*NCH + ch)*16, src, (gr < M) ? 16 : 0);
        }
        #pragma unroll
        for (int j = 0; j < 4; j++) {
            int row = l_row + j*16;
            int ch = l_ch ^ (row & 7);
            cp_async16_s(bbase + (row*NCH + ch)*16,
                         B + (size_t)(n0 + row)*K + k0 + l_ch*8, 16);
        }
        CP_COMMIT();
    };

    prefetch(0, 0);
    if (KT > 1) prefetch(1, 1); else CP_COMMIT();

    for (int kt = 0; kt < KT; kt++) {
        CP_WAIT1();
        __syncthreads();
        if (kt + 2 < KT) prefetch(kt+2, (kt+2) % STAGES);
        else CP_COMMIT();

        int buf = kt % STAGES;
        uint32_t abase = sbase + buf*A_STAGE_B;
        uint32_t bbase = bbase0 + buf*B_STAGE_B;

        #pragma unroll
        for (int s = 0; s < 4; s++) {
            int c0 = s*2;                         // chunk base for this k16 step
            uint32_t a[2][4];
            #pragma unroll
            for (int mt = 0; mt < 2; mt++) {
                int r = wm*32 + mt*16 + lr + (sub & 1)*8;
                int ch = (c0 + (sub >> 1)) ^ (r & 7);
                ldmatrix_x4(a[mt][0], a[mt][1], a[mt][2], a[mt][3],
                            abase + (r*NCH + ch)*16);
            }
            uint32_t b[4][2];
            #pragma unroll
            for (int nt = 0; nt < 4; nt++) {
                int rn = wn*32 + nt*8 + lrB;
                int ch = (c0 + subB) ^ (rn & 7);
                ldmatrix_x2(b[nt][0], b[nt][1], bbase + (rn*NCH + ch)*16);
            }
            #pragma unroll
            for (int mt = 0; mt < 2; mt++)
                #pragma unroll
                for (int nt = 0; nt < 4; nt++)
                    mma_f16(acc[mt][nt], a[mt][0], a[mt][1], a[mt][2], a[mt][3],
                            b[nt][0], b[nt][1]);
        }
    }

    // ---- epilogue (no k-split reduction) ----
    #pragma unroll
    for (int mt = 0; mt < 2; mt++) {
        #pragma unroll
        for (int nt = 0; nt < 4; nt++) {
            int mbase = m0 + wm*32 + mt*16 + g;
            int nbase = n0 + wn*32 + nt*8 + (tk << 1);
            #pragma unroll
            for (int c = 0; c < 4; c++) {
                int m = mbase + ((c >> 1) << 3);
                int n = nbase + (c & 1);
                if (m >= M) continue;
                float v = acc[mt][nt][c];
                if (bias) v += bias[n];
                if (mode == 0) {
                    size_t idx = (size_t)m*N + n;
                    if (res) v += res[idx];
                    C[idx] = v;
                    if (C16) C16[idx] = __float2half(v);
                } else if (mode == 2) {
                    ((__half*)C)[(size_t)m*N + n] = __float2half(v);
                } else {
                    size_t idx = ((size_t)(m >> 10)*CC + n)*HWP + (m & 1023);
                    C[idx] = v + res[idx];
                }
            }
        }
    }
}

// ---------------- flash-style masked self-attention (fp16 MMA m16n8k16) ----------------
// Q pre-scaled (scale folded into wq1). Q,K,V fp16 [row][CC] slices per head.
#define AQ_PAD 28   // uint32 pairs per Q/K row (20 real + 8 zero-pad)
#define AV_PAD 36   // uint32 pairs per V^T row (32 real + 4 pad)
#define AP_PAD 36   // uint32 pairs per P row (32 real + 4 pad)

__global__ __launch_bounds__(256) void self_attn_f16_kernel(
    const __half* __restrict__ Q, const __half* __restrict__ K,
    const __half* __restrict__ V, const unsigned int* __restrict__ mask,
    __half* __restrict__ O)
{
    __shared__ uint32_t Qs[64][AQ_PAD];
    __shared__ uint32_t Ks[64][AQ_PAD];
    __shared__ uint32_t Vs[DHEAD][AV_PAD];
    __shared__ uint32_t Ps[64][AP_PAD];
    __shared__ float comb[64][41];
    __shared__ float sm_m[64], sm_l[64], sm_alpha[64];
    __shared__ float smx[2][64], ssum[2][64];

    int b = blockIdx.z, h = blockIdx.y, q0 = blockIdx.x * 64;
    int tid = threadIdx.x, lane = tid & 31, w = tid >> 5;
    int wm = w >> 1, wn = w & 1;
    int g = lane >> 2, tk = lane & 3;
    int r_lo = wm*16 + g, r_hi = r_lo + 8;

    for (int i = tid; i < 64*AQ_PAD; i += 256) {
        Qs[i/AQ_PAD][i%AQ_PAD] = 0;
        Ks[i/AQ_PAD][i%AQ_PAD] = 0;
    }
    {
        const uint32_t* qb = (const uint32_t*)Q;
        for (int i = tid; i < 64*20; i += 256) {
            int r = i/20, p = i%20;
            Qs[r][p] = qb[(((size_t)b*HWP + q0 + r)*CC + h*DHEAD)/2 + p];
        }
    }
    if (tid < 64) { sm_m[tid] = NEGMAX; sm_l[tid] = 0.f; }
    __syncthreads();

    uint32_t aq[3][4];
    #pragma unroll
    for (int s = 0; s < 3; s++) {
        aq[s][0] = Qs[r_lo][s*8 + tk];
        aq[s][1] = Qs[r_hi][s*8 + tk];
        aq[s][2] = Qs[r_lo][s*8 + 4 + tk];
        aq[s][3] = Qs[r_hi][s*8 + 4 + tk];
    }

    float o[5][4] = {};

    for (int jt = 0; jt < HWP/64; jt++) {
        __syncthreads();
        {
            const uint32_t* kb = (const uint32_t*)K;
            for (int i = tid; i < 64*20; i += 256) {
                int j = i/20, p = i%20;
                Ks[j][p] = kb[(((size_t)b*HWP + jt*64 + j)*CC + h*DHEAD)/2 + p];
            }
            const __half* vb = V + ((size_t)b*HWP + jt*64)*CC + h*DHEAD;
            __half* vsh = (__half*)Vs;
            for (int i = tid; i < 64*DHEAD; i += 256) {
                int j = i/DHEAD, c = i%DHEAD;
                vsh[c*(2*AV_PAD) + j] = vb[(size_t)j*CC + c];
            }
        }
        __syncthreads();

        float s_[4][4] = {};
        #pragma unroll
        for (int s = 0; s < 3; s++) {
            #pragma unroll
            for (int nt = 0; nt < 4; nt++) {
                int jn = wn*32 + nt*8 + g;
                mma_f16(s_[nt], aq[s][0], aq[s][1], aq[s][2], aq[s][3],
                        Ks[jn][s*8 + tk], Ks[jn][s*8 + 4 + tk]);
            }
        }

        const unsigned int* mlo_p = mask + ((size_t)b*HWP + q0 + r_lo)*HWP + (size_t)jt*64;
        const unsigned int* mhi_p = mask + ((size_t)b*HWP + q0 + r_hi)*HWP + (size_t)jt*64;
        float mlo = NEGMAX, mhi = NEGMAX;
        #pragma unroll
        for (int nt = 0; nt < 4; nt++) {
            int col = wn*32 + nt*8 + tk*2;
            uint2 m0v = *(const uint2*)(mlo_p + col);
            uint2 m1v = *(const uint2*)(mhi_p + col);
            s_[nt][0] = m0v.x ? s_[nt][0] : NEGMAX;
            s_[nt][1] = m0v.y ? s_[nt][1] : NEGMAX;
            s_[nt][2] = m1v.x ? s_[nt][2] : NEGMAX;
            s_[nt][3] = m1v.y ? s_[nt][3] : NEGMAX;
            mlo = fmaxf(mlo, fmaxf(s_[nt][0], s_[nt][1]));
            mhi = fmaxf(mhi, fmaxf(s_[nt][2], s_[nt][3]));
        }
        mlo = fmaxf(mlo, __shfl_xor_sync(0xffffffffu, mlo, 1));
        mlo = fmaxf(mlo, __shfl_xor_sync(0xffffffffu, mlo, 2));
        mhi = fmaxf(mhi, __shfl_xor_sync(0xffffffffu, mhi, 1));
        mhi = fmaxf(mhi, __shfl_xor_sync(0xffffffffu, mhi, 2));
        if (tk == 0) { smx[wn][r_lo] = mlo; smx[wn][r_hi] = mhi; }
        __syncthreads();

        if (tid < 64) {
            float mo = sm_m[tid];
            float mn = fmaxf(mo, fmaxf(smx[0][tid], smx[1][tid]));
            sm_m[tid] = mn;
            sm_alpha[tid] = __expf(mo - mn);
        }
        __syncthreads();

        float mn_lo = sm_m[r_lo], mn_hi = sm_m[r_hi];
        float slo = 0.f, shi = 0.f;
        #pragma unroll
        for (int nt = 0; nt < 4; nt++) {
            int pr = wn*16 + nt*4 + tk;
            float p0 = __expf(s_[nt][0] - mn_lo);
            float p1 = __expf(s_[nt][1] - mn_lo);
            float p2 = __expf(s_[nt][2] - mn_hi);
            float p3 = __expf(s_[nt][3] - mn_hi);
            slo += p0 + p1; shi += p2 + p3;
            Ps[r_lo][pr] = h2_to_u32(__floats2half2_rn(p0, p1));
            Ps[r_hi][pr] = h2_to_u32(__floats2half2_rn(p2, p3));
        }
        slo += __shfl_xor_sync(0xffffffffu, slo, 1);
        slo += __shfl_xor_sync(0xffffffffu, slo, 2);
        shi += __shfl_xor_sync(0xffffffffu, shi, 1);
        shi += __shfl_xor_sync(0xffffffffu, shi, 2);
        if (tk == 0) { ssum[wn][r_lo] = slo; ssum[wn][r_hi] = shi; }

        float alo = sm_alpha[r_lo], ahi = sm_alpha[r_hi];
        #pragma unroll
        for (int nt = 0; nt < 5; nt++) {
            o[nt][0] *= alo; o[nt][1] *= alo;
            o[nt][2] *= ahi; o[nt][3] *= ahi;
        }
        __syncthreads();

        if (tid < 64)
            sm_l[tid] = sm_alpha[tid]*sm_l[tid] + ssum[0][tid] + ssum[1][tid];

        #pragma unroll
        for (int s2 = 0; s2 < 2; s2++) {
            int pb = wn*16 + s2*8;
            uint32_t a0 = Ps[r_lo][pb + tk];
            uint32_t a1 = Ps[r_hi][pb + tk];
            uint32_t a2 = Ps[r_lo][pb + 4 + tk];
            uint32_t a3 = Ps[r_hi][pb + 4 + tk];
            #pragma unroll
            for (int nt = 0; nt < 5; nt++) {
                int n = nt*8 + g;
                mma_f16(o[nt], a0, a1, a2, a3,
                        Vs[n][pb + tk], Vs[n][pb + 4 + tk]);
            }
        }
    }
    __syncthreads();

    if (wn == 1) {
        #pragma unroll
        for (int nt = 0; nt < 5; nt++) {
            int c = nt*8 + tk*2;
            comb[r_lo][c]   = o[nt][0];
            comb[r_lo][c+1] = o[nt][1];
            comb[r_hi][c]   = o[nt][2];
            comb[r_hi][c+1] = o[nt][3];
        }
    }
    __syncthreads();
    if (wn == 0) {
        float il_lo = 1.f / sm_l[r_lo];
        float il_hi = 1.f / sm_l[r_hi];
        __half* out_lo = O + ((size_t)b*HWP + q0 + r_lo)*CC + h*DHEAD;
        __half* out_hi = O + ((size_t)b*HWP + q0 + r_hi)*CC + h*DHEAD;
        #pragma unroll
        for (int nt = 0; nt < 5; nt++) {
            int c = nt*8 + tk*2;
            float v0 = (o[nt][0] + comb[r_lo][c])   * il_lo;
            float v1 = (o[nt][1] + comb[r_lo][c+1]) * il_lo;
            float v2 = (o[nt][2] + comb[r_hi][c])   * il_hi;
            float v3 = (o[nt][3] + comb[r_hi][c+1]) * il_hi;
            *(__half2*)(out_lo + c) = __floats2half2_rn(v0, v1);
            *(__half2*)(out_hi + c) = __floats2half2_rn(v2, v3);
        }
    }
}

// ---------------- masked cross-attention (keys = 77, fp16 output) ----------------
#define QT2 16
__global__ __launch_bounds__(256) void cross_attn_kernel(
    const float* __restrict__ Q, const float* __restrict__ Kc,
    const float* __restrict__ Vc, const unsigned int* __restrict__ mask,
    __half* __restrict__ O)
{
    __shared__ float sk[CTX][DHEAD];
    __shared__ float sv[CTX][DHEAD];
    __shared__ float sq[QT2][DHEAD];
    __shared__ float sc[QT2][CTX+3];
    int b = blockIdx.z, h = blockIdx.y, q0 = blockIdx.x * QT2;
    int tid = threadIdx.x;

    for (int i = tid; i < CTX*DHEAD; i += 256) {
        int r = i / DHEAD, d = i % DHEAD;
        sk[r][d] = Kc[((size_t)b*CTX + r)*CC + h*DHEAD + d];
        sv[r][d] = Vc[((size_t)b*CTX + r)*CC + h*DHEAD + d];
    }
    for (int i = tid; i < QT2*DHEAD; i += 256) {
        int r = i / DHEAD, d = i % DHEAD;
        sq[r][d] = Q[((size_t)b*HWP + q0 + r)*CC + h*DHEAD + d];
    }
    __syncthreads();

    const float scale = rsqrtf((float)DHEAD);
    for (int idx = tid; idx < QT2*CTX; idx += 256) {
        int qi = idx / CTX, j = idx % CTX;
        float s = 0.f;
        #pragma unroll
        for (int d = 0; d < DHEAD; d++) s += sq[qi][d]*sk[j][d];
        unsigned int m = mask[((size_t)b*HWP + q0 + qi)*CTX + j];
        sc[qi][j] = (m != 0u) ? s*scale : NEGMAX;
    }
    __syncthreads();

    if (tid < QT2) {
        int qi = tid;
        float mx = NEGMAX;
        for (int j = 0; j < CTX; j++) mx = fmaxf(mx, sc[qi][j]);
        float sum = 0.f;
        for (int j = 0; j < CTX; j++) { float e = __expf(sc[qi][j]-mx); sc[qi][j] = e; sum += e; }
        float inv = 1.f/sum;
        for (int j = 0; j < CTX; j++) sc[qi][j] *= inv;
    }
    __syncthreads();

    for (int idx = tid; idx < QT2*DHEAD; idx += 256) {
        int qi = idx / DHEAD, d = idx % DHEAD;
        float s = 0.f;
        #pragma unroll
        for (int j = 0; j < CTX; j++) s += sc[qi][j]*sv[j][d];
        O[((size_t)b*HWP + q0 + qi)*CC + h*DHEAD + d] = __float2half(s);
    }
}

// ---------------- GEGLU: u = a * gelu_exact(g) (fp16 in/out) ----------------
__global__ __launch_bounds__(256) void geglu_kernel(
    const __half* __restrict__ Y, __half* __restrict__ U)
{
    size_t i = (size_t)blockIdx.x*256 + threadIdx.x;
    if (i >= (size_t)MROWS*FFI) return;
    size_t m = i / FFI, c = i % FFI;
    float a = __half2float(Y[m*2*FFI + c]);
    float g = __half2float(Y[m*2*FFI + FFI + c]);
    float ge = 0.5f * g * (1.f + erff(g * 0.70710678118654752f));
    U[i] = __float2half(a * ge);
}

// ---------------- host orchestration ----------------
static inline void run_gemm1(const __half* A, const __half* B, const float* bias,
                             const float* res, float* C, __half* C16,
                             int M, int N, int K, int mode)
{
    int nblk = N / GBN;
    dim3 grid(nblk, (M + GBM - 1) / GBM);
    mma_gemm_kernel<<<grid, 128, GEMM_SMEM_BYTES>>>(
        A, B, nullptr, nullptr, bias, res, C, nullptr, nullptr, C16, M, N, K, mode, nblk);
}

static inline void run_gemm3(const __half* A,
                             const __half* B0, const __half* B1, const __half* B2,
                             float* C0, float* C1, float* C2,
                             int M, int N, int K, int nmat, int mode)
{
    int nblk = N / GBN;
    dim3 grid(nblk * nmat, (M + GBM - 1) / GBM);
    mma_gemm_kernel<<<grid, 128, GEMM_SMEM_BYTES>>>(
        A, B0, B1, B2, nullptr, nullptr, C0, C1, C2, nullptr, M, N, K, mode, nblk);
}

extern "C" void kernel_launch(void* const* d_in, const int* in_sizes, int n_in,
                              void* d_out, int out_size)
{
    const float* x         = (const float*)d_in[0];
    const float* context   = (const float*)d_in[1];
    const unsigned int* vis_mask = (const unsigned int*)d_in[2];
    const unsigned int* v2t_mask = (const unsigned int*)d_in[3];
    const float* gn_scale  = (const float*)d_in[4];
    const float* gn_bias   = (const float*)d_in[5];
    const float* proj_in_w = (const float*)d_in[6];
    const float* proj_in_b = (const float*)d_in[7];
    const float* n1_s = (const float*)d_in[8];
    const float* n1_b = (const float*)d_in[9];
    const float* wq1  = (const float*)d_in[10];
    const float* wk1  = (const float*)d_in[11];
    const float* wv1  = (const float*)d_in[12];
    const float* wo1  = (const float*)d_in[13];
    const float* bo1  = (const float*)d_in[14];
    const float* n2_s = (const float*)d_in[15];
    const float* n2_b = (const float*)d_in[16];
    const float* wq2  = (const float*)d_in[17];
    const float* wk2  = (const float*)d_in[18];
    const float* wv2  = (const float*)d_in[19];
    const float* wo2  = (const float*)d_in[20];
    const float* bo2  = (const float*)d_in[21];
    const float* n3_s = (const float*)d_in[22];
    const float* n3_b = (const float*)d_in[23];
    const float* ff_w1 = (const float*)d_in[24];
    const float* ff_b1 = (const float*)d_in[25];
    const float* ff_w2 = (const float*)d_in[26];
    const float* ff_b2 = (const float*)d_in[27];
    const float* proj_out_w = (const float*)d_in[28];
    const float* proj_out_b = (const float*)d_in[29];
    float* out = (float*)d_out;

    cudaFuncSetAttribute(mma_gemm_kernel,
                         cudaFuncAttributeMaxDynamicSharedMemorySize, GEMM_SMEM_BYTES);

    float *h, *q, *k, *v, *ff1;
    __half *gn16, *ln16, *ao16, *ffu16, *ctx16, *h16, *wt16;
    cudaGetSymbolAddress((void**)&h,    g_h);
    cudaGetSymbolAddress((void**)&q,    g_q);
    cudaGetSymbolAddress((void**)&k,    g_k);
    cudaGetSymbolAddress((void**)&v,    g_v);
    cudaGetSymbolAddress((void**)&ff1,  g_ff1);
    cudaGetSymbolAddress((void**)&gn16, g_gn16);
    cudaGetSymbolAddress((void**)&ln16, g_ln16);
    cudaGetSymbolAddress((void**)&ao16, g_ao16);
    cudaGetSymbolAddress((void**)&ffu16,g_ffu16);
    cudaGetSymbolAddress((void**)&ctx16,g_ctx16);
    cudaGetSymbolAddress((void**)&h16,  g_h16);
    cudaGetSymbolAddress((void**)&wt16, g_wt16);

    // 0a. transpose all weight matrices to fp16 [N][K]; fold 1/sqrt(DHEAD) into wq1
    {
        TransDesc td;
        const float* srcs[12] = {proj_in_w, wq1, wk1, wv1, wo1, wq2, wo2, proj_out_w,
                                 wk2, wv2, ff_w1, ff_w2};
        __half* dsts[12] = {wt16+OFF_PIN, wt16+OFF_Q1, wt16+OFF_K1, wt16+OFF_V1, wt16+OFF_O1,
                            wt16+OFF_Q2, wt16+OFF_O2, wt16+OFF_POUT, wt16+OFF_K2, wt16+OFF_V2,
                            wt16+OFF_FF1, wt16+OFF_FF2};
        int Ks[12] = {CC,CC,CC,CC,CC,CC,CC,CC, CTXD,CTXD, CC, FFI};
        int Ns[12] = {CC,CC,CC,CC,CC,CC,CC,CC, CC,CC, 2*FFI, CC};
        int acc = 0;
        float qs = rsqrtf((float)DHEAD);
        for (int i = 0; i < 12; i++) {
            td.src[i] = srcs[i]; td.dst[i] = dsts[i];
            td.scl[i] = (i == 1) ? qs : 1.f;
            td.K[i] = Ks[i]; td.N[i] = Ns[i];
            td.start[i] = acc;
            acc += (Ks[i]/32) * (Ns[i]/32);
        }
        td.start[12] = acc;
        transpose_all_kernel<<<acc, 256>>>(td);
    }
    // 0b. context -> fp16
    {
        int n = BB*CTX*CTXD;
        f2h_kernel<<<(n + 255)/256, 256>>>(context, ctx16, n);
    }

    // 1. GroupNorm + transpose to [B, HW, C] (fp16)
    groupnorm_kernel<<<BB*32, 256>>>(x, gn_scale, gn_bias, gn16);
    // 2. proj_in
    run_gemm1(gn16, wt16+OFF_PIN, proj_in_b, nullptr, h, nullptr, MROWS, CC, CC, 0);
    // 3. LN1 (fp16 out)
    layernorm_kernel<<<MROWS, CC>>>(h, n1_s, n1_b, ln16);
    // 4. fused q,k,v (self) -> fp16 (q pre-scaled via wq1)
    run_gemm3(ln16, wt16+OFF_Q1, wt16+OFF_K1, wt16+OFF_V1, q, k, v, MROWS, CC, CC, 3, 2);
    // 5. masked self-attention (fp16 MMA)
    {
        dim3 grid(HWP/64, NHEADS, BB);
        self_attn_f16_kernel<<<grid, 256>>>((const __half*)q, (const __half*)k,
                                            (const __half*)v, vis_mask, ao16);
    }
    // 6. out-proj + residual
    run_gemm1(ao16, wt16+OFF_O1, bo1, h, h, nullptr, MROWS, CC, CC, 0);
    // 7. LN2
    layernorm_kernel<<<MROWS, CC>>>(h, n2_s, n2_b, ln16);
    // 8. q (cross) -> fp32
    run_gemm1(ln16, wt16+OFF_Q2, nullptr, nullptr, q, nullptr, MROWS, CC, CC, 0);
    // 9. fused k,v from context -> fp32
    run_gemm3(ctx16, wt16+OFF_K2, wt16+OFF_V2, nullptr, k, v, nullptr, BB*CTX, CC, CTXD, 2, 0);
    // 10. masked cross-attention (fp16 out)
    {
        dim3 grid(HWP/QT2, NHEADS, BB);
        cross_attn_kernel<<<grid, 256>>>(q, k, v, v2t_mask, ao16);
    }
    // 11. out-proj + residual
    run_gemm1(ao16, wt16+OFF_O2, bo2, h, h, nullptr, MROWS, CC, CC, 0);
    // 12. LN3
    layernorm_kernel<<<MROWS, CC>>>(h, n3_s, n3_b, ln16);
    // 13. FF up (GEGLU input) -> fp16 only
    run_gemm1(ln16, wt16+OFF_FF1, ff_b1, nullptr, ff1, nullptr, MROWS, 2*FFI, CC, 2);
    // 14. GEGLU (fp16 in/out)
    {
        size_t n = (size_t)MROWS*FFI;
        geglu_kernel<<<(unsigned)((n + 255)/256), 256>>>((const __half*)ff1, ffu16);
    }
    // 15. FF down + residual (emit fp16 copy for final proj)
    run_gemm1(ffu16, wt16+OFF_FF2, ff_b2, h, h, h16, MROWS, CC, FFI, 0);
    // 16. proj_out + transpose back to [B,C,H,W] + input residual
    run_gemm1(h16, wt16+OFF_POUT, proj_out_b, x, out, nullptr, MROWS, CC, CC, 1);
}

// round 15
// speedup vs baseline: 4.9200x; 1.0378x over previous
#include <cuda_runtime.h>
#include <cuda_fp16.h>
#include <math.h>
#include <stdint.h>

// ---------------- problem constants ----------------
#define BB      8
#define CC      320
#define HWP     1024
#define NHEADS  8
#define DHEAD   40
#define CTX     77
#define CTXD    768
#define FFI     1280          // FF_INNER
#define MROWS   (BB*HWP)      // 8192
#define NEGMAX  (-3.402823466e38f)

// ---------------- scratch (device globals; no runtime allocs) ----------------
__device__ float  g_h  [MROWS*CC];
__device__ float  g_q  [MROWS*CC];
__device__ float  g_k  [MROWS*CC];
__device__ float  g_v  [MROWS*CC];
__device__ float  g_ff1[MROWS*2*FFI];     // used as __half buffer for ff1 output
__device__ __half g_gn16 [MROWS*CC];
__device__ __half g_ln16 [MROWS*CC];
__device__ __half g_ao16 [MROWS*CC];
__device__ __half g_ffu16[(size_t)MROWS*FFI];
__device__ __half g_ctx16[BB*CTX*CTXD];
__device__ __half g_h16  [MROWS*CC];
__device__ __half g_wt16 [2539520];        // transposed weights [N][K], fp16

// offsets into g_wt16 (halves)
#define OFF_PIN  0
#define OFF_Q1   102400
#define OFF_K1   204800
#define OFF_V1   307200
#define OFF_O1   409600
#define OFF_Q2   512000
#define OFF_O2   614400
#define OFF_POUT 716800
#define OFF_K2   819200
#define OFF_V2   1064960
#define OFF_FF1  1310720
#define OFF_FF2  2129920

__device__ __forceinline__ uint32_t h2_to_u32(__half2 h) {
    union { __half2 h2; uint32_t u; } cvt;
    cvt.h2 = h;
    return cvt.u;
}

// ---------------- block reductions ----------------
__device__ __forceinline__ float blockReduceSum(float v, float* scratch) {
    int lane = threadIdx.x & 31, wid = threadIdx.x >> 5;
    #pragma unroll
    for (int o = 16; o > 0; o >>= 1) v += __shfl_down_sync(0xffffffffu, v, o);
    if (lane == 0) scratch[wid] = v;
    __syncthreads();
    int nw = (blockDim.x + 31) >> 5;
    v = (threadIdx.x < nw) ? scratch[threadIdx.x] : 0.f;
    if (wid == 0) {
        #pragma unroll
        for (int o = 16; o > 0; o >>= 1) v += __shfl_down_sync(0xffffffffu, v, o);
        if (lane == 0) scratch[0] = v;
    }
    __syncthreads();
    v = scratch[0];
    __syncthreads();
    return v;
}

// ---------------- GroupNorm -> fp16 [B,HW,C] ----------------
__global__ __launch_bounds__(256) void groupnorm_kernel(
    const float* __restrict__ x, const float* __restrict__ scale,
    const float* __restrict__ bias, __half* __restrict__ out)
{
    __shared__ float scratch[32];
    __shared__ float s_mu, s_inv;
    int b = blockIdx.x >> 5, g = blockIdx.x & 31;
    const float* xp = x + ((size_t)b*CC + g*10) * HWP;
    float sum = 0.f, sq = 0.f;
    for (int i = threadIdx.x; i < 10*HWP; i += 256) { float v = xp[i]; sum += v; sq += v*v; }
    sum = blockReduceSum(sum, scratch);
    sq  = blockReduceSum(sq,  scratch);
    if (threadIdx.x == 0) {
        float mu  = sum * (1.f/10240.f);
        float var = sq * (1.f/10240.f) - mu*mu;
        s_mu = mu; s_inv = rsqrtf(var + 1e-6f);
    }
    __syncthreads();
    float mu = s_mu, inv = s_inv;
    for (int i = threadIdx.x; i < 10*HWP; i += 256) {
        int cl = i >> 10, p = i & 1023;
        int c = g*10 + cl;
        float xn = (xp[i] - mu) * inv;
        out[((size_t)b*HWP + p)*CC + c] = __float2half(xn * scale[c] + bias[c]);
    }
}

// ---------------- LayerNorm over last dim = 320 -> fp16 ----------------
__global__ __launch_bounds__(CC) void layernorm_kernel(
    const float* __restrict__ X, const float* __restrict__ s,
    const float* __restrict__ bpar, __half* __restrict__ Y)
{
    __shared__ float scratch[32];
    int row = blockIdx.x, t = threadIdx.x;
    float v = X[(size_t)row*CC + t];
    float mu = blockReduceSum(v, scratch) * (1.f/CC);
    float d = v - mu;
    float var = blockReduceSum(d*d, scratch) * (1.f/CC);
    Y[(size_t)row*CC + t] = __float2half(d * rsqrtf(var + 1e-5f) * s[t] + bpar[t]);
}

// ---------------- weight transpose to fp16 [N][K] (with optional scale) ----------------
struct TransDesc {
    const float* src[12];
    __half* dst[12];
    float scl[12];
    int K[12], N[12];
    int start[13];
};

__global__ __launch_bounds__(256) void transpose_all_kernel(TransDesc p) {
    __shared__ float t[32][33];
    int bid = blockIdx.x;
    int i = 0;
    while (bid >= p.start[i+1]) i++;
    const float* src = p.src[i];
    __half* dst = p.dst[i];
    float scl = p.scl[i];
    int K = p.K[i], N = p.N[i];
    int lt = bid - p.start[i];
    int tiles_n = N >> 5;
    int tk = lt / tiles_n, tn = lt - tk*tiles_n;
    int tx = threadIdx.x & 31, ty = threadIdx.x >> 5;   // 32 x 8
    #pragma unroll
    for (int j = 0; j < 32; j += 8)
        t[ty+j][tx] = src[(size_t)(tk*32+ty+j)*N + tn*32 + tx];
    __syncthreads();
    #pragma unroll
    for (int j = 0; j < 32; j += 8)
        dst[(size_t)(tn*32+ty+j)*K + tk*32 + tx] = __float2half(t[tx][ty+j] * scl);
}

// ---------------- context -> fp16 ----------------
__global__ __launch_bounds__(256) void f2h_kernel(
    const float* __restrict__ src, __half* __restrict__ dst, int n)
{
    int i = blockIdx.x*256 + threadIdx.x;
    if (i < n) dst[i] = __float2half(src[i]);
}

// ---------------- mma / ldmatrix helpers ----------------
__device__ __forceinline__ void mma_f16(float c[4], uint32_t a0, uint32_t a1,
                                        uint32_t a2, uint32_t a3,
                                        uint32_t b0, uint32_t b1) {
    asm volatile(
        "mma.sync.aligned.m16n8k16.row.col.f32.f16.f16.f32 "
        "{%0,%1,%2,%3}, {%4,%5,%6,%7}, {%8,%9}, {%0,%1,%2,%3};"
        : "+f"(c[0]), "+f"(c[1]), "+f"(c[2]), "+f"(c[3])
        : "r"(a0), "r"(a1), "r"(a2), "r"(a3), "r"(b0), "r"(b1));
}

__device__ __forceinline__ void ldmatrix_x4(uint32_t& d0, uint32_t& d1,
                                            uint32_t& d2, uint32_t& d3, uint32_t addr) {
    asm volatile("ldmatrix.sync.aligned.m8n8.x4.shared.b16 {%0,%1,%2,%3}, [%4];"
                 : "=r"(d0), "=r"(d1), "=r"(d2), "=r"(d3) : "r"(addr));
}
__device__ __forceinline__ void ldmatrix_x2(uint32_t& d0, uint32_t& d1, uint32_t addr) {
    asm volatile("ldmatrix.sync.aligned.m8n8.x2.shared.b16 {%0,%1}, [%2];"
                 : "=r"(d0), "=r"(d1) : "r"(addr));
}

__device__ __forceinline__ void cp_async16_s(uint32_t saddr, const void* gsrc, int src_bytes) {
    asm volatile("cp.async.cg.shared.global [%0], [%1], 16, %2;"
                 :: "r"(saddr), "l"(gsrc), "r"(src_bytes));
}
#define CP_COMMIT()  asm volatile("cp.async.commit_group;")
#define CP_WAIT1()   asm volatile("cp.async.wait_group 1;")

// ---------------- fp16 tensor-core GEMM (64x64x64, 128 thr, ldmatrix swizzle) ----------
#define GBM 64
#define GBN 64
#define GBK 64
#define NCH 8
#define STAGES 3
#define A_STAGE_B (GBM*NCH*16)
#define B_STAGE_B (GBN*NCH*16)
#define GEMM_SMEM_BYTES (STAGES*(A_STAGE_B + B_STAGE_B))   // 49152

__global__ __launch_bounds__(128, 4) void mma_gemm_kernel(
    const __half* __restrict__ A,
    const __half* __restrict__ B0, const __half* __restrict__ B1, const __half* __restrict__ B2,
    const float* __restrict__ bias, const float* __restrict__ res,
    float* __restrict__ C0, float* __restrict__ C1, float* __restrict__ C2,
    __half* __restrict__ C16,
    int M, int N, int K, int mode, int nblk)
{
    extern __shared__ __align__(16) char smemraw[];
    uint32_t sbase = (uint32_t)__cvta_generic_to_shared(smemraw);
    uint32_t bbase0 = sbase + STAGES*A_STAGE_B;

    int mat = blockIdx.x / nblk;
    const __half* B = (mat == 0) ? B0 : ((mat == 1) ? B1 : B2);
    float* C        = (mat == 0) ? C0 : ((mat == 1) ? C1 : C2);
    int n0 = (blockIdx.x - mat*nblk) * GBN;

    int tid = threadIdx.x;
    int lane = tid & 31, warp = tid >> 5;
    int wm = warp >> 1, wn = warp & 1;
    int m0 = blockIdx.y * GBM;

    float acc[2][4][4];
    #pragma unroll
    for (int i = 0; i < 2; i++)
        #pragma unroll
        for (int j = 0; j < 4; j++)
            #pragma unroll
            for (int c = 0; c < 4; c++) acc[i][j][c] = 0.f;

    int g = lane >> 2, tk = lane & 3;
    int l_row = tid >> 3, l_ch = tid & 7;
    int sub = lane >> 3, lr = lane & 7;
    int lrB = lane & 7, subB = (lane >> 3) & 1;

    int KT = K / GBK;

    auto prefetch = [&](int kt, int buf) {
        uint32_t abase = sbase + buf*A_STAGE_B;
        uint32_t bbase = bbase0 + buf*B_STAGE_B;
        int k0 = kt * GBK;
        #pragma unroll
        for (int j = 0; j < 4; j++) {
            int row = l_row + j*16;
            int gr = m0 + row;
            int ch = l_ch ^ (row & 7);
            const __half* src = A + ((gr < M) ? ((size_t)gr*K + k0 + l_ch*8) : 0);
            cp_async16_s(abase + (row*NCH + ch)*16, src, (gr < M) ? 16 : 0);
        }
        #pragma unroll
        for (int j = 0; j < 4; j++) {
            int row = l_row + j*16;
            int ch = l_ch ^ (row & 7);
            cp_async16_s(bbase + (row*NCH + ch)*16,
                         B + (size_t)(n0 + row)*K + k0 + l_ch*8, 16);
        }
        CP_COMMIT();
    };

    prefetch(0, 0);
    if (KT > 1) prefetch(1, 1); else CP_COMMIT();

    for (int kt = 0; kt < KT; kt++) {
        CP_WAIT1();
        __syncthreads();
        if (kt + 2 < KT) prefetch(kt+2, (kt+2) % STAGES);
        else CP_COMMIT();

        int buf = kt % STAGES;
        uint32_t abase = sbase + buf*A_STAGE_B;
        uint32_t bbase = bbase0 + buf*B_STAGE_B;

        #pragma unroll
        for (int s = 0; s < 4; s++) {
            int c0 = s*2;
            uint32_t a[2][4];
            #pragma unroll
            for (int mt = 0; mt < 2; mt++) {
                int r = wm*32 + mt*16 + lr + (sub & 1)*8;
                int ch = (c0 + (sub >> 1)) ^ (r & 7);
                ldmatrix_x4(a[mt][0], a[mt][1], a[mt][2], a[mt][3],
                            abase + (r*NCH + ch)*16);
            }
            uint32_t b[4][2];
            #pragma unroll
            for (int nt = 0; nt < 4; nt++) {
                int rn = wn*32 + nt*8 + lrB;
                int ch = (c0 + subB) ^ (rn & 7);
                ldmatrix_x2(b[nt][0], b[nt][1], bbase + (rn*NCH + ch)*16);
            }
            #pragma unroll
            for (int mt = 0; mt < 2; mt++)
                #pragma unroll
                for (int nt = 0; nt < 4; nt++)
                    mma_f16(acc[mt][nt], a[mt][0], a[mt][1], a[mt][2], a[mt][3],
                            b[nt][0], b[nt][1]);
        }
    }

    #pragma unroll
    for (int mt = 0; mt < 2; mt++) {
        #pragma unroll
        for (int nt = 0; nt < 4; nt++) {
            int mbase = m0 + wm*32 + mt*16 + g;
            int nbase = n0 + wn*32 + nt*8 + (tk << 1);
            #pragma unroll
            for (int c = 0; c < 4; c++) {
                int m = mbase + ((c >> 1) << 3);
                int n = nbase + (c & 1);
                if (m >= M) continue;
                float v = acc[mt][nt][c];
                if (bias) v += bias[n];
                if (mode == 0) {
                    size_t idx = (size_t)m*N + n;
                    if (res) v += res[idx];
                    C[idx] = v;
                    if (C16) C16[idx] = __float2half(v);
                } else if (mode == 2) {
                    ((__half*)C)[(size_t)m*N + n] = __float2half(v);
                } else {
                    size_t idx = ((size_t)(m >> 10)*CC + n)*HWP + (m & 1023);
                    C[idx] = v + res[idx];
                }
            }
        }
    }
}

// ---------------- flash-style masked self-attention (fp16, 128-key tiles) ----------------
// Q pre-scaled (folded into wq1). Dynamic SMEM layout (bytes):
#define AT_TK   128
#define AQ_PAD  28   // u32 pairs per Q/K row (20 real + 8 zero-pad)
#define AV2_PAD 68   // u32 pairs per V^T row (64 real + 4 pad)
#define AP2_PAD 68   // u32 pairs per P row (64 real + 4 pad)
#define SA_QS   0
#define SA_KS   (SA_QS + 64*AQ_PAD*4)          // 7168
#define SA_VS   (SA_KS + 128*AQ_PAD*4)         // 7168+14336=21504
#define SA_PS   (SA_VS + DHEAD*AV2_PAD*4)      // +10880=32384
#define SA_COMB (SA_PS + 64*AP2_PAD*4)         // +17408=49792
#define SA_M    (SA_COMB + 64*41*4)            // +10496=60288
#define SA_L    (SA_M + 256)
#define SA_AL   (SA_L + 256)
#define SA_MX   (SA_AL + 256)
#define SA_SS   (SA_MX + 512)
#define SA_SMEM (SA_SS + 512)                  // 62336

__global__ __launch_bounds__(256) void self_attn_f16_kernel(
    const __half* __restrict__ Q, const __half* __restrict__ K,
    const __half* __restrict__ V, const unsigned int* __restrict__ mask,
    __half* __restrict__ O)
{
    extern __shared__ __align__(16) char sa_smem[];
    uint32_t (*Qs)[AQ_PAD]  = (uint32_t(*)[AQ_PAD])(sa_smem + SA_QS);
    uint32_t (*Ks)[AQ_PAD]  = (uint32_t(*)[AQ_PAD])(sa_smem + SA_KS);
    uint32_t (*Vs)[AV2_PAD] = (uint32_t(*)[AV2_PAD])(sa_smem + SA_VS);
    uint32_t (*Ps)[AP2_PAD] = (uint32_t(*)[AP2_PAD])(sa_smem + SA_PS);
    float (*comb)[41] = (float(*)[41])(sa_smem + SA_COMB);
    float* sm_m     = (float*)(sa_smem + SA_M);
    float* sm_l     = (float*)(sa_smem + SA_L);
    float* sm_alpha = (float*)(sa_smem + SA_AL);
    float (*smx)[64]  = (float(*)[64])(sa_smem + SA_MX);
    float (*ssum)[64] = (float(*)[64])(sa_smem + SA_SS);

    int b = blockIdx.z, h = blockIdx.y, q0 = blockIdx.x * 64;
    int tid = threadIdx.x, lane = tid & 31, w = tid >> 5;
    int wm = w >> 1, wn = w & 1;
    int g = lane >> 2, tk = lane & 3;
    int r_lo = wm*16 + g, r_hi = r_lo + 8;

    // zero Q/K pads once
    for (int i = tid; i < 64*AQ_PAD; i += 256) Qs[i/AQ_PAD][i%AQ_PAD] = 0;
    for (int i = tid; i < 128*AQ_PAD; i += 256) Ks[i/AQ_PAD][i%AQ_PAD] = 0;
    {
        const uint32_t* qb = (const uint32_t*)Q;
        for (int i = tid; i < 64*20; i += 256) {
            int r = i/20, p = i%20;
            Qs[r][p] = qb[(((size_t)b*HWP + q0 + r)*CC + h*DHEAD)/2 + p];
        }
    }
    if (tid < 64) { sm_m[tid] = NEGMAX; sm_l[tid] = 0.f; }
    __syncthreads();

    uint32_t aq[3][4];
    #pragma unroll
    for (int s = 0; s < 3; s++) {
        aq[s][0] = Qs[r_lo][s*8 + tk];
        aq[s][1] = Qs[r_hi][s*8 + tk];
        aq[s][2] = Qs[r_lo][s*8 + 4 + tk];
        aq[s][3] = Qs[r_hi][s*8 + 4 + tk];
    }

    float o[5][4] = {};

    for (int jt = 0; jt < HWP/AT_TK; jt++) {
        __syncthreads();
        {
            const uint32_t* kb = (const uint32_t*)K;
            for (int i = tid; i < 128*20; i += 256) {
                int j = i/20, p = i%20;
                Ks[j][p] = kb[(((size_t)b*HWP + jt*AT_TK + j)*CC + h*DHEAD)/2 + p];
            }
            const __half* vb = V + ((size_t)b*HWP + jt*AT_TK)*CC + h*DHEAD;
            __half* vsh = (__half*)(sa_smem + SA_VS);
            for (int i = tid; i < AT_TK*DHEAD; i += 256) {
                int j = i/DHEAD, c = i%DHEAD;
                vsh[c*(2*AV2_PAD) + j] = vb[(size_t)j*CC + c];
            }
        }
        __syncthreads();

        // S = Q K^T over 64 columns per wn-half (8 n-tiles)
        float s_[8][4] = {};
        #pragma unroll
        for (int s = 0; s < 3; s++) {
            #pragma unroll
            for (int nt = 0; nt < 8; nt++) {
                int jn = wn*64 + nt*8 + g;
                mma_f16(s_[nt], aq[s][0], aq[s][1], aq[s][2], aq[s][3],
                        Ks[jn][s*8 + tk], Ks[jn][s*8 + 4 + tk]);
            }
        }

        const unsigned int* mlo_p = mask + ((size_t)b*HWP + q0 + r_lo)*HWP + (size_t)jt*AT_TK;
        const unsigned int* mhi_p = mask + ((size_t)b*HWP + q0 + r_hi)*HWP + (size_t)jt*AT_TK;
        float mlo = NEGMAX, mhi = NEGMAX;
        #pragma unroll
        for (int nt = 0; nt < 8; nt++) {
            int col = wn*64 + nt*8 + tk*2;
            uint2 m0v = *(const uint2*)(mlo_p + col);
            uint2 m1v = *(const uint2*)(mhi_p + col);
            s_[nt][0] = m0v.x ? s_[nt][0] : NEGMAX;
            s_[nt][1] = m0v.y ? s_[nt][1] : NEGMAX;
            s_[nt][2] = m1v.x ? s_[nt][2] : NEGMAX;
            s_[nt][3] = m1v.y ? s_[nt][3] : NEGMAX;
            mlo = fmaxf(mlo, fmaxf(s_[nt][0], s_[nt][1]));
            mhi = fmaxf(mhi, fmaxf(s_[nt][2], s_[nt][3]));
        }
        mlo = fmaxf(mlo, __shfl_xor_sync(0xffffffffu, mlo, 1));
        mlo = fmaxf(mlo, __shfl_xor_sync(0xffffffffu, mlo, 2));
        mhi = fmaxf(mhi, __shfl_xor_sync(0xffffffffu, mhi, 1));
        mhi = fmaxf(mhi, __shfl_xor_sync(0xffffffffu, mhi, 2));
        if (tk == 0) { smx[wn][r_lo] = mlo; smx[wn][r_hi] = mhi; }
        __syncthreads();

        if (tid < 64) {
            float mo = sm_m[tid];
            float mn = fmaxf(mo, fmaxf(smx[0][tid], smx[1][tid]));
            sm_m[tid] = mn;
            sm_alpha[tid] = __expf(mo - mn);
        }
        __syncthreads();

        float mn_lo = sm_m[r_lo], mn_hi = sm_m[r_hi];
        float slo = 0.f, shi = 0.f;
        #pragma unroll
        for (int nt = 0; nt < 8; nt++) {
            int pr = wn*32 + nt*4 + tk;
            float p0 = __expf(s_[nt][0] - mn_lo);
            float p1 = __expf(s_[nt][1] - mn_lo);
            float p2 = __expf(s_[nt][2] - mn_hi);
            float p3 = __expf(s_[nt][3] - mn_hi);
            slo += p0 + p1; shi += p2 + p3;
            Ps[r_lo][pr] = h2_to_u32(__floats2half2_rn(p0, p1));
            Ps[r_hi][pr] = h2_to_u32(__floats2half2_rn(p2, p3));
        }
        slo += __shfl_xor_sync(0xffffffffu, slo, 1);
        slo += __shfl_xor_sync(0xffffffffu, slo, 2);
        shi += __shfl_xor_sync(0xffffffffu, shi, 1);
        shi += __shfl_xor_sync(0xffffffffu, shi, 2);
        if (tk == 0) { ssum[wn][r_lo] = slo; ssum[wn][r_hi] = shi; }

        float alo = sm_alpha[r_lo], ahi = sm_alpha[r_hi];
        #pragma unroll
        for (int nt = 0; nt < 5; nt++) {
            o[nt][0] *= alo; o[nt][1] *= alo;
            o[nt][2] *= ahi; o[nt][3] *= ahi;
        }
        __syncthreads();

        if (tid < 64)
            sm_l[tid] = sm_alpha[tid]*sm_l[tid] + ssum[0][tid] + ssum[1][tid];

        // O += P V : wn half covers pairs [wn*32, wn*32+32) = keys [wn*64, wn*64+64)
        #pragma unroll
        for (int s2 = 0; s2 < 4; s2++) {
            int pb = wn*32 + s2*8;
            uint32_t a0 = Ps[r_lo][pb + tk];
            uint32_t a1 = Ps[r_hi][pb + tk];
            uint32_t a2 = Ps[r_lo][pb + 4 + tk];
            uint32_t a3 = Ps[r_hi][pb + 4 + tk];
            #pragma unroll
            for (int nt = 0; nt < 5; nt++) {
                int n = nt*8 + g;
                mma_f16(o[nt], a0, a1, a2, a3,
                        Vs[n][pb + tk], Vs[n][pb + 4 + tk]);
            }
        }
    }
    __syncthreads();

    if (wn == 1) {
        #pragma unroll
        for (int nt = 0; nt < 5; nt++) {
            int c = nt*8 + tk*2;
            comb[r_lo][c]   = o[nt][0];
            comb[r_lo][c+1] = o[nt][1];
            comb[r_hi][c]   = o[nt][2];
            comb[r_hi][c+1] = o[nt][3];
        }
    }
    __syncthreads();
    if (wn == 0) {
        float il_lo = 1.f / sm_l[r_lo];
        float il_hi = 1.f / sm_l[r_hi];
        __half* out_lo = O + ((size_t)b*HWP + q0 + r_lo)*CC + h*DHEAD;
        __half* out_hi = O + ((size_t)b*HWP + q0 + r_hi)*CC + h*DHEAD;
        #pragma unroll
        for (int nt = 0; nt < 5; nt++) {
            int c = nt*8 + tk*2;
            float v0 = (o[nt][0] + comb[r_lo][c])   * il_lo;
            float v1 = (o[nt][1] + comb[r_lo][c+1]) * il_lo;
            float v2 = (o[nt][2] + comb[r_hi][c])   * il_hi;
            float v3 = (o[nt][3] + comb[r_hi][c+1]) * il_hi;
            *(__half2*)(out_lo + c) = __floats2half2_rn(v0, v1);
            *(__half2*)(out_hi + c) = __floats2half2_rn(v2, v3);
        }
    }
}

// ---------------- masked cross-attention (keys = 77, fp16 output) ----------------
#define QT2 16
__global__ __launch_bounds__(256) void cross_attn_kernel(
    const float* __restrict__ Q, const float* __restrict__ Kc,
    const float* __restrict__ Vc, const unsigned int* __restrict__ mask,
    __half* __restrict__ O)
{
    __shared__ float sk[CTX][DHEAD];
    __shared__ float sv[CTX][DHEAD];
    __shared__ float sq[QT2][DHEAD];
    __shared__ float sc[QT2][CTX+3];
    int b = blockIdx.z, h = blockIdx.y, q0 = blockIdx.x * QT2;
    int tid = threadIdx.x;

    for (int i = tid; i < CTX*DHEAD; i += 256) {
        int r = i / DHEAD, d = i % DHEAD;
        sk[r][d] = Kc[((size_t)b*CTX + r)*CC + h*DHEAD + d];
        sv[r][d] = Vc[((size_t)b*CTX + r)*CC + h*DHEAD + d];
    }
    for (int i = tid; i < QT2*DHEAD; i += 256) {
        int r = i / DHEAD, d = i % DHEAD;
        sq[r][d] = Q[((size_t)b*HWP + q0 + r)*CC + h*DHEAD + d];
    }
    __syncthreads();

    const float scale = rsqrtf((float)DHEAD);
    for (int idx = tid; idx < QT2*CTX; idx += 256) {
        int qi = idx / CTX, j = idx % CTX;
        float s = 0.f;
        #pragma unroll
        for (int d = 0; d < DHEAD; d++) s += sq[qi][d]*sk[j][d];
        unsigned int m = mask[((size_t)b*HWP + q0 + qi)*CTX + j];
        sc[qi][j] = (m != 0u) ? s*scale : NEGMAX;
    }
    __syncthreads();

    if (tid < QT2) {
        int qi = tid;
        float mx = NEGMAX;
        for (int j = 0; j < CTX; j++) mx = fmaxf(mx, sc[qi][j]);
        float sum = 0.f;
        for (int j = 0; j < CTX; j++) { float e = __expf(sc[qi][j]-mx); sc[qi][j] = e; sum += e; }
        float inv = 1.f/sum;
        for (int j = 0; j < CTX; j++) sc[qi][j] *= inv;
    }
    __syncthreads();

    for (int idx = tid; idx < QT2*DHEAD; idx += 256) {
        int qi = idx / DHEAD, d = idx % DHEAD;
        float s = 0.f;
        #pragma unroll
        for (int j = 0; j < CTX; j++) s += sc[qi][j]*sv[j][d];
        O[((size_t)b*HWP + q0 + qi)*CC + h*DHEAD + d] = __float2half(s);
    }
}

// ---------------- GEGLU: u = a * gelu_exact(g) (fp16 in/out) ----------------
__global__ __launch_bounds__(256) void geglu_kernel(
    const __half* __restrict__ Y, __half* __restrict__ U)
{
    size_t i = (size_t)blockIdx.x*256 + threadIdx.x;
    if (i >= (size_t)MROWS*FFI) return;
    size_t m = i / FFI, c = i % FFI;
    float a = __half2float(Y[m*2*FFI + c]);
    float g = __half2float(Y[m*2*FFI + FFI + c]);
    float ge = 0.5f * g * (1.f + erff(g * 0.70710678118654752f));
    U[i] = __float2half(a * ge);
}

// ---------------- host orchestration ----------------
static inline void run_gemm1(const __half* A, const __half* B, const float* bias,
                             const float* res, float* C, __half* C16,
                             int M, int N, int K, int mode)
{
    int nblk = N / GBN;
    dim3 grid(nblk, (M + GBM - 1) / GBM);
    mma_gemm_kernel<<<grid, 128, GEMM_SMEM_BYTES>>>(
        A, B, nullptr, nullptr, bias, res, C, nullptr, nullptr, C16, M, N, K, mode, nblk);
}

static inline void run_gemm3(const __half* A,
                             const __half* B0, const __half* B1, const __half* B2,
                             float* C0, float* C1, float* C2,
                             int M, int N, int K, int nmat, int mode)
{
    int nblk = N / GBN;
    dim3 grid(nblk * nmat, (M + GBM - 1) / GBM);
    mma_gemm_kernel<<<grid, 128, GEMM_SMEM_BYTES>>>(
        A, B0, B1, B2, nullptr, nullptr, C0, C1, C2, nullptr, M, N, K, mode, nblk);
}

extern "C" void kernel_launch(void* const* d_in, const int* in_sizes, int n_in,
                              void* d_out, int out_size)
{
    const float* x         = (const float*)d_in[0];
    const float* context   = (const float*)d_in[1];
    const unsigned int* vis_mask = (const unsigned int*)d_in[2];
    const unsigned int* v2t_mask = (const unsigned int*)d_in[3];
    const float* gn_scale  = (const float*)d_in[4];
    const float* gn_bias   = (const float*)d_in[5];
    const float* proj_in_w = (const float*)d_in[6];
    const float* proj_in_b = (const float*)d_in[7];
    const float* n1_s = (const float*)d_in[8];
    const float* n1_b = (const float*)d_in[9];
    const float* wq1  = (const float*)d_in[10];
    const float* wk1  = (const float*)d_in[11];
    const float* wv1  = (const float*)d_in[12];
    const float* wo1  = (const float*)d_in[13];
    const float* bo1  = (const float*)d_in[14];
    const float* n2_s = (const float*)d_in[15];
    const float* n2_b = (const float*)d_in[16];
    const float* wq2  = (const float*)d_in[17];
    const float* wk2  = (const float*)d_in[18];
    const float* wv2  = (const float*)d_in[19];
    const float* wo2  = (const float*)d_in[20];
    const float* bo2  = (const float*)d_in[21];
    const float* n3_s = (const float*)d_in[22];
    const float* n3_b = (const float*)d_in[23];
    const float* ff_w1 = (const float*)d_in[24];
    const float* ff_b1 = (const float*)d_in[25];
    const float* ff_w2 = (const float*)d_in[26];
    const float* ff_b2 = (const float*)d_in[27];
    const float* proj_out_w = (const float*)d_in[28];
    const float* proj_out_b = (const float*)d_in[29];
    float* out = (float*)d_out;

    cudaFuncSetAttribute(mma_gemm_kernel,
                         cudaFuncAttributeMaxDynamicSharedMemorySize, GEMM_SMEM_BYTES);
    cudaFuncSetAttribute(self_attn_f16_kernel,
                         cudaFuncAttributeMaxDynamicSharedMemorySize, SA_SMEM);

    float *h, *q, *k, *v, *ff1;
    __half *gn16, *ln16, *ao16, *ffu16, *ctx16, *h16, *wt16;
    cudaGetSymbolAddress((void**)&h,    g_h);
    cudaGetSymbolAddress((void**)&q,    g_q);
    cudaGetSymbolAddress((void**)&k,    g_k);
    cudaGetSymbolAddress((void**)&v,    g_v);
    cudaGetSymbolAddress((void**)&ff1,  g_ff1);
    cudaGetSymbolAddress((void**)&gn16, g_gn16);
    cudaGetSymbolAddress((void**)&ln16, g_ln16);
    cudaGetSymbolAddress((void**)&ao16, g_ao16);
    cudaGetSymbolAddress((void**)&ffu16,g_ffu16);
    cudaGetSymbolAddress((void**)&ctx16,g_ctx16);
    cudaGetSymbolAddress((void**)&h16,  g_h16);
    cudaGetSymbolAddress((void**)&wt16, g_wt16);

    // 0a. transpose all weight matrices to fp16 [N][K]; fold 1/sqrt(DHEAD) into wq1
    {
        TransDesc td;
        const float* srcs[12] = {proj_in_w, wq1, wk1, wv1, wo1, wq2, wo2, proj_out_w,
                                 wk2, wv2, ff_w1, ff_w2};
        __half* dsts[12] = {wt16+OFF_PIN, wt16+OFF_Q1, wt16+OFF_K1, wt16+OFF_V1, wt16+OFF_O1,
                            wt16+OFF_Q2, wt16+OFF_O2, wt16+OFF_POUT, wt16+OFF_K2, wt16+OFF_V2,
                            wt16+OFF_FF1, wt16+OFF_FF2};
        int Ks[12] = {CC,CC,CC,CC,CC,CC,CC,CC, CTXD,CTXD, CC, FFI};
        int Ns[12] = {CC,CC,CC,CC,CC,CC,CC,CC, CC,CC, 2*FFI, CC};
        int acc = 0;
        float qs = rsqrtf((float)DHEAD);
        for (int i = 0; i < 12; i++) {
            td.src[i] = srcs[i]; td.dst[i] = dsts[i];
            td.scl[i] = (i == 1) ? qs : 1.f;
            td.K[i] = Ks[i]; td.N[i] = Ns[i];
            td.start[i] = acc;
            acc += (Ks[i]/32) * (Ns[i]/32);
        }
        td.start[12] = acc;
        transpose_all_kernel<<<acc, 256>>>(td);
    }
    // 0b. context -> fp16
    {
        int n = BB*CTX*CTXD;
        f2h_kernel<<<(n + 255)/256, 256>>>(context, ctx16, n);
    }

    // 1. GroupNorm + transpose to [B, HW, C] (fp16)
    groupnorm_kernel<<<BB*32, 256>>>(x, gn_scale, gn_bias, gn16);
    // 2. proj_in
    run_gemm1(gn16, wt16+OFF_PIN, proj_in_b, nullptr, h, nullptr, MROWS, CC, CC, 0);
    // 3. LN1 (fp16 out)
    layernorm_kernel<<<MROWS, CC>>>(h, n1_s, n1_b, ln16);
    // 4. fused q,k,v (self) -> fp16 (q pre-scaled via wq1)
    run_gemm3(ln16, wt16+OFF_Q1, wt16+OFF_K1, wt16+OFF_V1, q, k, v, MROWS, CC, CC, 3, 2);
    // 5. masked self-attention (fp16 MMA, 128-key tiles)
    {
        dim3 grid(HWP/64, NHEADS, BB);
        self_attn_f16_kernel<<<grid, 256, SA_SMEM>>>((const __half*)q, (const __half*)k,
                                                     (const __half*)v, vis_mask, ao16);
    }
    // 6. out-proj + residual
    run_gemm1(ao16, wt16+OFF_O1, bo1, h, h, nullptr, MROWS, CC, CC, 0);
    // 7. LN2
    layernorm_kernel<<<MROWS, CC>>>(h, n2_s, n2_b, ln16);
    // 8. q (cross) -> fp32
    run_gemm1(ln16, wt16+OFF_Q2, nullptr, nullptr, q, nullptr, MROWS, CC, CC, 0);
    // 9. fused k,v from context -> fp32
    run_gemm3(ctx16, wt16+OFF_K2, wt16+OFF_V2, nullptr, k, v, nullptr, BB*CTX, CC, CTXD, 2, 0);
    // 10. masked cross-attention (fp16 out)
    {
        dim3 grid(HWP/QT2, NHEADS, BB);
        cross_attn_kernel<<<grid, 256>>>(q, k, v, v2t_mask, ao16);
    }
    // 11. out-proj + residual
    run_gemm1(ao16, wt16+OFF_O2, bo2, h, h, nullptr, MROWS, CC, CC, 0);
    // 12. LN3
    layernorm_kernel<<<MROWS, CC>>>(h, n3_s, n3_b, ln16);
    // 13. FF up (GEGLU input) -> fp16 only
    run_gemm1(ln16, wt16+OFF_FF1, ff_b1, nullptr, ff1, nullptr, MROWS, 2*FFI, CC, 2);
    // 14. GEGLU (fp16 in/out)
    {
        size_t n = (size_t)MROWS*FFI;
        geglu_kernel<<<(unsigned)((n + 255)/256), 256>>>((const __half*)ff1, ffu16);
    }
    // 15. FF down + residual (emit fp16 copy for final proj)
    run_gemm1(ffu16, wt16+OFF_FF2, ff_b2, h, h, h16, MROWS, CC, FFI, 0);
    // 16. proj_out + transpose back to [B,C,H,W] + input residual
    run_gemm1(h16, wt16+OFF_POUT, proj_out_b, x, out, nullptr, MROWS, CC, CC, 1);
}

// round 16
// speedup vs baseline: 5.0962x; 1.0358x over previous
#include <cuda_runtime.h>
#include <cuda_fp16.h>
#include <math.h>
#include <stdint.h>

// ---------------- problem constants ----------------
#define BB      8
#define CC      320
#define HWP     1024
#define NHEADS  8
#define DHEAD   40
#define CTX     77
#define CTXD    768
#define FFI     1280          // FF_INNER
#define MROWS   (BB*HWP)      // 8192
#define NEGMAX  (-3.402823466e38f)

// ---------------- scratch (device globals; no runtime allocs) ----------------
__device__ float  g_h  [MROWS*CC];
__device__ float  g_q  [MROWS*CC];
__device__ float  g_k  [MROWS*CC];
__device__ float  g_v  [MROWS*CC];
__device__ float  g_ff1[MROWS*2*FFI];     // used as __half buffer for ff1 output
__device__ __half g_gn16 [MROWS*CC];
__device__ __half g_ln16 [MROWS*CC];
__device__ __half g_ao16 [MROWS*CC];
__device__ __half g_ffu16[(size_t)MROWS*FFI];
__device__ __half g_ctx16[BB*CTX*CTXD];
__device__ __half g_h16  [MROWS*CC];
__device__ __half g_wt16 [2539520];        // transposed weights [N][K], fp16

// offsets into g_wt16 (halves)
#define OFF_PIN  0
#define OFF_Q1   102400
#define OFF_K1   204800
#define OFF_V1   307200
#define OFF_O1   409600
#define OFF_Q2   512000
#define OFF_O2   614400
#define OFF_POUT 716800
#define OFF_K2   819200
#define OFF_V2   1064960
#define OFF_FF1  1310720
#define OFF_FF2  2129920

__device__ __forceinline__ uint32_t h2_to_u32(__half2 h) {
    union { __half2 h2; uint32_t u; } cvt;
    cvt.h2 = h;
    return cvt.u;
}

// ---------------- block reductions ----------------
__device__ __forceinline__ float blockReduceSum(float v, float* scratch) {
    int lane = threadIdx.x & 31, wid = threadIdx.x >> 5;
    #pragma unroll
    for (int o = 16; o > 0; o >>= 1) v += __shfl_down_sync(0xffffffffu, v, o);
    if (lane == 0) scratch[wid] = v;
    __syncthreads();
    int nw = (blockDim.x + 31) >> 5;
    v = (threadIdx.x < nw) ? scratch[threadIdx.x] : 0.f;
    if (wid == 0) {
        #pragma unroll
        for (int o = 16; o > 0; o >>= 1) v += __shfl_down_sync(0xffffffffu, v, o);
        if (lane == 0) scratch[0] = v;
    }
    __syncthreads();
    v = scratch[0];
    __syncthreads();
    return v;
}

// ---------------- GroupNorm -> fp16 [B,HW,C] ----------------
__global__ __launch_bounds__(256) void groupnorm_kernel(
    const float* __restrict__ x, const float* __restrict__ scale,
    const float* __restrict__ bias, __half* __restrict__ out)
{
    __shared__ float scratch[32];
    __shared__ float s_mu, s_inv;
    int b = blockIdx.x >> 5, g = blockIdx.x & 31;
    const float* xp = x + ((size_t)b*CC + g*10) * HWP;
    float sum = 0.f, sq = 0.f;
    for (int i = threadIdx.x; i < 10*HWP; i += 256) { float v = xp[i]; sum += v; sq += v*v; }
    sum = blockReduceSum(sum, scratch);
    sq  = blockReduceSum(sq,  scratch);
    if (threadIdx.x == 0) {
        float mu  = sum * (1.f/10240.f);
        float var = sq * (1.f/10240.f) - mu*mu;
        s_mu = mu; s_inv = rsqrtf(var + 1e-6f);
    }
    __syncthreads();
    float mu = s_mu, inv = s_inv;
    for (int i = threadIdx.x; i < 10*HWP; i += 256) {
        int cl = i >> 10, p = i & 1023;
        int c = g*10 + cl;
        float xn = (xp[i] - mu) * inv;
        out[((size_t)b*HWP + p)*CC + c] = __float2half(xn * scale[c] + bias[c]);
    }
}

// ---------------- LayerNorm over last dim = 320 -> fp16 ----------------
__global__ __launch_bounds__(CC) void layernorm_kernel(
    const float* __restrict__ X, const float* __restrict__ s,
    const float* __restrict__ bpar, __half* __restrict__ Y)
{
    __shared__ float scratch[32];
    int row = blockIdx.x, t = threadIdx.x;
    float v = X[(size_t)row*CC + t];
    float mu = blockReduceSum(v, scratch) * (1.f/CC);
    float d = v - mu;
    float var = blockReduceSum(d*d, scratch) * (1.f/CC);
    Y[(size_t)row*CC + t] = __float2half(d * rsqrtf(var + 1e-5f) * s[t] + bpar[t]);
}

// ---------------- weight transpose to fp16 [N][K] (with optional scale) ----------------
struct TransDesc {
    const float* src[12];
    __half* dst[12];
    float scl[12];
    int K[12], N[12];
    int start[13];
};

__global__ __launch_bounds__(256) void transpose_all_kernel(TransDesc p) {
    __shared__ float t[32][33];
    int bid = blockIdx.x;
    int i = 0;
    while (bid >= p.start[i+1]) i++;
    const float* src = p.src[i];
    __half* dst = p.dst[i];
    float scl = p.scl[i];
    int K = p.K[i], N = p.N[i];
    int lt = bid - p.start[i];
    int tiles_n = N >> 5;
    int tk = lt / tiles_n, tn = lt - tk*tiles_n;
    int tx = threadIdx.x & 31, ty = threadIdx.x >> 5;   // 32 x 8
    #pragma unroll
    for (int j = 0; j < 32; j += 8)
        t[ty+j][tx] = src[(size_t)(tk*32+ty+j)*N + tn*32 + tx];
    __syncthreads();
    #pragma unroll
    for (int j = 0; j < 32; j += 8)
        dst[(size_t)(tn*32+ty+j)*K + tk*32 + tx] = __float2half(t[tx][ty+j] * scl);
}

// ---------------- context -> fp16 ----------------
__global__ __launch_bounds__(256) void f2h_kernel(
    const float* __restrict__ src, __half* __restrict__ dst, int n)
{
    int i = blockIdx.x*256 + threadIdx.x;
    if (i < n) dst[i] = __float2half(src[i]);
}

// ---------------- mma / ldmatrix helpers ----------------
__device__ __forceinline__ void mma_f16(float c[4], uint32_t a0, uint32_t a1,
                                        uint32_t a2, uint32_t a3,
                                        uint32_t b0, uint32_t b1) {
    asm volatile(
        "mma.sync.aligned.m16n8k16.row.col.f32.f16.f16.f32 "
        "{%0,%1,%2,%3}, {%4,%5,%6,%7}, {%8,%9}, {%0,%1,%2,%3};"
        : "+f"(c[0]), "+f"(c[1]), "+f"(c[2]), "+f"(c[3])
        : "r"(a0), "r"(a1), "r"(a2), "r"(a3), "r"(b0), "r"(b1));
}

__device__ __forceinline__ void ldmatrix_x4(uint32_t& d0, uint32_t& d1,
                                            uint32_t& d2, uint32_t& d3, uint32_t addr) {
    asm volatile("ldmatrix.sync.aligned.m8n8.x4.shared.b16 {%0,%1,%2,%3}, [%4];"
                 : "=r"(d0), "=r"(d1), "=r"(d2), "=r"(d3) : "r"(addr));
}
__device__ __forceinline__ void ldmatrix_x2(uint32_t& d0, uint32_t& d1, uint32_t addr) {
    asm volatile("ldmatrix.sync.aligned.m8n8.x2.shared.b16 {%0,%1}, [%2];"
                 : "=r"(d0), "=r"(d1) : "r"(addr));
}

__device__ __forceinline__ void cp_async16_s(uint32_t saddr, const void* gsrc, int src_bytes) {
    asm volatile("cp.async.cg.shared.global [%0], [%1], 16, %2;"
                 :: "r"(saddr), "l"(gsrc), "r"(src_bytes));
}
#define CP_COMMIT()  asm volatile("cp.async.commit_group;")
#define CP_WAIT1()   asm volatile("cp.async.wait_group 1;")

// ---------------- fp16 tensor-core GEMM (64x64x64, 128 thr, ldmatrix swizzle) ----------
#define GBM 64
#define GBN 64
#define GBK 64
#define NCH 8
#define STAGES 3
#define A_STAGE_B (GBM*NCH*16)
#define B_STAGE_B (GBN*NCH*16)
#define GEMM_SMEM_BYTES (STAGES*(A_STAGE_B + B_STAGE_B))   // 49152

__global__ __launch_bounds__(128, 4) void mma_gemm_kernel(
    const __half* __restrict__ A,
    const __half* __restrict__ B0, const __half* __restrict__ B1, const __half* __restrict__ B2,
    const float* __restrict__ bias, const float* __restrict__ res,
    float* __restrict__ C0, float* __restrict__ C1, float* __restrict__ C2,
    __half* __restrict__ C16,
    int M, int N, int K, int mode, int nblk)
{
    extern __shared__ __align__(16) char smemraw[];
    uint32_t sbase = (uint32_t)__cvta_generic_to_shared(smemraw);
    uint32_t bbase0 = sbase + STAGES*A_STAGE_B;

    int mat = blockIdx.x / nblk;
    const __half* B = (mat == 0) ? B0 : ((mat == 1) ? B1 : B2);
    float* C        = (mat == 0) ? C0 : ((mat == 1) ? C1 : C2);
    int n0 = (blockIdx.x - mat*nblk) * GBN;

    int tid = threadIdx.x;
    int lane = tid & 31, warp = tid >> 5;
    int wm = warp >> 1, wn = warp & 1;
    int m0 = blockIdx.y * GBM;

    float acc[2][4][4];
    #pragma unroll
    for (int i = 0; i < 2; i++)
        #pragma unroll
        for (int j = 0; j < 4; j++)
            #pragma unroll
            for (int c = 0; c < 4; c++) acc[i][j][c] = 0.f;

    int g = lane >> 2, tk = lane & 3;
    int l_row = tid >> 3, l_ch = tid & 7;
    int sub = lane >> 3, lr = lane & 7;
    int lrB = lane & 7, subB = (lane >> 3) & 1;

    int KT = K / GBK;

    auto prefetch = [&](int kt, int buf) {
        uint32_t abase = sbase + buf*A_STAGE_B;
        uint32_t bbase = bbase0 + buf*B_STAGE_B;
        int k0 = kt * GBK;
        #pragma unroll
        for (int j = 0; j < 4; j++) {
            int row = l_row + j*16;
            int gr = m0 + row;
            int ch = l_ch ^ (row & 7);
            const __half* src = A + ((gr < M) ? ((size_t)gr*K + k0 + l_ch*8) : 0);
            cp_async16_s(abase + (row*NCH + ch)*16, src, (gr < M) ? 16 : 0);
        }
        #pragma unroll
        for (int j = 0; j < 4; j++) {
            int row = l_row + j*16;
            int ch = l_ch ^ (row & 7);
            cp_async16_s(bbase + (row*NCH + ch)*16,
                         B + (size_t)(n0 + row)*K + k0 + l_ch*8, 16);
        }
        CP_COMMIT();
    };

    prefetch(0, 0);
    if (KT > 1) prefetch(1, 1); else CP_COMMIT();

    for (int kt = 0; kt < KT; kt++) {
        CP_WAIT1();
        __syncthreads();
        if (kt + 2 < KT) prefetch(kt+2, (kt+2) % STAGES);
        else CP_COMMIT();

        int buf = kt % STAGES;
        uint32_t abase = sbase + buf*A_STAGE_B;
        uint32_t bbase = bbase0 + buf*B_STAGE_B;

        #pragma unroll
        for (int s = 0; s < 4; s++) {
            int c0 = s*2;
            uint32_t a[2][4];
            #pragma unroll
            for (int mt = 0; mt < 2; mt++) {
                int r = wm*32 + mt*16 + lr + (sub & 1)*8;
                int ch = (c0 + (sub >> 1)) ^ (r & 7);
                ldmatrix_x4(a[mt][0], a[mt][1], a[mt][2], a[mt][3],
                            abase + (r*NCH + ch)*16);
            }
            uint32_t b[4][2];
            #pragma unroll
            for (int nt = 0; nt < 4; nt++) {
                int rn = wn*32 + nt*8 + lrB;
                int ch = (c0 + subB) ^ (rn & 7);
                ldmatrix_x2(b[nt][0], b[nt][1], bbase + (rn*NCH + ch)*16);
            }
            #pragma unroll
            for (int mt = 0; mt < 2; mt++)
                #pragma unroll
                for (int nt = 0; nt < 4; nt++)
                    mma_f16(acc[mt][nt], a[mt][0], a[mt][1], a[mt][2], a[mt][3],
                            b[nt][0], b[nt][1]);
        }
    }

    #pragma unroll
    for (int mt = 0; mt < 2; mt++) {
        #pragma unroll
        for (int nt = 0; nt < 4; nt++) {
            int mbase = m0 + wm*32 + mt*16 + g;
            int nbase = n0 + wn*32 + nt*8 + (tk << 1);
            #pragma unroll
            for (int c = 0; c < 4; c++) {
                int m = mbase + ((c >> 1) << 3);
                int n = nbase + (c & 1);
                if (m >= M) continue;
                float v = acc[mt][nt][c];
                if (bias) v += bias[n];
                if (mode == 0) {
                    size_t idx = (size_t)m*N + n;
                    if (res) v += res[idx];
                    C[idx] = v;
                    if (C16) C16[idx] = __float2half(v);
                } else if (mode == 2) {
                    ((__half*)C)[(size_t)m*N + n] = __float2half(v);
                } else {
                    size_t idx = ((size_t)(m >> 10)*CC + n)*HWP + (m & 1023);
                    C[idx] = v + res[idx];
                }
            }
        }
    }
}

// ---------------- flash self-attention: warp-local softmax, register-resident P --------
// 128 threads / 4 warps; warp w owns query rows q0 + w*16 .. +15 for ALL keys.
// Per 64-key tile: only 2 block syncs (K/V staging). P stays in registers
// (S C-fragment pairs pack directly into the P*V A-fragment as half2).
#define AQ_PAD 28   // u32 pairs per Q/K row (20 real + 8 zero-pad)
#define AV_PAD 36   // u32 pairs per V^T row (32 real + 4 pad)

__global__ __launch_bounds__(128) void self_attn_f16_kernel(
    const __half* __restrict__ Q, const __half* __restrict__ K,
    const __half* __restrict__ V, const unsigned int* __restrict__ mask,
    __half* __restrict__ O)
{
    __shared__ uint32_t Qs[64][AQ_PAD];
    __shared__ uint32_t Ks[64][AQ_PAD];
    __shared__ uint32_t Vs[DHEAD][AV_PAD];   // V^T: [dhead][keys] halves

    int b = blockIdx.z, h = blockIdx.y, q0 = blockIdx.x * 64;
    int tid = threadIdx.x, lane = tid & 31, w = tid >> 5;
    int g = lane >> 2, tk = lane & 3;
    int r_lo = w*16 + g, r_hi = r_lo + 8;

    // zero pads once (loads only touch cols 0..19 afterwards)
    for (int i = tid; i < 64*AQ_PAD; i += 128) {
        Qs[i/AQ_PAD][i%AQ_PAD] = 0;
        Ks[i/AQ_PAD][i%AQ_PAD] = 0;
    }
    {
        const uint32_t* qb = (const uint32_t*)Q;
        for (int i = tid; i < 64*20; i += 128) {
            int r = i/20, p = i%20;
            Qs[r][p] = qb[(((size_t)b*HWP + q0 + r)*CC + h*DHEAD)/2 + p];
        }
    }
    __syncthreads();

    uint32_t aq[3][4];
    #pragma unroll
    for (int s = 0; s < 3; s++) {
        aq[s][0] = Qs[r_lo][s*8 + tk];
        aq[s][1] = Qs[r_hi][s*8 + tk];
        aq[s][2] = Qs[r_lo][s*8 + 4 + tk];
        aq[s][3] = Qs[r_hi][s*8 + 4 + tk];
    }

    float o[5][4] = {};
    float m_lo = NEGMAX, m_hi = NEGMAX, l_lo = 0.f, l_hi = 0.f;

    for (int jt = 0; jt < HWP/64; jt++) {
        __syncthreads();
        {
            const uint32_t* kb = (const uint32_t*)K;
            for (int i = tid; i < 64*20; i += 128) {
                int j = i/20, p = i%20;
                Ks[j][p] = kb[(((size_t)b*HWP + jt*64 + j)*CC + h*DHEAD)/2 + p];
            }
            const __half* vb = V + ((size_t)b*HWP + jt*64)*CC + h*DHEAD;
            __half* vsh = (__half*)Vs;
            for (int i = tid; i < 64*DHEAD; i += 128) {
                int j = i/DHEAD, c = i%DHEAD;
                vsh[c*(2*AV_PAD) + j] = vb[(size_t)j*CC + c];
            }
        }
        __syncthreads();

        // S = Q K^T : 16 rows x 64 cols per warp (8 n-tiles)
        float s_[8][4] = {};
        #pragma unroll
        for (int s = 0; s < 3; s++) {
            #pragma unroll
            for (int nt = 0; nt < 8; nt++) {
                int jn = nt*8 + g;
                mma_f16(s_[nt], aq[s][0], aq[s][1], aq[s][2], aq[s][3],
                        Ks[jn][s*8 + tk], Ks[jn][s*8 + 4 + tk]);
            }
        }

        // mask + tile row max (warp-local: quad shfl over tk)
        const unsigned int* mlo_p = mask + ((size_t)b*HWP + q0 + r_lo)*HWP + (size_t)jt*64;
        const unsigned int* mhi_p = mask + ((size_t)b*HWP + q0 + r_hi)*HWP + (size_t)jt*64;
        float mlo = NEGMAX, mhi = NEGMAX;
        #pragma unroll
        for (int nt = 0; nt < 8; nt++) {
            int col = nt*8 + tk*2;
            uint2 m0v = *(const uint2*)(mlo_p + col);
            uint2 m1v = *(const uint2*)(mhi_p + col);
            s_[nt][0] = m0v.x ? s_[nt][0] : NEGMAX;
            s_[nt][1] = m0v.y ? s_[nt][1] : NEGMAX;
            s_[nt][2] = m1v.x ? s_[nt][2] : NEGMAX;
            s_[nt][3] = m1v.y ? s_[nt][3] : NEGMAX;
            mlo = fmaxf(mlo, fmaxf(s_[nt][0], s_[nt][1]));
            mhi = fmaxf(mhi, fmaxf(s_[nt][2], s_[nt][3]));
        }
        mlo = fmaxf(mlo, __shfl_xor_sync(0xffffffffu, mlo, 1));
        mlo = fmaxf(mlo, __shfl_xor_sync(0xffffffffu, mlo, 2));
        mhi = fmaxf(mhi, __shfl_xor_sync(0xffffffffu, mhi, 1));
        mhi = fmaxf(mhi, __shfl_xor_sync(0xffffffffu, mhi, 2));

        float mn_lo = fmaxf(m_lo, mlo);
        float mn_hi = fmaxf(m_hi, mhi);
        float alo = __expf(m_lo - mn_lo);
        float ahi = __expf(m_hi - mn_hi);
        m_lo = mn_lo; m_hi = mn_hi;

        // P = exp(S - m), pack into A-fragments (registers), row sums
        uint32_t pa[4][4];
        float slo = 0.f, shi = 0.f;
        #pragma unroll
        for (int t2 = 0; t2 < 4; t2++) {
            float p00 = __expf(s_[2*t2][0]   - mn_lo);
            float p01 = __expf(s_[2*t2][1]   - mn_lo);
            float p02 = __expf(s_[2*t2][2]   - mn_hi);
            float p03 = __expf(s_[2*t2][3]   - mn_hi);
            float p10 = __expf(s_[2*t2+1][0] - mn_lo);
            float p11 = __expf(s_[2*t2+1][1] - mn_lo);
            float p12 = __expf(s_[2*t2+1][2] - mn_hi);
            float p13 = __expf(s_[2*t2+1][3] - mn_hi);
            slo += p00 + p01 + p10 + p11;
            shi += p02 + p03 + p12 + p13;
            pa[t2][0] = h2_to_u32(__floats2half2_rn(p00, p01));
            pa[t2][1] = h2_to_u32(__floats2half2_rn(p02, p03));
            pa[t2][2] = h2_to_u32(__floats2half2_rn(p10, p11));
            pa[t2][3] = h2_to_u32(__floats2half2_rn(p12, p13));
        }
        slo += __shfl_xor_sync(0xffffffffu, slo, 1);
        slo += __shfl_xor_sync(0xffffffffu, slo, 2);
        shi += __shfl_xor_sync(0xffffffffu, shi, 1);
        shi += __shfl_xor_sync(0xffffffffu, shi, 2);
        l_lo = alo*l_lo + slo;
        l_hi = ahi*l_hi + shi;

        // rescale O, accumulate P V (4 k16 steps, B from V^T smem)
        #pragma unroll
        for (int nt = 0; nt < 5; nt++) {
            o[nt][0] *= alo; o[nt][1] *= alo;
            o[nt][2] *= ahi; o[nt][3] *= ahi;
        }
        #pragma unroll
        for (int t2 = 0; t2 < 4; t2++) {
            int pb = t2*8;
            #pragma unroll
            for (int nt = 0; nt < 5; nt++) {
                int n = nt*8 + g;
                mma_f16(o[nt], pa[t2][0], pa[t2][1], pa[t2][2], pa[t2][3],
                        Vs[n][pb + tk], Vs[n][pb + 4 + tk]);
            }
        }
    }

    // normalize + direct write (warp owns its rows fully)
    float il_lo = 1.f / l_lo;
    float il_hi = 1.f / l_hi;
    __half* out_lo = O + ((size_t)b*HWP + q0 + r_lo)*CC + h*DHEAD;
    __half* out_hi = O + ((size_t)b*HWP + q0 + r_hi)*CC + h*DHEAD;
    #pragma unroll
    for (int nt = 0; nt < 5; nt++) {
        int c = nt*8 + tk*2;
        *(__half2*)(out_lo + c) = __floats2half2_rn(o[nt][0]*il_lo, o[nt][1]*il_lo);
        *(__half2*)(out_hi + c) = __floats2half2_rn(o[nt][2]*il_hi, o[nt][3]*il_hi);
    }
}

// ---------------- masked cross-attention (keys = 77, fp16 output) ----------------
#define QT2 16
__global__ __launch_bounds__(256) void cross_attn_kernel(
    const float* __restrict__ Q, const float* __restrict__ Kc,
    const float* __restrict__ Vc, const unsigned int* __restrict__ mask,
    __half* __restrict__ O)
{
    __shared__ float sk[CTX][DHEAD];
    __shared__ float sv[CTX][DHEAD];
    __shared__ float sq[QT2][DHEAD];
    __shared__ float sc[QT2][CTX+3];
    int b = blockIdx.z, h = blockIdx.y, q0 = blockIdx.x * QT2;
    int tid = threadIdx.x;

    for (int i = tid; i < CTX*DHEAD; i += 256) {
        int r = i / DHEAD, d = i % DHEAD;
        sk[r][d] = Kc[((size_t)b*CTX + r)*CC + h*DHEAD + d];
        sv[r][d] = Vc[((size_t)b*CTX + r)*CC + h*DHEAD + d];
    }
    for (int i = tid; i < QT2*DHEAD; i += 256) {
        int r = i / DHEAD, d = i % DHEAD;
        sq[r][d] = Q[((size_t)b*HWP + q0 + r)*CC + h*DHEAD + d];
    }
    __syncthreads();

    const float scale = rsqrtf((float)DHEAD);
    for (int idx = tid; idx < QT2*CTX; idx += 256) {
        int qi = idx / CTX, j = idx % CTX;
        float s = 0.f;
        #pragma unroll
        for (int d = 0; d < DHEAD; d++) s += sq[qi][d]*sk[j][d];
        unsigned int m = mask[((size_t)b*HWP + q0 + qi)*CTX + j];
        sc[qi][j] = (m != 0u) ? s*scale : NEGMAX;
    }
    __syncthreads();

    if (tid < QT2) {
        int qi = tid;
        float mx = NEGMAX;
        for (int j = 0; j < CTX; j++) mx = fmaxf(mx, sc[qi][j]);
        float sum = 0.f;
        for (int j = 0; j < CTX; j++) { float e = __expf(sc[qi][j]-mx); sc[qi][j] = e; sum += e; }
        float inv = 1.f/sum;
        for (int j = 0; j < CTX; j++) sc[qi][j] *= inv;
    }
    __syncthreads();

    for (int idx = tid; idx < QT2*DHEAD; idx += 256) {
        int qi = idx / DHEAD, d = idx % DHEAD;
        float s = 0.f;
        #pragma unroll
        for (int j = 0; j < CTX; j++) s += sc[qi][j]*sv[j][d];
        O[((size_t)b*HWP + q0 + qi)*CC + h*DHEAD + d] = __float2half(s);
    }
}

// ---------------- GEGLU: u = a * gelu_exact(g) (fp16 in/out) ----------------
__global__ __launch_bounds__(256) void geglu_kernel(
    const __half* __restrict__ Y, __half* __restrict__ U)
{
    size_t i = (size_t)blockIdx.x*256 + threadIdx.x;
    if (i >= (size_t)MROWS*FFI) return;
    size_t m = i / FFI, c = i % FFI;
    float a = __half2float(Y[m*2*FFI + c]);
    float g = __half2float(Y[m*2*FFI + FFI + c]);
    float ge = 0.5f * g * (1.f + erff(g * 0.70710678118654752f));
    U[i] = __float2half(a * ge);
}

// ---------------- host orchestration ----------------
static inline void run_gemm1(const __half* A, const __half* B, const float* bias,
                             const float* res, float* C, __half* C16,
                             int M, int N, int K, int mode)
{
    int nblk = N / GBN;
    dim3 grid(nblk, (M + GBM - 1) / GBM);
    mma_gemm_kernel<<<grid, 128, GEMM_SMEM_BYTES>>>(
        A, B, nullptr, nullptr, bias, res, C, nullptr, nullptr, C16, M, N, K, mode, nblk);
}

static inline void run_gemm3(const __half* A,
                             const __half* B0, const __half* B1, const __half* B2,
                             float* C0, float* C1, float* C2,
                             int M, int N, int K, int nmat, int mode)
{
    int nblk = N / GBN;
    dim3 grid(nblk * nmat, (M + GBM - 1) / GBM);
    mma_gemm_kernel<<<grid, 128, GEMM_SMEM_BYTES>>>(
        A, B0, B1, B2, nullptr, nullptr, C0, C1, C2, nullptr, M, N, K, mode, nblk);
}

extern "C" void kernel_launch(void* const* d_in, const int* in_sizes, int n_in,
                              void* d_out, int out_size)
{
    const float* x         = (const float*)d_in[0];
    const float* context   = (const float*)d_in[1];
    const unsigned int* vis_mask = (const unsigned int*)d_in[2];
    const unsigned int* v2t_mask = (const unsigned int*)d_in[3];
    const float* gn_scale  = (const float*)d_in[4];
    const float* gn_bias   = (const float*)d_in[5];
    const float* proj_in_w = (const float*)d_in[6];
    const float* proj_in_b = (const float*)d_in[7];
    const float* n1_s = (const float*)d_in[8];
    const float* n1_b = (const float*)d_in[9];
    const float* wq1  = (const float*)d_in[10];
    const float* wk1  = (const float*)d_in[11];
    const float* wv1  = (const float*)d_in[12];
    const float* wo1  = (const float*)d_in[13];
    const float* bo1  = (const float*)d_in[14];
    const float* n2_s = (const float*)d_in[15];
    const float* n2_b = (const float*)d_in[16];
    const float* wq2  = (const float*)d_in[17];
    const float* wk2  = (const float*)d_in[18];
    const float* wv2  = (const float*)d_in[19];
    const float* wo2  = (const float*)d_in[20];
    const float* bo2  = (const float*)d_in[21];
    const float* n3_s = (const float*)d_in[22];
    const float* n3_b = (const float*)d_in[23];
    const float* ff_w1 = (const float*)d_in[24];
    const float* ff_b1 = (const float*)d_in[25];
    const float* ff_w2 = (const float*)d_in[26];
    const float* ff_b2 = (const float*)d_in[27];
    const float* proj_out_w = (const float*)d_in[28];
    const float* proj_out_b = (const float*)d_in[29];
    float* out = (float*)d_out;

    cudaFuncSetAttribute(mma_gemm_kernel,
                         cudaFuncAttributeMaxDynamicSharedMemorySize, GEMM_SMEM_BYTES);

    float *h, *q, *k, *v, *ff1;
    __half *gn16, *ln16, *ao16, *ffu16, *ctx16, *h16, *wt16;
    cudaGetSymbolAddress((void**)&h,    g_h);
    cudaGetSymbolAddress((void**)&q,    g_q);
    cudaGetSymbolAddress((void**)&k,    g_k);
    cudaGetSymbolAddress((void**)&v,    g_v);
    cudaGetSymbolAddress((void**)&ff1,  g_ff1);
    cudaGetSymbolAddress((void**)&gn16, g_gn16);
    cudaGetSymbolAddress((void**)&ln16, g_ln16);
    cudaGetSymbolAddress((void**)&ao16, g_ao16);
    cudaGetSymbolAddress((void**)&ffu16,g_ffu16);
    cudaGetSymbolAddress((void**)&ctx16,g_ctx16);
    cudaGetSymbolAddress((void**)&h16,  g_h16);
    cudaGetSymbolAddress((void**)&wt16, g_wt16);

    // 0a. transpose all weight matrices to fp16 [N][K]; fold 1/sqrt(DHEAD) into wq1
    {
        TransDesc td;
        const float* srcs[12] = {proj_in_w, wq1, wk1, wv1, wo1, wq2, wo2, proj_out_w,
                                 wk2, wv2, ff_w1, ff_w2};
        __half* dsts[12] = {wt16+OFF_PIN, wt16+OFF_Q1, wt16+OFF_K1, wt16+OFF_V1, wt16+OFF_O1,
                            wt16+OFF_Q2, wt16+OFF_O2, wt16+OFF_POUT, wt16+OFF_K2, wt16+OFF_V2,
                            wt16+OFF_FF1, wt16+OFF_FF2};
        int Ks[12] = {CC,CC,CC,CC,CC,CC,CC,CC, CTXD,CTXD, CC, FFI};
        int Ns[12] = {CC,CC,CC,CC,CC,CC,CC,CC, CC,CC, 2*FFI, CC};
        int acc = 0;
        float qs = rsqrtf((float)DHEAD);
        for (int i = 0; i < 12; i++) {
            td.src[i] = srcs[i]; td.dst[i] = dsts[i];
            td.scl[i] = (i == 1) ? qs : 1.f;
            td.K[i] = Ks[i]; td.N[i] = Ns[i];
            td.start[i] = acc;
            acc += (Ks[i]/32) * (Ns[i]/32);
        }
        td.start[12] = acc;
        transpose_all_kernel<<<acc, 256>>>(td);
    }
    // 0b. context -> fp16
    {
        int n = BB*CTX*CTXD;
        f2h_kernel<<<(n + 255)/256, 256>>>(context, ctx16, n);
    }

    // 1. GroupNorm + transpose to [B, HW, C] (fp16)
    groupnorm_kernel<<<BB*32, 256>>>(x, gn_scale, gn_bias, gn16);
    // 2. proj_in
    run_gemm1(gn16, wt16+OFF_PIN, proj_in_b, nullptr, h, nullptr, MROWS, CC, CC, 0);
    // 3. LN1 (fp16 out)
    layernorm_kernel<<<MROWS, CC>>>(h, n1_s, n1_b, ln16);
    // 4. fused q,k,v (self) -> fp16 (q pre-scaled via wq1)
    run_gemm3(ln16, wt16+OFF_Q1, wt16+OFF_K1, wt16+OFF_V1, q, k, v, MROWS, CC, CC, 3, 2);
    // 5. masked self-attention (warp-local flash, fp16 MMA)
    {
        dim3 grid(HWP/64, NHEADS, BB);
        self_attn_f16_kernel<<<grid, 128>>>((const __half*)q, (const __half*)k,
                                            (const __half*)v, vis_mask, ao16);
    }
    // 6. out-proj + residual
    run_gemm1(ao16, wt16+OFF_O1, bo1, h, h, nullptr, MROWS, CC, CC, 0);
    // 7. LN2
    layernorm_kernel<<<MROWS, CC>>>(h, n2_s, n2_b, ln16);
    // 8. q (cross) -> fp32
    run_gemm1(ln16, wt16+OFF_Q2, nullptr, nullptr, q, nullptr, MROWS, CC, CC, 0);
    // 9. fused k,v from context -> fp32
    run_gemm3(ctx16, wt16+OFF_K2, wt16+OFF_V2, nullptr, k, v, nullptr, BB*CTX, CC, CTXD, 2, 0);
    // 10. masked cross-attention (fp16 out)
    {
        dim3 grid(HWP/QT2, NHEADS, BB);
        cross_attn_kernel<<<grid, 256>>>(q, k, v, v2t_mask, ao16);
    }
    // 11. out-proj + residual
    run_gemm1(ao16, wt16+OFF_O2, bo2, h, h, nullptr, MROWS, CC, CC, 0);
    // 12. LN3
    layernorm_kernel<<<MROWS, CC>>>(h, n3_s, n3_b, ln16);
    // 13. FF up (GEGLU input) -> fp16 only
    run_gemm1(ln16, wt16+OFF_FF1, ff_b1, nullptr, ff1, nullptr, MROWS, 2*FFI, CC, 2);
    // 14. GEGLU (fp16 in/out)
    {
        size_t n = (size_t)MROWS*FFI;
        geglu_kernel<<<(unsigned)((n + 255)/256), 256>>>((const __half*)ff1, ffu16);
    }
    // 15. FF down + residual (emit fp16 copy for final proj)
    run_gemm1(ffu16, wt16+OFF_FF2, ff_b2, h, h, h16, MROWS, CC, FFI, 0);
    // 16. proj_out + transpose back to [B,C,H,W] + input residual
    run_gemm1(h16, wt16+OFF_POUT, proj_out_b, x, out, nullptr, MROWS, CC, CC, 1);
}

// round 17
// speedup vs baseline: 5.4076x; 1.0611x over previous
#include <cuda_runtime.h>
#include <cuda_fp16.h>
#include <math.h>
#include <stdint.h>

// ---------------- problem constants ----------------
#define BB      8
#define CC      320
#define HWP     1024
#define NHEADS  8
#define DHEAD   40
#define CTX     77
#define CTXD    768
#define FFI     1280          // FF_INNER
#define MROWS   (BB*HWP)      // 8192
#define NEGMAX  (-3.402823466e38f)

// ---------------- scratch (device globals; no runtime allocs) ----------------
__device__ float  g_h  [MROWS*CC];
__device__ float  g_q  [MROWS*CC];
__device__ float  g_k  [MROWS*CC];
__device__ float  g_v  [MROWS*CC];
__device__ float  g_ff1[MROWS*2*FFI];     // used as __half buffer for ff1 output
__device__ __half g_gn16 [MROWS*CC];
__device__ __half g_ln16 [MROWS*CC];
__device__ __half g_ao16 [MROWS*CC];
__device__ __half g_ffu16[(size_t)MROWS*FFI];
__device__ __half g_ctx16[BB*CTX*CTXD];
__device__ __half g_h16  [MROWS*CC];
__device__ __half g_wt16 [2539520];        // transposed weights [N][K], fp16
__device__ uint32_t g_mbits[BB*HWP*(HWP/32)];   // packed vis_mask bits (1 MB)

// offsets into g_wt16 (halves)
#define OFF_PIN  0
#define OFF_Q1   102400
#define OFF_K1   204800
#define OFF_V1   307200
#define OFF_O1   409600
#define OFF_Q2   512000
#define OFF_O2   614400
#define OFF_POUT 716800
#define OFF_K2   819200
#define OFF_V2   1064960
#define OFF_FF1  1310720
#define OFF_FF2  2129920

__device__ __forceinline__ uint32_t h2_to_u32(__half2 h) {
    union { __half2 h2; uint32_t u; } cvt;
    cvt.h2 = h;
    return cvt.u;
}

// ---------------- block reductions ----------------
__device__ __forceinline__ float blockReduceSum(float v, float* scratch) {
    int lane = threadIdx.x & 31, wid = threadIdx.x >> 5;
    #pragma unroll
    for (int o = 16; o > 0; o >>= 1) v += __shfl_down_sync(0xffffffffu, v, o);
    if (lane == 0) scratch[wid] = v;
    __syncthreads();
    int nw = (blockDim.x + 31) >> 5;
    v = (threadIdx.x < nw) ? scratch[threadIdx.x] : 0.f;
    if (wid == 0) {
        #pragma unroll
        for (int o = 16; o > 0; o >>= 1) v += __shfl_down_sync(0xffffffffu, v, o);
        if (lane == 0) scratch[0] = v;
    }
    __syncthreads();
    v = scratch[0];
    __syncthreads();
    return v;
}

// ---------------- GroupNorm -> fp16 [B,HW,C] ----------------
__global__ __launch_bounds__(256) void groupnorm_kernel(
    const float* __restrict__ x, const float* __restrict__ scale,
    const float* __restrict__ bias, __half* __restrict__ out)
{
    __shared__ float scratch[32];
    __shared__ float s_mu, s_inv;
    int b = blockIdx.x >> 5, g = blockIdx.x & 31;
    const float* xp = x + ((size_t)b*CC + g*10) * HWP;
    float sum = 0.f, sq = 0.f;
    for (int i = threadIdx.x; i < 10*HWP; i += 256) { float v = xp[i]; sum += v; sq += v*v; }
    sum = blockReduceSum(sum, scratch);
    sq  = blockReduceSum(sq,  scratch);
    if (threadIdx.x == 0) {
        float mu  = sum * (1.f/10240.f);
        float var = sq * (1.f/10240.f) - mu*mu;
        s_mu = mu; s_inv = rsqrtf(var + 1e-6f);
    }
    __syncthreads();
    float mu = s_mu, inv = s_inv;
    for (int i = threadIdx.x; i < 10*HWP; i += 256) {
        int cl = i >> 10, p = i & 1023;
        int c = g*10 + cl;
        float xn = (xp[i] - mu) * inv;
        out[((size_t)b*HWP + p)*CC + c] = __float2half(xn * scale[c] + bias[c]);
    }
}

// ---------------- LayerNorm over last dim = 320 -> fp16 ----------------
__global__ __launch_bounds__(CC) void layernorm_kernel(
    const float* __restrict__ X, const float* __restrict__ s,
    const float* __restrict__ bpar, __half* __restrict__ Y)
{
    __shared__ float scratch[32];
    int row = blockIdx.x, t = threadIdx.x;
    float v = X[(size_t)row*CC + t];
    float mu = blockReduceSum(v, scratch) * (1.f/CC);
    float d = v - mu;
    float var = blockReduceSum(d*d, scratch) * (1.f/CC);
    Y[(size_t)row*CC + t] = __float2half(d * rsqrtf(var + 1e-5f) * s[t] + bpar[t]);
}

// ---------------- pack vis_mask (uint bools) -> bit words ----------------
__global__ __launch_bounds__(256) void maskbits_kernel(
    const unsigned int* __restrict__ m, uint32_t* __restrict__ out, int nwords)
{
    int warp = (blockIdx.x*blockDim.x + threadIdx.x) >> 5;
    int lane = threadIdx.x & 31;
    int step = (gridDim.x*blockDim.x) >> 5;
    for (int wdx = warp; wdx < nwords; wdx += step) {
        unsigned int v = m[(size_t)wdx*32 + lane];
        unsigned int bal = __ballot_sync(0xffffffffu, v != 0u);
        if (lane == 0) out[wdx] = bal;
    }
}

// ---------------- weight transpose to fp16 [N][K] (with optional scale) ----------------
struct TransDesc {
    const float* src[12];
    __half* dst[12];
    float scl[12];
    int K[12], N[12];
    int start[13];
};

__global__ __launch_bounds__(256) void transpose_all_kernel(TransDesc p) {
    __shared__ float t[32][33];
    int bid = blockIdx.x;
    int i = 0;
    while (bid >= p.start[i+1]) i++;
    const float* src = p.src[i];
    __half* dst = p.dst[i];
    float scl = p.scl[i];
    int K = p.K[i], N = p.N[i];
    int lt = bid - p.start[i];
    int tiles_n = N >> 5;
    int tk = lt / tiles_n, tn = lt - tk*tiles_n;
    int tx = threadIdx.x & 31, ty = threadIdx.x >> 5;   // 32 x 8
    #pragma unroll
    for (int j = 0; j < 32; j += 8)
        t[ty+j][tx] = src[(size_t)(tk*32+ty+j)*N + tn*32 + tx];
    __syncthreads();
    #pragma unroll
    for (int j = 0; j < 32; j += 8)
        dst[(size_t)(tn*32+ty+j)*K + tk*32 + tx] = __float2half(t[tx][ty+j] * scl);
}

// ---------------- context -> fp16 ----------------
__global__ __launch_bounds__(256) void f2h_kernel(
    const float* __restrict__ src, __half* __restrict__ dst, int n)
{
    int i = blockIdx.x*256 + threadIdx.x;
    if (i < n) dst[i] = __float2half(src[i]);
}

// ---------------- mma / ldmatrix helpers ----------------
__device__ __forceinline__ void mma_f16(float c[4], uint32_t a0, uint32_t a1,
                                        uint32_t a2, uint32_t a3,
                                        uint32_t b0, uint32_t b1) {
    asm volatile(
        "mma.sync.aligned.m16n8k16.row.col.f32.f16.f16.f32 "
        "{%0,%1,%2,%3}, {%4,%5,%6,%7}, {%8,%9}, {%0,%1,%2,%3};"
        : "+f"(c[0]), "+f"(c[1]), "+f"(c[2]), "+f"(c[3])
        : "r"(a0), "r"(a1), "r"(a2), "r"(a3), "r"(b0), "r"(b1));
}

__device__ __forceinline__ void ldmatrix_x4(uint32_t& d0, uint32_t& d1,
                                            uint32_t& d2, uint32_t& d3, uint32_t addr) {
    asm volatile("ldmatrix.sync.aligned.m8n8.x4.shared.b16 {%0,%1,%2,%3}, [%4];"
                 : "=r"(d0), "=r"(d1), "=r"(d2), "=r"(d3) : "r"(addr));
}
__device__ __forceinline__ void ldmatrix_x2(uint32_t& d0, uint32_t& d1, uint32_t addr) {
    asm volatile("ldmatrix.sync.aligned.m8n8.x2.shared.b16 {%0,%1}, [%2];"
                 : "=r"(d0), "=r"(d1) : "r"(addr));
}

__device__ __forceinline__ void cp_async16_s(uint32_t saddr, const void* gsrc, int src_bytes) {
    asm volatile("cp.async.cg.shared.global [%0], [%1], 16, %2;"
                 :: "r"(saddr), "l"(gsrc), "r"(src_bytes));
}
#define CP_COMMIT()  asm volatile("cp.async.commit_group;")
#define CP_WAIT1()   asm volatile("cp.async.wait_group 1;")

// ---------------- fp16 tensor-core GEMM (64x64x64, 128 thr, ldmatrix swizzle) ----------
#define GBM 64
#define GBN 64
#define GBK 64
#define NCH 8
#define STAGES 3
#define A_STAGE_B (GBM*NCH*16)
#define B_STAGE_B (GBN*NCH*16)
#define GEMM_SMEM_BYTES (STAGES*(A_STAGE_B + B_STAGE_B))   // 49152

__global__ __launch_bounds__(128, 4) void mma_gemm_kernel(
    const __half* __restrict__ A,
    const __half* __restrict__ B0, const __half* __restrict__ B1, const __half* __restrict__ B2,
    const float* __restrict__ bias, const float* __restrict__ res,
    float* __restrict__ C0, float* __restrict__ C1, float* __restrict__ C2,
    __half* __restrict__ C16,
    int M, int N, int K, int mode, int nblk)
{
    extern __shared__ __align__(16) char smemraw[];
    uint32_t sbase = (uint32_t)__cvta_generic_to_shared(smemraw);
    uint32_t bbase0 = sbase + STAGES*A_STAGE_B;

    int mat = blockIdx.x / nblk;
    const __half* B = (mat == 0) ? B0 : ((mat == 1) ? B1 : B2);
    float* C        = (mat == 0) ? C0 : ((mat == 1) ? C1 : C2);
    int n0 = (blockIdx.x - mat*nblk) * GBN;

    int tid = threadIdx.x;
    int lane = tid & 31, warp = tid >> 5;
    int wm = warp >> 1, wn = warp & 1;
    int m0 = blockIdx.y * GBM;

    float acc[2][4][4];
    #pragma unroll
    for (int i = 0; i < 2; i++)
        #pragma unroll
        for (int j = 0; j < 4; j++)
            #pragma unroll
            for (int c = 0; c < 4; c++) acc[i][j][c] = 0.f;

    int g = lane >> 2, tk = lane & 3;
    int l_row = tid >> 3, l_ch = tid & 7;
    int sub = lane >> 3, lr = lane & 7;
    int lrB = lane & 7, subB = (lane >> 3) & 1;

    int KT = K / GBK;

    auto prefetch = [&](int kt, int buf) {
        uint32_t abase = sbase + buf*A_STAGE_B;
        uint32_t bbase = bbase0 + buf*B_STAGE_B;
        int k0 = kt * GBK;
        #pragma unroll
        for (int j = 0; j < 4; j++) {
            int row = l_row + j*16;
            int gr = m0 + row;
            int ch = l_ch ^ (row & 7);
            const __half* src = A + ((gr < M) ? ((size_t)gr*K + k0 + l_ch*8) : 0);
            cp_async16_s(abase + (row*NCH + ch)*16, src, (gr < M) ? 16 : 0);
        }
        #pragma unroll
        for (int j = 0; j < 4; j++) {
            int row = l_row + j*16;
            int ch = l_ch ^ (row & 7);
            cp_async16_s(bbase + (row*NCH + ch)*16,
                         B + (size_t)(n0 + row)*K + k0 + l_ch*8, 16);
        }
        CP_COMMIT();
    };

    prefetch(0, 0);
    if (KT > 1) prefetch(1, 1); else CP_COMMIT();

    for (int kt = 0; kt < KT; kt++) {
        CP_WAIT1();
        __syncthreads();
        if (kt + 2 < KT) prefetch(kt+2, (kt+2) % STAGES);
        else CP_COMMIT();

        int buf = kt % STAGES;
        uint32_t abase = sbase + buf*A_STAGE_B;
        uint32_t bbase = bbase0 + buf*B_STAGE_B;

        #pragma unroll
        for (int s = 0; s < 4; s++) {
            int c0 = s*2;
            uint32_t a[2][4];
            #pragma unroll
            for (int mt = 0; mt < 2; mt++) {
                int r = wm*32 + mt*16 + lr + (sub & 1)*8;
                int ch = (c0 + (sub >> 1)) ^ (r & 7);
                ldmatrix_x4(a[mt][0], a[mt][1], a[mt][2], a[mt][3],
                            abase + (r*NCH + ch)*16);
            }
            uint32_t b[4][2];
            #pragma unroll
            for (int nt = 0; nt < 4; nt++) {
                int rn = wn*32 + nt*8 + lrB;
                int ch = (c0 + subB) ^ (rn & 7);
                ldmatrix_x2(b[nt][0], b[nt][1], bbase + (rn*NCH + ch)*16);
            }
            #pragma unroll
            for (int mt = 0; mt < 2; mt++)
                #pragma unroll
                for (int nt = 0; nt < 4; nt++)
                    mma_f16(acc[mt][nt], a[mt][0], a[mt][1], a[mt][2], a[mt][3],
                            b[nt][0], b[nt][1]);
        }
    }

    #pragma unroll
    for (int mt = 0; mt < 2; mt++) {
        #pragma unroll
        for (int nt = 0; nt < 4; nt++) {
            int mbase = m0 + wm*32 + mt*16 + g;
            int nbase = n0 + wn*32 + nt*8 + (tk << 1);
            #pragma unroll
            for (int c = 0; c < 4; c++) {
                int m = mbase + ((c >> 1) << 3);
                int n = nbase + (c & 1);
                if (m >= M) continue;
                float v = acc[mt][nt][c];
                if (bias) v += bias[n];
                if (mode == 0) {
                    size_t idx = (size_t)m*N + n;
                    if (res) v += res[idx];
                    C[idx] = v;
                    if (C16) C16[idx] = __float2half(v);
                } else if (mode == 2) {
                    ((__half*)C)[(size_t)m*N + n] = __float2half(v);
                } else {
                    size_t idx = ((size_t)(m >> 10)*CC + n)*HWP + (m & 1023);
                    C[idx] = v + res[idx];
                }
            }
        }
    }
}

// ---------------- flash self-attention: warp-local softmax, pipelined K/V, bitmask ----
// 128 threads / 4 warps; warp w owns query rows q0 + w*16 .. +15 for ALL keys.
// K/V double-buffered: next tile LDG'd into regs before compute, STS after, 1 sync/tile.
#define AQ_PAD 28   // u32 pairs per Q/K row (20 real + 8 zero-pad)
#define AV_PAD 36   // u32 pairs per V^T row (32 real + 4 pad)

__global__ __launch_bounds__(128) void self_attn_f16_kernel(
    const __half* __restrict__ Q, const __half* __restrict__ K,
    const __half* __restrict__ V, const uint32_t* __restrict__ mbits,
    __half* __restrict__ O)
{
    __shared__ uint32_t Qs[64][AQ_PAD];
    __shared__ uint32_t Ks[2][64][AQ_PAD];
    __shared__ uint32_t Vs[2][DHEAD][AV_PAD];   // V^T: [dhead][keys] halves

    int b = blockIdx.z, h = blockIdx.y, q0 = blockIdx.x * 64;
    int tid = threadIdx.x, lane = tid & 31, w = tid >> 5;
    int g = lane >> 2, tk = lane & 3;
    int r_lo = w*16 + g, r_hi = r_lo + 8;

    // zero pads once
    for (int i = tid; i < 64*AQ_PAD; i += 128) {
        Qs[i/AQ_PAD][i%AQ_PAD] = 0;
        Ks[0][i/AQ_PAD][i%AQ_PAD] = 0;
        Ks[1][i/AQ_PAD][i%AQ_PAD] = 0;
    }
    const uint32_t* qb = (const uint32_t*)Q;
    const uint32_t* kb = (const uint32_t*)K;
    for (int i = tid; i < 64*20; i += 128) {
        int r = i/20, p = i%20;
        Qs[r][p] = qb[(((size_t)b*HWP + q0 + r)*CC + h*DHEAD)/2 + p];
    }
    // tile 0 direct load
    for (int i = tid; i < 64*20; i += 128) {
        int j = i/20, p = i%20;
        Ks[0][j][p] = kb[(((size_t)b*HWP + j)*CC + h*DHEAD)/2 + p];
    }
    {
        const uint32_t* vb = (const uint32_t*)(V + ((size_t)b*HWP)*CC + h*DHEAD);
        __half* vsh = (__half*)Vs[0];
        for (int i = tid; i < 64*20; i += 128) {
            int j = i/20, u = i%20;
            uint32_t val = vb[(size_t)j*(CC/2) + u];
            __half2 hv = *(__half2*)&val;
            vsh[(2*u)*(2*AV_PAD) + j]   = __low2half(hv);
            vsh[(2*u+1)*(2*AV_PAD) + j] = __high2half(hv);
        }
    }
    __syncthreads();

    uint32_t aq[3][4];
    #pragma unroll
    for (int s = 0; s < 3; s++) {
        aq[s][0] = Qs[r_lo][s*8 + tk];
        aq[s][1] = Qs[r_hi][s*8 + tk];
        aq[s][2] = Qs[r_lo][s*8 + 4 + tk];
        aq[s][3] = Qs[r_hi][s*8 + 4 + tk];
    }

    float o[5][4] = {};
    float m_lo = NEGMAX, m_hi = NEGMAX, l_lo = 0.f, l_hi = 0.f;
    const uint32_t* mrow_lo = mbits + ((size_t)b*HWP + q0 + r_lo)*(HWP/32);
    const uint32_t* mrow_hi = mbits + ((size_t)b*HWP + q0 + r_hi)*(HWP/32);

    for (int jt = 0; jt < HWP/64; jt++) {
        int buf = jt & 1;

        // prefetch next tile into registers (latency hidden by compute below)
        uint32_t kreg[10], vreg[10];
        if (jt + 1 < HWP/64) {
            #pragma unroll
            for (int k2 = 0; k2 < 10; k2++) {
                int i = tid + k2*128;
                int j = i/20, p = i%20;
                kreg[k2] = kb[(((size_t)b*HWP + (jt+1)*64 + j)*CC + h*DHEAD)/2 + p];
            }
            const uint32_t* vb = (const uint32_t*)(V + ((size_t)b*HWP + (jt+1)*64)*CC + h*DHEAD);
            #pragma unroll
            for (int k2 = 0; k2 < 10; k2++) {
                int i = tid + k2*128;
                int j = i/20, u = i%20;
                vreg[k2] = vb[(size_t)j*(CC/2) + u];
            }
        }

        uint2 mb_lo = *(const uint2*)(mrow_lo + jt*2);
        uint2 mb_hi = *(const uint2*)(mrow_hi + jt*2);

        // S = Q K^T : 16 rows x 64 cols per warp (8 n-tiles)
        float s_[8][4] = {};
        #pragma unroll
        for (int s = 0; s < 3; s++) {
            #pragma unroll
            for (int nt = 0; nt < 8; nt++) {
                int jn = nt*8 + g;
                mma_f16(s_[nt], aq[s][0], aq[s][1], aq[s][2], aq[s][3],
                        Ks[buf][jn][s*8 + tk], Ks[buf][jn][s*8 + 4 + tk]);
            }
        }

        // mask from bits + tile row max (warp-local quad shfl)
        float mlo = NEGMAX, mhi = NEGMAX;
        #pragma unroll
        for (int nt = 0; nt < 8; nt++) {
            int sh = (nt & 3)*8 + tk*2;
            uint32_t wl = (nt < 4) ? mb_lo.x : mb_lo.y;
            uint32_t wh = (nt < 4) ? mb_hi.x : mb_hi.y;
            s_[nt][0] = ((wl >> sh) & 1u)     ? s_[nt][0] : NEGMAX;
            s_[nt][1] = ((wl >> (sh+1)) & 1u) ? s_[nt][1] : NEGMAX;
            s_[nt][2] = ((wh >> sh) & 1u)     ? s_[nt][2] : NEGMAX;
            s_[nt][3] = ((wh >> (sh+1)) & 1u) ? s_[nt][3] : NEGMAX;
            mlo = fmaxf(mlo, fmaxf(s_[nt][0], s_[nt][1]));
            mhi = fmaxf(mhi, fmaxf(s_[nt][2], s_[nt][3]));
        }
        mlo = fmaxf(mlo, __shfl_xor_sync(0xffffffffu, mlo, 1));
        mlo = fmaxf(mlo, __shfl_xor_sync(0xffffffffu, mlo, 2));
        mhi = fmaxf(mhi, __shfl_xor_sync(0xffffffffu, mhi, 1));
        mhi = fmaxf(mhi, __shfl_xor_sync(0xffffffffu, mhi, 2));

        float mn_lo = fmaxf(m_lo, mlo);
        float mn_hi = fmaxf(m_hi, mhi);
        float alo = __expf(m_lo - mn_lo);
        float ahi = __expf(m_hi - mn_hi);
        m_lo = mn_lo; m_hi = mn_hi;

        // P = exp(S - m), pack into A-fragments (registers), row sums
        uint32_t pa[4][4];
        float slo = 0.f, shi = 0.f;
        #pragma unroll
        for (int t2 = 0; t2 < 4; t2++) {
            float p00 = __expf(s_[2*t2][0]   - mn_lo);
            float p01 = __expf(s_[2*t2][1]   - mn_lo);
            float p02 = __expf(s_[2*t2][2]   - mn_hi);
            float p03 = __expf(s_[2*t2][3]   - mn_hi);
            float p10 = __expf(s_[2*t2+1][0] - mn_lo);
            float p11 = __expf(s_[2*t2+1][1] - mn_lo);
            float p12 = __expf(s_[2*t2+1][2] - mn_hi);
            float p13 = __expf(s_[2*t2+1][3] - mn_hi);
            slo += p00 + p01 + p10 + p11;
            shi += p02 + p03 + p12 + p13;
            pa[t2][0] = h2_to_u32(__floats2half2_rn(p00, p01));
            pa[t2][1] = h2_to_u32(__floats2half2_rn(p02, p03));
            pa[t2][2] = h2_to_u32(__floats2half2_rn(p10, p11));
            pa[t2][3] = h2_to_u32(__floats2half2_rn(p12, p13));
        }
        slo += __shfl_xor_sync(0xffffffffu, slo, 1);
        slo += __shfl_xor_sync(0xffffffffu, slo, 2);
        shi += __shfl_xor_sync(0xffffffffu, shi, 1);
        shi += __shfl_xor_sync(0xffffffffu, shi, 2);
        l_lo = alo*l_lo + slo;
        l_hi = ahi*l_hi + shi;

        // rescale O, accumulate P V (4 k16 steps, B from V^T smem)
        #pragma unroll
        for (int nt = 0; nt < 5; nt++) {
            o[nt][0] *= alo; o[nt][1] *= alo;
            o[nt][2] *= ahi; o[nt][3] *= ahi;
        }
        #pragma unroll
        for (int t2 = 0; t2 < 4; t2++) {
            int pb = t2*8;
            #pragma unroll
            for (int nt = 0; nt < 5; nt++) {
                int n = nt*8 + g;
                mma_f16(o[nt], pa[t2][0], pa[t2][1], pa[t2][2], pa[t2][3],
                        Vs[buf][n][pb + tk], Vs[buf][n][pb + 4 + tk]);
            }
        }

        // stage next tile into the other buffer
        if (jt + 1 < HWP/64) {
            #pragma unroll
            for (int k2 = 0; k2 < 10; k2++) {
                int i = tid + k2*128;
                int j = i/20, p = i%20;
                Ks[buf^1][j][p] = kreg[k2];
            }
            __half* vsh = (__half*)Vs[buf^1];
            #pragma unroll
            for (int k2 = 0; k2 < 10; k2++) {
                int i = tid + k2*128;
                int j = i/20, u = i%20;
                __half2 hv = *(__half2*)&vreg[k2];
                vsh[(2*u)*(2*AV_PAD) + j]   = __low2half(hv);
                vsh[(2*u+1)*(2*AV_PAD) + j] = __high2half(hv);
            }
        }
        __syncthreads();
    }

    // normalize + direct write (warp owns its rows fully)
    float il_lo = 1.f / l_lo;
    float il_hi = 1.f / l_hi;
    __half* out_lo = O + ((size_t)b*HWP + q0 + r_lo)*CC + h*DHEAD;
    __half* out_hi = O + ((size_t)b*HWP + q0 + r_hi)*CC + h*DHEAD;
    #pragma unroll
    for (int nt = 0; nt < 5; nt++) {
        int c = nt*8 + tk*2;
        *(__half2*)(out_lo + c) = __floats2half2_rn(o[nt][0]*il_lo, o[nt][1]*il_lo);
        *(__half2*)(out_hi + c) = __floats2half2_rn(o[nt][2]*il_hi, o[nt][3]*il_hi);
    }
}

// ---------------- masked cross-attention (keys = 77, fp16 output) ----------------
#define QT2 16
__global__ __launch_bounds__(256) void cross_attn_kernel(
    const float* __restrict__ Q, const float* __restrict__ Kc,
    const float* __restrict__ Vc, const unsigned int* __restrict__ mask,
    __half* __restrict__ O)
{
    __shared__ float sk[CTX][DHEAD];
    __shared__ float sv[CTX][DHEAD];
    __shared__ float sq[QT2][DHEAD];
    __shared__ float sc[QT2][CTX+3];
    int b = blockIdx.z, h = blockIdx.y, q0 = blockIdx.x * QT2;
    int tid = threadIdx.x;

    for (int i = tid; i < CTX*DHEAD; i += 256) {
        int r = i / DHEAD, d = i % DHEAD;
        sk[r][d] = Kc[((size_t)b*CTX + r)*CC + h*DHEAD + d];
        sv[r][d] = Vc[((size_t)b*CTX + r)*CC + h*DHEAD + d];
    }
    for (int i = tid; i < QT2*DHEAD; i += 256) {
        int r = i / DHEAD, d = i % DHEAD;
        sq[r][d] = Q[((size_t)b*HWP + q0 + r)*CC + h*DHEAD + d];
    }
    __syncthreads();

    const float scale = rsqrtf((float)DHEAD);
    for (int idx = tid; idx < QT2*CTX; idx += 256) {
        int qi = idx / CTX, j = idx % CTX;
        float s = 0.f;
        #pragma unroll
        for (int d = 0; d < DHEAD; d++) s += sq[qi][d]*sk[j][d];
        unsigned int m = mask[((size_t)b*HWP + q0 + qi)*CTX + j];
        sc[qi][j] = (m != 0u) ? s*scale : NEGMAX;
    }
    __syncthreads();

    if (tid < QT2) {
        int qi = tid;
        float mx = NEGMAX;
        for (int j = 0; j < CTX; j++) mx = fmaxf(mx, sc[qi][j]);
        float sum = 0.f;
        for (int j = 0; j < CTX; j++) { float e = __expf(sc[qi][j]-mx); sc[qi][j] = e; sum += e; }
        float inv = 1.f/sum;
        for (int j = 0; j < CTX; j++) sc[qi][j] *= inv;
    }
    __syncthreads();

    for (int idx = tid; idx < QT2*DHEAD; idx += 256) {
        int qi = idx / DHEAD, d = idx % DHEAD;
        float s = 0.f;
        #pragma unroll
        for (int j = 0; j < CTX; j++) s += sc[qi][j]*sv[j][d];
        O[((size_t)b*HWP + q0 + qi)*CC + h*DHEAD + d] = __float2half(s);
    }
}

// ---------------- GEGLU: u = a * gelu_exact(g) (fp16 in/out) ----------------
__global__ __launch_bounds__(256) void geglu_kernel(
    const __half* __restrict__ Y, __half* __restrict__ U)
{
    size_t i = (size_t)blockIdx.x*256 + threadIdx.x;
    if (i >= (size_t)MROWS*FFI) return;
    size_t m = i / FFI, c = i % FFI;
    float a = __half2float(Y[m*2*FFI + c]);
    float g = __half2float(Y[m*2*FFI + FFI + c]);
    float ge = 0.5f * g * (1.f + erff(g * 0.70710678118654752f));
    U[i] = __float2half(a * ge);
}

// ---------------- host orchestration ----------------
static inline void run_gemm1(const __half* A, const __half* B, const float* bias,
                             const float* res, float* C, __half* C16,
                             int M, int N, int K, int mode)
{
    int nblk = N / GBN;
    dim3 grid(nblk, (M + GBM - 1) / GBM);
    mma_gemm_kernel<<<grid, 128, GEMM_SMEM_BYTES>>>(
        A, B, nullptr, nullptr, bias, res, C, nullptr, nullptr, C16, M, N, K, mode, nblk);
}

static inline void run_gemm3(const __half* A,
                             const __half* B0, const __half* B1, const __half* B2,
                             float* C0, float* C1, float* C2,
                             int M, int N, int K, int nmat, int mode)
{
    int nblk = N / GBN;
    dim3 grid(nblk * nmat, (M + GBM - 1) / GBM);
    mma_gemm_kernel<<<grid, 128, GEMM_SMEM_BYTES>>>(
        A, B0, B1, B2, nullptr, nullptr, C0, C1, C2, nullptr, M, N, K, mode, nblk);
}

extern "C" void kernel_launch(void* const* d_in, const int* in_sizes, int n_in,
                              void* d_out, int out_size)
{
    const float* x         = (const float*)d_in[0];
    const float* context   = (const float*)d_in[1];
    const unsigned int* vis_mask = (const unsigned int*)d_in[2];
    const unsigned int* v2t_mask = (const unsigned int*)d_in[3];
    const float* gn_scale  = (const float*)d_in[4];
    const float* gn_bias   = (const float*)d_in[5];
    const float* proj_in_w = (const float*)d_in[6];
    const float* proj_in_b = (const float*)d_in[7];
    const float* n1_s = (const float*)d_in[8];
    const float* n1_b = (const float*)d_in[9];
    const float* wq1  = (const float*)d_in[10];
    const float* wk1  = (const float*)d_in[11];
    const float* wv1  = (const float*)d_in[12];
    const float* wo1  = (const float*)d_in[13];
    const float* bo1  = (const float*)d_in[14];
    const float* n2_s = (const float*)d_in[15];
    const float* n2_b = (const float*)d_in[16];
    const float* wq2  = (const float*)d_in[17];
    const float* wk2  = (const float*)d_in[18];
    const float* wv2  = (const float*)d_in[19];
    const float* wo2  = (const float*)d_in[20];
    const float* bo2  = (const float*)d_in[21];
    const float* n3_s = (const float*)d_in[22];
    const float* n3_b = (const float*)d_in[23];
    const float* ff_w1 = (const float*)d_in[24];
    const float* ff_b1 = (const float*)d_in[25];
    const float* ff_w2 = (const float*)d_in[26];
    const float* ff_b2 = (const float*)d_in[27];
    const float* proj_out_w = (const float*)d_in[28];
    const float* proj_out_b = (const float*)d_in[29];
    float* out = (float*)d_out;

    cudaFuncSetAttribute(mma_gemm_kernel,
                         cudaFuncAttributeMaxDynamicSharedMemorySize, GEMM_SMEM_BYTES);

    float *h, *q, *k, *v, *ff1;
    __half *gn16, *ln16, *ao16, *ffu16, *ctx16, *h16, *wt16;
    uint32_t* mbits;
    cudaGetSymbolAddress((void**)&h,    g_h);
    cudaGetSymbolAddress((void**)&q,    g_q);
    cudaGetSymbolAddress((void**)&k,    g_k);
    cudaGetSymbolAddress((void**)&v,    g_v);
    cudaGetSymbolAddress((void**)&ff1,  g_ff1);
    cudaGetSymbolAddress((void**)&gn16, g_gn16);
    cudaGetSymbolAddress((void**)&ln16, g_ln16);
    cudaGetSymbolAddress((void**)&ao16, g_ao16);
    cudaGetSymbolAddress((void**)&ffu16,g_ffu16);
    cudaGetSymbolAddress((void**)&ctx16,g_ctx16);
    cudaGetSymbolAddress((void**)&h16,  g_h16);
    cudaGetSymbolAddress((void**)&wt16, g_wt16);
    cudaGetSymbolAddress((void**)&mbits,g_mbits);

    // 0a. transpose all weight matrices to fp16 [N][K]; fold 1/sqrt(DHEAD) into wq1
    {
        TransDesc td;
        const float* srcs[12] = {proj_in_w, wq1, wk1, wv1, wo1, wq2, wo2, proj_out_w,
                                 wk2, wv2, ff_w1, ff_w2};
        __half* dsts[12] = {wt16+OFF_PIN, wt16+OFF_Q1, wt16+OFF_K1, wt16+OFF_V1, wt16+OFF_O1,
                            wt16+OFF_Q2, wt16+OFF_O2, wt16+OFF_POUT, wt16+OFF_K2, wt16+OFF_V2,
                            wt16+OFF_FF1, wt16+OFF_FF2};
        int Ks[12] = {CC,CC,CC,CC,CC,CC,CC,CC, CTXD,CTXD, CC, FFI};
        int Ns[12] = {CC,CC,CC,CC,CC,CC,CC,CC, CC,CC, 2*FFI, CC};
        int acc = 0;
        float qs = rsqrtf((float)DHEAD);
        for (int i = 0; i < 12; i++) {
            td.src[i] = srcs[i]; td.dst[i] = dsts[i];
            td.scl[i] = (i == 1) ? qs : 1.f;
            td.K[i] = Ks[i]; td.N[i] = Ns[i];
            td.start[i] = acc;
            acc += (Ks[i]/32) * (Ns[i]/32);
        }
        td.start[12] = acc;
        transpose_all_kernel<<<acc, 256>>>(td);
    }
    // 0b. context -> fp16 ; vis mask -> bits
    {
        int n = BB*CTX*CTXD;
        f2h_kernel<<<(n + 255)/256, 256>>>(context, ctx16, n);
        maskbits_kernel<<<512, 256>>>(vis_mask, mbits, BB*HWP*(HWP/32));
    }

    // 1. GroupNorm + transpose to [B, HW, C] (fp16)
    groupnorm_kernel<<<BB*32, 256>>>(x, gn_scale, gn_bias, gn16);
    // 2. proj_in
    run_gemm1(gn16, wt16+OFF_PIN, proj_in_b, nullptr, h, nullptr, MROWS, CC, CC, 0);
    // 3. LN1 (fp16 out)
    layernorm_kernel<<<MROWS, CC>>>(h, n1_s, n1_b, ln16);
    // 4. fused q,k,v (self) -> fp16 (q pre-scaled via wq1)
    run_gemm3(ln16, wt16+OFF_Q1, wt16+OFF_K1, wt16+OFF_V1, q, k, v, MROWS, CC, CC, 3, 2);
    // 5. masked self-attention (warp-local flash, pipelined, bitmask)
    {
        dim3 grid(HWP/64, NHEADS, BB);
        self_attn_f16_kernel<<<grid, 128>>>((const __half*)q, (const __half*)k,
                                            (const __half*)v, mbits, ao16);
    }
    // 6. out-proj + residual
    run_gemm1(ao16, wt16+OFF_O1, bo1, h, h, nullptr, MROWS, CC, CC, 0);
    // 7. LN2
    layernorm_kernel<<<MROWS, CC>>>(h, n2_s, n2_b, ln16);
    // 8. q (cross) -> fp32
    run_gemm1(ln16, wt16+OFF_Q2, nullptr, nullptr, q, nullptr, MROWS, CC, CC, 0);
    // 9. fused k,v from context -> fp32
    run_gemm3(ctx16, wt16+OFF_K2, wt16+OFF_V2, nullptr, k, v, nullptr, BB*CTX, CC, CTXD, 2, 0);
    // 10. masked cross-attention (fp16 out)
    {
        dim3 grid(HWP/QT2, NHEADS, BB);
        cross_attn_kernel<<<grid, 256>>>(q, k, v, v2t_mask, ao16);
    }
    // 11. out-proj + residual
    run_gemm1(ao16, wt16+OFF_O2, bo2, h, h, nullptr, MROWS, CC, CC, 0);
    // 12. LN3
    layernorm_kernel<<<MROWS, CC>>>(h, n3_s, n3_b, ln16);
    // 13. FF up (GEGLU input) -> fp16 only
    run_gemm1(ln16, wt16+OFF_FF1, ff_b1, nullptr, ff1, nullptr, MROWS, 2*FFI, CC, 2);
    // 14. GEGLU (fp16 in/out)
    {
        size_t n = (size_t)MROWS*FFI;
        geglu_kernel<<<(unsigned)((n + 255)/256), 256>>>((const __half*)ff1, ffu16);
    }
    // 15. FF down + residual (emit fp16 copy for final proj)
    run_gemm1(ffu16, wt16+OFF_FF2, ff_b2, h, h, h16, MROWS, CC, FFI, 0);
    // 16. proj_out + transpose back to [B,C,H,W] + input residual
    run_gemm1(h16, wt16+OFF_POUT, proj_out_b, x, out, nullptr, MROWS, CC, CC, 1);
}